// round 5
// baseline (speedup 1.0000x reference)
#include <cuda_runtime.h>
#include <cuda_bf16.h>
#include <math.h>
#include <stdint.h>

#define SEQ    2048
#define TOKENS 4096
#define DIM    512
#define HEADS  8
#define HDIM   64
#define RANK   64
#define LAYERS 6
#define VOCAB  32000
#define FFD    2048
#define KTOP   409

typedef unsigned short u16;

// ---------------- fp32 scratch ----------------
__device__ float g_x[TOKENS * DIM];
__device__ float g_qkv[TOKENS * 3 * DIM];
__device__ float g_scores[(size_t)16 * SEQ * SEQ];   // also reused for qk logits
__device__ float g_dense[TOKENS * DIM];
__device__ float g_aproj[TOKENS * DIM];
__device__ float g_Qs[TOKENS * RANK];
__device__ float g_Ks[TOKENS * RANK];
__device__ float g_Vs[TOKENS * DIM];
__device__ float g_sparse[TOKENS * DIM];
__device__ float g_ffh[TOKENS * FFD];
__device__ float g_fft[TOKENS * DIM];

// ---------------- bf16 hi/lo planes (activations) ----------------
__device__ alignas(16) u16 g_xh[TOKENS * DIM],       g_xl[TOKENS * DIM];
__device__ alignas(16) u16 g_qkvh[TOKENS * 3 * DIM], g_qkvl[TOKENS * 3 * DIM];
__device__ alignas(16) u16 g_Ph[(size_t)16 * SEQ * SEQ], g_Pl[(size_t)16 * SEQ * SEQ];
__device__ alignas(16) u16 g_dh[TOKENS * DIM],       g_dl[TOKENS * DIM];
__device__ alignas(16) u16 g_fh[TOKENS * FFD],       g_fl[TOKENS * FFD];
__device__ alignas(16) u16 g_vth[16 * HDIM * SEQ],   g_vtl[16 * HDIM * SEQ];
__device__ alignas(16) u16 g_qsh[TOKENS * RANK],     g_qsl[TOKENS * RANK];
__device__ alignas(16) u16 g_ksh[TOKENS * RANK],     g_ksl[TOKENS * RANK];
__device__ alignas(16) u16 g_sph[(size_t)2 * SEQ * SEQ], g_spl[(size_t)2 * SEQ * SEQ];
__device__ alignas(16) u16 g_vsth[2 * DIM * SEQ],    g_vstl[2 * DIM * SEQ];

// ---------------- bf16 hi/lo planes (weights) ----------------
__device__ alignas(16) u16 g_inwh[LAYERS * 3 * DIM * DIM], g_inwl[LAYERS * 3 * DIM * DIM];
__device__ alignas(16) u16 g_outwh[LAYERS * DIM * DIM],    g_outwl[LAYERS * DIM * DIM];
__device__ alignas(16) u16 g_qpwh[LAYERS * RANK * DIM],    g_qpwl[LAYERS * RANK * DIM];
__device__ alignas(16) u16 g_kpwh[LAYERS * RANK * DIM],    g_kpwl[LAYERS * RANK * DIM];
__device__ alignas(16) u16 g_vpwh[LAYERS * DIM * DIM],     g_vpwl[LAYERS * DIM * DIM];
__device__ alignas(16) u16 g_f1wh[LAYERS * FFD * DIM],     g_f1wl[LAYERS * FFD * DIM];
__device__ alignas(16) u16 g_f2wh[LAYERS * DIM * FFD],     g_f2wl[LAYERS * DIM * FFD];
__device__ alignas(16) u16 g_finwh[VOCAB * DIM],           g_finwl[VOCAB * DIM];

// ---------------- small device helpers ----------------
__device__ __forceinline__ void fsplit(float x, u16& h, u16& l)
{
    __nv_bfloat16 bh = __float2bfloat16_rn(x);
    float fh = __bfloat162float(bh);
    __nv_bfloat16 bl = __float2bfloat16_rn(x - fh);
    h = *reinterpret_cast<u16*>(&bh);
    l = *reinterpret_cast<u16*>(&bl);
}

__device__ __forceinline__ uint32_t smem_u32(const void* p)
{
    uint32_t a;
    asm("{ .reg .u64 t; cvta.to.shared.u64 t, %1; cvt.u32.u64 %0, t; }" : "=r"(a) : "l"(p));
    return a;
}

__device__ __forceinline__ void cpa16(uint32_t dst, const void* src)
{
    asm volatile("cp.async.cg.shared.global [%0], [%1], 16;" :: "r"(dst), "l"(src) : "memory");
}

__device__ __forceinline__ void ldsm4(uint32_t* r, uint32_t addr)
{
    asm volatile("ldmatrix.sync.aligned.m8n8.x4.shared.b16 {%0,%1,%2,%3}, [%4];"
                 : "=r"(r[0]), "=r"(r[1]), "=r"(r[2]), "=r"(r[3]) : "r"(addr));
}

__device__ __forceinline__ void mma16816(float* c, const uint32_t* a, uint32_t b0, uint32_t b1)
{
    asm volatile(
        "mma.sync.aligned.m16n8k16.row.col.f32.bf16.bf16.f32 "
        "{%0,%1,%2,%3}, {%4,%5,%6,%7}, {%8,%9}, {%0,%1,%2,%3};"
        : "+f"(c[0]), "+f"(c[1]), "+f"(c[2]), "+f"(c[3])
        : "r"(a[0]), "r"(a[1]), "r"(a[2]), "r"(a[3]), "r"(b0), "r"(b1));
}

// ---------------- HMMA bf16x3 GEMM: C = alpha * (A @ B^T) + bias ----------------
template <int TN>
__global__ void __launch_bounds__(256)
mm_gemm(const u16* __restrict__ Ah, const u16* __restrict__ Al,
        const u16* __restrict__ Bh, const u16* __restrict__ Bl,
        const float* __restrict__ bias, float* __restrict__ C,
        u16* __restrict__ Ch, u16* __restrict__ Cl,
        int K, int lda, int ldb, int ldc,
        long sAo, long sAi, long sBo, long sBi, long sCo, long sCi,
        int zdiv, float alpha, int relu)
{
    constexpr int MI  = (TN == 128) ? 4 : 2;
    constexpr int APB = 128 * 80;
    constexpr int BPB = TN * 80;
    constexpr int STAGE = 2 * APB + 2 * BPB;

    extern __shared__ char smem[];
    const uint32_t su = smem_u32(smem);
    const int tid = threadIdx.x;
    const int wid = tid >> 5;
    const int lane = tid & 31;

    int z = blockIdx.z;
    int zo = z / zdiv, zi = z - zo * zdiv;
    long ao = (long)zo * sAo + (long)zi * sAi;
    long bo = (long)zo * sBo + (long)zi * sBi;
    long co = (long)zo * sCo + (long)zi * sCi;
    Ah += ao; Al += ao; Bh += bo; Bl += bo; C += co;
    if (Ch) { Ch += co; Cl += co; }
    const int m0 = blockIdx.y * 128;
    const int n0 = blockIdx.x * TN;

    const int wmBase = (TN == 128) ? (wid & 1) * 64 : (wid & 3) * 32;
    const int wnBase = (TN == 128) ? (wid >> 1) * 32 : (wid >> 2) * 32;

    float acc[MI][4][4];
#pragma unroll
    for (int mi = 0; mi < MI; mi++)
#pragma unroll
        for (int n8 = 0; n8 < 4; n8++)
#pragma unroll
            for (int q = 0; q < 4; q++) acc[mi][n8][q] = 0.f;

    const int nch = K >> 5;
    const int ar = tid >> 2, ac = tid & 3;
    auto issue = [&](int i) {
        int s = i & 1;
        int k0 = i << 5;
        uint32_t st = su + s * STAGE;
#pragma unroll
        for (int j = 0; j < 2; j++) {
            int r = ar + 64 * j;
            long g = (long)(m0 + r) * lda + k0 + ac * 8;
            uint32_t d = st + r * 80 + ac * 16;
            cpa16(d, Ah + g);
            cpa16(d + APB, Al + g);
        }
#pragma unroll
        for (int j = 0; j < TN / 64; j++) {
            int r = ar + 64 * j;
            long g = (long)(n0 + r) * ldb + k0 + ac * 8;
            uint32_t d = st + 2 * APB + r * 80 + ac * 16;
            cpa16(d, Bh + g);
            cpa16(d + BPB, Bl + g);
        }
        asm volatile("cp.async.commit_group;" ::: "memory");
    };

    issue(0);
    const uint32_t lrow = lane & 15;
    const uint32_t lcol = (lane >> 4) * 16;

    for (int i = 0; i < nch; i++) {
        if (i + 1 < nch) {
            issue(i + 1);
            asm volatile("cp.async.wait_group 1;" ::: "memory");
        } else {
            asm volatile("cp.async.wait_group 0;" ::: "memory");
        }
        __syncthreads();

        int s = i & 1;
        uint32_t aH = su + s * STAGE;
        uint32_t aL = aH + APB;
        uint32_t bH = aH + 2 * APB;
        uint32_t bL = bH + BPB;

#pragma unroll
        for (int ks = 0; ks < 2; ks++) {
            uint32_t a[MI][4], bh[2][4], bl[2][4];
            uint32_t kb = ks * 32 + lcol;
#pragma unroll
            for (int mi = 0; mi < MI; mi++)
                ldsm4(a[mi], aH + (wmBase + mi * 16 + lrow) * 80 + kb);
#pragma unroll
            for (int ni = 0; ni < 2; ni++)
                ldsm4(bh[ni], bH + (wnBase + ni * 16 + lrow) * 80 + kb);
#pragma unroll
            for (int mi = 0; mi < MI; mi++)
#pragma unroll
                for (int ni = 0; ni < 2; ni++) {
                    mma16816(acc[mi][2 * ni],     a[mi], bh[ni][0], bh[ni][2]);
                    mma16816(acc[mi][2 * ni + 1], a[mi], bh[ni][1], bh[ni][3]);
                }
#pragma unroll
            for (int ni = 0; ni < 2; ni++)
                ldsm4(bl[ni], bL + (wnBase + ni * 16 + lrow) * 80 + kb);
#pragma unroll
            for (int mi = 0; mi < MI; mi++)
#pragma unroll
                for (int ni = 0; ni < 2; ni++) {
                    mma16816(acc[mi][2 * ni],     a[mi], bl[ni][0], bl[ni][2]);
                    mma16816(acc[mi][2 * ni + 1], a[mi], bl[ni][1], bl[ni][3]);
                }
#pragma unroll
            for (int mi = 0; mi < MI; mi++)
                ldsm4(a[mi], aL + (wmBase + mi * 16 + lrow) * 80 + kb);
#pragma unroll
            for (int mi = 0; mi < MI; mi++)
#pragma unroll
                for (int ni = 0; ni < 2; ni++) {
                    mma16816(acc[mi][2 * ni],     a[mi], bh[ni][0], bh[ni][2]);
                    mma16816(acc[mi][2 * ni + 1], a[mi], bh[ni][1], bh[ni][3]);
                }
        }
        __syncthreads();
    }

#pragma unroll
    for (int mi = 0; mi < MI; mi++) {
        int r0 = m0 + wmBase + mi * 16 + (lane >> 2);
#pragma unroll
        for (int n8 = 0; n8 < 4; n8++) {
            int c = n0 + wnBase + n8 * 8 + (lane & 3) * 2;
            float2 o0, o1;
            o0.x = acc[mi][n8][0] * alpha; o0.y = acc[mi][n8][1] * alpha;
            o1.x = acc[mi][n8][2] * alpha; o1.y = acc[mi][n8][3] * alpha;
            if (bias) {
                float b0 = bias[c], b1 = bias[c + 1];
                o0.x += b0; o0.y += b1; o1.x += b0; o1.y += b1;
            }
            if (relu) {
                o0.x = fmaxf(o0.x, 0.f); o0.y = fmaxf(o0.y, 0.f);
                o1.x = fmaxf(o1.x, 0.f); o1.y = fmaxf(o1.y, 0.f);
            }
            long off0 = (long)r0 * ldc + c;
            long off1 = off0 + (long)8 * ldc;
            *(float2*)(C + off0) = o0;
            *(float2*)(C + off1) = o1;
            if (Ch) {
                ushort2 hh, ll;
                fsplit(o0.x, hh.x, ll.x); fsplit(o0.y, hh.y, ll.y);
                *(ushort2*)(Ch + off0) = hh; *(ushort2*)(Cl + off0) = ll;
                fsplit(o1.x, hh.x, ll.x); fsplit(o1.y, hh.y, ll.y);
                *(ushort2*)(Ch + off1) = hh; *(ushort2*)(Cl + off1) = ll;
            }
        }
    }
}

// ---------------- converters ----------------
__global__ void cvt_k(const float4* __restrict__ s, ushort4* __restrict__ h,
                      ushort4* __restrict__ l, int n4)
{
    int i = blockIdx.x * 256 + threadIdx.x;
    if (i >= n4) return;
    float4 v = s[i];
    ushort4 hh, ll;
    fsplit(v.x, hh.x, ll.x); fsplit(v.y, hh.y, ll.y);
    fsplit(v.z, hh.z, ll.z); fsplit(v.w, hh.w, ll.w);
    h[i] = hh; l[i] = ll;
}

// V^T planes from qkv fp32 (dense path)
__global__ void vt_k(const float* __restrict__ qkv, u16* __restrict__ vh, u16* __restrict__ vl)
{
    int s = blockIdx.x * 256 + threadIdx.x;
    int d = blockIdx.y;
    int z = blockIdx.z;
    int b = z >> 3, h = z & 7;
    float v = qkv[((long)(b * SEQ + s)) * (3 * DIM) + 2 * DIM + h * HDIM + d];
    long o = ((long)z * HDIM + d) * SEQ + s;
    fsplit(v, vh[o], vl[o]);
}

// Vs^T planes (sparse path): vst[b][d][s] = vs[(b*SEQ+s)][d]
__global__ void vst_k(const float* __restrict__ vs, u16* __restrict__ vh, u16* __restrict__ vl)
{
    int s = blockIdx.x * 256 + threadIdx.x;
    int d = blockIdx.y;
    int b = blockIdx.z;
    float v = vs[((long)(b * SEQ + s)) * DIM + d];
    long o = ((long)(b * DIM + d)) * SEQ + s;
    fsplit(v, vh[o], vl[o]);
}

// ---------------- embedding (+ x planes) ----------------
__global__ void embed_k(const int* __restrict__ src, const float* __restrict__ emb,
                        const float* __restrict__ pe, float* __restrict__ x,
                        u16* __restrict__ xh, u16* __restrict__ xl)
{
    int t = blockIdx.x;
    int tid = threadIdx.x;
    int s = t & (SEQ - 1);
    int tok = src[t];
    int d = tid * 2;
    float2 e = *(const float2*)(emb + (long)tok * DIM + d);
    float2 p = *(const float2*)(pe + (long)s * DIM + d);
    float2 o;
    o.x = e.x * 22.627416998f + p.x;
    o.y = e.y * 22.627416998f + p.y;
    long off = (long)t * DIM + d;
    *(float2*)(x + off) = o;
    ushort2 hh, ll;
    fsplit(o.x, hh.x, ll.x); fsplit(o.y, hh.y, ll.y);
    *(ushort2*)(xh + off) = hh;
    *(ushort2*)(xl + off) = ll;
}

// ---------------- row softmax -> P hi/lo planes ----------------
__global__ void softmax_rows(const float* __restrict__ S, u16* __restrict__ Ph,
                             u16* __restrict__ Pl)
{
    __shared__ float red[256];
    long row = blockIdx.x;
    const float* p = S + row * (long)SEQ;
    int tid = threadIdx.x;
    float4 v0 = *(const float4*)(p + 4 * tid);
    float4 v1 = *(const float4*)(p + 4 * tid + 1024);
    float m = fmaxf(fmaxf(fmaxf(v0.x, v0.y), fmaxf(v0.z, v0.w)),
                    fmaxf(fmaxf(v1.x, v1.y), fmaxf(v1.z, v1.w)));
    red[tid] = m; __syncthreads();
    for (int s = 128; s > 0; s >>= 1) { if (tid < s) red[tid] = fmaxf(red[tid], red[tid + s]); __syncthreads(); }
    float M = red[0]; __syncthreads();
    v0.x = __expf(v0.x - M); v0.y = __expf(v0.y - M); v0.z = __expf(v0.z - M); v0.w = __expf(v0.w - M);
    v1.x = __expf(v1.x - M); v1.y = __expf(v1.y - M); v1.z = __expf(v1.z - M); v1.w = __expf(v1.w - M);
    float sum = v0.x + v0.y + v0.z + v0.w + v1.x + v1.y + v1.z + v1.w;
    red[tid] = sum; __syncthreads();
    for (int s = 128; s > 0; s >>= 1) { if (tid < s) red[tid] += red[tid + s]; __syncthreads(); }
    float inv = 1.f / red[0];
    v0.x *= inv; v0.y *= inv; v0.z *= inv; v0.w *= inv;
    v1.x *= inv; v1.y *= inv; v1.z *= inv; v1.w *= inv;
    long b0 = row * (long)SEQ + 4 * tid;
    ushort4 hh, ll;
    fsplit(v0.x, hh.x, ll.x); fsplit(v0.y, hh.y, ll.y);
    fsplit(v0.z, hh.z, ll.z); fsplit(v0.w, hh.w, ll.w);
    *(ushort4*)(Ph + b0) = hh; *(ushort4*)(Pl + b0) = ll;
    fsplit(v1.x, hh.x, ll.x); fsplit(v1.y, hh.y, ll.y);
    fsplit(v1.z, hh.z, ll.z); fsplit(v1.w, hh.w, ll.w);
    *(ushort4*)(Ph + b0 + 1024) = hh; *(ushort4*)(Pl + b0 + 1024) = ll;
}

// ---------------- sparse select: exact top-409 radix select -> dense weight planes ----------------
__device__ __forceinline__ unsigned f2k(float f)
{
    unsigned u = __float_as_uint(f);
    return (u & 0x80000000u) ? ~u : (u | 0x80000000u);
}

__global__ void __launch_bounds__(256) sparse_sel(
    const float* __restrict__ qk, u16* __restrict__ sph, u16* __restrict__ spl)
{
    __shared__ float logit[SEQ];
    __shared__ unsigned hist[256];
    __shared__ unsigned suf[256];
    __shared__ float red[256];
    __shared__ unsigned sh_prefix;
    __shared__ int sh_remaining;

    long row = blockIdx.x;
    int tid = threadIdx.x;
    const float* p = qk + row * (long)SEQ;

    for (int k = tid; k < SEQ; k += 256) logit[k] = p[k];
    __syncthreads();

    // row max
    float lm = -3.4e38f;
    for (int k = tid; k < SEQ; k += 256) lm = fmaxf(lm, logit[k]);
    red[tid] = lm; __syncthreads();
    for (int s = 128; s > 0; s >>= 1) { if (tid < s) red[tid] = fmaxf(red[tid], red[tid + s]); __syncthreads(); }
    float Lmax = red[0]; __syncthreads();

    // full partition function Z (for the reference's +1e-9 term)
    float zacc = 0.f;
    for (int k = tid; k < SEQ; k += 256) zacc += __expf(logit[k] - Lmax);
    red[tid] = zacc; __syncthreads();
    for (int s = 128; s > 0; s >>= 1) { if (tid < s) red[tid] += red[tid + s]; __syncthreads(); }
    float Z = red[0]; __syncthreads();

    // exact 409th-largest via 4x8-bit MSB radix select
    unsigned prefix = 0; int remaining = KTOP;
    for (int shift = 24; shift >= 0; shift -= 8) {
        hist[tid] = 0; __syncthreads();
        unsigned upmask = (shift == 24) ? 0u : (0xFFFFFFFFu << (shift + 8));
        for (int k = tid; k < SEQ; k += 256) {
            unsigned key = f2k(logit[k]);
            if ((key & upmask) == prefix)
                atomicAdd(&hist[(key >> shift) & 255], 1u);
        }
        __syncthreads();
        suf[tid] = hist[tid]; __syncthreads();
        for (int off = 1; off < 256; off <<= 1) {
            unsigned add = (tid + off < 256) ? suf[tid + off] : 0u;
            __syncthreads();
            suf[tid] += add;
            __syncthreads();
        }
        unsigned shere = suf[tid];
        unsigned snext = (tid < 255) ? suf[tid + 1] : 0u;
        if (shere >= (unsigned)remaining && snext < (unsigned)remaining) {
            sh_prefix = prefix | ((unsigned)tid << shift);
            sh_remaining = remaining - (int)snext;
        }
        __syncthreads();
        prefix = sh_prefix; remaining = sh_remaining;
        __syncthreads();
    }
    unsigned thr = prefix;

    // kept-weight sum
    float w8[8];
    float dsum = 0.f;
#pragma unroll
    for (int j = 0; j < 8; j++) {
        int k = tid + 256 * j;
        float l = logit[k];
        bool keep = (f2k(l) >= thr);
        float w = keep ? __expf(l - Lmax) : 0.f;
        w8[j] = w;
        dsum += w;
    }
    red[tid] = dsum; __syncthreads();
    for (int s = 128; s > 0; s >>= 1) { if (tid < s) red[tid] += red[tid + s]; __syncthreads(); }
    float inv = 1.f / (red[0] + 1e-9f * Z);

    // write dense renormalized weight row as hi/lo planes
#pragma unroll
    for (int j = 0; j < 8; j++) {
        int k = tid + 256 * j;
        float w = w8[j] * inv;
        u16 h, l;
        fsplit(w, h, l);
        long o = row * (long)SEQ + k;
        sph[o] = h; spl[o] = l;
    }
}

// ---------------- gated fusion + LN1 (overwrites x, emits x planes) ----------------
__global__ void fuse_ln1_k(float* __restrict__ x, const float* __restrict__ dn,
                           const float* __restrict__ sp, const float* __restrict__ lam,
                           int layer, const float* __restrict__ gam, const float* __restrict__ bet,
                           u16* __restrict__ xh, u16* __restrict__ xl)
{
    __shared__ float red[256];
    int row = blockIdx.x, tid = threadIdx.x;
    long off = (long)row * DIM + 2 * tid;
    float g = 1.f / (1.f + expf(-lam[layer]));
    float2 xv = *(const float2*)(x + off);
    float2 dv = *(const float2*)(dn + off);
    float2 sv = *(const float2*)(sp + off);
    float y0 = xv.x + g * dv.x + (1.f - g) * sv.x;
    float y1 = xv.y + g * dv.y + (1.f - g) * sv.y;
    red[tid] = y0 + y1; __syncthreads();
    for (int s = 128; s > 0; s >>= 1) { if (tid < s) red[tid] += red[tid + s]; __syncthreads(); }
    float mean = red[0] * (1.f / DIM); __syncthreads();
    float d0 = y0 - mean, d1 = y1 - mean;
    red[tid] = d0 * d0 + d1 * d1; __syncthreads();
    for (int s = 128; s > 0; s >>= 1) { if (tid < s) red[tid] += red[tid + s]; __syncthreads(); }
    float inv = 1.f / sqrtf(red[0] * (1.f / DIM) + 1e-5f);
    int dc = 2 * tid;
    float2 gm = *(const float2*)(gam + dc);
    float2 bt = *(const float2*)(bet + dc);
    float2 o; o.x = d0 * inv * gm.x + bt.x; o.y = d1 * inv * gm.y + bt.y;
    *(float2*)(x + off) = o;
    ushort2 hh, ll;
    fsplit(o.x, hh.x, ll.x); fsplit(o.y, hh.y, ll.y);
    *(ushort2*)(xh + off) = hh;
    *(ushort2*)(xl + off) = ll;
}

// ---------------- residual + LN2 (overwrites x, emits x planes) ----------------
__global__ void add_ln2_k(float* __restrict__ x, const float* __restrict__ f,
                          const float* __restrict__ gam, const float* __restrict__ bet,
                          u16* __restrict__ xh, u16* __restrict__ xl)
{
    __shared__ float red[256];
    int row = blockIdx.x, tid = threadIdx.x;
    long off = (long)row * DIM + 2 * tid;
    float2 xv = *(const float2*)(x + off);
    float2 fv = *(const float2*)(f + off);
    float y0 = xv.x + fv.x;
    float y1 = xv.y + fv.y;
    red[tid] = y0 + y1; __syncthreads();
    for (int s = 128; s > 0; s >>= 1) { if (tid < s) red[tid] += red[tid + s]; __syncthreads(); }
    float mean = red[0] * (1.f / DIM); __syncthreads();
    float d0 = y0 - mean, d1 = y1 - mean;
    red[tid] = d0 * d0 + d1 * d1; __syncthreads();
    for (int s = 128; s > 0; s >>= 1) { if (tid < s) red[tid] += red[tid + s]; __syncthreads(); }
    float inv = 1.f / sqrtf(red[0] * (1.f / DIM) + 1e-5f);
    int dc = 2 * tid;
    float2 gm = *(const float2*)(gam + dc);
    float2 bt = *(const float2*)(bet + dc);
    float2 o; o.x = d0 * inv * gm.x + bt.x; o.y = d1 * inv * gm.y + bt.y;
    *(float2*)(x + off) = o;
    ushort2 hh, ll;
    fsplit(o.x, hh.x, ll.x); fsplit(o.y, hh.y, ll.y);
    *(ushort2*)(xh + off) = hh;
    *(ushort2*)(xl + off) = ll;
}

// ---------------- host-side helpers ----------------
template <int TN>
static void launch_tc(const u16* Ah, const u16* Al, const u16* Bh, const u16* Bl,
                      const float* bias, float* C, u16* Ch, u16* Cl,
                      int M, int N, int K, int lda, int ldb, int ldc,
                      int Z = 1, long sAo = 0, long sAi = 0, long sBo = 0, long sBi = 0,
                      long sCo = 0, long sCi = 0, int zdiv = 1,
                      float alpha = 1.f, int relu = 0)
{
    constexpr int SM = 2 * (2 * 128 * 80 + 2 * TN * 80);
    static bool attr_set = false;
    if (!attr_set) {
        cudaFuncSetAttribute(mm_gemm<TN>, cudaFuncAttributeMaxDynamicSharedMemorySize, SM);
        attr_set = true;
    }
    dim3 g(N / TN, M / 128, Z);
    mm_gemm<TN><<<g, 256, SM>>>(Ah, Al, Bh, Bl, bias, C, Ch, Cl,
                                K, lda, ldb, ldc,
                                sAo, sAi, sBo, sBi, sCo, sCi, zdiv, alpha, relu);
}

static void cvt(const float* s, u16* h, u16* l, long n)
{
    long n4 = n >> 2;
    cvt_k<<<(unsigned)((n4 + 255) / 256), 256>>>((const float4*)s, (ushort4*)h, (ushort4*)l, (int)n4);
}

extern "C" void kernel_launch(void* const* d_in, const int* in_sizes, int n_in,
                              void* d_out, int out_size)
{
    const int*   SRC   = (const int*)  d_in[0];
    const float* EMB   = (const float*)d_in[1];
    const float* PE    = (const float*)d_in[2];
    const float* IN_W  = (const float*)d_in[3];
    const float* IN_B  = (const float*)d_in[4];
    const float* OUT_W = (const float*)d_in[5];
    const float* OUT_B = (const float*)d_in[6];
    const float* QP_W  = (const float*)d_in[7];
    const float* QP_B  = (const float*)d_in[8];
    const float* KP_W  = (const float*)d_in[9];
    const float* KP_B  = (const float*)d_in[10];
    const float* VP_W  = (const float*)d_in[11];
    const float* VP_B  = (const float*)d_in[12];
    const float* LAM   = (const float*)d_in[13];
    const float* FF1_W = (const float*)d_in[14];
    const float* FF1_B = (const float*)d_in[15];
    const float* FF2_W = (const float*)d_in[16];
    const float* FF2_B = (const float*)d_in[17];
    const float* LN1S  = (const float*)d_in[18];
    const float* LN1B  = (const float*)d_in[19];
    const float* LN2S  = (const float*)d_in[20];
    const float* LN2B  = (const float*)d_in[21];
    const float* FIN_W = (const float*)d_in[22];
    const float* FIN_B = (const float*)d_in[23];
    float* OUT = (float*)d_out;

    float *x, *qkv, *scores, *dense, *aproj, *qs, *ks, *vs, *sp, *ffh, *fft;
    cudaGetSymbolAddress((void**)&x, g_x);         cudaGetSymbolAddress((void**)&qkv, g_qkv);
    cudaGetSymbolAddress((void**)&scores, g_scores); cudaGetSymbolAddress((void**)&dense, g_dense);
    cudaGetSymbolAddress((void**)&aproj, g_aproj); cudaGetSymbolAddress((void**)&qs, g_Qs);
    cudaGetSymbolAddress((void**)&ks, g_Ks);       cudaGetSymbolAddress((void**)&vs, g_Vs);
    cudaGetSymbolAddress((void**)&sp, g_sparse);   cudaGetSymbolAddress((void**)&ffh, g_ffh);
    cudaGetSymbolAddress((void**)&fft, g_fft);

    u16 *xh, *xl, *qkvh, *qkvl, *Ph, *Pl, *dh, *dl, *fh, *fl, *vth, *vtl;
    u16 *qsh, *qsl, *ksh, *ksl, *sph, *spl, *vsth, *vstl;
    cudaGetSymbolAddress((void**)&xh, g_xh);   cudaGetSymbolAddress((void**)&xl, g_xl);
    cudaGetSymbolAddress((void**)&qkvh, g_qkvh); cudaGetSymbolAddress((void**)&qkvl, g_qkvl);
    cudaGetSymbolAddress((void**)&Ph, g_Ph);   cudaGetSymbolAddress((void**)&Pl, g_Pl);
    cudaGetSymbolAddress((void**)&dh, g_dh);   cudaGetSymbolAddress((void**)&dl, g_dl);
    cudaGetSymbolAddress((void**)&fh, g_fh);   cudaGetSymbolAddress((void**)&fl, g_fl);
    cudaGetSymbolAddress((void**)&vth, g_vth); cudaGetSymbolAddress((void**)&vtl, g_vtl);
    cudaGetSymbolAddress((void**)&qsh, g_qsh); cudaGetSymbolAddress((void**)&qsl, g_qsl);
    cudaGetSymbolAddress((void**)&ksh, g_ksh); cudaGetSymbolAddress((void**)&ksl, g_ksl);
    cudaGetSymbolAddress((void**)&sph, g_sph); cudaGetSymbolAddress((void**)&spl, g_spl);
    cudaGetSymbolAddress((void**)&vsth, g_vsth); cudaGetSymbolAddress((void**)&vstl, g_vstl);

    u16 *inwh, *inwl, *outwh, *outwl, *qpwh, *qpwl, *kpwh, *kpwl, *vpwh, *vpwl;
    u16 *f1wh, *f1wl, *f2wh, *f2wl, *finwh, *finwl;
    cudaGetSymbolAddress((void**)&inwh, g_inwh);   cudaGetSymbolAddress((void**)&inwl, g_inwl);
    cudaGetSymbolAddress((void**)&outwh, g_outwh); cudaGetSymbolAddress((void**)&outwl, g_outwl);
    cudaGetSymbolAddress((void**)&qpwh, g_qpwh);   cudaGetSymbolAddress((void**)&qpwl, g_qpwl);
    cudaGetSymbolAddress((void**)&kpwh, g_kpwh);   cudaGetSymbolAddress((void**)&kpwl, g_kpwl);
    cudaGetSymbolAddress((void**)&vpwh, g_vpwh);   cudaGetSymbolAddress((void**)&vpwl, g_vpwl);
    cudaGetSymbolAddress((void**)&f1wh, g_f1wh);   cudaGetSymbolAddress((void**)&f1wl, g_f1wl);
    cudaGetSymbolAddress((void**)&f2wh, g_f2wh);   cudaGetSymbolAddress((void**)&f2wl, g_f2wl);
    cudaGetSymbolAddress((void**)&finwh, g_finwh); cudaGetSymbolAddress((void**)&finwl, g_finwl);

    // convert all weights once
    cvt(IN_W,  inwh,  inwl,  (long)LAYERS * 3 * DIM * DIM);
    cvt(OUT_W, outwh, outwl, (long)LAYERS * DIM * DIM);
    cvt(QP_W,  qpwh,  qpwl,  (long)LAYERS * RANK * DIM);
    cvt(KP_W,  kpwh,  kpwl,  (long)LAYERS * RANK * DIM);
    cvt(VP_W,  vpwh,  vpwl,  (long)LAYERS * DIM * DIM);
    cvt(FF1_W, f1wh,  f1wl,  (long)LAYERS * FFD * DIM);
    cvt(FF2_W, f2wh,  f2wl,  (long)LAYERS * DIM * FFD);
    cvt(FIN_W, finwh, finwl, (long)VOCAB * DIM);

    embed_k<<<TOKENS, 256>>>(SRC, EMB, PE, x, xh, xl);

    for (int l = 0; l < LAYERS; l++) {
        long wq  = (long)l * 3 * DIM * DIM;
        long wo  = (long)l * DIM * DIM;
        long wp  = (long)l * RANK * DIM;
        long wf1 = (long)l * FFD * DIM;
        long wf2 = (long)l * DIM * FFD;

        // qkv = x @ in_w^T + in_b  (fp32 + bf16 planes)
        launch_tc<128>(xh, xl, inwh + wq, inwl + wq, IN_B + (long)l * 3 * DIM,
                       qkv, qkvh, qkvl, TOKENS, 3 * DIM, DIM, DIM, DIM, 3 * DIM);

        // dense scores = Q @ K^T / 8 per (b,h)
        launch_tc<128>(qkvh, qkvl, qkvh + DIM, qkvl + DIM, nullptr,
                       scores, nullptr, nullptr,
                       SEQ, SEQ, HDIM, 3 * DIM, 3 * DIM, SEQ,
                       16, (long)SEQ * 3 * DIM, (long)HDIM,
                       (long)SEQ * 3 * DIM, (long)HDIM,
                       (long)HEADS * SEQ * SEQ, (long)SEQ * SEQ,
                       HEADS, 0.125f, 0);

        // softmax -> P hi/lo planes (frees scores buffer)
        softmax_rows<<<16 * SEQ, 256>>>(scores, Ph, Pl);

        // V^T planes (dense)
        vt_k<<<dim3(SEQ / 256, HDIM, 16), 256>>>(qkv, vth, vtl);

        // dense = P @ V per (b,h)
        launch_tc<64>(Ph, Pl, vth, vtl, nullptr, dense, dh, dl,
                      SEQ, HDIM, SEQ, SEQ, SEQ, DIM,
                      16, (long)HEADS * SEQ * SEQ, (long)SEQ * SEQ,
                      (long)HEADS * HDIM * SEQ, (long)HDIM * SEQ,
                      (long)SEQ * DIM, (long)HDIM,
                      HEADS, 1.f, 0);

        // dense projection
        launch_tc<128>(dh, dl, outwh + wo, outwl + wo, OUT_B + (long)l * DIM,
                       aproj, nullptr, nullptr, TOKENS, DIM, DIM, DIM, DIM, DIM);

        // low-rank projections (with plane outputs for Qs/Ks)
        launch_tc<64>(xh, xl, qpwh + wp, qpwl + wp, QP_B + (long)l * RANK,
                      qs, qsh, qsl, TOKENS, RANK, DIM, DIM, DIM, RANK);
        launch_tc<64>(xh, xl, kpwh + wp, kpwl + wp, KP_B + (long)l * RANK,
                      ks, ksh, ksl, TOKENS, RANK, DIM, DIM, DIM, RANK);
        launch_tc<128>(xh, xl, vpwh + wo, vpwl + wo, VP_B + (long)l * DIM,
                       vs, nullptr, nullptr, TOKENS, DIM, DIM, DIM, DIM, DIM);

        // Vs^T planes (sparse)
        vst_k<<<dim3(SEQ / 256, DIM, 2), 256>>>(vs, vsth, vstl);

        // low-rank logits qk = Qs @ Ks^T / sqrt(R)  per batch (reuse scores buffer)
        launch_tc<128>(qsh, qsl, ksh, ksl, nullptr, scores, nullptr, nullptr,
                       SEQ, SEQ, RANK, RANK, RANK, SEQ,
                       2, (long)SEQ * RANK, 0, (long)SEQ * RANK, 0,
                       (long)SEQ * SEQ, 0, 1, 0.125f, 0);

        // exact top-409 select -> dense renormalized weight planes
        sparse_sel<<<TOKENS, 256>>>(scores, sph, spl);

        // sparse = sp @ Vs  per batch (GEMM over dense sparse-weight planes)
        launch_tc<128>(sph, spl, vsth, vstl, nullptr, sp, nullptr, nullptr,
                       SEQ, DIM, SEQ, SEQ, SEQ, DIM,
                       2, (long)SEQ * SEQ, 0, (long)DIM * SEQ, 0,
                       (long)SEQ * DIM, 0, 1, 1.f, 0);

        // gated fusion + LN1
        fuse_ln1_k<<<TOKENS, 256>>>(x, aproj, sp, LAM, l,
                                    LN1S + (long)l * DIM, LN1B + (long)l * DIM, xh, xl);

        // FFN
        launch_tc<128>(xh, xl, f1wh + wf1, f1wl + wf1, FF1_B + (long)l * FFD,
                       ffh, fh, fl, TOKENS, FFD, DIM, DIM, DIM, FFD,
                       1, 0, 0, 0, 0, 0, 0, 1, 1.f, 1);
        launch_tc<128>(fh, fl, f2wh + wf2, f2wl + wf2, FF2_B + (long)l * DIM,
                       fft, nullptr, nullptr, TOKENS, DIM, FFD, FFD, FFD, DIM);

        add_ln2_k<<<TOKENS, 256>>>(x, fft, LN2S + (long)l * DIM, LN2B + (long)l * DIM, xh, xl);
    }

    // final vocab projection
    launch_tc<128>(xh, xl, finwh, finwl, FIN_B, OUT, nullptr, nullptr,
                   TOKENS, VOCAB, DIM, DIM, DIM, VOCAB);
}

// round 6
// speedup vs baseline: 1.4443x; 1.4443x over previous
#include <cuda_runtime.h>
#include <cuda_bf16.h>
#include <math.h>
#include <stdint.h>

#define SEQ    2048
#define TOKENS 4096
#define DIM    512
#define HEADS  8
#define HDIM   64
#define RANK   64
#define LAYERS 6
#define VOCAB  32000
#define FFD    2048
#define KTOP   409

typedef unsigned short u16;

// ---------------- fp32 scratch ----------------
__device__ float g_x[TOKENS * DIM];
__device__ float g_qkv[TOKENS * 3 * DIM];
__device__ float g_scores[(size_t)16 * SEQ * SEQ];   // also reused for qk logits
__device__ float g_dense[TOKENS * DIM];
__device__ float g_aproj[TOKENS * DIM];
__device__ float g_Qs[TOKENS * RANK];
__device__ float g_Ks[TOKENS * RANK];
__device__ float g_Vs[TOKENS * DIM];
__device__ float g_sparse[TOKENS * DIM];
__device__ float g_ffh[TOKENS * FFD];
__device__ float g_fft[TOKENS * DIM];

// ---------------- bf16 hi/lo planes (activations) ----------------
__device__ alignas(16) u16 g_xh[TOKENS * DIM],       g_xl[TOKENS * DIM];
__device__ alignas(16) u16 g_qkvh[TOKENS * 3 * DIM], g_qkvl[TOKENS * 3 * DIM];
__device__ alignas(16) u16 g_Ph[(size_t)16 * SEQ * SEQ], g_Pl[(size_t)16 * SEQ * SEQ];
__device__ alignas(16) u16 g_dh[TOKENS * DIM],       g_dl[TOKENS * DIM];
__device__ alignas(16) u16 g_fh[TOKENS * FFD],       g_fl[TOKENS * FFD];
__device__ alignas(16) u16 g_vth[16 * HDIM * SEQ],   g_vtl[16 * HDIM * SEQ];
__device__ alignas(16) u16 g_qsh[TOKENS * RANK],     g_qsl[TOKENS * RANK];
__device__ alignas(16) u16 g_ksh[TOKENS * RANK],     g_ksl[TOKENS * RANK];
__device__ alignas(16) u16 g_sph[(size_t)2 * SEQ * SEQ], g_spl[(size_t)2 * SEQ * SEQ];
__device__ alignas(16) u16 g_vsth[2 * DIM * SEQ],    g_vstl[2 * DIM * SEQ];

// ---------------- bf16 hi/lo planes (weights) ----------------
__device__ alignas(16) u16 g_inwh[LAYERS * 3 * DIM * DIM], g_inwl[LAYERS * 3 * DIM * DIM];
__device__ alignas(16) u16 g_outwh[LAYERS * DIM * DIM],    g_outwl[LAYERS * DIM * DIM];
__device__ alignas(16) u16 g_qpwh[LAYERS * RANK * DIM],    g_qpwl[LAYERS * RANK * DIM];
__device__ alignas(16) u16 g_kpwh[LAYERS * RANK * DIM],    g_kpwl[LAYERS * RANK * DIM];
__device__ alignas(16) u16 g_vpwh[LAYERS * DIM * DIM],     g_vpwl[LAYERS * DIM * DIM];
__device__ alignas(16) u16 g_f1wh[LAYERS * FFD * DIM],     g_f1wl[LAYERS * FFD * DIM];
__device__ alignas(16) u16 g_f2wh[LAYERS * DIM * FFD],     g_f2wl[LAYERS * DIM * FFD];
__device__ alignas(16) u16 g_finwh[VOCAB * DIM],           g_finwl[VOCAB * DIM];

// ---------------- small device helpers ----------------
__device__ __forceinline__ void fsplit(float x, u16& h, u16& l)
{
    __nv_bfloat16 bh = __float2bfloat16_rn(x);
    float fh = __bfloat162float(bh);
    __nv_bfloat16 bl = __float2bfloat16_rn(x - fh);
    h = *reinterpret_cast<u16*>(&bh);
    l = *reinterpret_cast<u16*>(&bl);
}

__device__ __forceinline__ uint32_t smem_u32(const void* p)
{
    uint32_t a;
    asm("{ .reg .u64 t; cvta.to.shared.u64 t, %1; cvt.u32.u64 %0, t; }" : "=r"(a) : "l"(p));
    return a;
}

__device__ __forceinline__ void cpa16(uint32_t dst, const void* src)
{
    asm volatile("cp.async.cg.shared.global [%0], [%1], 16;" :: "r"(dst), "l"(src) : "memory");
}

__device__ __forceinline__ void ldsm4(uint32_t* r, uint32_t addr)
{
    asm volatile("ldmatrix.sync.aligned.m8n8.x4.shared.b16 {%0,%1,%2,%3}, [%4];"
                 : "=r"(r[0]), "=r"(r[1]), "=r"(r[2]), "=r"(r[3]) : "r"(addr));
}

__device__ __forceinline__ void mma16816(float* c, const uint32_t* a, uint32_t b0, uint32_t b1)
{
    asm volatile(
        "mma.sync.aligned.m16n8k16.row.col.f32.bf16.bf16.f32 "
        "{%0,%1,%2,%3}, {%4,%5,%6,%7}, {%8,%9}, {%0,%1,%2,%3};"
        : "+f"(c[0]), "+f"(c[1]), "+f"(c[2]), "+f"(c[3])
        : "r"(a[0]), "r"(a[1]), "r"(a[2]), "r"(a[3]), "r"(b0), "r"(b1));
}

// ---------------- HMMA bf16x3 GEMM: C = alpha * (A @ B^T) + bias ----------------
// TN=256: warps 2Mx4N (64x64 each). TN=128: 2Mx4N (64x32). TN=64: 4Mx2N (32x32).
template <int TN>
__global__ void __launch_bounds__(256)
mm_gemm(const u16* __restrict__ Ah, const u16* __restrict__ Al,
        const u16* __restrict__ Bh, const u16* __restrict__ Bl,
        const float* __restrict__ bias, float* __restrict__ C,
        u16* __restrict__ Ch, u16* __restrict__ Cl,
        int K, int lda, int ldb, int ldc,
        long sAo, long sAi, long sBo, long sBi, long sCo, long sCi,
        int zdiv, float alpha, int relu)
{
    constexpr int MI  = (TN >= 128) ? 4 : 2;
    constexpr int NI  = (TN == 256) ? 4 : 2;
    constexpr int APB = 128 * 80;
    constexpr int BPB = TN * 80;
    constexpr int STAGE = 2 * APB + 2 * BPB;

    extern __shared__ char smem[];
    const uint32_t su = smem_u32(smem);
    const int tid = threadIdx.x;
    const int wid = tid >> 5;
    const int lane = tid & 31;

    int z = blockIdx.z;
    int zo = z / zdiv, zi = z - zo * zdiv;
    long ao = (long)zo * sAo + (long)zi * sAi;
    long bo = (long)zo * sBo + (long)zi * sBi;
    long co = (long)zo * sCo + (long)zi * sCi;
    Ah += ao; Al += ao; Bh += bo; Bl += bo; C += co;
    if (Ch) { Ch += co; Cl += co; }
    const int m0 = blockIdx.y * 128;
    const int n0 = blockIdx.x * TN;

    const int wmBase = (TN >= 128) ? (wid & 1) * 64 : (wid & 3) * 32;
    const int wnBase = (TN == 256) ? (wid >> 1) * 64
                     : (TN == 128) ? (wid >> 1) * 32 : (wid >> 2) * 32;

    float acc[MI][2 * NI][4];
#pragma unroll
    for (int mi = 0; mi < MI; mi++)
#pragma unroll
        for (int n8 = 0; n8 < 2 * NI; n8++)
#pragma unroll
            for (int q = 0; q < 4; q++) acc[mi][n8][q] = 0.f;

    const int nch = K >> 5;
    const int ar = tid >> 2, ac = tid & 3;
    auto issue = [&](int i) {
        int s = i & 1;
        int k0 = i << 5;
        uint32_t st = su + s * STAGE;
#pragma unroll
        for (int j = 0; j < 2; j++) {
            int r = ar + 64 * j;
            long g = (long)(m0 + r) * lda + k0 + ac * 8;
            uint32_t d = st + r * 80 + ac * 16;
            cpa16(d, Ah + g);
            cpa16(d + APB, Al + g);
        }
#pragma unroll
        for (int j = 0; j < TN / 64; j++) {
            int r = ar + 64 * j;
            long g = (long)(n0 + r) * ldb + k0 + ac * 8;
            uint32_t d = st + 2 * APB + r * 80 + ac * 16;
            cpa16(d, Bh + g);
            cpa16(d + BPB, Bl + g);
        }
        asm volatile("cp.async.commit_group;" ::: "memory");
    };

    issue(0);
    const uint32_t lrow = lane & 15;
    const uint32_t lcol = (lane >> 4) * 16;

    for (int i = 0; i < nch; i++) {
        if (i + 1 < nch) {
            issue(i + 1);
            asm volatile("cp.async.wait_group 1;" ::: "memory");
        } else {
            asm volatile("cp.async.wait_group 0;" ::: "memory");
        }
        __syncthreads();

        int s = i & 1;
        uint32_t aH = su + s * STAGE;
        uint32_t aL = aH + APB;
        uint32_t bH = aH + 2 * APB;
        uint32_t bL = bH + BPB;

#pragma unroll
        for (int ks = 0; ks < 2; ks++) {
            uint32_t a[MI][4], bh[NI][4], bl[NI][4];
            uint32_t kb = ks * 32 + lcol;
#pragma unroll
            for (int mi = 0; mi < MI; mi++)
                ldsm4(a[mi], aH + (wmBase + mi * 16 + lrow) * 80 + kb);
#pragma unroll
            for (int ni = 0; ni < NI; ni++)
                ldsm4(bh[ni], bH + (wnBase + ni * 16 + lrow) * 80 + kb);
#pragma unroll
            for (int mi = 0; mi < MI; mi++)
#pragma unroll
                for (int ni = 0; ni < NI; ni++) {
                    mma16816(acc[mi][2 * ni],     a[mi], bh[ni][0], bh[ni][2]);
                    mma16816(acc[mi][2 * ni + 1], a[mi], bh[ni][1], bh[ni][3]);
                }
#pragma unroll
            for (int ni = 0; ni < NI; ni++)
                ldsm4(bl[ni], bL + (wnBase + ni * 16 + lrow) * 80 + kb);
#pragma unroll
            for (int mi = 0; mi < MI; mi++)
#pragma unroll
                for (int ni = 0; ni < NI; ni++) {
                    mma16816(acc[mi][2 * ni],     a[mi], bl[ni][0], bl[ni][2]);
                    mma16816(acc[mi][2 * ni + 1], a[mi], bl[ni][1], bl[ni][3]);
                }
#pragma unroll
            for (int mi = 0; mi < MI; mi++)
                ldsm4(a[mi], aL + (wmBase + mi * 16 + lrow) * 80 + kb);
#pragma unroll
            for (int mi = 0; mi < MI; mi++)
#pragma unroll
                for (int ni = 0; ni < NI; ni++) {
                    mma16816(acc[mi][2 * ni],     a[mi], bh[ni][0], bh[ni][2]);
                    mma16816(acc[mi][2 * ni + 1], a[mi], bh[ni][1], bh[ni][3]);
                }
        }
        __syncthreads();
    }

#pragma unroll
    for (int mi = 0; mi < MI; mi++) {
        int r0 = m0 + wmBase + mi * 16 + (lane >> 2);
#pragma unroll
        for (int n8 = 0; n8 < 2 * NI; n8++) {
            int c = n0 + wnBase + n8 * 8 + (lane & 3) * 2;
            float2 o0, o1;
            o0.x = acc[mi][n8][0] * alpha; o0.y = acc[mi][n8][1] * alpha;
            o1.x = acc[mi][n8][2] * alpha; o1.y = acc[mi][n8][3] * alpha;
            if (bias) {
                float b0 = bias[c], b1 = bias[c + 1];
                o0.x += b0; o0.y += b1; o1.x += b0; o1.y += b1;
            }
            if (relu) {
                o0.x = fmaxf(o0.x, 0.f); o0.y = fmaxf(o0.y, 0.f);
                o1.x = fmaxf(o1.x, 0.f); o1.y = fmaxf(o1.y, 0.f);
            }
            long off0 = (long)r0 * ldc + c;
            long off1 = off0 + (long)8 * ldc;
            *(float2*)(C + off0) = o0;
            *(float2*)(C + off1) = o1;
            if (Ch) {
                ushort2 hh, ll;
                fsplit(o0.x, hh.x, ll.x); fsplit(o0.y, hh.y, ll.y);
                *(ushort2*)(Ch + off0) = hh; *(ushort2*)(Cl + off0) = ll;
                fsplit(o1.x, hh.x, ll.x); fsplit(o1.y, hh.y, ll.y);
                *(ushort2*)(Ch + off1) = hh; *(ushort2*)(Cl + off1) = ll;
            }
        }
    }
}

// ---------------- converters ----------------
__global__ void cvt_k(const float4* __restrict__ s, ushort4* __restrict__ h,
                      ushort4* __restrict__ l, int n4)
{
    int i = blockIdx.x * 256 + threadIdx.x;
    if (i >= n4) return;
    float4 v = s[i];
    ushort4 hh, ll;
    fsplit(v.x, hh.x, ll.x); fsplit(v.y, hh.y, ll.y);
    fsplit(v.z, hh.z, ll.z); fsplit(v.w, hh.w, ll.w);
    h[i] = hh; l[i] = ll;
}

// V^T planes (dense): smem-tiled transpose, coalesced both sides.
// vt[z][d][s] = qkv[(b*SEQ+s)*(3D) + 2D + h*HDIM + d]
__global__ void vt_k(const float* __restrict__ qkv, u16* __restrict__ vh, u16* __restrict__ vl)
{
    __shared__ float t[32][33];
    int z = blockIdx.z, b = z >> 3, h = z & 7;
    int s0 = blockIdx.x * 32, d0 = blockIdx.y * 32;
    int tx = threadIdx.x, ty = threadIdx.y;   // (32, 8)
#pragma unroll
    for (int j = 0; j < 4; j++) {
        int s = s0 + ty + j * 8;
        t[ty + j * 8][tx] = qkv[((long)(b * SEQ + s)) * (3 * DIM) + 2 * DIM + h * HDIM + d0 + tx];
    }
    __syncthreads();
#pragma unroll
    for (int j = 0; j < 4; j++) {
        int d = d0 + ty + j * 8;
        long o = ((long)z * HDIM + d) * SEQ + s0 + tx;
        u16 hh, ll;
        fsplit(t[tx][ty + j * 8], hh, ll);
        vh[o] = hh; vl[o] = ll;
    }
}

// Vs^T planes (sparse): vst[b][d][s] = vs[(b*SEQ+s)*DIM + d]
__global__ void vst_k(const float* __restrict__ vs, u16* __restrict__ vh, u16* __restrict__ vl)
{
    __shared__ float t[32][33];
    int b = blockIdx.z;
    int s0 = blockIdx.x * 32, d0 = blockIdx.y * 32;
    int tx = threadIdx.x, ty = threadIdx.y;   // (32, 8)
#pragma unroll
    for (int j = 0; j < 4; j++) {
        int s = s0 + ty + j * 8;
        t[ty + j * 8][tx] = vs[((long)(b * SEQ + s)) * DIM + d0 + tx];
    }
    __syncthreads();
#pragma unroll
    for (int j = 0; j < 4; j++) {
        int d = d0 + ty + j * 8;
        long o = ((long)(b * DIM + d)) * SEQ + s0 + tx;
        u16 hh, ll;
        fsplit(t[tx][ty + j * 8], hh, ll);
        vh[o] = hh; vl[o] = ll;
    }
}

// ---------------- embedding (+ x planes) ----------------
__global__ void embed_k(const int* __restrict__ src, const float* __restrict__ emb,
                        const float* __restrict__ pe, float* __restrict__ x,
                        u16* __restrict__ xh, u16* __restrict__ xl)
{
    int t = blockIdx.x;
    int tid = threadIdx.x;
    int s = t & (SEQ - 1);
    int tok = src[t];
    int d = tid * 2;
    float2 e = *(const float2*)(emb + (long)tok * DIM + d);
    float2 p = *(const float2*)(pe + (long)s * DIM + d);
    float2 o;
    o.x = e.x * 22.627416998f + p.x;
    o.y = e.y * 22.627416998f + p.y;
    long off = (long)t * DIM + d;
    *(float2*)(x + off) = o;
    ushort2 hh, ll;
    fsplit(o.x, hh.x, ll.x); fsplit(o.y, hh.y, ll.y);
    *(ushort2*)(xh + off) = hh;
    *(ushort2*)(xl + off) = ll;
}

// ---------------- row softmax -> P hi/lo planes ----------------
__global__ void softmax_rows(const float* __restrict__ S, u16* __restrict__ Ph,
                             u16* __restrict__ Pl)
{
    __shared__ float red[256];
    long row = blockIdx.x;
    const float* p = S + row * (long)SEQ;
    int tid = threadIdx.x;
    float4 v0 = *(const float4*)(p + 4 * tid);
    float4 v1 = *(const float4*)(p + 4 * tid + 1024);
    float m = fmaxf(fmaxf(fmaxf(v0.x, v0.y), fmaxf(v0.z, v0.w)),
                    fmaxf(fmaxf(v1.x, v1.y), fmaxf(v1.z, v1.w)));
    red[tid] = m; __syncthreads();
    for (int s = 128; s > 0; s >>= 1) { if (tid < s) red[tid] = fmaxf(red[tid], red[tid + s]); __syncthreads(); }
    float M = red[0]; __syncthreads();
    v0.x = __expf(v0.x - M); v0.y = __expf(v0.y - M); v0.z = __expf(v0.z - M); v0.w = __expf(v0.w - M);
    v1.x = __expf(v1.x - M); v1.y = __expf(v1.y - M); v1.z = __expf(v1.z - M); v1.w = __expf(v1.w - M);
    float sum = v0.x + v0.y + v0.z + v0.w + v1.x + v1.y + v1.z + v1.w;
    red[tid] = sum; __syncthreads();
    for (int s = 128; s > 0; s >>= 1) { if (tid < s) red[tid] += red[tid + s]; __syncthreads(); }
    float inv = 1.f / red[0];
    v0.x *= inv; v0.y *= inv; v0.z *= inv; v0.w *= inv;
    v1.x *= inv; v1.y *= inv; v1.z *= inv; v1.w *= inv;
    long b0 = row * (long)SEQ + 4 * tid;
    ushort4 hh, ll;
    fsplit(v0.x, hh.x, ll.x); fsplit(v0.y, hh.y, ll.y);
    fsplit(v0.z, hh.z, ll.z); fsplit(v0.w, hh.w, ll.w);
    *(ushort4*)(Ph + b0) = hh; *(ushort4*)(Pl + b0) = ll;
    fsplit(v1.x, hh.x, ll.x); fsplit(v1.y, hh.y, ll.y);
    fsplit(v1.z, hh.z, ll.z); fsplit(v1.w, hh.w, ll.w);
    *(ushort4*)(Ph + b0 + 1024) = hh; *(ushort4*)(Pl + b0 + 1024) = ll;
}

// ---------------- sparse select: exact top-409 radix select -> dense weight planes ----------------
__device__ __forceinline__ unsigned f2k(float f)
{
    unsigned u = __float_as_uint(f);
    return (u & 0x80000000u) ? ~u : (u | 0x80000000u);
}

__global__ void __launch_bounds__(256) sparse_sel(
    const float* __restrict__ qk, u16* __restrict__ sph, u16* __restrict__ spl)
{
    __shared__ float logit[SEQ];
    __shared__ unsigned hist[256];
    __shared__ unsigned suf[256];
    __shared__ float red[256];
    __shared__ unsigned sh_prefix;
    __shared__ int sh_remaining;

    long row = blockIdx.x;
    int tid = threadIdx.x;
    const float* p = qk + row * (long)SEQ;

    for (int k = tid; k < SEQ; k += 256) logit[k] = p[k];
    __syncthreads();

    float lm = -3.4e38f;
    for (int k = tid; k < SEQ; k += 256) lm = fmaxf(lm, logit[k]);
    red[tid] = lm; __syncthreads();
    for (int s = 128; s > 0; s >>= 1) { if (tid < s) red[tid] = fmaxf(red[tid], red[tid + s]); __syncthreads(); }
    float Lmax = red[0]; __syncthreads();

    float zacc = 0.f;
    for (int k = tid; k < SEQ; k += 256) zacc += __expf(logit[k] - Lmax);
    red[tid] = zacc; __syncthreads();
    for (int s = 128; s > 0; s >>= 1) { if (tid < s) red[tid] += red[tid + s]; __syncthreads(); }
    float Z = red[0]; __syncthreads();

    unsigned prefix = 0; int remaining = KTOP;
    for (int shift = 24; shift >= 0; shift -= 8) {
        hist[tid] = 0; __syncthreads();
        unsigned upmask = (shift == 24) ? 0u : (0xFFFFFFFFu << (shift + 8));
        for (int k = tid; k < SEQ; k += 256) {
            unsigned key = f2k(logit[k]);
            if ((key & upmask) == prefix)
                atomicAdd(&hist[(key >> shift) & 255], 1u);
        }
        __syncthreads();
        suf[tid] = hist[tid]; __syncthreads();
        for (int off = 1; off < 256; off <<= 1) {
            unsigned add = (tid + off < 256) ? suf[tid + off] : 0u;
            __syncthreads();
            suf[tid] += add;
            __syncthreads();
        }
        unsigned shere = suf[tid];
        unsigned snext = (tid < 255) ? suf[tid + 1] : 0u;
        if (shere >= (unsigned)remaining && snext < (unsigned)remaining) {
            sh_prefix = prefix | ((unsigned)tid << shift);
            sh_remaining = remaining - (int)snext;
        }
        __syncthreads();
        prefix = sh_prefix; remaining = sh_remaining;
        __syncthreads();
    }
    unsigned thr = prefix;

    float w8[8];
    float dsum = 0.f;
#pragma unroll
    for (int j = 0; j < 8; j++) {
        int k = tid + 256 * j;
        float l = logit[k];
        bool keep = (f2k(l) >= thr);
        float w = keep ? __expf(l - Lmax) : 0.f;
        w8[j] = w;
        dsum += w;
    }
    red[tid] = dsum; __syncthreads();
    for (int s = 128; s > 0; s >>= 1) { if (tid < s) red[tid] += red[tid + s]; __syncthreads(); }
    float inv = 1.f / (red[0] + 1e-9f * Z);

#pragma unroll
    for (int j = 0; j < 8; j++) {
        int k = tid + 256 * j;
        float w = w8[j] * inv;
        u16 h, l;
        fsplit(w, h, l);
        long o = row * (long)SEQ + k;
        sph[o] = h; spl[o] = l;
    }
}

// ---------------- gated fusion + LN1 (overwrites x, emits x planes) ----------------
__global__ void fuse_ln1_k(float* __restrict__ x, const float* __restrict__ dn,
                           const float* __restrict__ sp, const float* __restrict__ lam,
                           int layer, const float* __restrict__ gam, const float* __restrict__ bet,
                           u16* __restrict__ xh, u16* __restrict__ xl)
{
    __shared__ float red[256];
    int row = blockIdx.x, tid = threadIdx.x;
    long off = (long)row * DIM + 2 * tid;
    float g = 1.f / (1.f + expf(-lam[layer]));
    float2 xv = *(const float2*)(x + off);
    float2 dv = *(const float2*)(dn + off);
    float2 sv = *(const float2*)(sp + off);
    float y0 = xv.x + g * dv.x + (1.f - g) * sv.x;
    float y1 = xv.y + g * dv.y + (1.f - g) * sv.y;
    red[tid] = y0 + y1; __syncthreads();
    for (int s = 128; s > 0; s >>= 1) { if (tid < s) red[tid] += red[tid + s]; __syncthreads(); }
    float mean = red[0] * (1.f / DIM); __syncthreads();
    float d0 = y0 - mean, d1 = y1 - mean;
    red[tid] = d0 * d0 + d1 * d1; __syncthreads();
    for (int s = 128; s > 0; s >>= 1) { if (tid < s) red[tid] += red[tid + s]; __syncthreads(); }
    float inv = 1.f / sqrtf(red[0] * (1.f / DIM) + 1e-5f);
    int dc = 2 * tid;
    float2 gm = *(const float2*)(gam + dc);
    float2 bt = *(const float2*)(bet + dc);
    float2 o; o.x = d0 * inv * gm.x + bt.x; o.y = d1 * inv * gm.y + bt.y;
    *(float2*)(x + off) = o;
    ushort2 hh, ll;
    fsplit(o.x, hh.x, ll.x); fsplit(o.y, hh.y, ll.y);
    *(ushort2*)(xh + off) = hh;
    *(ushort2*)(xl + off) = ll;
}

// ---------------- residual + LN2 (overwrites x, emits x planes) ----------------
__global__ void add_ln2_k(float* __restrict__ x, const float* __restrict__ f,
                          const float* __restrict__ gam, const float* __restrict__ bet,
                          u16* __restrict__ xh, u16* __restrict__ xl)
{
    __shared__ float red[256];
    int row = blockIdx.x, tid = threadIdx.x;
    long off = (long)row * DIM + 2 * tid;
    float2 xv = *(const float2*)(x + off);
    float2 fv = *(const float2*)(f + off);
    float y0 = xv.x + fv.x;
    float y1 = xv.y + fv.y;
    red[tid] = y0 + y1; __syncthreads();
    for (int s = 128; s > 0; s >>= 1) { if (tid < s) red[tid] += red[tid + s]; __syncthreads(); }
    float mean = red[0] * (1.f / DIM); __syncthreads();
    float d0 = y0 - mean, d1 = y1 - mean;
    red[tid] = d0 * d0 + d1 * d1; __syncthreads();
    for (int s = 128; s > 0; s >>= 1) { if (tid < s) red[tid] += red[tid + s]; __syncthreads(); }
    float inv = 1.f / sqrtf(red[0] * (1.f / DIM) + 1e-5f);
    int dc = 2 * tid;
    float2 gm = *(const float2*)(gam + dc);
    float2 bt = *(const float2*)(bet + dc);
    float2 o; o.x = d0 * inv * gm.x + bt.x; o.y = d1 * inv * gm.y + bt.y;
    *(float2*)(x + off) = o;
    ushort2 hh, ll;
    fsplit(o.x, hh.x, ll.x); fsplit(o.y, hh.y, ll.y);
    *(ushort2*)(xh + off) = hh;
    *(ushort2*)(xl + off) = ll;
}

// ---------------- host-side helpers ----------------
template <int TN>
static void launch_tc(const u16* Ah, const u16* Al, const u16* Bh, const u16* Bl,
                      const float* bias, float* C, u16* Ch, u16* Cl,
                      int M, int N, int K, int lda, int ldb, int ldc,
                      int Z = 1, long sAo = 0, long sAi = 0, long sBo = 0, long sBi = 0,
                      long sCo = 0, long sCi = 0, int zdiv = 1,
                      float alpha = 1.f, int relu = 0)
{
    constexpr int SM = 2 * (2 * 128 * 80 + 2 * TN * 80);
    static bool attr_set = false;
    if (!attr_set) {
        cudaFuncSetAttribute(mm_gemm<TN>, cudaFuncAttributeMaxDynamicSharedMemorySize, SM);
        attr_set = true;
    }
    dim3 g(N / TN, M / 128, Z);
    mm_gemm<TN><<<g, 256, SM>>>(Ah, Al, Bh, Bl, bias, C, Ch, Cl,
                                K, lda, ldb, ldc,
                                sAo, sAi, sBo, sBi, sCo, sCi, zdiv, alpha, relu);
}

static void cvt(const float* s, u16* h, u16* l, long n)
{
    long n4 = n >> 2;
    cvt_k<<<(unsigned)((n4 + 255) / 256), 256>>>((const float4*)s, (ushort4*)h, (ushort4*)l, (int)n4);
}

extern "C" void kernel_launch(void* const* d_in, const int* in_sizes, int n_in,
                              void* d_out, int out_size)
{
    const int*   SRC   = (const int*)  d_in[0];
    const float* EMB   = (const float*)d_in[1];
    const float* PE    = (const float*)d_in[2];
    const float* IN_W  = (const float*)d_in[3];
    const float* IN_B  = (const float*)d_in[4];
    const float* OUT_W = (const float*)d_in[5];
    const float* OUT_B = (const float*)d_in[6];
    const float* QP_W  = (const float*)d_in[7];
    const float* QP_B  = (const float*)d_in[8];
    const float* KP_W  = (const float*)d_in[9];
    const float* KP_B  = (const float*)d_in[10];
    const float* VP_W  = (const float*)d_in[11];
    const float* VP_B  = (const float*)d_in[12];
    const float* LAM   = (const float*)d_in[13];
    const float* FF1_W = (const float*)d_in[14];
    const float* FF1_B = (const float*)d_in[15];
    const float* FF2_W = (const float*)d_in[16];
    const float* FF2_B = (const float*)d_in[17];
    const float* LN1S  = (const float*)d_in[18];
    const float* LN1B  = (const float*)d_in[19];
    const float* LN2S  = (const float*)d_in[20];
    const float* LN2B  = (const float*)d_in[21];
    const float* FIN_W = (const float*)d_in[22];
    const float* FIN_B = (const float*)d_in[23];
    float* OUT = (float*)d_out;

    float *x, *qkv, *scores, *dense, *aproj, *qs, *ks, *vs, *sp, *ffh, *fft;
    cudaGetSymbolAddress((void**)&x, g_x);         cudaGetSymbolAddress((void**)&qkv, g_qkv);
    cudaGetSymbolAddress((void**)&scores, g_scores); cudaGetSymbolAddress((void**)&dense, g_dense);
    cudaGetSymbolAddress((void**)&aproj, g_aproj); cudaGetSymbolAddress((void**)&qs, g_Qs);
    cudaGetSymbolAddress((void**)&ks, g_Ks);       cudaGetSymbolAddress((void**)&vs, g_Vs);
    cudaGetSymbolAddress((void**)&sp, g_sparse);   cudaGetSymbolAddress((void**)&ffh, g_ffh);
    cudaGetSymbolAddress((void**)&fft, g_fft);

    u16 *xh, *xl, *qkvh, *qkvl, *Ph, *Pl, *dh, *dl, *fh, *fl, *vth, *vtl;
    u16 *qsh, *qsl, *ksh, *ksl, *sph, *spl, *vsth, *vstl;
    cudaGetSymbolAddress((void**)&xh, g_xh);   cudaGetSymbolAddress((void**)&xl, g_xl);
    cudaGetSymbolAddress((void**)&qkvh, g_qkvh); cudaGetSymbolAddress((void**)&qkvl, g_qkvl);
    cudaGetSymbolAddress((void**)&Ph, g_Ph);   cudaGetSymbolAddress((void**)&Pl, g_Pl);
    cudaGetSymbolAddress((void**)&dh, g_dh);   cudaGetSymbolAddress((void**)&dl, g_dl);
    cudaGetSymbolAddress((void**)&fh, g_fh);   cudaGetSymbolAddress((void**)&fl, g_fl);
    cudaGetSymbolAddress((void**)&vth, g_vth); cudaGetSymbolAddress((void**)&vtl, g_vtl);
    cudaGetSymbolAddress((void**)&qsh, g_qsh); cudaGetSymbolAddress((void**)&qsl, g_qsl);
    cudaGetSymbolAddress((void**)&ksh, g_ksh); cudaGetSymbolAddress((void**)&ksl, g_ksl);
    cudaGetSymbolAddress((void**)&sph, g_sph); cudaGetSymbolAddress((void**)&spl, g_spl);
    cudaGetSymbolAddress((void**)&vsth, g_vsth); cudaGetSymbolAddress((void**)&vstl, g_vstl);

    u16 *inwh, *inwl, *outwh, *outwl, *qpwh, *qpwl, *kpwh, *kpwl, *vpwh, *vpwl;
    u16 *f1wh, *f1wl, *f2wh, *f2wl, *finwh, *finwl;
    cudaGetSymbolAddress((void**)&inwh, g_inwh);   cudaGetSymbolAddress((void**)&inwl, g_inwl);
    cudaGetSymbolAddress((void**)&outwh, g_outwh); cudaGetSymbolAddress((void**)&outwl, g_outwl);
    cudaGetSymbolAddress((void**)&qpwh, g_qpwh);   cudaGetSymbolAddress((void**)&qpwl, g_qpwl);
    cudaGetSymbolAddress((void**)&kpwh, g_kpwh);   cudaGetSymbolAddress((void**)&kpwl, g_kpwl);
    cudaGetSymbolAddress((void**)&vpwh, g_vpwh);   cudaGetSymbolAddress((void**)&vpwl, g_vpwl);
    cudaGetSymbolAddress((void**)&f1wh, g_f1wh);   cudaGetSymbolAddress((void**)&f1wl, g_f1wl);
    cudaGetSymbolAddress((void**)&f2wh, g_f2wh);   cudaGetSymbolAddress((void**)&f2wl, g_f2wl);
    cudaGetSymbolAddress((void**)&finwh, g_finwh); cudaGetSymbolAddress((void**)&finwl, g_finwl);

    // convert all weights once
    cvt(IN_W,  inwh,  inwl,  (long)LAYERS * 3 * DIM * DIM);
    cvt(OUT_W, outwh, outwl, (long)LAYERS * DIM * DIM);
    cvt(QP_W,  qpwh,  qpwl,  (long)LAYERS * RANK * DIM);
    cvt(KP_W,  kpwh,  kpwl,  (long)LAYERS * RANK * DIM);
    cvt(VP_W,  vpwh,  vpwl,  (long)LAYERS * DIM * DIM);
    cvt(FF1_W, f1wh,  f1wl,  (long)LAYERS * FFD * DIM);
    cvt(FF2_W, f2wh,  f2wl,  (long)LAYERS * DIM * FFD);
    cvt(FIN_W, finwh, finwl, (long)VOCAB * DIM);

    embed_k<<<TOKENS, 256>>>(SRC, EMB, PE, x, xh, xl);

    for (int l = 0; l < LAYERS; l++) {
        long wq  = (long)l * 3 * DIM * DIM;
        long wo  = (long)l * DIM * DIM;
        long wp  = (long)l * RANK * DIM;
        long wf1 = (long)l * FFD * DIM;
        long wf2 = (long)l * DIM * FFD;

        // qkv = x @ in_w^T + in_b  (fp32 + bf16 planes)
        launch_tc<256>(xh, xl, inwh + wq, inwl + wq, IN_B + (long)l * 3 * DIM,
                       qkv, qkvh, qkvl, TOKENS, 3 * DIM, DIM, DIM, DIM, 3 * DIM);

        // dense scores = Q @ K^T / 8 per (b,h)
        launch_tc<256>(qkvh, qkvl, qkvh + DIM, qkvl + DIM, nullptr,
                       scores, nullptr, nullptr,
                       SEQ, SEQ, HDIM, 3 * DIM, 3 * DIM, SEQ,
                       16, (long)SEQ * 3 * DIM, (long)HDIM,
                       (long)SEQ * 3 * DIM, (long)HDIM,
                       (long)HEADS * SEQ * SEQ, (long)SEQ * SEQ,
                       HEADS, 0.125f, 0);

        // softmax -> P hi/lo planes (frees scores buffer)
        softmax_rows<<<16 * SEQ, 256>>>(scores, Ph, Pl);

        // V^T planes (dense), tiled transpose
        vt_k<<<dim3(SEQ / 32, HDIM / 32, 16), dim3(32, 8)>>>(qkv, vth, vtl);

        // dense = P @ V per (b,h)
        launch_tc<64>(Ph, Pl, vth, vtl, nullptr, dense, dh, dl,
                      SEQ, HDIM, SEQ, SEQ, SEQ, DIM,
                      16, (long)HEADS * SEQ * SEQ, (long)SEQ * SEQ,
                      (long)HEADS * HDIM * SEQ, (long)HDIM * SEQ,
                      (long)SEQ * DIM, (long)HDIM,
                      HEADS, 1.f, 0);

        // dense projection
        launch_tc<128>(dh, dl, outwh + wo, outwl + wo, OUT_B + (long)l * DIM,
                       aproj, nullptr, nullptr, TOKENS, DIM, DIM, DIM, DIM, DIM);

        // low-rank projections (with plane outputs for Qs/Ks)
        launch_tc<64>(xh, xl, qpwh + wp, qpwl + wp, QP_B + (long)l * RANK,
                      qs, qsh, qsl, TOKENS, RANK, DIM, DIM, DIM, RANK);
        launch_tc<64>(xh, xl, kpwh + wp, kpwl + wp, KP_B + (long)l * RANK,
                      ks, ksh, ksl, TOKENS, RANK, DIM, DIM, DIM, RANK);
        launch_tc<128>(xh, xl, vpwh + wo, vpwl + wo, VP_B + (long)l * DIM,
                       vs, nullptr, nullptr, TOKENS, DIM, DIM, DIM, DIM, DIM);

        // Vs^T planes (sparse), tiled transpose
        vst_k<<<dim3(SEQ / 32, DIM / 32, 2), dim3(32, 8)>>>(vs, vsth, vstl);

        // low-rank logits qk = Qs @ Ks^T / sqrt(R) per batch (reuse scores buffer)
        launch_tc<256>(qsh, qsl, ksh, ksl, nullptr, scores, nullptr, nullptr,
                       SEQ, SEQ, RANK, RANK, RANK, SEQ,
                       2, (long)SEQ * RANK, 0, (long)SEQ * RANK, 0,
                       (long)SEQ * SEQ, 0, 1, 0.125f, 0);

        // exact top-409 select -> dense renormalized weight planes
        sparse_sel<<<TOKENS, 256>>>(scores, sph, spl);

        // sparse = sp @ Vs per batch
        launch_tc<128>(sph, spl, vsth, vstl, nullptr, sp, nullptr, nullptr,
                       SEQ, DIM, SEQ, SEQ, SEQ, DIM,
                       2, (long)SEQ * SEQ, 0, (long)DIM * SEQ, 0,
                       (long)SEQ * DIM, 0, 1, 1.f, 0);

        // gated fusion + LN1
        fuse_ln1_k<<<TOKENS, 256>>>(x, aproj, sp, LAM, l,
                                    LN1S + (long)l * DIM, LN1B + (long)l * DIM, xh, xl);

        // FFN
        launch_tc<256>(xh, xl, f1wh + wf1, f1wl + wf1, FF1_B + (long)l * FFD,
                       ffh, fh, fl, TOKENS, FFD, DIM, DIM, DIM, FFD,
                       1, 0, 0, 0, 0, 0, 0, 1, 1.f, 1);
        launch_tc<128>(fh, fl, f2wh + wf2, f2wl + wf2, FF2_B + (long)l * DIM,
                       fft, nullptr, nullptr, TOKENS, DIM, FFD, FFD, FFD, DIM);

        add_ln2_k<<<TOKENS, 256>>>(x, fft, LN2S + (long)l * DIM, LN2B + (long)l * DIM, xh, xl);
    }

    // final vocab projection
    launch_tc<256>(xh, xl, finwh, finwl, FIN_B, OUT, nullptr, nullptr,
                   TOKENS, VOCAB, DIM, DIM, DIM, VOCAB);
}

// round 7
// speedup vs baseline: 1.5168x; 1.0502x over previous
#include <cuda_runtime.h>
#include <cuda_bf16.h>
#include <math.h>
#include <stdint.h>

#define SEQ    2048
#define TOKENS 4096
#define DIM    512
#define HEADS  8
#define HDIM   64
#define RANK   64
#define LAYERS 6
#define VOCAB  32000
#define FFD    2048
#define KTOP   409
#define NPACK  2304   // 1536 qkv | 64 qs | 64 ks | 512 vs | 128 pad
#define COL_QS 1536
#define COL_KS 1600
#define COL_VS 1664

typedef unsigned short u16;

// ---------------- fp32 scratch ----------------
__device__ float g_px[(size_t)TOKENS * NPACK];     // packed projections fp32
__device__ float g_x[TOKENS * DIM];
__device__ float g_scores[(size_t)16 * SEQ * SEQ]; // dense scores / qk logits
__device__ float g_aproj[TOKENS * DIM];
__device__ float g_sparse[TOKENS * DIM];
__device__ float g_fft[TOKENS * DIM];

// ---------------- bf16 hi/lo planes (activations) ----------------
__device__ alignas(16) u16 g_pxh[(size_t)TOKENS * NPACK], g_pxl[(size_t)TOKENS * NPACK];
__device__ alignas(16) u16 g_xh[TOKENS * DIM],       g_xl[TOKENS * DIM];
__device__ alignas(16) u16 g_Ph[(size_t)16 * SEQ * SEQ], g_Pl[(size_t)16 * SEQ * SEQ];
__device__ alignas(16) u16 g_dh[TOKENS * DIM],       g_dl[TOKENS * DIM];
__device__ alignas(16) u16 g_fh[TOKENS * FFD],       g_fl[TOKENS * FFD];
__device__ alignas(16) u16 g_vth[16 * HDIM * SEQ],   g_vtl[16 * HDIM * SEQ];
__device__ alignas(16) u16 g_sph[(size_t)2 * SEQ * SEQ], g_spl[(size_t)2 * SEQ * SEQ];
__device__ alignas(16) u16 g_vsth[2 * DIM * SEQ],    g_vstl[2 * DIM * SEQ];

// ---------------- bf16 hi/lo planes (weights) ----------------
__device__ alignas(16) u16 g_pwh[LAYERS * NPACK * DIM], g_pwl[LAYERS * NPACK * DIM];
__device__ float g_pb[LAYERS * NPACK];
__device__ alignas(16) u16 g_outwh[LAYERS * DIM * DIM],  g_outwl[LAYERS * DIM * DIM];
__device__ alignas(16) u16 g_f1wh[LAYERS * FFD * DIM],   g_f1wl[LAYERS * FFD * DIM];
__device__ alignas(16) u16 g_f2wh[LAYERS * DIM * FFD],   g_f2wl[LAYERS * DIM * FFD];
__device__ alignas(16) u16 g_finwh[VOCAB * DIM],         g_finwl[VOCAB * DIM];

// ---------------- small device helpers ----------------
__device__ __forceinline__ void fsplit(float x, u16& h, u16& l)
{
    __nv_bfloat16 bh = __float2bfloat16_rn(x);
    float fh = __bfloat162float(bh);
    __nv_bfloat16 bl = __float2bfloat16_rn(x - fh);
    h = *reinterpret_cast<u16*>(&bh);
    l = *reinterpret_cast<u16*>(&bl);
}

__device__ __forceinline__ uint32_t smem_u32(const void* p)
{
    uint32_t a;
    asm("{ .reg .u64 t; cvta.to.shared.u64 t, %1; cvt.u32.u64 %0, t; }" : "=r"(a) : "l"(p));
    return a;
}

__device__ __forceinline__ void cpa16(uint32_t dst, const void* src)
{
    asm volatile("cp.async.cg.shared.global [%0], [%1], 16;" :: "r"(dst), "l"(src) : "memory");
}

__device__ __forceinline__ void ldsm4(uint32_t* r, uint32_t addr)
{
    asm volatile("ldmatrix.sync.aligned.m8n8.x4.shared.b16 {%0,%1,%2,%3}, [%4];"
                 : "=r"(r[0]), "=r"(r[1]), "=r"(r[2]), "=r"(r[3]) : "r"(addr));
}

__device__ __forceinline__ void mma16816(float* c, const uint32_t* a, uint32_t b0, uint32_t b1)
{
    asm volatile(
        "mma.sync.aligned.m16n8k16.row.col.f32.bf16.bf16.f32 "
        "{%0,%1,%2,%3}, {%4,%5,%6,%7}, {%8,%9}, {%0,%1,%2,%3};"
        : "+f"(c[0]), "+f"(c[1]), "+f"(c[2]), "+f"(c[3])
        : "r"(a[0]), "r"(a[1]), "r"(a[2]), "r"(a[3]), "r"(b0), "r"(b1));
}

// ---------------- HMMA bf16x3 GEMM: C = alpha * (A @ B^T) + bias, 3-stage pipeline ----------------
template <int TN>
__global__ void __launch_bounds__(256)
mm_gemm(const u16* __restrict__ Ah, const u16* __restrict__ Al,
        const u16* __restrict__ Bh, const u16* __restrict__ Bl,
        const float* __restrict__ bias, float* __restrict__ C,
        u16* __restrict__ Ch, u16* __restrict__ Cl,
        int K, int lda, int ldb, int ldc,
        long sAo, long sAi, long sBo, long sBi, long sCo, long sCi,
        int zdiv, float alpha, int relu)
{
    constexpr int MI  = (TN >= 128) ? 4 : 2;
    constexpr int NI  = (TN == 256) ? 4 : 2;
    constexpr int APB = 128 * 80;
    constexpr int BPB = TN * 80;
    constexpr int STAGE = 2 * APB + 2 * BPB;
    constexpr int NST = 3;

    extern __shared__ char smem[];
    const uint32_t su = smem_u32(smem);
    const int tid = threadIdx.x;
    const int wid = tid >> 5;
    const int lane = tid & 31;

    int z = blockIdx.z;
    int zo = z / zdiv, zi = z - zo * zdiv;
    long ao = (long)zo * sAo + (long)zi * sAi;
    long bo = (long)zo * sBo + (long)zi * sBi;
    long co = (long)zo * sCo + (long)zi * sCi;
    Ah += ao; Al += ao; Bh += bo; Bl += bo;
    if (C)  C  += co;
    if (Ch) { Ch += co; Cl += co; }
    const int m0 = blockIdx.y * 128;
    const int n0 = blockIdx.x * TN;

    const int wmBase = (TN >= 128) ? (wid & 1) * 64 : (wid & 3) * 32;
    const int wnBase = (TN == 256) ? (wid >> 1) * 64
                     : (TN == 128) ? (wid >> 1) * 32 : (wid >> 2) * 32;

    float acc[MI][2 * NI][4];
#pragma unroll
    for (int mi = 0; mi < MI; mi++)
#pragma unroll
        for (int n8 = 0; n8 < 2 * NI; n8++)
#pragma unroll
            for (int q = 0; q < 4; q++) acc[mi][n8][q] = 0.f;

    const int nch = K >> 5;
    const int ar = tid >> 2, ac = tid & 3;
    auto issue = [&](int i) {
        int s = i % NST;
        int k0 = i << 5;
        uint32_t st = su + s * STAGE;
#pragma unroll
        for (int j = 0; j < 2; j++) {
            int r = ar + 64 * j;
            long g = (long)(m0 + r) * lda + k0 + ac * 8;
            uint32_t d = st + r * 80 + ac * 16;
            cpa16(d, Ah + g);
            cpa16(d + APB, Al + g);
        }
#pragma unroll
        for (int j = 0; j < TN / 64; j++) {
            int r = ar + 64 * j;
            long g = (long)(n0 + r) * ldb + k0 + ac * 8;
            uint32_t d = st + 2 * APB + r * 80 + ac * 16;
            cpa16(d, Bh + g);
            cpa16(d + BPB, Bl + g);
        }
        asm volatile("cp.async.commit_group;" ::: "memory");
    };

    issue(0);
    if (nch > 1) issue(1);
    const uint32_t lrow = lane & 15;
    const uint32_t lcol = (lane >> 4) * 16;

    for (int i = 0; i < nch; i++) {
        if (i + 2 < nch) {
            issue(i + 2);
            asm volatile("cp.async.wait_group 2;" ::: "memory");
        } else if (i + 1 < nch) {
            asm volatile("cp.async.wait_group 1;" ::: "memory");
        } else {
            asm volatile("cp.async.wait_group 0;" ::: "memory");
        }
        __syncthreads();

        int s = i % NST;
        uint32_t aH = su + s * STAGE;
        uint32_t aL = aH + APB;
        uint32_t bH = aH + 2 * APB;
        uint32_t bL = bH + BPB;

#pragma unroll
        for (int ks = 0; ks < 2; ks++) {
            uint32_t a[MI][4], bh[NI][4], bl[NI][4];
            uint32_t kb = ks * 32 + lcol;
#pragma unroll
            for (int mi = 0; mi < MI; mi++)
                ldsm4(a[mi], aH + (wmBase + mi * 16 + lrow) * 80 + kb);
#pragma unroll
            for (int ni = 0; ni < NI; ni++)
                ldsm4(bh[ni], bH + (wnBase + ni * 16 + lrow) * 80 + kb);
#pragma unroll
            for (int mi = 0; mi < MI; mi++)
#pragma unroll
                for (int ni = 0; ni < NI; ni++) {
                    mma16816(acc[mi][2 * ni],     a[mi], bh[ni][0], bh[ni][2]);
                    mma16816(acc[mi][2 * ni + 1], a[mi], bh[ni][1], bh[ni][3]);
                }
#pragma unroll
            for (int ni = 0; ni < NI; ni++)
                ldsm4(bl[ni], bL + (wnBase + ni * 16 + lrow) * 80 + kb);
#pragma unroll
            for (int mi = 0; mi < MI; mi++)
#pragma unroll
                for (int ni = 0; ni < NI; ni++) {
                    mma16816(acc[mi][2 * ni],     a[mi], bl[ni][0], bl[ni][2]);
                    mma16816(acc[mi][2 * ni + 1], a[mi], bl[ni][1], bl[ni][3]);
                }
#pragma unroll
            for (int mi = 0; mi < MI; mi++)
                ldsm4(a[mi], aL + (wmBase + mi * 16 + lrow) * 80 + kb);
#pragma unroll
            for (int mi = 0; mi < MI; mi++)
#pragma unroll
                for (int ni = 0; ni < NI; ni++) {
                    mma16816(acc[mi][2 * ni],     a[mi], bh[ni][0], bh[ni][2]);
                    mma16816(acc[mi][2 * ni + 1], a[mi], bh[ni][1], bh[ni][3]);
                }
        }
        __syncthreads();
    }

#pragma unroll
    for (int mi = 0; mi < MI; mi++) {
        int r0 = m0 + wmBase + mi * 16 + (lane >> 2);
#pragma unroll
        for (int n8 = 0; n8 < 2 * NI; n8++) {
            int c = n0 + wnBase + n8 * 8 + (lane & 3) * 2;
            float2 o0, o1;
            o0.x = acc[mi][n8][0] * alpha; o0.y = acc[mi][n8][1] * alpha;
            o1.x = acc[mi][n8][2] * alpha; o1.y = acc[mi][n8][3] * alpha;
            if (bias) {
                float b0 = bias[c], b1 = bias[c + 1];
                o0.x += b0; o0.y += b1; o1.x += b0; o1.y += b1;
            }
            if (relu) {
                o0.x = fmaxf(o0.x, 0.f); o0.y = fmaxf(o0.y, 0.f);
                o1.x = fmaxf(o1.x, 0.f); o1.y = fmaxf(o1.y, 0.f);
            }
            long off0 = (long)r0 * ldc + c;
            long off1 = off0 + (long)8 * ldc;
            if (C) {
                *(float2*)(C + off0) = o0;
                *(float2*)(C + off1) = o1;
            }
            if (Ch) {
                ushort2 hh, ll;
                fsplit(o0.x, hh.x, ll.x); fsplit(o0.y, hh.y, ll.y);
                *(ushort2*)(Ch + off0) = hh; *(ushort2*)(Cl + off0) = ll;
                fsplit(o1.x, hh.x, ll.x); fsplit(o1.y, hh.y, ll.y);
                *(ushort2*)(Ch + off1) = hh; *(ushort2*)(Cl + off1) = ll;
            }
        }
    }
}

// ---------------- weight converters ----------------
// Packed projection weights: rows [0,1536)=in_w, [1536,1600)=qp, [1600,1664)=kp, [1664,2176)=vp, rest 0
__global__ void cvt_pack_k(const float* __restrict__ in_w, const float* __restrict__ qp_w,
                           const float* __restrict__ kp_w, const float* __restrict__ vp_w,
                           ushort4* __restrict__ h, ushort4* __restrict__ l)
{
    int i = blockIdx.x * 256 + threadIdx.x;               // one float4 per thread
    const int PER_L = NPACK * (DIM / 4);
    if (i >= LAYERS * PER_L) return;
    int lay = i / PER_L;
    int rem = i - lay * PER_L;
    int r = rem / (DIM / 4);
    int c4 = rem - r * (DIM / 4);
    float4 v = make_float4(0.f, 0.f, 0.f, 0.f);
    if (r < COL_QS)
        v = ((const float4*)(in_w + ((long)lay * 1536 + r) * DIM))[c4];
    else if (r < COL_KS)
        v = ((const float4*)(qp_w + ((long)lay * RANK + (r - COL_QS)) * DIM))[c4];
    else if (r < COL_VS)
        v = ((const float4*)(kp_w + ((long)lay * RANK + (r - COL_KS)) * DIM))[c4];
    else if (r < COL_VS + DIM)
        v = ((const float4*)(vp_w + ((long)lay * DIM + (r - COL_VS)) * DIM))[c4];
    ushort4 hh, ll;
    fsplit(v.x, hh.x, ll.x); fsplit(v.y, hh.y, ll.y);
    fsplit(v.z, hh.z, ll.z); fsplit(v.w, hh.w, ll.w);
    long o = (long)lay * NPACK * (DIM / 4) + (long)r * (DIM / 4) + c4;
    h[o] = hh; l[o] = ll;
}

__global__ void cvt_pb_k(const float* __restrict__ in_b, const float* __restrict__ qp_b,
                         const float* __restrict__ kp_b, const float* __restrict__ vp_b,
                         float* __restrict__ pb)
{
    int i = blockIdx.x * 256 + threadIdx.x;
    if (i >= LAYERS * NPACK) return;
    int lay = i / NPACK;
    int r = i - lay * NPACK;
    float v = 0.f;
    if (r < COL_QS) v = in_b[lay * 1536 + r];
    else if (r < COL_KS) v = qp_b[lay * RANK + (r - COL_QS)];
    else if (r < COL_VS) v = kp_b[lay * RANK + (r - COL_KS)];
    else if (r < COL_VS + DIM) v = vp_b[lay * DIM + (r - COL_VS)];
    pb[i] = v;
}

// fused dual-tensor converter
__global__ void cvt2_k(const float4* __restrict__ s1, ushort4* __restrict__ h1,
                       ushort4* __restrict__ l1, int n1,
                       const float4* __restrict__ s2, ushort4* __restrict__ h2,
                       ushort4* __restrict__ l2, int n2)
{
    int i = blockIdx.x * 256 + threadIdx.x;
    if (i >= n1 + n2) return;
    const float4* s; ushort4 *h, *l; int j;
    if (i < n1) { s = s1; h = h1; l = l1; j = i; }
    else        { s = s2; h = h2; l = l2; j = i - n1; }
    float4 v = s[j];
    ushort4 hh, ll;
    fsplit(v.x, hh.x, ll.x); fsplit(v.y, hh.y, ll.y);
    fsplit(v.z, hh.z, ll.z); fsplit(v.w, hh.w, ll.w);
    h[j] = hh; l[j] = ll;
}

// V^T planes (dense) from packed px: vt[z][d][s] = px[(b*SEQ+s)*NPACK + 1024 + h*64 + d]
__global__ void vt_k(const float* __restrict__ px, u16* __restrict__ vh, u16* __restrict__ vl)
{
    __shared__ float t[32][33];
    int z = blockIdx.z, b = z >> 3, h = z & 7;
    int s0 = blockIdx.x * 32, d0 = blockIdx.y * 32;
    int tx = threadIdx.x, ty = threadIdx.y;   // (32, 8)
#pragma unroll
    for (int j = 0; j < 4; j++) {
        int s = s0 + ty + j * 8;
        t[ty + j * 8][tx] = px[((long)(b * SEQ + s)) * NPACK + 2 * DIM + h * HDIM + d0 + tx];
    }
    __syncthreads();
#pragma unroll
    for (int j = 0; j < 4; j++) {
        int d = d0 + ty + j * 8;
        long o = ((long)z * HDIM + d) * SEQ + s0 + tx;
        u16 hh, ll;
        fsplit(t[tx][ty + j * 8], hh, ll);
        vh[o] = hh; vl[o] = ll;
    }
}

// Vs^T planes (sparse) from packed px cols [COL_VS, COL_VS+512)
__global__ void vst_k(const float* __restrict__ px, u16* __restrict__ vh, u16* __restrict__ vl)
{
    __shared__ float t[32][33];
    int b = blockIdx.z;
    int s0 = blockIdx.x * 32, d0 = blockIdx.y * 32;
    int tx = threadIdx.x, ty = threadIdx.y;   // (32, 8)
#pragma unroll
    for (int j = 0; j < 4; j++) {
        int s = s0 + ty + j * 8;
        t[ty + j * 8][tx] = px[((long)(b * SEQ + s)) * NPACK + COL_VS + d0 + tx];
    }
    __syncthreads();
#pragma unroll
    for (int j = 0; j < 4; j++) {
        int d = d0 + ty + j * 8;
        long o = ((long)(b * DIM + d)) * SEQ + s0 + tx;
        u16 hh, ll;
        fsplit(t[tx][ty + j * 8], hh, ll);
        vh[o] = hh; vl[o] = ll;
    }
}

// ---------------- embedding (+ x planes) ----------------
__global__ void embed_k(const int* __restrict__ src, const float* __restrict__ emb,
                        const float* __restrict__ pe, float* __restrict__ x,
                        u16* __restrict__ xh, u16* __restrict__ xl)
{
    int t = blockIdx.x;
    int tid = threadIdx.x;
    int s = t & (SEQ - 1);
    int tok = src[t];
    int d = tid * 2;
    float2 e = *(const float2*)(emb + (long)tok * DIM + d);
    float2 p = *(const float2*)(pe + (long)s * DIM + d);
    float2 o;
    o.x = e.x * 22.627416998f + p.x;
    o.y = e.y * 22.627416998f + p.y;
    long off = (long)t * DIM + d;
    *(float2*)(x + off) = o;
    ushort2 hh, ll;
    fsplit(o.x, hh.x, ll.x); fsplit(o.y, hh.y, ll.y);
    *(ushort2*)(xh + off) = hh;
    *(ushort2*)(xl + off) = ll;
}

// ---------------- row softmax -> P hi/lo planes ----------------
__global__ void softmax_rows(const float* __restrict__ S, u16* __restrict__ Ph,
                             u16* __restrict__ Pl)
{
    __shared__ float red[256];
    long row = blockIdx.x;
    const float* p = S + row * (long)SEQ;
    int tid = threadIdx.x;
    float4 v0 = *(const float4*)(p + 4 * tid);
    float4 v1 = *(const float4*)(p + 4 * tid + 1024);
    float m = fmaxf(fmaxf(fmaxf(v0.x, v0.y), fmaxf(v0.z, v0.w)),
                    fmaxf(fmaxf(v1.x, v1.y), fmaxf(v1.z, v1.w)));
    red[tid] = m; __syncthreads();
    for (int s = 128; s > 0; s >>= 1) { if (tid < s) red[tid] = fmaxf(red[tid], red[tid + s]); __syncthreads(); }
    float M = red[0]; __syncthreads();
    v0.x = __expf(v0.x - M); v0.y = __expf(v0.y - M); v0.z = __expf(v0.z - M); v0.w = __expf(v0.w - M);
    v1.x = __expf(v1.x - M); v1.y = __expf(v1.y - M); v1.z = __expf(v1.z - M); v1.w = __expf(v1.w - M);
    float sum = v0.x + v0.y + v0.z + v0.w + v1.x + v1.y + v1.z + v1.w;
    red[tid] = sum; __syncthreads();
    for (int s = 128; s > 0; s >>= 1) { if (tid < s) red[tid] += red[tid + s]; __syncthreads(); }
    float inv = 1.f / red[0];
    v0.x *= inv; v0.y *= inv; v0.z *= inv; v0.w *= inv;
    v1.x *= inv; v1.y *= inv; v1.z *= inv; v1.w *= inv;
    long b0 = row * (long)SEQ + 4 * tid;
    ushort4 hh, ll;
    fsplit(v0.x, hh.x, ll.x); fsplit(v0.y, hh.y, ll.y);
    fsplit(v0.z, hh.z, ll.z); fsplit(v0.w, hh.w, ll.w);
    *(ushort4*)(Ph + b0) = hh; *(ushort4*)(Pl + b0) = ll;
    fsplit(v1.x, hh.x, ll.x); fsplit(v1.y, hh.y, ll.y);
    fsplit(v1.z, hh.z, ll.z); fsplit(v1.w, hh.w, ll.w);
    *(ushort4*)(Ph + b0 + 1024) = hh; *(ushort4*)(Pl + b0 + 1024) = ll;
}

// ---------------- sparse select ----------------
__device__ __forceinline__ unsigned f2k(float f)
{
    unsigned u = __float_as_uint(f);
    return (u & 0x80000000u) ? ~u : (u | 0x80000000u);
}

__global__ void __launch_bounds__(256) sparse_sel(
    const float* __restrict__ qk, u16* __restrict__ sph, u16* __restrict__ spl)
{
    __shared__ float logit[SEQ];
    __shared__ unsigned hist[256];
    __shared__ unsigned suf[256];
    __shared__ float red[256];
    __shared__ unsigned sh_prefix;
    __shared__ int sh_remaining;

    long row = blockIdx.x;
    int tid = threadIdx.x;
    const float* p = qk + row * (long)SEQ;

    for (int k = tid; k < SEQ; k += 256) logit[k] = p[k];
    __syncthreads();

    float lm = -3.4e38f;
    for (int k = tid; k < SEQ; k += 256) lm = fmaxf(lm, logit[k]);
    red[tid] = lm; __syncthreads();
    for (int s = 128; s > 0; s >>= 1) { if (tid < s) red[tid] = fmaxf(red[tid], red[tid + s]); __syncthreads(); }
    float Lmax = red[0]; __syncthreads();

    float zacc = 0.f;
    for (int k = tid; k < SEQ; k += 256) zacc += __expf(logit[k] - Lmax);
    red[tid] = zacc; __syncthreads();
    for (int s = 128; s > 0; s >>= 1) { if (tid < s) red[tid] += red[tid + s]; __syncthreads(); }
    float Z = red[0]; __syncthreads();

    unsigned prefix = 0; int remaining = KTOP;
    for (int shift = 24; shift >= 0; shift -= 8) {
        hist[tid] = 0; __syncthreads();
        unsigned upmask = (shift == 24) ? 0u : (0xFFFFFFFFu << (shift + 8));
        for (int k = tid; k < SEQ; k += 256) {
            unsigned key = f2k(logit[k]);
            if ((key & upmask) == prefix)
                atomicAdd(&hist[(key >> shift) & 255], 1u);
        }
        __syncthreads();
        suf[tid] = hist[tid]; __syncthreads();
        for (int off = 1; off < 256; off <<= 1) {
            unsigned add = (tid + off < 256) ? suf[tid + off] : 0u;
            __syncthreads();
            suf[tid] += add;
            __syncthreads();
        }
        unsigned shere = suf[tid];
        unsigned snext = (tid < 255) ? suf[tid + 1] : 0u;
        if (shere >= (unsigned)remaining && snext < (unsigned)remaining) {
            sh_prefix = prefix | ((unsigned)tid << shift);
            sh_remaining = remaining - (int)snext;
        }
        __syncthreads();
        prefix = sh_prefix; remaining = sh_remaining;
        __syncthreads();
    }
    unsigned thr = prefix;

    float w8[8];
    float dsum = 0.f;
#pragma unroll
    for (int j = 0; j < 8; j++) {
        int k = tid + 256 * j;
        float l = logit[k];
        bool keep = (f2k(l) >= thr);
        float w = keep ? __expf(l - Lmax) : 0.f;
        w8[j] = w;
        dsum += w;
    }
    red[tid] = dsum; __syncthreads();
    for (int s = 128; s > 0; s >>= 1) { if (tid < s) red[tid] += red[tid + s]; __syncthreads(); }
    float inv = 1.f / (red[0] + 1e-9f * Z);

#pragma unroll
    for (int j = 0; j < 8; j++) {
        int k = tid + 256 * j;
        float w = w8[j] * inv;
        u16 h, l;
        fsplit(w, h, l);
        long o = row * (long)SEQ + k;
        sph[o] = h; spl[o] = l;
    }
}

// ---------------- gated fusion + LN1 ----------------
__global__ void fuse_ln1_k(float* __restrict__ x, const float* __restrict__ dn,
                           const float* __restrict__ sp, const float* __restrict__ lam,
                           int layer, const float* __restrict__ gam, const float* __restrict__ bet,
                           u16* __restrict__ xh, u16* __restrict__ xl)
{
    __shared__ float red[256];
    int row = blockIdx.x, tid = threadIdx.x;
    long off = (long)row * DIM + 2 * tid;
    float g = 1.f / (1.f + expf(-lam[layer]));
    float2 xv = *(const float2*)(x + off);
    float2 dv = *(const float2*)(dn + off);
    float2 sv = *(const float2*)(sp + off);
    float y0 = xv.x + g * dv.x + (1.f - g) * sv.x;
    float y1 = xv.y + g * dv.y + (1.f - g) * sv.y;
    red[tid] = y0 + y1; __syncthreads();
    for (int s = 128; s > 0; s >>= 1) { if (tid < s) red[tid] += red[tid + s]; __syncthreads(); }
    float mean = red[0] * (1.f / DIM); __syncthreads();
    float d0 = y0 - mean, d1 = y1 - mean;
    red[tid] = d0 * d0 + d1 * d1; __syncthreads();
    for (int s = 128; s > 0; s >>= 1) { if (tid < s) red[tid] += red[tid + s]; __syncthreads(); }
    float inv = 1.f / sqrtf(red[0] * (1.f / DIM) + 1e-5f);
    int dc = 2 * tid;
    float2 gm = *(const float2*)(gam + dc);
    float2 bt = *(const float2*)(bet + dc);
    float2 o; o.x = d0 * inv * gm.x + bt.x; o.y = d1 * inv * gm.y + bt.y;
    *(float2*)(x + off) = o;
    ushort2 hh, ll;
    fsplit(o.x, hh.x, ll.x); fsplit(o.y, hh.y, ll.y);
    *(ushort2*)(xh + off) = hh;
    *(ushort2*)(xl + off) = ll;
}

// ---------------- residual + LN2 ----------------
__global__ void add_ln2_k(float* __restrict__ x, const float* __restrict__ f,
                          const float* __restrict__ gam, const float* __restrict__ bet,
                          u16* __restrict__ xh, u16* __restrict__ xl)
{
    __shared__ float red[256];
    int row = blockIdx.x, tid = threadIdx.x;
    long off = (long)row * DIM + 2 * tid;
    float2 xv = *(const float2*)(x + off);
    float2 fv = *(const float2*)(f + off);
    float y0 = xv.x + fv.x;
    float y1 = xv.y + fv.y;
    red[tid] = y0 + y1; __syncthreads();
    for (int s = 128; s > 0; s >>= 1) { if (tid < s) red[tid] += red[tid + s]; __syncthreads(); }
    float mean = red[0] * (1.f / DIM); __syncthreads();
    float d0 = y0 - mean, d1 = y1 - mean;
    red[tid] = d0 * d0 + d1 * d1; __syncthreads();
    for (int s = 128; s > 0; s >>= 1) { if (tid < s) red[tid] += red[tid + s]; __syncthreads(); }
    float inv = 1.f / sqrtf(red[0] * (1.f / DIM) + 1e-5f);
    int dc = 2 * tid;
    float2 gm = *(const float2*)(gam + dc);
    float2 bt = *(const float2*)(bet + dc);
    float2 o; o.x = d0 * inv * gm.x + bt.x; o.y = d1 * inv * gm.y + bt.y;
    *(float2*)(x + off) = o;
    ushort2 hh, ll;
    fsplit(o.x, hh.x, ll.x); fsplit(o.y, hh.y, ll.y);
    *(ushort2*)(xh + off) = hh;
    *(ushort2*)(xl + off) = ll;
}

// ---------------- host-side helpers ----------------
template <int TN>
static void launch_tc(const u16* Ah, const u16* Al, const u16* Bh, const u16* Bl,
                      const float* bias, float* C, u16* Ch, u16* Cl,
                      int M, int N, int K, int lda, int ldb, int ldc,
                      int Z = 1, long sAo = 0, long sAi = 0, long sBo = 0, long sBi = 0,
                      long sCo = 0, long sCi = 0, int zdiv = 1,
                      float alpha = 1.f, int relu = 0)
{
    constexpr int SM = 3 * (2 * 128 * 80 + 2 * TN * 80);
    static bool attr_set = false;
    if (!attr_set) {
        cudaFuncSetAttribute(mm_gemm<TN>, cudaFuncAttributeMaxDynamicSharedMemorySize, SM);
        attr_set = true;
    }
    dim3 g(N / TN, M / 128, Z);
    mm_gemm<TN><<<g, 256, SM>>>(Ah, Al, Bh, Bl, bias, C, Ch, Cl,
                                K, lda, ldb, ldc,
                                sAo, sAi, sBo, sBi, sCo, sCi, zdiv, alpha, relu);
}

extern "C" void kernel_launch(void* const* d_in, const int* in_sizes, int n_in,
                              void* d_out, int out_size)
{
    const int*   SRC   = (const int*)  d_in[0];
    const float* EMB   = (const float*)d_in[1];
    const float* PE    = (const float*)d_in[2];
    const float* IN_W  = (const float*)d_in[3];
    const float* IN_B  = (const float*)d_in[4];
    const float* OUT_W = (const float*)d_in[5];
    const float* OUT_B = (const float*)d_in[6];
    const float* QP_W  = (const float*)d_in[7];
    const float* QP_B  = (const float*)d_in[8];
    const float* KP_W  = (const float*)d_in[9];
    const float* KP_B  = (const float*)d_in[10];
    const float* VP_W  = (const float*)d_in[11];
    const float* VP_B  = (const float*)d_in[12];
    const float* LAM   = (const float*)d_in[13];
    const float* FF1_W = (const float*)d_in[14];
    const float* FF1_B = (const float*)d_in[15];
    const float* FF2_W = (const float*)d_in[16];
    const float* FF2_B = (const float*)d_in[17];
    const float* LN1S  = (const float*)d_in[18];
    const float* LN1B  = (const float*)d_in[19];
    const float* LN2S  = (const float*)d_in[20];
    const float* LN2B  = (const float*)d_in[21];
    const float* FIN_W = (const float*)d_in[22];
    const float* FIN_B = (const float*)d_in[23];
    float* OUT = (float*)d_out;

    float *px, *x, *scores, *aproj, *sp, *fft, *pb;
    cudaGetSymbolAddress((void**)&px, g_px);       cudaGetSymbolAddress((void**)&x, g_x);
    cudaGetSymbolAddress((void**)&scores, g_scores); cudaGetSymbolAddress((void**)&aproj, g_aproj);
    cudaGetSymbolAddress((void**)&sp, g_sparse);   cudaGetSymbolAddress((void**)&fft, g_fft);
    cudaGetSymbolAddress((void**)&pb, g_pb);

    u16 *pxh, *pxl, *xh, *xl, *Ph, *Pl, *dh, *dl, *fh, *fl, *vth, *vtl;
    u16 *sph, *spl, *vsth, *vstl;
    cudaGetSymbolAddress((void**)&pxh, g_pxh); cudaGetSymbolAddress((void**)&pxl, g_pxl);
    cudaGetSymbolAddress((void**)&xh, g_xh);   cudaGetSymbolAddress((void**)&xl, g_xl);
    cudaGetSymbolAddress((void**)&Ph, g_Ph);   cudaGetSymbolAddress((void**)&Pl, g_Pl);
    cudaGetSymbolAddress((void**)&dh, g_dh);   cudaGetSymbolAddress((void**)&dl, g_dl);
    cudaGetSymbolAddress((void**)&fh, g_fh);   cudaGetSymbolAddress((void**)&fl, g_fl);
    cudaGetSymbolAddress((void**)&vth, g_vth); cudaGetSymbolAddress((void**)&vtl, g_vtl);
    cudaGetSymbolAddress((void**)&sph, g_sph); cudaGetSymbolAddress((void**)&spl, g_spl);
    cudaGetSymbolAddress((void**)&vsth, g_vsth); cudaGetSymbolAddress((void**)&vstl, g_vstl);

    u16 *pwh, *pwl, *outwh, *outwl, *f1wh, *f1wl, *f2wh, *f2wl, *finwh, *finwl;
    cudaGetSymbolAddress((void**)&pwh, g_pwh);     cudaGetSymbolAddress((void**)&pwl, g_pwl);
    cudaGetSymbolAddress((void**)&outwh, g_outwh); cudaGetSymbolAddress((void**)&outwl, g_outwl);
    cudaGetSymbolAddress((void**)&f1wh, g_f1wh);   cudaGetSymbolAddress((void**)&f1wl, g_f1wl);
    cudaGetSymbolAddress((void**)&f2wh, g_f2wh);   cudaGetSymbolAddress((void**)&f2wl, g_f2wl);
    cudaGetSymbolAddress((void**)&finwh, g_finwh); cudaGetSymbolAddress((void**)&finwl, g_finwl);

    // 1: embedding (independent of weight conversion)
    embed_k<<<TOKENS, 256>>>(SRC, EMB, PE, x, xh, xl);

    // 2-5: weight conversion (packed + fused rest)
    {
        int tot = LAYERS * NPACK * (DIM / 4);
        cvt_pack_k<<<(tot + 255) / 256, 256>>>(IN_W, QP_W, KP_W, VP_W,
                                               (ushort4*)pwh, (ushort4*)pwl);
    }
    cvt_pb_k<<<(LAYERS * NPACK + 255) / 256, 256>>>(IN_B, QP_B, KP_B, VP_B, pb);
    {
        int n1 = LAYERS * DIM * DIM / 4, n2 = LAYERS * FFD * DIM / 4;
        cvt2_k<<<(n1 + n2 + 255) / 256, 256>>>(
            (const float4*)OUT_W, (ushort4*)outwh, (ushort4*)outwl, n1,
            (const float4*)FF1_W, (ushort4*)f1wh, (ushort4*)f1wl, n2);
    }
    {
        int n1 = LAYERS * DIM * FFD / 4, n2 = VOCAB * DIM / 4;
        cvt2_k<<<(n1 + n2 + 255) / 256, 256>>>(
            (const float4*)FF2_W, (ushort4*)f2wh, (ushort4*)f2wl, n1,
            (const float4*)FIN_W, (ushort4*)finwh, (ushort4*)finwl, n2);
    }

    for (int l = 0; l < LAYERS; l++) {
        long wq  = (long)l * NPACK * DIM;
        long wo  = (long)l * DIM * DIM;
        long wf1 = (long)l * FFD * DIM;
        long wf2 = (long)l * DIM * FFD;

        // 6 (layer 0): packed projections = x @ [in|qp|kp|vp]^T + b  -> px + planes
        launch_tc<256>(xh, xl, pwh + wq, pwl + wq, pb + (long)l * NPACK,
                       px, pxh, pxl, TOKENS, NPACK, DIM, DIM, DIM, NPACK);

        // dense scores = Q @ K^T / 8 per (b,h)
        launch_tc<256>(pxh, pxl, pxh + DIM, pxl + DIM, nullptr,
                       scores, nullptr, nullptr,
                       SEQ, SEQ, HDIM, NPACK, NPACK, SEQ,
                       16, (long)SEQ * NPACK, (long)HDIM,
                       (long)SEQ * NPACK, (long)HDIM,
                       (long)HEADS * SEQ * SEQ, (long)SEQ * SEQ,
                       HEADS, 0.125f, 0);

        softmax_rows<<<16 * SEQ, 256>>>(scores, Ph, Pl);

        vt_k<<<dim3(SEQ / 32, HDIM / 32, 16), dim3(32, 8)>>>(px, vth, vtl);

        // dense = P @ V per (b,h) -> planes only
        launch_tc<64>(Ph, Pl, vth, vtl, nullptr, nullptr, dh, dl,
                      SEQ, HDIM, SEQ, SEQ, SEQ, DIM,
                      16, (long)HEADS * SEQ * SEQ, (long)SEQ * SEQ,
                      (long)HEADS * HDIM * SEQ, (long)HDIM * SEQ,
                      (long)SEQ * DIM, (long)HDIM,
                      HEADS, 1.f, 0);

        // dense projection -> aproj fp32
        launch_tc<128>(dh, dl, outwh + wo, outwl + wo, OUT_B + (long)l * DIM,
                       aproj, nullptr, nullptr, TOKENS, DIM, DIM, DIM, DIM, DIM);

        // low-rank logits qk = Qs @ Ks^T / sqrt(R) per batch (cols from packed planes)
        launch_tc<256>(pxh + COL_QS, pxl + COL_QS, pxh + COL_KS, pxl + COL_KS, nullptr,
                       scores, nullptr, nullptr,
                       SEQ, SEQ, RANK, NPACK, NPACK, SEQ,
                       2, (long)SEQ * NPACK, 0, (long)SEQ * NPACK, 0,
                       (long)SEQ * SEQ, 0, 1, 0.125f, 0);

        sparse_sel<<<TOKENS, 256>>>(scores, sph, spl);

        vst_k<<<dim3(SEQ / 32, DIM / 32, 2), dim3(32, 8)>>>(px, vsth, vstl);

        // sparse = sp @ Vs per batch
        launch_tc<128>(sph, spl, vsth, vstl, nullptr, sp, nullptr, nullptr,
                       SEQ, DIM, SEQ, SEQ, SEQ, DIM,
                       2, (long)SEQ * SEQ, 0, (long)DIM * SEQ, 0,
                       (long)SEQ * DIM, 0, 1, 1.f, 0);

        fuse_ln1_k<<<TOKENS, 256>>>(x, aproj, sp, LAM, l,
                                    LN1S + (long)l * DIM, LN1B + (long)l * DIM, xh, xl);

        // FFN (planes only for hidden)
        launch_tc<256>(xh, xl, f1wh + wf1, f1wl + wf1, FF1_B + (long)l * FFD,
                       nullptr, fh, fl, TOKENS, FFD, DIM, DIM, DIM, FFD,
                       1, 0, 0, 0, 0, 0, 0, 1, 1.f, 1);
        launch_tc<128>(fh, fl, f2wh + wf2, f2wl + wf2, FF2_B + (long)l * DIM,
                       fft, nullptr, nullptr, TOKENS, DIM, FFD, FFD, FFD, DIM);

        add_ln2_k<<<TOKENS, 256>>>(x, fft, LN2S + (long)l * DIM, LN2B + (long)l * DIM, xh, xl);
    }

    // final vocab projection
    launch_tc<256>(xh, xl, finwh, finwl, FIN_B, OUT, nullptr, nullptr,
                   TOKENS, VOCAB, DIM, DIM, DIM, VOCAB);
}

// round 8
// speedup vs baseline: 1.5245x; 1.0050x over previous
#include <cuda_runtime.h>
#include <cuda_bf16.h>
#include <math.h>
#include <stdint.h>

#define SEQ    2048
#define TOKENS 4096
#define DIM    512
#define HEADS  8
#define HDIM   64
#define RANK   64
#define LAYERS 6
#define VOCAB  32000
#define FFD    2048
#define KTOP   409
#define NPACK  2304   // 1536 qkv | 64 qs | 64 ks | 512 vs | 128 pad
#define COL_QS 1536
#define COL_KS 1600
#define COL_VS 1664

typedef unsigned short u16;

// ---------------- fp32 scratch ----------------
__device__ float g_px[(size_t)TOKENS * NPACK];     // packed projections fp32
__device__ float g_x[TOKENS * DIM];
__device__ float g_scores[(size_t)16 * SEQ * SEQ]; // dense scores / qk logits
__device__ float g_aproj[TOKENS * DIM];
__device__ float g_sparse[TOKENS * DIM];
__device__ float g_fft[TOKENS * DIM];

// ---------------- bf16 hi/lo planes (activations) ----------------
__device__ alignas(16) u16 g_pxh[(size_t)TOKENS * NPACK], g_pxl[(size_t)TOKENS * NPACK];
__device__ alignas(16) u16 g_xh[TOKENS * DIM],       g_xl[TOKENS * DIM];
__device__ alignas(16) u16 g_Ph[(size_t)16 * SEQ * SEQ], g_Pl[(size_t)16 * SEQ * SEQ];
__device__ alignas(16) u16 g_dh[TOKENS * DIM],       g_dl[TOKENS * DIM];
__device__ alignas(16) u16 g_fh[TOKENS * FFD],       g_fl[TOKENS * FFD];
__device__ alignas(16) u16 g_vth[16 * HDIM * SEQ],   g_vtl[16 * HDIM * SEQ];
__device__ alignas(16) u16 g_sph[(size_t)2 * SEQ * SEQ], g_spl[(size_t)2 * SEQ * SEQ];
__device__ alignas(16) u16 g_vsth[2 * DIM * SEQ],    g_vstl[2 * DIM * SEQ];

// ---------------- bf16 hi/lo planes (weights) ----------------
__device__ alignas(16) u16 g_pwh[LAYERS * NPACK * DIM], g_pwl[LAYERS * NPACK * DIM];
__device__ float g_pb[LAYERS * NPACK];
__device__ alignas(16) u16 g_outwh[LAYERS * DIM * DIM],  g_outwl[LAYERS * DIM * DIM];
__device__ alignas(16) u16 g_f1wh[LAYERS * FFD * DIM],   g_f1wl[LAYERS * FFD * DIM];
__device__ alignas(16) u16 g_f2wh[LAYERS * DIM * FFD],   g_f2wl[LAYERS * DIM * FFD];
__device__ alignas(16) u16 g_finwh[VOCAB * DIM],         g_finwl[VOCAB * DIM];

// ---------------- small device helpers ----------------
__device__ __forceinline__ void fsplit(float x, u16& h, u16& l)
{
    __nv_bfloat16 bh = __float2bfloat16_rn(x);
    float fh = __bfloat162float(bh);
    __nv_bfloat16 bl = __float2bfloat16_rn(x - fh);
    h = *reinterpret_cast<u16*>(&bh);
    l = *reinterpret_cast<u16*>(&bl);
}

__device__ __forceinline__ uint32_t smem_u32(const void* p)
{
    uint32_t a;
    asm("{ .reg .u64 t; cvta.to.shared.u64 t, %1; cvt.u32.u64 %0, t; }" : "=r"(a) : "l"(p));
    return a;
}

__device__ __forceinline__ void cpa16(uint32_t dst, const void* src)
{
    asm volatile("cp.async.cg.shared.global [%0], [%1], 16;" :: "r"(dst), "l"(src) : "memory");
}

__device__ __forceinline__ void ldsm4(uint32_t* r, uint32_t addr)
{
    asm volatile("ldmatrix.sync.aligned.m8n8.x4.shared.b16 {%0,%1,%2,%3}, [%4];"
                 : "=r"(r[0]), "=r"(r[1]), "=r"(r[2]), "=r"(r[3]) : "r"(addr));
}

__device__ __forceinline__ void mma16816(float* c, const uint32_t* a, uint32_t b0, uint32_t b1)
{
    asm volatile(
        "mma.sync.aligned.m16n8k16.row.col.f32.bf16.bf16.f32 "
        "{%0,%1,%2,%3}, {%4,%5,%6,%7}, {%8,%9}, {%0,%1,%2,%3};"
        : "+f"(c[0]), "+f"(c[1]), "+f"(c[2]), "+f"(c[3])
        : "r"(a[0]), "r"(a[1]), "r"(a[2]), "r"(a[3]), "r"(b0), "r"(b1));
}

// ---------------- HMMA bf16x3 GEMM: C = alpha * (A @ B^T) + bias ----------------
// 3-stage cp.async pipeline, single barrier per K-chunk, front-loaded fragments.
template <int TN>
__global__ void __launch_bounds__(256)
mm_gemm(const u16* __restrict__ Ah, const u16* __restrict__ Al,
        const u16* __restrict__ Bh, const u16* __restrict__ Bl,
        const float* __restrict__ bias, float* __restrict__ C,
        u16* __restrict__ Ch, u16* __restrict__ Cl,
        int K, int lda, int ldb, int ldc,
        long sAo, long sAi, long sBo, long sBi, long sCo, long sCi,
        int zdiv, float alpha, int relu)
{
    constexpr int MI  = (TN >= 128) ? 4 : 2;
    constexpr int NI  = (TN == 256) ? 4 : 2;
    constexpr int APB = 128 * 80;
    constexpr int BPB = TN * 80;
    constexpr int STAGE = 2 * APB + 2 * BPB;
    constexpr int NST = 3;

    extern __shared__ char smem[];
    const uint32_t su = smem_u32(smem);
    const int tid = threadIdx.x;
    const int wid = tid >> 5;
    const int lane = tid & 31;

    int z = blockIdx.z;
    int zo = z / zdiv, zi = z - zo * zdiv;
    long ao = (long)zo * sAo + (long)zi * sAi;
    long bo = (long)zo * sBo + (long)zi * sBi;
    long co = (long)zo * sCo + (long)zi * sCi;
    Ah += ao; Al += ao; Bh += bo; Bl += bo;
    if (C)  C  += co;
    if (Ch) { Ch += co; Cl += co; }
    const int m0 = blockIdx.y * 128;
    const int n0 = blockIdx.x * TN;

    const int wmBase = (TN >= 128) ? (wid & 1) * 64 : (wid & 3) * 32;
    const int wnBase = (TN == 256) ? (wid >> 1) * 64
                     : (TN == 128) ? (wid >> 1) * 32 : (wid >> 2) * 32;

    float acc[MI][2 * NI][4];
#pragma unroll
    for (int mi = 0; mi < MI; mi++)
#pragma unroll
        for (int n8 = 0; n8 < 2 * NI; n8++)
#pragma unroll
            for (int q = 0; q < 4; q++) acc[mi][n8][q] = 0.f;

    const int nch = K >> 5;
    const int ar = tid >> 2, ac = tid & 3;
    auto issue = [&](int i) {
        int s = i % NST;
        int k0 = i << 5;
        uint32_t st = su + s * STAGE;
#pragma unroll
        for (int j = 0; j < 2; j++) {
            int r = ar + 64 * j;
            long g = (long)(m0 + r) * lda + k0 + ac * 8;
            uint32_t d = st + r * 80 + ac * 16;
            cpa16(d, Ah + g);
            cpa16(d + APB, Al + g);
        }
#pragma unroll
        for (int j = 0; j < TN / 64; j++) {
            int r = ar + 64 * j;
            long g = (long)(n0 + r) * ldb + k0 + ac * 8;
            uint32_t d = st + 2 * APB + r * 80 + ac * 16;
            cpa16(d, Bh + g);
            cpa16(d + BPB, Bl + g);
        }
        asm volatile("cp.async.commit_group;" ::: "memory");
    };

    issue(0);
    if (nch > 1) issue(1);
    const uint32_t lrow = lane & 15;
    const uint32_t lcol = (lane >> 4) * 16;

    for (int i = 0; i < nch; i++) {
        if (i + 1 < nch) {
            asm volatile("cp.async.wait_group 1;" ::: "memory");
        } else {
            asm volatile("cp.async.wait_group 0;" ::: "memory");
        }
        __syncthreads();
        // stage (i+2)%NST was last READ at iteration i-1; the barrier above
        // ordered those reads, so overwriting it now is safe.
        if (i + 2 < nch) issue(i + 2);

        int s = i % NST;
        uint32_t aH = su + s * STAGE;
        uint32_t aL = aH + APB;
        uint32_t bH = aH + 2 * APB;
        uint32_t bL = bH + BPB;

#pragma unroll
        for (int ks = 0; ks < 2; ks++) {
            uint32_t a[MI][4], al[MI][4], bh[NI][4], bl[NI][4];
            uint32_t kb = ks * 32 + lcol;
            // front-load ALL fragments for this ks-step
#pragma unroll
            for (int mi = 0; mi < MI; mi++)
                ldsm4(a[mi], aH + (wmBase + mi * 16 + lrow) * 80 + kb);
#pragma unroll
            for (int ni = 0; ni < NI; ni++)
                ldsm4(bh[ni], bH + (wnBase + ni * 16 + lrow) * 80 + kb);
#pragma unroll
            for (int ni = 0; ni < NI; ni++)
                ldsm4(bl[ni], bL + (wnBase + ni * 16 + lrow) * 80 + kb);
#pragma unroll
            for (int mi = 0; mi < MI; mi++)
                ldsm4(al[mi], aL + (wmBase + mi * 16 + lrow) * 80 + kb);
            // pass 1: Ah * Bh
#pragma unroll
            for (int mi = 0; mi < MI; mi++)
#pragma unroll
                for (int ni = 0; ni < NI; ni++) {
                    mma16816(acc[mi][2 * ni],     a[mi], bh[ni][0], bh[ni][2]);
                    mma16816(acc[mi][2 * ni + 1], a[mi], bh[ni][1], bh[ni][3]);
                }
            // pass 2: Ah * Bl
#pragma unroll
            for (int mi = 0; mi < MI; mi++)
#pragma unroll
                for (int ni = 0; ni < NI; ni++) {
                    mma16816(acc[mi][2 * ni],     a[mi], bl[ni][0], bl[ni][2]);
                    mma16816(acc[mi][2 * ni + 1], a[mi], bl[ni][1], bl[ni][3]);
                }
            // pass 3: Al * Bh
#pragma unroll
            for (int mi = 0; mi < MI; mi++)
#pragma unroll
                for (int ni = 0; ni < NI; ni++) {
                    mma16816(acc[mi][2 * ni],     al[mi], bh[ni][0], bh[ni][2]);
                    mma16816(acc[mi][2 * ni + 1], al[mi], bh[ni][1], bh[ni][3]);
                }
        }
    }

#pragma unroll
    for (int mi = 0; mi < MI; mi++) {
        int r0 = m0 + wmBase + mi * 16 + (lane >> 2);
#pragma unroll
        for (int n8 = 0; n8 < 2 * NI; n8++) {
            int c = n0 + wnBase + n8 * 8 + (lane & 3) * 2;
            float2 o0, o1;
            o0.x = acc[mi][n8][0] * alpha; o0.y = acc[mi][n8][1] * alpha;
            o1.x = acc[mi][n8][2] * alpha; o1.y = acc[mi][n8][3] * alpha;
            if (bias) {
                float b0 = bias[c], b1 = bias[c + 1];
                o0.x += b0; o0.y += b1; o1.x += b0; o1.y += b1;
            }
            if (relu) {
                o0.x = fmaxf(o0.x, 0.f); o0.y = fmaxf(o0.y, 0.f);
                o1.x = fmaxf(o1.x, 0.f); o1.y = fmaxf(o1.y, 0.f);
            }
            long off0 = (long)r0 * ldc + c;
            long off1 = off0 + (long)8 * ldc;
            if (C) {
                *(float2*)(C + off0) = o0;
                *(float2*)(C + off1) = o1;
            }
            if (Ch) {
                ushort2 hh, ll;
                fsplit(o0.x, hh.x, ll.x); fsplit(o0.y, hh.y, ll.y);
                *(ushort2*)(Ch + off0) = hh; *(ushort2*)(Cl + off0) = ll;
                fsplit(o1.x, hh.x, ll.x); fsplit(o1.y, hh.y, ll.y);
                *(ushort2*)(Ch + off1) = hh; *(ushort2*)(Cl + off1) = ll;
            }
        }
    }
}

// ---------------- weight converters ----------------
// Packed projection weights + bias in one kernel.
__global__ void cvt_pack_k(const float* __restrict__ in_w, const float* __restrict__ qp_w,
                           const float* __restrict__ kp_w, const float* __restrict__ vp_w,
                           const float* __restrict__ in_b, const float* __restrict__ qp_b,
                           const float* __restrict__ kp_b, const float* __restrict__ vp_b,
                           ushort4* __restrict__ h, ushort4* __restrict__ l,
                           float* __restrict__ pb)
{
    int i = blockIdx.x * 256 + threadIdx.x;
    if (i < LAYERS * NPACK) {                 // bias lanes
        int lay = i / NPACK;
        int r = i - lay * NPACK;
        float v = 0.f;
        if (r < COL_QS) v = in_b[lay * 1536 + r];
        else if (r < COL_KS) v = qp_b[lay * RANK + (r - COL_QS)];
        else if (r < COL_VS) v = kp_b[lay * RANK + (r - COL_KS)];
        else if (r < COL_VS + DIM) v = vp_b[lay * DIM + (r - COL_VS)];
        pb[i] = v;
    }
    const int PER_L = NPACK * (DIM / 4);
    if (i >= LAYERS * PER_L) return;
    int lay = i / PER_L;
    int rem = i - lay * PER_L;
    int r = rem / (DIM / 4);
    int c4 = rem - r * (DIM / 4);
    float4 v = make_float4(0.f, 0.f, 0.f, 0.f);
    if (r < COL_QS)
        v = ((const float4*)(in_w + ((long)lay * 1536 + r) * DIM))[c4];
    else if (r < COL_KS)
        v = ((const float4*)(qp_w + ((long)lay * RANK + (r - COL_QS)) * DIM))[c4];
    else if (r < COL_VS)
        v = ((const float4*)(kp_w + ((long)lay * RANK + (r - COL_KS)) * DIM))[c4];
    else if (r < COL_VS + DIM)
        v = ((const float4*)(vp_w + ((long)lay * DIM + (r - COL_VS)) * DIM))[c4];
    ushort4 hh, ll;
    fsplit(v.x, hh.x, ll.x); fsplit(v.y, hh.y, ll.y);
    fsplit(v.z, hh.z, ll.z); fsplit(v.w, hh.w, ll.w);
    long o = (long)lay * NPACK * (DIM / 4) + (long)r * (DIM / 4) + c4;
    h[o] = hh; l[o] = ll;
}

// fused quad-tensor converter
__global__ void cvt4_k(const float4* __restrict__ s1, ushort4* __restrict__ h1, ushort4* __restrict__ l1, int n1,
                       const float4* __restrict__ s2, ushort4* __restrict__ h2, ushort4* __restrict__ l2, int n2,
                       const float4* __restrict__ s3, ushort4* __restrict__ h3, ushort4* __restrict__ l3, int n3,
                       const float4* __restrict__ s4, ushort4* __restrict__ h4, ushort4* __restrict__ l4, int n4)
{
    int i = blockIdx.x * 256 + threadIdx.x;
    const float4* s; ushort4 *h, *l; int j;
    if (i < n1) { s = s1; h = h1; l = l1; j = i; }
    else if (i < n1 + n2) { s = s2; h = h2; l = l2; j = i - n1; }
    else if (i < n1 + n2 + n3) { s = s3; h = h3; l = l3; j = i - n1 - n2; }
    else if (i < n1 + n2 + n3 + n4) { s = s4; h = h4; l = l4; j = i - n1 - n2 - n3; }
    else return;
    float4 v = s[j];
    ushort4 hh, ll;
    fsplit(v.x, hh.x, ll.x); fsplit(v.y, hh.y, ll.y);
    fsplit(v.z, hh.z, ll.z); fsplit(v.w, hh.w, ll.w);
    h[j] = hh; l[j] = ll;
}

// V^T planes (dense) from packed px
__global__ void vt_k(const float* __restrict__ px, u16* __restrict__ vh, u16* __restrict__ vl)
{
    __shared__ float t[32][33];
    int z = blockIdx.z, b = z >> 3, h = z & 7;
    int s0 = blockIdx.x * 32, d0 = blockIdx.y * 32;
    int tx = threadIdx.x, ty = threadIdx.y;
#pragma unroll
    for (int j = 0; j < 4; j++) {
        int s = s0 + ty + j * 8;
        t[ty + j * 8][tx] = px[((long)(b * SEQ + s)) * NPACK + 2 * DIM + h * HDIM + d0 + tx];
    }
    __syncthreads();
#pragma unroll
    for (int j = 0; j < 4; j++) {
        int d = d0 + ty + j * 8;
        long o = ((long)z * HDIM + d) * SEQ + s0 + tx;
        u16 hh, ll;
        fsplit(t[tx][ty + j * 8], hh, ll);
        vh[o] = hh; vl[o] = ll;
    }
}

// Vs^T planes (sparse) from packed px cols [COL_VS, COL_VS+512)
__global__ void vst_k(const float* __restrict__ px, u16* __restrict__ vh, u16* __restrict__ vl)
{
    __shared__ float t[32][33];
    int b = blockIdx.z;
    int s0 = blockIdx.x * 32, d0 = blockIdx.y * 32;
    int tx = threadIdx.x, ty = threadIdx.y;
#pragma unroll
    for (int j = 0; j < 4; j++) {
        int s = s0 + ty + j * 8;
        t[ty + j * 8][tx] = px[((long)(b * SEQ + s)) * NPACK + COL_VS + d0 + tx];
    }
    __syncthreads();
#pragma unroll
    for (int j = 0; j < 4; j++) {
        int d = d0 + ty + j * 8;
        long o = ((long)(b * DIM + d)) * SEQ + s0 + tx;
        u16 hh, ll;
        fsplit(t[tx][ty + j * 8], hh, ll);
        vh[o] = hh; vl[o] = ll;
    }
}

// ---------------- embedding (+ x planes) ----------------
__global__ void embed_k(const int* __restrict__ src, const float* __restrict__ emb,
                        const float* __restrict__ pe, float* __restrict__ x,
                        u16* __restrict__ xh, u16* __restrict__ xl)
{
    int t = blockIdx.x;
    int tid = threadIdx.x;
    int s = t & (SEQ - 1);
    int tok = src[t];
    int d = tid * 2;
    float2 e = *(const float2*)(emb + (long)tok * DIM + d);
    float2 p = *(const float2*)(pe + (long)s * DIM + d);
    float2 o;
    o.x = e.x * 22.627416998f + p.x;
    o.y = e.y * 22.627416998f + p.y;
    long off = (long)t * DIM + d;
    *(float2*)(x + off) = o;
    ushort2 hh, ll;
    fsplit(o.x, hh.x, ll.x); fsplit(o.y, hh.y, ll.y);
    *(ushort2*)(xh + off) = hh;
    *(ushort2*)(xl + off) = ll;
}

// ---------------- row softmax -> P hi/lo planes ----------------
__global__ void softmax_rows(const float* __restrict__ S, u16* __restrict__ Ph,
                             u16* __restrict__ Pl)
{
    __shared__ float red[256];
    long row = blockIdx.x;
    const float* p = S + row * (long)SEQ;
    int tid = threadIdx.x;
    float4 v0 = *(const float4*)(p + 4 * tid);
    float4 v1 = *(const float4*)(p + 4 * tid + 1024);
    float m = fmaxf(fmaxf(fmaxf(v0.x, v0.y), fmaxf(v0.z, v0.w)),
                    fmaxf(fmaxf(v1.x, v1.y), fmaxf(v1.z, v1.w)));
    red[tid] = m; __syncthreads();
    for (int s = 128; s > 0; s >>= 1) { if (tid < s) red[tid] = fmaxf(red[tid], red[tid + s]); __syncthreads(); }
    float M = red[0]; __syncthreads();
    v0.x = __expf(v0.x - M); v0.y = __expf(v0.y - M); v0.z = __expf(v0.z - M); v0.w = __expf(v0.w - M);
    v1.x = __expf(v1.x - M); v1.y = __expf(v1.y - M); v1.z = __expf(v1.z - M); v1.w = __expf(v1.w - M);
    float sum = v0.x + v0.y + v0.z + v0.w + v1.x + v1.y + v1.z + v1.w;
    red[tid] = sum; __syncthreads();
    for (int s = 128; s > 0; s >>= 1) { if (tid < s) red[tid] += red[tid + s]; __syncthreads(); }
    float inv = 1.f / red[0];
    v0.x *= inv; v0.y *= inv; v0.z *= inv; v0.w *= inv;
    v1.x *= inv; v1.y *= inv; v1.z *= inv; v1.w *= inv;
    long b0 = row * (long)SEQ + 4 * tid;
    ushort4 hh, ll;
    fsplit(v0.x, hh.x, ll.x); fsplit(v0.y, hh.y, ll.y);
    fsplit(v0.z, hh.z, ll.z); fsplit(v0.w, hh.w, ll.w);
    *(ushort4*)(Ph + b0) = hh; *(ushort4*)(Pl + b0) = ll;
    fsplit(v1.x, hh.x, ll.x); fsplit(v1.y, hh.y, ll.y);
    fsplit(v1.z, hh.z, ll.z); fsplit(v1.w, hh.w, ll.w);
    *(ushort4*)(Ph + b0 + 1024) = hh; *(ushort4*)(Pl + b0 + 1024) = ll;
}

// ---------------- sparse select ----------------
__device__ __forceinline__ unsigned f2k(float f)
{
    unsigned u = __float_as_uint(f);
    return (u & 0x80000000u) ? ~u : (u | 0x80000000u);
}

__global__ void __launch_bounds__(256) sparse_sel(
    const float* __restrict__ qk, u16* __restrict__ sph, u16* __restrict__ spl)
{
    __shared__ float logit[SEQ];
    __shared__ unsigned hist[256];
    __shared__ unsigned suf[256];
    __shared__ float red[256];
    __shared__ unsigned sh_prefix;
    __shared__ int sh_remaining;

    long row = blockIdx.x;
    int tid = threadIdx.x;
    const float* p = qk + row * (long)SEQ;

    for (int k = tid; k < SEQ; k += 256) logit[k] = p[k];
    __syncthreads();

    float lm = -3.4e38f;
    for (int k = tid; k < SEQ; k += 256) lm = fmaxf(lm, logit[k]);
    red[tid] = lm; __syncthreads();
    for (int s = 128; s > 0; s >>= 1) { if (tid < s) red[tid] = fmaxf(red[tid], red[tid + s]); __syncthreads(); }
    float Lmax = red[0]; __syncthreads();

    float zacc = 0.f;
    for (int k = tid; k < SEQ; k += 256) zacc += __expf(logit[k] - Lmax);
    red[tid] = zacc; __syncthreads();
    for (int s = 128; s > 0; s >>= 1) { if (tid < s) red[tid] += red[tid + s]; __syncthreads(); }
    float Z = red[0]; __syncthreads();

    unsigned prefix = 0; int remaining = KTOP;
    for (int shift = 24; shift >= 0; shift -= 8) {
        hist[tid] = 0; __syncthreads();
        unsigned upmask = (shift == 24) ? 0u : (0xFFFFFFFFu << (shift + 8));
        for (int k = tid; k < SEQ; k += 256) {
            unsigned key = f2k(logit[k]);
            if ((key & upmask) == prefix)
                atomicAdd(&hist[(key >> shift) & 255], 1u);
        }
        __syncthreads();
        suf[tid] = hist[tid]; __syncthreads();
        for (int off = 1; off < 256; off <<= 1) {
            unsigned add = (tid + off < 256) ? suf[tid + off] : 0u;
            __syncthreads();
            suf[tid] += add;
            __syncthreads();
        }
        unsigned shere = suf[tid];
        unsigned snext = (tid < 255) ? suf[tid + 1] : 0u;
        if (shere >= (unsigned)remaining && snext < (unsigned)remaining) {
            sh_prefix = prefix | ((unsigned)tid << shift);
            sh_remaining = remaining - (int)snext;
        }
        __syncthreads();
        prefix = sh_prefix; remaining = sh_remaining;
        __syncthreads();
    }
    unsigned thr = prefix;

    float w8[8];
    float dsum = 0.f;
#pragma unroll
    for (int j = 0; j < 8; j++) {
        int k = tid + 256 * j;
        float l = logit[k];
        bool keep = (f2k(l) >= thr);
        float w = keep ? __expf(l - Lmax) : 0.f;
        w8[j] = w;
        dsum += w;
    }
    red[tid] = dsum; __syncthreads();
    for (int s = 128; s > 0; s >>= 1) { if (tid < s) red[tid] += red[tid + s]; __syncthreads(); }
    float inv = 1.f / (red[0] + 1e-9f * Z);

#pragma unroll
    for (int j = 0; j < 8; j++) {
        int k = tid + 256 * j;
        float w = w8[j] * inv;
        u16 h, l;
        fsplit(w, h, l);
        long o = row * (long)SEQ + k;
        sph[o] = h; spl[o] = l;
    }
}

// ---------------- gated fusion + LN1 ----------------
__global__ void fuse_ln1_k(float* __restrict__ x, const float* __restrict__ dn,
                           const float* __restrict__ sp, const float* __restrict__ lam,
                           int layer, const float* __restrict__ gam, const float* __restrict__ bet,
                           u16* __restrict__ xh, u16* __restrict__ xl)
{
    __shared__ float red[256];
    int row = blockIdx.x, tid = threadIdx.x;
    long off = (long)row * DIM + 2 * tid;
    float g = 1.f / (1.f + expf(-lam[layer]));
    float2 xv = *(const float2*)(x + off);
    float2 dv = *(const float2*)(dn + off);
    float2 sv = *(const float2*)(sp + off);
    float y0 = xv.x + g * dv.x + (1.f - g) * sv.x;
    float y1 = xv.y + g * dv.y + (1.f - g) * sv.y;
    red[tid] = y0 + y1; __syncthreads();
    for (int s = 128; s > 0; s >>= 1) { if (tid < s) red[tid] += red[tid + s]; __syncthreads(); }
    float mean = red[0] * (1.f / DIM); __syncthreads();
    float d0 = y0 - mean, d1 = y1 - mean;
    red[tid] = d0 * d0 + d1 * d1; __syncthreads();
    for (int s = 128; s > 0; s >>= 1) { if (tid < s) red[tid] += red[tid + s]; __syncthreads(); }
    float inv = 1.f / sqrtf(red[0] * (1.f / DIM) + 1e-5f);
    int dc = 2 * tid;
    float2 gm = *(const float2*)(gam + dc);
    float2 bt = *(const float2*)(bet + dc);
    float2 o; o.x = d0 * inv * gm.x + bt.x; o.y = d1 * inv * gm.y + bt.y;
    *(float2*)(x + off) = o;
    ushort2 hh, ll;
    fsplit(o.x, hh.x, ll.x); fsplit(o.y, hh.y, ll.y);
    *(ushort2*)(xh + off) = hh;
    *(ushort2*)(xl + off) = ll;
}

// ---------------- residual + LN2 ----------------
__global__ void add_ln2_k(float* __restrict__ x, const float* __restrict__ f,
                          const float* __restrict__ gam, const float* __restrict__ bet,
                          u16* __restrict__ xh, u16* __restrict__ xl)
{
    __shared__ float red[256];
    int row = blockIdx.x, tid = threadIdx.x;
    long off = (long)row * DIM + 2 * tid;
    float2 xv = *(const float2*)(x + off);
    float2 fv = *(const float2*)(f + off);
    float y0 = xv.x + fv.x;
    float y1 = xv.y + fv.y;
    red[tid] = y0 + y1; __syncthreads();
    for (int s = 128; s > 0; s >>= 1) { if (tid < s) red[tid] += red[tid + s]; __syncthreads(); }
    float mean = red[0] * (1.f / DIM); __syncthreads();
    float d0 = y0 - mean, d1 = y1 - mean;
    red[tid] = d0 * d0 + d1 * d1; __syncthreads();
    for (int s = 128; s > 0; s >>= 1) { if (tid < s) red[tid] += red[tid + s]; __syncthreads(); }
    float inv = 1.f / sqrtf(red[0] * (1.f / DIM) + 1e-5f);
    int dc = 2 * tid;
    float2 gm = *(const float2*)(gam + dc);
    float2 bt = *(const float2*)(bet + dc);
    float2 o; o.x = d0 * inv * gm.x + bt.x; o.y = d1 * inv * gm.y + bt.y;
    *(float2*)(x + off) = o;
    ushort2 hh, ll;
    fsplit(o.x, hh.x, ll.x); fsplit(o.y, hh.y, ll.y);
    *(ushort2*)(xh + off) = hh;
    *(ushort2*)(xl + off) = ll;
}

// ---------------- host-side helpers ----------------
template <int TN>
static void launch_tc(const u16* Ah, const u16* Al, const u16* Bh, const u16* Bl,
                      const float* bias, float* C, u16* Ch, u16* Cl,
                      int M, int N, int K, int lda, int ldb, int ldc,
                      int Z = 1, long sAo = 0, long sAi = 0, long sBo = 0, long sBi = 0,
                      long sCo = 0, long sCi = 0, int zdiv = 1,
                      float alpha = 1.f, int relu = 0)
{
    constexpr int SM = 3 * (2 * 128 * 80 + 2 * TN * 80);
    static bool attr_set = false;
    if (!attr_set) {
        cudaFuncSetAttribute(mm_gemm<TN>, cudaFuncAttributeMaxDynamicSharedMemorySize, SM);
        attr_set = true;
    }
    dim3 g(N / TN, M / 128, Z);
    mm_gemm<TN><<<g, 256, SM>>>(Ah, Al, Bh, Bl, bias, C, Ch, Cl,
                                K, lda, ldb, ldc,
                                sAo, sAi, sBo, sBi, sCo, sCi, zdiv, alpha, relu);
}

extern "C" void kernel_launch(void* const* d_in, const int* in_sizes, int n_in,
                              void* d_out, int out_size)
{
    const int*   SRC   = (const int*)  d_in[0];
    const float* EMB   = (const float*)d_in[1];
    const float* PE    = (const float*)d_in[2];
    const float* IN_W  = (const float*)d_in[3];
    const float* IN_B  = (const float*)d_in[4];
    const float* OUT_W = (const float*)d_in[5];
    const float* OUT_B = (const float*)d_in[6];
    const float* QP_W  = (const float*)d_in[7];
    const float* QP_B  = (const float*)d_in[8];
    const float* KP_W  = (const float*)d_in[9];
    const float* KP_B  = (const float*)d_in[10];
    const float* VP_W  = (const float*)d_in[11];
    const float* VP_B  = (const float*)d_in[12];
    const float* LAM   = (const float*)d_in[13];
    const float* FF1_W = (const float*)d_in[14];
    const float* FF1_B = (const float*)d_in[15];
    const float* FF2_W = (const float*)d_in[16];
    const float* FF2_B = (const float*)d_in[17];
    const float* LN1S  = (const float*)d_in[18];
    const float* LN1B  = (const float*)d_in[19];
    const float* LN2S  = (const float*)d_in[20];
    const float* LN2B  = (const float*)d_in[21];
    const float* FIN_W = (const float*)d_in[22];
    const float* FIN_B = (const float*)d_in[23];
    float* OUT = (float*)d_out;

    float *px, *x, *scores, *aproj, *sp, *fft, *pb;
    cudaGetSymbolAddress((void**)&px, g_px);       cudaGetSymbolAddress((void**)&x, g_x);
    cudaGetSymbolAddress((void**)&scores, g_scores); cudaGetSymbolAddress((void**)&aproj, g_aproj);
    cudaGetSymbolAddress((void**)&sp, g_sparse);   cudaGetSymbolAddress((void**)&fft, g_fft);
    cudaGetSymbolAddress((void**)&pb, g_pb);

    u16 *pxh, *pxl, *xh, *xl, *Ph, *Pl, *dh, *dl, *fh, *fl, *vth, *vtl;
    u16 *sph, *spl, *vsth, *vstl;
    cudaGetSymbolAddress((void**)&pxh, g_pxh); cudaGetSymbolAddress((void**)&pxl, g_pxl);
    cudaGetSymbolAddress((void**)&xh, g_xh);   cudaGetSymbolAddress((void**)&xl, g_xl);
    cudaGetSymbolAddress((void**)&Ph, g_Ph);   cudaGetSymbolAddress((void**)&Pl, g_Pl);
    cudaGetSymbolAddress((void**)&dh, g_dh);   cudaGetSymbolAddress((void**)&dl, g_dl);
    cudaGetSymbolAddress((void**)&fh, g_fh);   cudaGetSymbolAddress((void**)&fl, g_fl);
    cudaGetSymbolAddress((void**)&vth, g_vth); cudaGetSymbolAddress((void**)&vtl, g_vtl);
    cudaGetSymbolAddress((void**)&sph, g_sph); cudaGetSymbolAddress((void**)&spl, g_spl);
    cudaGetSymbolAddress((void**)&vsth, g_vsth); cudaGetSymbolAddress((void**)&vstl, g_vstl);

    u16 *pwh, *pwl, *outwh, *outwl, *f1wh, *f1wl, *f2wh, *f2wl, *finwh, *finwl;
    cudaGetSymbolAddress((void**)&pwh, g_pwh);     cudaGetSymbolAddress((void**)&pwl, g_pwl);
    cudaGetSymbolAddress((void**)&outwh, g_outwh); cudaGetSymbolAddress((void**)&outwl, g_outwl);
    cudaGetSymbolAddress((void**)&f1wh, g_f1wh);   cudaGetSymbolAddress((void**)&f1wl, g_f1wl);
    cudaGetSymbolAddress((void**)&f2wh, g_f2wh);   cudaGetSymbolAddress((void**)&f2wl, g_f2wl);
    cudaGetSymbolAddress((void**)&finwh, g_finwh); cudaGetSymbolAddress((void**)&finwl, g_finwl);

    // launch 1: embedding
    embed_k<<<TOKENS, 256>>>(SRC, EMB, PE, x, xh, xl);

    // launch 2: packed weights + bias
    {
        int tot = LAYERS * NPACK * (DIM / 4);
        cvt_pack_k<<<(tot + 255) / 256, 256>>>(IN_W, QP_W, KP_W, VP_W,
                                               IN_B, QP_B, KP_B, VP_B,
                                               (ushort4*)pwh, (ushort4*)pwl, pb);
    }
    // launch 3: remaining weights fused
    {
        int n1 = LAYERS * DIM * DIM / 4, n2 = LAYERS * FFD * DIM / 4;
        int n3 = LAYERS * DIM * FFD / 4, n4 = VOCAB * DIM / 4;
        cvt4_k<<<(n1 + n2 + n3 + n4 + 255) / 256, 256>>>(
            (const float4*)OUT_W, (ushort4*)outwh, (ushort4*)outwl, n1,
            (const float4*)FF1_W, (ushort4*)f1wh, (ushort4*)f1wl, n2,
            (const float4*)FF2_W, (ushort4*)f2wh, (ushort4*)f2wl, n3,
            (const float4*)FIN_W, (ushort4*)finwh, (ushort4*)finwl, n4);
    }

    for (int l = 0; l < LAYERS; l++) {
        long wq  = (long)l * NPACK * DIM;
        long wo  = (long)l * DIM * DIM;
        long wf1 = (long)l * FFD * DIM;
        long wf2 = (long)l * DIM * FFD;

        // launch 4 (layer 0): packed projections -> px + planes  [PROFILED]
        launch_tc<256>(xh, xl, pwh + wq, pwl + wq, pb + (long)l * NPACK,
                       px, pxh, pxl, TOKENS, NPACK, DIM, DIM, DIM, NPACK);

        // dense scores = Q @ K^T / 8 per (b,h)
        launch_tc<256>(pxh, pxl, pxh + DIM, pxl + DIM, nullptr,
                       scores, nullptr, nullptr,
                       SEQ, SEQ, HDIM, NPACK, NPACK, SEQ,
                       16, (long)SEQ * NPACK, (long)HDIM,
                       (long)SEQ * NPACK, (long)HDIM,
                       (long)HEADS * SEQ * SEQ, (long)SEQ * SEQ,
                       HEADS, 0.125f, 0);

        softmax_rows<<<16 * SEQ, 256>>>(scores, Ph, Pl);

        vt_k<<<dim3(SEQ / 32, HDIM / 32, 16), dim3(32, 8)>>>(px, vth, vtl);

        // dense = P @ V per (b,h) -> planes only
        launch_tc<64>(Ph, Pl, vth, vtl, nullptr, nullptr, dh, dl,
                      SEQ, HDIM, SEQ, SEQ, SEQ, DIM,
                      16, (long)HEADS * SEQ * SEQ, (long)SEQ * SEQ,
                      (long)HEADS * HDIM * SEQ, (long)HDIM * SEQ,
                      (long)SEQ * DIM, (long)HDIM,
                      HEADS, 1.f, 0);

        // dense projection -> aproj fp32
        launch_tc<128>(dh, dl, outwh + wo, outwl + wo, OUT_B + (long)l * DIM,
                       aproj, nullptr, nullptr, TOKENS, DIM, DIM, DIM, DIM, DIM);

        // low-rank logits qk = Qs @ Ks^T / sqrt(R) per batch
        launch_tc<256>(pxh + COL_QS, pxl + COL_QS, pxh + COL_KS, pxl + COL_KS, nullptr,
                       scores, nullptr, nullptr,
                       SEQ, SEQ, RANK, NPACK, NPACK, SEQ,
                       2, (long)SEQ * NPACK, 0, (long)SEQ * NPACK, 0,
                       (long)SEQ * SEQ, 0, 1, 0.125f, 0);

        sparse_sel<<<TOKENS, 256>>>(scores, sph, spl);

        vst_k<<<dim3(SEQ / 32, DIM / 32, 2), dim3(32, 8)>>>(px, vsth, vstl);

        // sparse = sp @ Vs per batch
        launch_tc<128>(sph, spl, vsth, vstl, nullptr, sp, nullptr, nullptr,
                       SEQ, DIM, SEQ, SEQ, SEQ, DIM,
                       2, (long)SEQ * SEQ, 0, (long)DIM * SEQ, 0,
                       (long)SEQ * DIM, 0, 1, 1.f, 0);

        fuse_ln1_k<<<TOKENS, 256>>>(x, aproj, sp, LAM, l,
                                    LN1S + (long)l * DIM, LN1B + (long)l * DIM, xh, xl);

        // FFN
        launch_tc<256>(xh, xl, f1wh + wf1, f1wl + wf1, FF1_B + (long)l * FFD,
                       nullptr, fh, fl, TOKENS, FFD, DIM, DIM, DIM, FFD,
                       1, 0, 0, 0, 0, 0, 0, 1, 1.f, 1);
        launch_tc<128>(fh, fl, f2wh + wf2, f2wl + wf2, FF2_B + (long)l * DIM,
                       fft, nullptr, nullptr, TOKENS, DIM, FFD, FFD, FFD, DIM);

        add_ln2_k<<<TOKENS, 256>>>(x, fft, LN2S + (long)l * DIM, LN2B + (long)l * DIM, xh, xl);
    }

    // final vocab projection
    launch_tc<256>(xh, xl, finwh, finwl, FIN_B, OUT, nullptr, nullptr,
                   TOKENS, VOCAB, DIM, DIM, DIM, VOCAB);
}

// round 9
// speedup vs baseline: 1.5660x; 1.0273x over previous
#include <cuda_runtime.h>
#include <cuda_bf16.h>
#include <math.h>
#include <stdint.h>

#define SEQ    2048
#define TOKENS 4096
#define DIM    512
#define HEADS  8
#define HDIM   64
#define RANK   64
#define LAYERS 6
#define VOCAB  32000
#define FFD    2048
#define KTOP   409
#define NPACK  2304   // 1536 qkv | 64 qs | 64 ks | 512 vs | 128 pad
#define COL_QS 1536
#define COL_KS 1600
#define COL_VS 1664

typedef unsigned short u16;

// ---------------- fp32 scratch ----------------
__device__ float g_px[(size_t)TOKENS * NPACK];
__device__ float g_x[TOKENS * DIM];
__device__ float g_scores[(size_t)16 * SEQ * SEQ];
__device__ float g_aproj[TOKENS * DIM];
__device__ float g_sparse[TOKENS * DIM];
__device__ float g_fft[TOKENS * DIM];

// ---------------- bf16 hi/lo planes (activations) ----------------
__device__ alignas(16) u16 g_pxh[(size_t)TOKENS * NPACK], g_pxl[(size_t)TOKENS * NPACK];
__device__ alignas(16) u16 g_xh[TOKENS * DIM],       g_xl[TOKENS * DIM];
__device__ alignas(16) u16 g_Ph[(size_t)16 * SEQ * SEQ], g_Pl[(size_t)16 * SEQ * SEQ];
__device__ alignas(16) u16 g_dh[TOKENS * DIM],       g_dl[TOKENS * DIM];
__device__ alignas(16) u16 g_fh[TOKENS * FFD],       g_fl[TOKENS * FFD];
__device__ alignas(16) u16 g_vth[16 * HDIM * SEQ],   g_vtl[16 * HDIM * SEQ];
__device__ alignas(16) u16 g_sph[(size_t)2 * SEQ * SEQ], g_spl[(size_t)2 * SEQ * SEQ];
__device__ alignas(16) u16 g_vsth[2 * DIM * SEQ],    g_vstl[2 * DIM * SEQ];

// ---------------- bf16 hi/lo planes (weights) ----------------
__device__ alignas(16) u16 g_pwh[LAYERS * NPACK * DIM], g_pwl[LAYERS * NPACK * DIM];
__device__ float g_pb[LAYERS * NPACK];
__device__ alignas(16) u16 g_outwh[LAYERS * DIM * DIM],  g_outwl[LAYERS * DIM * DIM];
__device__ alignas(16) u16 g_f1wh[LAYERS * FFD * DIM],   g_f1wl[LAYERS * FFD * DIM];
__device__ alignas(16) u16 g_f2wh[LAYERS * DIM * FFD],   g_f2wl[LAYERS * DIM * FFD];
__device__ alignas(16) u16 g_finwh[VOCAB * DIM],         g_finwl[VOCAB * DIM];

// ---------------- small device helpers ----------------
__device__ __forceinline__ void fsplit(float x, u16& h, u16& l)
{
    __nv_bfloat16 bh = __float2bfloat16_rn(x);
    float fh = __bfloat162float(bh);
    __nv_bfloat16 bl = __float2bfloat16_rn(x - fh);
    h = *reinterpret_cast<u16*>(&bh);
    l = *reinterpret_cast<u16*>(&bl);
}

__device__ __forceinline__ uint32_t smem_u32(const void* p)
{
    uint32_t a;
    asm("{ .reg .u64 t; cvta.to.shared.u64 t, %1; cvt.u32.u64 %0, t; }" : "=r"(a) : "l"(p));
    return a;
}

__device__ __forceinline__ void cpa16(uint32_t dst, const void* src)
{
    asm volatile("cp.async.cg.shared.global [%0], [%1], 16;" :: "r"(dst), "l"(src) : "memory");
}

__device__ __forceinline__ void ldsm4(uint32_t* r, uint32_t addr)
{
    asm volatile("ldmatrix.sync.aligned.m8n8.x4.shared.b16 {%0,%1,%2,%3}, [%4];"
                 : "=r"(r[0]), "=r"(r[1]), "=r"(r[2]), "=r"(r[3]) : "r"(addr));
}

__device__ __forceinline__ void mma16816(float* c, const uint32_t* a, uint32_t b0, uint32_t b1)
{
    asm volatile(
        "mma.sync.aligned.m16n8k16.row.col.f32.bf16.bf16.f32 "
        "{%0,%1,%2,%3}, {%4,%5,%6,%7}, {%8,%9}, {%0,%1,%2,%3};"
        : "+f"(c[0]), "+f"(c[1]), "+f"(c[2]), "+f"(c[3])
        : "r"(a[0]), "r"(a[1]), "r"(a[2]), "r"(a[3]), "r"(b0), "r"(b1));
}

// ---------------- HMMA bf16x3 GEMM: C = alpha * (A @ B^T) + bias ----------------
// TN=256: 512 threads, 16 warps (4Mx4N, 32x64 warp tile) -> ~128 regs, 4 warps/SMSP.
// TN=128: 256 threads, 8 warps (2Mx4N, 64x32).  TN=64: 256 threads (4Mx2N, 32x32), 2 CTAs/SM.
template <int TN>
__global__ void __launch_bounds__((TN == 256) ? 512 : 256, (TN == 64) ? 2 : 1)
mm_gemm(const u16* __restrict__ Ah, const u16* __restrict__ Al,
        const u16* __restrict__ Bh, const u16* __restrict__ Bl,
        const float* __restrict__ bias, float* __restrict__ C,
        u16* __restrict__ Ch, u16* __restrict__ Cl,
        int K, int lda, int ldb, int ldc,
        long sAo, long sAi, long sBo, long sBi, long sCo, long sCi,
        int zdiv, float alpha, int relu)
{
    constexpr int NT  = (TN == 256) ? 512 : 256;
    constexpr int MI  = (TN == 128) ? 4 : 2;
    constexpr int NI  = (TN == 256) ? 4 : 2;
    constexpr int APB = 128 * 80;
    constexpr int BPB = TN * 80;
    constexpr int STAGE = 2 * APB + 2 * BPB;
    constexpr int NST = 3;
    constexpr int ROWS = NT / 4;          // rows loaded per cp.async pass

    extern __shared__ char smem[];
    const uint32_t su = smem_u32(smem);
    const int tid = threadIdx.x;
    const int wid = tid >> 5;
    const int lane = tid & 31;

    int z = blockIdx.z;
    int zo = z / zdiv, zi = z - zo * zdiv;
    long ao = (long)zo * sAo + (long)zi * sAi;
    long bo = (long)zo * sBo + (long)zi * sBi;
    long co = (long)zo * sCo + (long)zi * sCi;
    Ah += ao; Al += ao; Bh += bo; Bl += bo;
    if (C)  C  += co;
    if (Ch) { Ch += co; Cl += co; }
    const int m0 = blockIdx.y * 128;
    const int n0 = blockIdx.x * TN;

    const int wmBase = (TN == 256) ? (wid & 3) * 32
                     : (TN == 128) ? (wid & 1) * 64 : (wid & 3) * 32;
    const int wnBase = (TN == 256) ? (wid >> 2) * 64
                     : (TN == 128) ? (wid >> 1) * 32 : (wid >> 2) * 32;

    float acc[MI][2 * NI][4];
#pragma unroll
    for (int mi = 0; mi < MI; mi++)
#pragma unroll
        for (int n8 = 0; n8 < 2 * NI; n8++)
#pragma unroll
            for (int q = 0; q < 4; q++) acc[mi][n8][q] = 0.f;

    const int nch = K >> 5;
    const int ar = tid >> 2, ac = tid & 3;
    auto issue = [&](int i) {
        int s = i % NST;
        int k0 = i << 5;
        uint32_t st = su + s * STAGE;
#pragma unroll
        for (int j = 0; j < 128 / ROWS; j++) {
            int r = ar + ROWS * j;
            long g = (long)(m0 + r) * lda + k0 + ac * 8;
            uint32_t d = st + r * 80 + ac * 16;
            cpa16(d, Ah + g);
            cpa16(d + APB, Al + g);
        }
#pragma unroll
        for (int j = 0; j < TN / ROWS; j++) {
            int r = ar + ROWS * j;
            long g = (long)(n0 + r) * ldb + k0 + ac * 8;
            uint32_t d = st + 2 * APB + r * 80 + ac * 16;
            cpa16(d, Bh + g);
            cpa16(d + BPB, Bl + g);
        }
        asm volatile("cp.async.commit_group;" ::: "memory");
    };

    issue(0);
    if (nch > 1) issue(1);
    const uint32_t lrow = lane & 15;
    const uint32_t lcol = (lane >> 4) * 16;

    for (int i = 0; i < nch; i++) {
        if (i + 1 < nch) {
            asm volatile("cp.async.wait_group 1;" ::: "memory");
        } else {
            asm volatile("cp.async.wait_group 0;" ::: "memory");
        }
        __syncthreads();
        if (i + 2 < nch) issue(i + 2);

        int s = i % NST;
        uint32_t aH = su + s * STAGE;
        uint32_t aL = aH + APB;
        uint32_t bH = aH + 2 * APB;
        uint32_t bL = bH + BPB;

#pragma unroll
        for (int ks = 0; ks < 2; ks++) {
            uint32_t kb = ks * 32 + lcol;
            uint32_t a[MI][4], bh[NI][4];
#pragma unroll
            for (int mi = 0; mi < MI; mi++)
                ldsm4(a[mi], aH + (wmBase + mi * 16 + lrow) * 80 + kb);
#pragma unroll
            for (int ni = 0; ni < NI; ni++)
                ldsm4(bh[ni], bH + (wnBase + ni * 16 + lrow) * 80 + kb);
            // pass 1: Ah * Bh
#pragma unroll
            for (int mi = 0; mi < MI; mi++)
#pragma unroll
                for (int ni = 0; ni < NI; ni++) {
                    mma16816(acc[mi][2 * ni],     a[mi], bh[ni][0], bh[ni][2]);
                    mma16816(acc[mi][2 * ni + 1], a[mi], bh[ni][1], bh[ni][3]);
                }
            // pass 3: Al * Bh (reuses bh, then both die)
            {
                uint32_t al[MI][4];
#pragma unroll
                for (int mi = 0; mi < MI; mi++)
                    ldsm4(al[mi], aL + (wmBase + mi * 16 + lrow) * 80 + kb);
#pragma unroll
                for (int mi = 0; mi < MI; mi++)
#pragma unroll
                    for (int ni = 0; ni < NI; ni++) {
                        mma16816(acc[mi][2 * ni],     al[mi], bh[ni][0], bh[ni][2]);
                        mma16816(acc[mi][2 * ni + 1], al[mi], bh[ni][1], bh[ni][3]);
                    }
            }
            // pass 2: Ah * Bl
            {
                uint32_t bl[NI][4];
#pragma unroll
                for (int ni = 0; ni < NI; ni++)
                    ldsm4(bl[ni], bL + (wnBase + ni * 16 + lrow) * 80 + kb);
#pragma unroll
                for (int mi = 0; mi < MI; mi++)
#pragma unroll
                    for (int ni = 0; ni < NI; ni++) {
                        mma16816(acc[mi][2 * ni],     a[mi], bl[ni][0], bl[ni][2]);
                        mma16816(acc[mi][2 * ni + 1], a[mi], bl[ni][1], bl[ni][3]);
                    }
            }
        }
    }

#pragma unroll
    for (int mi = 0; mi < MI; mi++) {
        int r0 = m0 + wmBase + mi * 16 + (lane >> 2);
#pragma unroll
        for (int n8 = 0; n8 < 2 * NI; n8++) {
            int c = n0 + wnBase + n8 * 8 + (lane & 3) * 2;
            float2 o0, o1;
            o0.x = acc[mi][n8][0] * alpha; o0.y = acc[mi][n8][1] * alpha;
            o1.x = acc[mi][n8][2] * alpha; o1.y = acc[mi][n8][3] * alpha;
            if (bias) {
                float b0 = bias[c], b1 = bias[c + 1];
                o0.x += b0; o0.y += b1; o1.x += b0; o1.y += b1;
            }
            if (relu) {
                o0.x = fmaxf(o0.x, 0.f); o0.y = fmaxf(o0.y, 0.f);
                o1.x = fmaxf(o1.x, 0.f); o1.y = fmaxf(o1.y, 0.f);
            }
            long off0 = (long)r0 * ldc + c;
            long off1 = off0 + (long)8 * ldc;
            if (C) {
                *(float2*)(C + off0) = o0;
                *(float2*)(C + off1) = o1;
            }
            if (Ch) {
                ushort2 hh, ll;
                fsplit(o0.x, hh.x, ll.x); fsplit(o0.y, hh.y, ll.y);
                *(ushort2*)(Ch + off0) = hh; *(ushort2*)(Cl + off0) = ll;
                fsplit(o1.x, hh.x, ll.x); fsplit(o1.y, hh.y, ll.y);
                *(ushort2*)(Ch + off1) = hh; *(ushort2*)(Cl + off1) = ll;
            }
        }
    }
}

// ---------------- weight converters ----------------
__global__ void cvt_pack_k(const float* __restrict__ in_w, const float* __restrict__ qp_w,
                           const float* __restrict__ kp_w, const float* __restrict__ vp_w,
                           const float* __restrict__ in_b, const float* __restrict__ qp_b,
                           const float* __restrict__ kp_b, const float* __restrict__ vp_b,
                           ushort4* __restrict__ h, ushort4* __restrict__ l,
                           float* __restrict__ pb)
{
    int i = blockIdx.x * 256 + threadIdx.x;
    if (i < LAYERS * NPACK) {
        int lay = i / NPACK;
        int r = i - lay * NPACK;
        float v = 0.f;
        if (r < COL_QS) v = in_b[lay * 1536 + r];
        else if (r < COL_KS) v = qp_b[lay * RANK + (r - COL_QS)];
        else if (r < COL_VS) v = kp_b[lay * RANK + (r - COL_KS)];
        else if (r < COL_VS + DIM) v = vp_b[lay * DIM + (r - COL_VS)];
        pb[i] = v;
    }
    const int PER_L = NPACK * (DIM / 4);
    if (i >= LAYERS * PER_L) return;
    int lay = i / PER_L;
    int rem = i - lay * PER_L;
    int r = rem / (DIM / 4);
    int c4 = rem - r * (DIM / 4);
    float4 v = make_float4(0.f, 0.f, 0.f, 0.f);
    if (r < COL_QS)
        v = ((const float4*)(in_w + ((long)lay * 1536 + r) * DIM))[c4];
    else if (r < COL_KS)
        v = ((const float4*)(qp_w + ((long)lay * RANK + (r - COL_QS)) * DIM))[c4];
    else if (r < COL_VS)
        v = ((const float4*)(kp_w + ((long)lay * RANK + (r - COL_KS)) * DIM))[c4];
    else if (r < COL_VS + DIM)
        v = ((const float4*)(vp_w + ((long)lay * DIM + (r - COL_VS)) * DIM))[c4];
    ushort4 hh, ll;
    fsplit(v.x, hh.x, ll.x); fsplit(v.y, hh.y, ll.y);
    fsplit(v.z, hh.z, ll.z); fsplit(v.w, hh.w, ll.w);
    long o = (long)lay * NPACK * (DIM / 4) + (long)r * (DIM / 4) + c4;
    h[o] = hh; l[o] = ll;
}

__global__ void cvt4_k(const float4* __restrict__ s1, ushort4* __restrict__ h1, ushort4* __restrict__ l1, int n1,
                       const float4* __restrict__ s2, ushort4* __restrict__ h2, ushort4* __restrict__ l2, int n2,
                       const float4* __restrict__ s3, ushort4* __restrict__ h3, ushort4* __restrict__ l3, int n3,
                       const float4* __restrict__ s4, ushort4* __restrict__ h4, ushort4* __restrict__ l4, int n4)
{
    int i = blockIdx.x * 256 + threadIdx.x;
    const float4* s; ushort4 *h, *l; int j;
    if (i < n1) { s = s1; h = h1; l = l1; j = i; }
    else if (i < n1 + n2) { s = s2; h = h2; l = l2; j = i - n1; }
    else if (i < n1 + n2 + n3) { s = s3; h = h3; l = l3; j = i - n1 - n2; }
    else if (i < n1 + n2 + n3 + n4) { s = s4; h = h4; l = l4; j = i - n1 - n2 - n3; }
    else return;
    float4 v = s[j];
    ushort4 hh, ll;
    fsplit(v.x, hh.x, ll.x); fsplit(v.y, hh.y, ll.y);
    fsplit(v.z, hh.z, ll.z); fsplit(v.w, hh.w, ll.w);
    h[j] = hh; l[j] = ll;
}

// V^T planes (dense) from packed px
__global__ void vt_k(const float* __restrict__ px, u16* __restrict__ vh, u16* __restrict__ vl)
{
    __shared__ float t[32][33];
    int z = blockIdx.z, b = z >> 3, h = z & 7;
    int s0 = blockIdx.x * 32, d0 = blockIdx.y * 32;
    int tx = threadIdx.x, ty = threadIdx.y;
#pragma unroll
    for (int j = 0; j < 4; j++) {
        int s = s0 + ty + j * 8;
        t[ty + j * 8][tx] = px[((long)(b * SEQ + s)) * NPACK + 2 * DIM + h * HDIM + d0 + tx];
    }
    __syncthreads();
#pragma unroll
    for (int j = 0; j < 4; j++) {
        int d = d0 + ty + j * 8;
        long o = ((long)z * HDIM + d) * SEQ + s0 + tx;
        u16 hh, ll;
        fsplit(t[tx][ty + j * 8], hh, ll);
        vh[o] = hh; vl[o] = ll;
    }
}

// Vs^T planes (sparse) from packed px cols [COL_VS, COL_VS+512)
__global__ void vst_k(const float* __restrict__ px, u16* __restrict__ vh, u16* __restrict__ vl)
{
    __shared__ float t[32][33];
    int b = blockIdx.z;
    int s0 = blockIdx.x * 32, d0 = blockIdx.y * 32;
    int tx = threadIdx.x, ty = threadIdx.y;
#pragma unroll
    for (int j = 0; j < 4; j++) {
        int s = s0 + ty + j * 8;
        t[ty + j * 8][tx] = px[((long)(b * SEQ + s)) * NPACK + COL_VS + d0 + tx];
    }
    __syncthreads();
#pragma unroll
    for (int j = 0; j < 4; j++) {
        int d = d0 + ty + j * 8;
        long o = ((long)(b * DIM + d)) * SEQ + s0 + tx;
        u16 hh, ll;
        fsplit(t[tx][ty + j * 8], hh, ll);
        vh[o] = hh; vl[o] = ll;
    }
}

// ---------------- embedding (+ x planes) ----------------
__global__ void embed_k(const int* __restrict__ src, const float* __restrict__ emb,
                        const float* __restrict__ pe, float* __restrict__ x,
                        u16* __restrict__ xh, u16* __restrict__ xl)
{
    int t = blockIdx.x;
    int tid = threadIdx.x;
    int s = t & (SEQ - 1);
    int tok = src[t];
    int d = tid * 2;
    float2 e = *(const float2*)(emb + (long)tok * DIM + d);
    float2 p = *(const float2*)(pe + (long)s * DIM + d);
    float2 o;
    o.x = e.x * 22.627416998f + p.x;
    o.y = e.y * 22.627416998f + p.y;
    long off = (long)t * DIM + d;
    *(float2*)(x + off) = o;
    ushort2 hh, ll;
    fsplit(o.x, hh.x, ll.x); fsplit(o.y, hh.y, ll.y);
    *(ushort2*)(xh + off) = hh;
    *(ushort2*)(xl + off) = ll;
}

// ---------------- row softmax -> P hi/lo planes ----------------
__global__ void softmax_rows(const float* __restrict__ S, u16* __restrict__ Ph,
                             u16* __restrict__ Pl)
{
    __shared__ float red[256];
    long row = blockIdx.x;
    const float* p = S + row * (long)SEQ;
    int tid = threadIdx.x;
    float4 v0 = *(const float4*)(p + 4 * tid);
    float4 v1 = *(const float4*)(p + 4 * tid + 1024);
    float m = fmaxf(fmaxf(fmaxf(v0.x, v0.y), fmaxf(v0.z, v0.w)),
                    fmaxf(fmaxf(v1.x, v1.y), fmaxf(v1.z, v1.w)));
    red[tid] = m; __syncthreads();
    for (int s = 128; s > 0; s >>= 1) { if (tid < s) red[tid] = fmaxf(red[tid], red[tid + s]); __syncthreads(); }
    float M = red[0]; __syncthreads();
    v0.x = __expf(v0.x - M); v0.y = __expf(v0.y - M); v0.z = __expf(v0.z - M); v0.w = __expf(v0.w - M);
    v1.x = __expf(v1.x - M); v1.y = __expf(v1.y - M); v1.z = __expf(v1.z - M); v1.w = __expf(v1.w - M);
    float sum = v0.x + v0.y + v0.z + v0.w + v1.x + v1.y + v1.z + v1.w;
    red[tid] = sum; __syncthreads();
    for (int s = 128; s > 0; s >>= 1) { if (tid < s) red[tid] += red[tid + s]; __syncthreads(); }
    float inv = 1.f / red[0];
    v0.x *= inv; v0.y *= inv; v0.z *= inv; v0.w *= inv;
    v1.x *= inv; v1.y *= inv; v1.z *= inv; v1.w *= inv;
    long b0 = row * (long)SEQ + 4 * tid;
    ushort4 hh, ll;
    fsplit(v0.x, hh.x, ll.x); fsplit(v0.y, hh.y, ll.y);
    fsplit(v0.z, hh.z, ll.z); fsplit(v0.w, hh.w, ll.w);
    *(ushort4*)(Ph + b0) = hh; *(ushort4*)(Pl + b0) = ll;
    fsplit(v1.x, hh.x, ll.x); fsplit(v1.y, hh.y, ll.y);
    fsplit(v1.z, hh.z, ll.z); fsplit(v1.w, hh.w, ll.w);
    *(ushort4*)(Ph + b0 + 1024) = hh; *(ushort4*)(Pl + b0 + 1024) = ll;
}

// ---------------- sparse select ----------------
__device__ __forceinline__ unsigned f2k(float f)
{
    unsigned u = __float_as_uint(f);
    return (u & 0x80000000u) ? ~u : (u | 0x80000000u);
}

__global__ void __launch_bounds__(256) sparse_sel(
    const float* __restrict__ qk, u16* __restrict__ sph, u16* __restrict__ spl)
{
    __shared__ float logit[SEQ];
    __shared__ unsigned hist[256];
    __shared__ unsigned suf[256];
    __shared__ float red[256];
    __shared__ unsigned sh_prefix;
    __shared__ int sh_remaining;

    long row = blockIdx.x;
    int tid = threadIdx.x;
    const float* p = qk + row * (long)SEQ;

    for (int k = tid; k < SEQ; k += 256) logit[k] = p[k];
    __syncthreads();

    float lm = -3.4e38f;
    for (int k = tid; k < SEQ; k += 256) lm = fmaxf(lm, logit[k]);
    red[tid] = lm; __syncthreads();
    for (int s = 128; s > 0; s >>= 1) { if (tid < s) red[tid] = fmaxf(red[tid], red[tid + s]); __syncthreads(); }
    float Lmax = red[0]; __syncthreads();

    float zacc = 0.f;
    for (int k = tid; k < SEQ; k += 256) zacc += __expf(logit[k] - Lmax);
    red[tid] = zacc; __syncthreads();
    for (int s = 128; s > 0; s >>= 1) { if (tid < s) red[tid] += red[tid + s]; __syncthreads(); }
    float Z = red[0]; __syncthreads();

    unsigned prefix = 0; int remaining = KTOP;
    for (int shift = 24; shift >= 0; shift -= 8) {
        hist[tid] = 0; __syncthreads();
        unsigned upmask = (shift == 24) ? 0u : (0xFFFFFFFFu << (shift + 8));
        for (int k = tid; k < SEQ; k += 256) {
            unsigned key = f2k(logit[k]);
            if ((key & upmask) == prefix)
                atomicAdd(&hist[(key >> shift) & 255], 1u);
        }
        __syncthreads();
        suf[tid] = hist[tid]; __syncthreads();
        for (int off = 1; off < 256; off <<= 1) {
            unsigned add = (tid + off < 256) ? suf[tid + off] : 0u;
            __syncthreads();
            suf[tid] += add;
            __syncthreads();
        }
        unsigned shere = suf[tid];
        unsigned snext = (tid < 255) ? suf[tid + 1] : 0u;
        if (shere >= (unsigned)remaining && snext < (unsigned)remaining) {
            sh_prefix = prefix | ((unsigned)tid << shift);
            sh_remaining = remaining - (int)snext;
        }
        __syncthreads();
        prefix = sh_prefix; remaining = sh_remaining;
        __syncthreads();
    }
    unsigned thr = prefix;

    float w8[8];
    float dsum = 0.f;
#pragma unroll
    for (int j = 0; j < 8; j++) {
        int k = tid + 256 * j;
        float l = logit[k];
        bool keep = (f2k(l) >= thr);
        float w = keep ? __expf(l - Lmax) : 0.f;
        w8[j] = w;
        dsum += w;
    }
    red[tid] = dsum; __syncthreads();
    for (int s = 128; s > 0; s >>= 1) { if (tid < s) red[tid] += red[tid + s]; __syncthreads(); }
    float inv = 1.f / (red[0] + 1e-9f * Z);

#pragma unroll
    for (int j = 0; j < 8; j++) {
        int k = tid + 256 * j;
        float w = w8[j] * inv;
        u16 h, l;
        fsplit(w, h, l);
        long o = row * (long)SEQ + k;
        sph[o] = h; spl[o] = l;
    }
}

// ---------------- gated fusion + LN1 ----------------
__global__ void fuse_ln1_k(float* __restrict__ x, const float* __restrict__ dn,
                           const float* __restrict__ sp, const float* __restrict__ lam,
                           int layer, const float* __restrict__ gam, const float* __restrict__ bet,
                           u16* __restrict__ xh, u16* __restrict__ xl)
{
    __shared__ float red[256];
    int row = blockIdx.x, tid = threadIdx.x;
    long off = (long)row * DIM + 2 * tid;
    float g = 1.f / (1.f + expf(-lam[layer]));
    float2 xv = *(const float2*)(x + off);
    float2 dv = *(const float2*)(dn + off);
    float2 sv = *(const float2*)(sp + off);
    float y0 = xv.x + g * dv.x + (1.f - g) * sv.x;
    float y1 = xv.y + g * dv.y + (1.f - g) * sv.y;
    red[tid] = y0 + y1; __syncthreads();
    for (int s = 128; s > 0; s >>= 1) { if (tid < s) red[tid] += red[tid + s]; __syncthreads(); }
    float mean = red[0] * (1.f / DIM); __syncthreads();
    float d0 = y0 - mean, d1 = y1 - mean;
    red[tid] = d0 * d0 + d1 * d1; __syncthreads();
    for (int s = 128; s > 0; s >>= 1) { if (tid < s) red[tid] += red[tid + s]; __syncthreads(); }
    float inv = 1.f / sqrtf(red[0] * (1.f / DIM) + 1e-5f);
    int dc = 2 * tid;
    float2 gm = *(const float2*)(gam + dc);
    float2 bt = *(const float2*)(bet + dc);
    float2 o; o.x = d0 * inv * gm.x + bt.x; o.y = d1 * inv * gm.y + bt.y;
    *(float2*)(x + off) = o;
    ushort2 hh, ll;
    fsplit(o.x, hh.x, ll.x); fsplit(o.y, hh.y, ll.y);
    *(ushort2*)(xh + off) = hh;
    *(ushort2*)(xl + off) = ll;
}

// ---------------- residual + LN2 ----------------
__global__ void add_ln2_k(float* __restrict__ x, const float* __restrict__ f,
                          const float* __restrict__ gam, const float* __restrict__ bet,
                          u16* __restrict__ xh, u16* __restrict__ xl)
{
    __shared__ float red[256];
    int row = blockIdx.x, tid = threadIdx.x;
    long off = (long)row * DIM + 2 * tid;
    float2 xv = *(const float2*)(x + off);
    float2 fv = *(const float2*)(f + off);
    float y0 = xv.x + fv.x;
    float y1 = xv.y + fv.y;
    red[tid] = y0 + y1; __syncthreads();
    for (int s = 128; s > 0; s >>= 1) { if (tid < s) red[tid] += red[tid + s]; __syncthreads(); }
    float mean = red[0] * (1.f / DIM); __syncthreads();
    float d0 = y0 - mean, d1 = y1 - mean;
    red[tid] = d0 * d0 + d1 * d1; __syncthreads();
    for (int s = 128; s > 0; s >>= 1) { if (tid < s) red[tid] += red[tid + s]; __syncthreads(); }
    float inv = 1.f / sqrtf(red[0] * (1.f / DIM) + 1e-5f);
    int dc = 2 * tid;
    float2 gm = *(const float2*)(gam + dc);
    float2 bt = *(const float2*)(bet + dc);
    float2 o; o.x = d0 * inv * gm.x + bt.x; o.y = d1 * inv * gm.y + bt.y;
    *(float2*)(x + off) = o;
    ushort2 hh, ll;
    fsplit(o.x, hh.x, ll.x); fsplit(o.y, hh.y, ll.y);
    *(ushort2*)(xh + off) = hh;
    *(ushort2*)(xl + off) = ll;
}

// ---------------- host-side helpers ----------------
template <int TN>
static void launch_tc(const u16* Ah, const u16* Al, const u16* Bh, const u16* Bl,
                      const float* bias, float* C, u16* Ch, u16* Cl,
                      int M, int N, int K, int lda, int ldb, int ldc,
                      int Z = 1, long sAo = 0, long sAi = 0, long sBo = 0, long sBi = 0,
                      long sCo = 0, long sCi = 0, int zdiv = 1,
                      float alpha = 1.f, int relu = 0)
{
    constexpr int NT = (TN == 256) ? 512 : 256;
    constexpr int SM = 3 * (2 * 128 * 80 + 2 * TN * 80);
    static bool attr_set = false;
    if (!attr_set) {
        cudaFuncSetAttribute(mm_gemm<TN>, cudaFuncAttributeMaxDynamicSharedMemorySize, SM);
        attr_set = true;
    }
    dim3 g(N / TN, M / 128, Z);
    mm_gemm<TN><<<g, NT, SM>>>(Ah, Al, Bh, Bl, bias, C, Ch, Cl,
                               K, lda, ldb, ldc,
                               sAo, sAi, sBo, sBi, sCo, sCi, zdiv, alpha, relu);
}

extern "C" void kernel_launch(void* const* d_in, const int* in_sizes, int n_in,
                              void* d_out, int out_size)
{
    const int*   SRC   = (const int*)  d_in[0];
    const float* EMB   = (const float*)d_in[1];
    const float* PE    = (const float*)d_in[2];
    const float* IN_W  = (const float*)d_in[3];
    const float* IN_B  = (const float*)d_in[4];
    const float* OUT_W = (const float*)d_in[5];
    const float* OUT_B = (const float*)d_in[6];
    const float* QP_W  = (const float*)d_in[7];
    const float* QP_B  = (const float*)d_in[8];
    const float* KP_W  = (const float*)d_in[9];
    const float* KP_B  = (const float*)d_in[10];
    const float* VP_W  = (const float*)d_in[11];
    const float* VP_B  = (const float*)d_in[12];
    const float* LAM   = (const float*)d_in[13];
    const float* FF1_W = (const float*)d_in[14];
    const float* FF1_B = (const float*)d_in[15];
    const float* FF2_W = (const float*)d_in[16];
    const float* FF2_B = (const float*)d_in[17];
    const float* LN1S  = (const float*)d_in[18];
    const float* LN1B  = (const float*)d_in[19];
    const float* LN2S  = (const float*)d_in[20];
    const float* LN2B  = (const float*)d_in[21];
    const float* FIN_W = (const float*)d_in[22];
    const float* FIN_B = (const float*)d_in[23];
    float* OUT = (float*)d_out;

    float *px, *x, *scores, *aproj, *sp, *fft, *pb;
    cudaGetSymbolAddress((void**)&px, g_px);       cudaGetSymbolAddress((void**)&x, g_x);
    cudaGetSymbolAddress((void**)&scores, g_scores); cudaGetSymbolAddress((void**)&aproj, g_aproj);
    cudaGetSymbolAddress((void**)&sp, g_sparse);   cudaGetSymbolAddress((void**)&fft, g_fft);
    cudaGetSymbolAddress((void**)&pb, g_pb);

    u16 *pxh, *pxl, *xh, *xl, *Ph, *Pl, *dh, *dl, *fh, *fl, *vth, *vtl;
    u16 *sph, *spl, *vsth, *vstl;
    cudaGetSymbolAddress((void**)&pxh, g_pxh); cudaGetSymbolAddress((void**)&pxl, g_pxl);
    cudaGetSymbolAddress((void**)&xh, g_xh);   cudaGetSymbolAddress((void**)&xl, g_xl);
    cudaGetSymbolAddress((void**)&Ph, g_Ph);   cudaGetSymbolAddress((void**)&Pl, g_Pl);
    cudaGetSymbolAddress((void**)&dh, g_dh);   cudaGetSymbolAddress((void**)&dl, g_dl);
    cudaGetSymbolAddress((void**)&fh, g_fh);   cudaGetSymbolAddress((void**)&fl, g_fl);
    cudaGetSymbolAddress((void**)&vth, g_vth); cudaGetSymbolAddress((void**)&vtl, g_vtl);
    cudaGetSymbolAddress((void**)&sph, g_sph); cudaGetSymbolAddress((void**)&spl, g_spl);
    cudaGetSymbolAddress((void**)&vsth, g_vsth); cudaGetSymbolAddress((void**)&vstl, g_vstl);

    u16 *pwh, *pwl, *outwh, *outwl, *f1wh, *f1wl, *f2wh, *f2wl, *finwh, *finwl;
    cudaGetSymbolAddress((void**)&pwh, g_pwh);     cudaGetSymbolAddress((void**)&pwl, g_pwl);
    cudaGetSymbolAddress((void**)&outwh, g_outwh); cudaGetSymbolAddress((void**)&outwl, g_outwl);
    cudaGetSymbolAddress((void**)&f1wh, g_f1wh);   cudaGetSymbolAddress((void**)&f1wl, g_f1wl);
    cudaGetSymbolAddress((void**)&f2wh, g_f2wh);   cudaGetSymbolAddress((void**)&f2wl, g_f2wl);
    cudaGetSymbolAddress((void**)&finwh, g_finwh); cudaGetSymbolAddress((void**)&finwl, g_finwl);

    // launch 1: embedding
    embed_k<<<TOKENS, 256>>>(SRC, EMB, PE, x, xh, xl);

    // launch 2: packed weights + bias
    {
        int tot = LAYERS * NPACK * (DIM / 4);
        cvt_pack_k<<<(tot + 255) / 256, 256>>>(IN_W, QP_W, KP_W, VP_W,
                                               IN_B, QP_B, KP_B, VP_B,
                                               (ushort4*)pwh, (ushort4*)pwl, pb);
    }
    // launch 3: remaining weights fused
    {
        int n1 = LAYERS * DIM * DIM / 4, n2 = LAYERS * FFD * DIM / 4;
        int n3 = LAYERS * DIM * FFD / 4, n4 = VOCAB * DIM / 4;
        cvt4_k<<<(n1 + n2 + n3 + n4 + 255) / 256, 256>>>(
            (const float4*)OUT_W, (ushort4*)outwh, (ushort4*)outwl, n1,
            (const float4*)FF1_W, (ushort4*)f1wh, (ushort4*)f1wl, n2,
            (const float4*)FF2_W, (ushort4*)f2wh, (ushort4*)f2wl, n3,
            (const float4*)FIN_W, (ushort4*)finwh, (ushort4*)finwl, n4);
    }

    for (int l = 0; l < LAYERS; l++) {
        long wq  = (long)l * NPACK * DIM;
        long wo  = (long)l * DIM * DIM;
        long wf1 = (long)l * FFD * DIM;
        long wf2 = (long)l * DIM * FFD;

        // launch 4 (layer 0): packed projections -> px + planes  [PROFILED]
        launch_tc<256>(xh, xl, pwh + wq, pwl + wq, pb + (long)l * NPACK,
                       px, pxh, pxl, TOKENS, NPACK, DIM, DIM, DIM, NPACK);

        // dense scores = Q @ K^T / 8 per (b,h)
        launch_tc<256>(pxh, pxl, pxh + DIM, pxl + DIM, nullptr,
                       scores, nullptr, nullptr,
                       SEQ, SEQ, HDIM, NPACK, NPACK, SEQ,
                       16, (long)SEQ * NPACK, (long)HDIM,
                       (long)SEQ * NPACK, (long)HDIM,
                       (long)HEADS * SEQ * SEQ, (long)SEQ * SEQ,
                       HEADS, 0.125f, 0);

        softmax_rows<<<16 * SEQ, 256>>>(scores, Ph, Pl);

        vt_k<<<dim3(SEQ / 32, HDIM / 32, 16), dim3(32, 8)>>>(px, vth, vtl);

        // dense = P @ V per (b,h) -> planes only
        launch_tc<64>(Ph, Pl, vth, vtl, nullptr, nullptr, dh, dl,
                      SEQ, HDIM, SEQ, SEQ, SEQ, DIM,
                      16, (long)HEADS * SEQ * SEQ, (long)SEQ * SEQ,
                      (long)HEADS * HDIM * SEQ, (long)HDIM * SEQ,
                      (long)SEQ * DIM, (long)HDIM,
                      HEADS, 1.f, 0);

        // dense projection -> aproj fp32
        launch_tc<128>(dh, dl, outwh + wo, outwl + wo, OUT_B + (long)l * DIM,
                       aproj, nullptr, nullptr, TOKENS, DIM, DIM, DIM, DIM, DIM);

        // low-rank logits qk = Qs @ Ks^T / sqrt(R) per batch
        launch_tc<256>(pxh + COL_QS, pxl + COL_QS, pxh + COL_KS, pxl + COL_KS, nullptr,
                       scores, nullptr, nullptr,
                       SEQ, SEQ, RANK, NPACK, NPACK, SEQ,
                       2, (long)SEQ * NPACK, 0, (long)SEQ * NPACK, 0,
                       (long)SEQ * SEQ, 0, 1, 0.125f, 0);

        sparse_sel<<<TOKENS, 256>>>(scores, sph, spl);

        vst_k<<<dim3(SEQ / 32, DIM / 32, 2), dim3(32, 8)>>>(px, vsth, vstl);

        // sparse = sp @ Vs per batch
        launch_tc<128>(sph, spl, vsth, vstl, nullptr, sp, nullptr, nullptr,
                       SEQ, DIM, SEQ, SEQ, SEQ, DIM,
                       2, (long)SEQ * SEQ, 0, (long)DIM * SEQ, 0,
                       (long)SEQ * DIM, 0, 1, 1.f, 0);

        fuse_ln1_k<<<TOKENS, 256>>>(x, aproj, sp, LAM, l,
                                    LN1S + (long)l * DIM, LN1B + (long)l * DIM, xh, xl);

        // FFN
        launch_tc<256>(xh, xl, f1wh + wf1, f1wl + wf1, FF1_B + (long)l * FFD,
                       nullptr, fh, fl, TOKENS, FFD, DIM, DIM, DIM, FFD,
                       1, 0, 0, 0, 0, 0, 0, 1, 1.f, 1);
        launch_tc<128>(fh, fl, f2wh + wf2, f2wl + wf2, FF2_B + (long)l * DIM,
                       fft, nullptr, nullptr, TOKENS, DIM, FFD, FFD, FFD, DIM);

        add_ln2_k<<<TOKENS, 256>>>(x, fft, LN2S + (long)l * DIM, LN2B + (long)l * DIM, xh, xl);
    }

    // final vocab projection
    launch_tc<256>(xh, xl, finwh, finwl, FIN_B, OUT, nullptr, nullptr,
                   TOKENS, VOCAB, DIM, DIM, DIM, VOCAB);
}

// round 10
// speedup vs baseline: 1.6453x; 1.0506x over previous
#include <cuda_runtime.h>
#include <cuda_bf16.h>
#include <math.h>
#include <stdint.h>

#define SEQ    2048
#define TOKENS 4096
#define DIM    512
#define HEADS  8
#define HDIM   64
#define RANK   64
#define LAYERS 6
#define VOCAB  32000
#define FFD    2048
#define KTOP   409
#define NPACK  2304   // 1536 qkv | 64 qs | 64 ks | 512 vs | 128 pad
#define COL_QS 1536
#define COL_KS 1600
#define COL_VS 1664

typedef unsigned short u16;

// ---------------- fp32 scratch ----------------
__device__ float g_px[(size_t)TOKENS * NPACK];
__device__ float g_x[TOKENS * DIM];
__device__ float g_scores[(size_t)16 * SEQ * SEQ];
__device__ float g_aproj[TOKENS * DIM];
__device__ float g_sparse[TOKENS * DIM];
__device__ float g_fft[TOKENS * DIM];

// ---------------- bf16 hi/lo planes (activations) ----------------
__device__ alignas(16) u16 g_pxh[(size_t)TOKENS * NPACK], g_pxl[(size_t)TOKENS * NPACK];
__device__ alignas(16) u16 g_xh[TOKENS * DIM],       g_xl[TOKENS * DIM];
__device__ alignas(16) u16 g_Ph[(size_t)16 * SEQ * SEQ], g_Pl[(size_t)16 * SEQ * SEQ];
__device__ alignas(16) u16 g_dh[TOKENS * DIM],       g_dl[TOKENS * DIM];
__device__ alignas(16) u16 g_fh[TOKENS * FFD],       g_fl[TOKENS * FFD];
__device__ alignas(16) u16 g_vth[16 * HDIM * SEQ],   g_vtl[16 * HDIM * SEQ];
__device__ alignas(16) u16 g_sph[(size_t)2 * SEQ * SEQ], g_spl[(size_t)2 * SEQ * SEQ];
__device__ alignas(16) u16 g_vsth[2 * DIM * SEQ],    g_vstl[2 * DIM * SEQ];

// ---------------- bf16 hi/lo planes (weights) ----------------
__device__ alignas(16) u16 g_pwh[LAYERS * NPACK * DIM], g_pwl[LAYERS * NPACK * DIM];
__device__ float g_pb[LAYERS * NPACK];
__device__ alignas(16) u16 g_outwh[LAYERS * DIM * DIM],  g_outwl[LAYERS * DIM * DIM];
__device__ alignas(16) u16 g_f1wh[LAYERS * FFD * DIM],   g_f1wl[LAYERS * FFD * DIM];
__device__ alignas(16) u16 g_f2wh[LAYERS * DIM * FFD],   g_f2wl[LAYERS * DIM * FFD];
__device__ alignas(16) u16 g_finwh[VOCAB * DIM],         g_finwl[VOCAB * DIM];

// ---------------- small device helpers ----------------
__device__ __forceinline__ void fsplit(float x, u16& h, u16& l)
{
    __nv_bfloat16 bh = __float2bfloat16_rn(x);
    float fh = __bfloat162float(bh);
    __nv_bfloat16 bl = __float2bfloat16_rn(x - fh);
    h = *reinterpret_cast<u16*>(&bh);
    l = *reinterpret_cast<u16*>(&bl);
}

__device__ __forceinline__ uint32_t smem_u32(const void* p)
{
    uint32_t a;
    asm("{ .reg .u64 t; cvta.to.shared.u64 t, %1; cvt.u32.u64 %0, t; }" : "=r"(a) : "l"(p));
    return a;
}

__device__ __forceinline__ void cpa16(uint32_t dst, const void* src)
{
    asm volatile("cp.async.cg.shared.global [%0], [%1], 16;" :: "r"(dst), "l"(src) : "memory");
}

__device__ __forceinline__ void ldsm4(uint32_t* r, uint32_t addr)
{
    asm volatile("ldmatrix.sync.aligned.m8n8.x4.shared.b16 {%0,%1,%2,%3}, [%4];"
                 : "=r"(r[0]), "=r"(r[1]), "=r"(r[2]), "=r"(r[3]) : "r"(addr));
}

__device__ __forceinline__ void mma16816(float* c, const uint32_t* a, uint32_t b0, uint32_t b1)
{
    asm volatile(
        "mma.sync.aligned.m16n8k16.row.col.f32.bf16.bf16.f32 "
        "{%0,%1,%2,%3}, {%4,%5,%6,%7}, {%8,%9}, {%0,%1,%2,%3};"
        : "+f"(c[0]), "+f"(c[1]), "+f"(c[2]), "+f"(c[3])
        : "r"(a[0]), "r"(a[1]), "r"(a[2]), "r"(a[3]), "r"(b0), "r"(b1));
}

// ---------------- HMMA bf16x3 GEMM: C = alpha * (A @ B^T) + bias ----------------
// Super-chunk K=64 (4 ks-steps per barrier), 144B-padded rows (conflict-free ldsm),
// 2 super-stages, issue-after-wait pipeline (zero steady-state exposed latency).
// TN=256: 512 thr, 16 warps (4Mx4N, 32x64). TN=128: 256 thr (2Mx4N, 64x32).
// TN=64: 256 thr (4Mx2N, 32x32), 2 CTAs/SM.
template <int TN>
__global__ void __launch_bounds__((TN == 256) ? 512 : 256, (TN == 64) ? 2 : 1)
mm_gemm(const u16* __restrict__ Ah, const u16* __restrict__ Al,
        const u16* __restrict__ Bh, const u16* __restrict__ Bl,
        const float* __restrict__ bias, float* __restrict__ C,
        u16* __restrict__ Ch, u16* __restrict__ Cl,
        int K, int lda, int ldb, int ldc,
        long sAo, long sAi, long sBo, long sBi, long sCo, long sCi,
        int zdiv, float alpha, int relu)
{
    constexpr int NT  = (TN == 256) ? 512 : 256;
    constexpr int MI  = (TN == 128) ? 4 : 2;
    constexpr int NI  = (TN == 256) ? 4 : 2;
    constexpr int RB  = 144;                 // padded row bytes (K=64 bf16 = 128B data)
    constexpr int APB = 128 * RB;
    constexpr int BPB = TN * RB;
    constexpr int STAGE = 2 * APB + 2 * BPB;
    constexpr int ROWSP = NT / 8;            // rows per cp.async pass (8 thr/row)

    extern __shared__ char smem[];
    const uint32_t su = smem_u32(smem);
    const int tid = threadIdx.x;
    const int wid = tid >> 5;
    const int lane = tid & 31;

    int z = blockIdx.z;
    int zo = z / zdiv, zi = z - zo * zdiv;
    long ao = (long)zo * sAo + (long)zi * sAi;
    long bo = (long)zo * sBo + (long)zi * sBi;
    long co = (long)zo * sCo + (long)zi * sCi;
    Ah += ao; Al += ao; Bh += bo; Bl += bo;
    if (C)  C  += co;
    if (Ch) { Ch += co; Cl += co; }
    const int m0 = blockIdx.y * 128;
    const int n0 = blockIdx.x * TN;

    const int wmBase = (TN == 256) ? (wid & 3) * 32
                     : (TN == 128) ? (wid & 1) * 64 : (wid & 3) * 32;
    const int wnBase = (TN == 256) ? (wid >> 2) * 64
                     : (TN == 128) ? (wid >> 1) * 32 : (wid >> 2) * 32;

    float acc[MI][2 * NI][4];
#pragma unroll
    for (int mi = 0; mi < MI; mi++)
#pragma unroll
        for (int n8 = 0; n8 < 2 * NI; n8++)
#pragma unroll
            for (int q = 0; q < 4; q++) acc[mi][n8][q] = 0.f;

    const int nsch = K >> 6;                 // super-chunks of K=64
    const int ar = tid >> 3, ac = tid & 7;   // 8 x 16B per 128B row
    auto issue = [&](int i) {
        int s = i & 1;
        int k0 = i << 6;
        uint32_t st = su + s * STAGE;
#pragma unroll
        for (int j = 0; j < 128 / ROWSP; j++) {
            int r = ar + ROWSP * j;
            long g = (long)(m0 + r) * lda + k0 + ac * 8;
            uint32_t d = st + r * RB + ac * 16;
            cpa16(d, Ah + g);
            cpa16(d + APB, Al + g);
        }
#pragma unroll
        for (int j = 0; j < TN / ROWSP; j++) {
            int r = ar + ROWSP * j;
            long g = (long)(n0 + r) * ldb + k0 + ac * 8;
            uint32_t d = st + 2 * APB + r * RB + ac * 16;
            cpa16(d, Bh + g);
            cpa16(d + BPB, Bl + g);
        }
        asm volatile("cp.async.commit_group;" ::: "memory");
    };

    issue(0);
    const uint32_t lrow = lane & 15;
    const uint32_t lcol = (lane >> 4) * 16;

    for (int i = 0; i < nsch; i++) {
        asm volatile("cp.async.wait_group 0;" ::: "memory");
        __syncthreads();
        if (i + 1 < nsch) issue(i + 1);

        int s = i & 1;
        uint32_t aH = su + s * STAGE;
        uint32_t aL = aH + APB;
        uint32_t bH = aH + 2 * APB;
        uint32_t bL = bH + BPB;

#pragma unroll
        for (int ks = 0; ks < 4; ks++) {
            uint32_t kb = ks * 32 + lcol;
            uint32_t a[MI][4], bh[NI][4];
#pragma unroll
            for (int mi = 0; mi < MI; mi++)
                ldsm4(a[mi], aH + (wmBase + mi * 16 + lrow) * RB + kb);
#pragma unroll
            for (int ni = 0; ni < NI; ni++)
                ldsm4(bh[ni], bH + (wnBase + ni * 16 + lrow) * RB + kb);
            // pass 1: Ah * Bh
#pragma unroll
            for (int mi = 0; mi < MI; mi++)
#pragma unroll
                for (int ni = 0; ni < NI; ni++) {
                    mma16816(acc[mi][2 * ni],     a[mi], bh[ni][0], bh[ni][2]);
                    mma16816(acc[mi][2 * ni + 1], a[mi], bh[ni][1], bh[ni][3]);
                }
            // pass 3: Al * Bh (reuses bh)
            {
                uint32_t al[MI][4];
#pragma unroll
                for (int mi = 0; mi < MI; mi++)
                    ldsm4(al[mi], aL + (wmBase + mi * 16 + lrow) * RB + kb);
#pragma unroll
                for (int mi = 0; mi < MI; mi++)
#pragma unroll
                    for (int ni = 0; ni < NI; ni++) {
                        mma16816(acc[mi][2 * ni],     al[mi], bh[ni][0], bh[ni][2]);
                        mma16816(acc[mi][2 * ni + 1], al[mi], bh[ni][1], bh[ni][3]);
                    }
            }
            // pass 2: Ah * Bl
            {
                uint32_t bl[NI][4];
#pragma unroll
                for (int ni = 0; ni < NI; ni++)
                    ldsm4(bl[ni], bL + (wnBase + ni * 16 + lrow) * RB + kb);
#pragma unroll
                for (int mi = 0; mi < MI; mi++)
#pragma unroll
                    for (int ni = 0; ni < NI; ni++) {
                        mma16816(acc[mi][2 * ni],     a[mi], bl[ni][0], bl[ni][2]);
                        mma16816(acc[mi][2 * ni + 1], a[mi], bl[ni][1], bl[ni][3]);
                    }
            }
        }
    }

#pragma unroll
    for (int mi = 0; mi < MI; mi++) {
        int r0 = m0 + wmBase + mi * 16 + (lane >> 2);
#pragma unroll
        for (int n8 = 0; n8 < 2 * NI; n8++) {
            int c = n0 + wnBase + n8 * 8 + (lane & 3) * 2;
            float2 o0, o1;
            o0.x = acc[mi][n8][0] * alpha; o0.y = acc[mi][n8][1] * alpha;
            o1.x = acc[mi][n8][2] * alpha; o1.y = acc[mi][n8][3] * alpha;
            if (bias) {
                float b0 = bias[c], b1 = bias[c + 1];
                o0.x += b0; o0.y += b1; o1.x += b0; o1.y += b1;
            }
            if (relu) {
                o0.x = fmaxf(o0.x, 0.f); o0.y = fmaxf(o0.y, 0.f);
                o1.x = fmaxf(o1.x, 0.f); o1.y = fmaxf(o1.y, 0.f);
            }
            long off0 = (long)r0 * ldc + c;
            long off1 = off0 + (long)8 * ldc;
            if (C) {
                *(float2*)(C + off0) = o0;
                *(float2*)(C + off1) = o1;
            }
            if (Ch) {
                ushort2 hh, ll;
                fsplit(o0.x, hh.x, ll.x); fsplit(o0.y, hh.y, ll.y);
                *(ushort2*)(Ch + off0) = hh; *(ushort2*)(Cl + off0) = ll;
                fsplit(o1.x, hh.x, ll.x); fsplit(o1.y, hh.y, ll.y);
                *(ushort2*)(Ch + off1) = hh; *(ushort2*)(Cl + off1) = ll;
            }
        }
    }
}

// ---------------- weight converters ----------------
__global__ void cvt_pack_k(const float* __restrict__ in_w, const float* __restrict__ qp_w,
                           const float* __restrict__ kp_w, const float* __restrict__ vp_w,
                           const float* __restrict__ in_b, const float* __restrict__ qp_b,
                           const float* __restrict__ kp_b, const float* __restrict__ vp_b,
                           ushort4* __restrict__ h, ushort4* __restrict__ l,
                           float* __restrict__ pb)
{
    int i = blockIdx.x * 256 + threadIdx.x;
    if (i < LAYERS * NPACK) {
        int lay = i / NPACK;
        int r = i - lay * NPACK;
        float v = 0.f;
        if (r < COL_QS) v = in_b[lay * 1536 + r];
        else if (r < COL_KS) v = qp_b[lay * RANK + (r - COL_QS)];
        else if (r < COL_VS) v = kp_b[lay * RANK + (r - COL_KS)];
        else if (r < COL_VS + DIM) v = vp_b[lay * DIM + (r - COL_VS)];
        pb[i] = v;
    }
    const int PER_L = NPACK * (DIM / 4);
    if (i >= LAYERS * PER_L) return;
    int lay = i / PER_L;
    int rem = i - lay * PER_L;
    int r = rem / (DIM / 4);
    int c4 = rem - r * (DIM / 4);
    float4 v = make_float4(0.f, 0.f, 0.f, 0.f);
    if (r < COL_QS)
        v = ((const float4*)(in_w + ((long)lay * 1536 + r) * DIM))[c4];
    else if (r < COL_KS)
        v = ((const float4*)(qp_w + ((long)lay * RANK + (r - COL_QS)) * DIM))[c4];
    else if (r < COL_VS)
        v = ((const float4*)(kp_w + ((long)lay * RANK + (r - COL_KS)) * DIM))[c4];
    else if (r < COL_VS + DIM)
        v = ((const float4*)(vp_w + ((long)lay * DIM + (r - COL_VS)) * DIM))[c4];
    ushort4 hh, ll;
    fsplit(v.x, hh.x, ll.x); fsplit(v.y, hh.y, ll.y);
    fsplit(v.z, hh.z, ll.z); fsplit(v.w, hh.w, ll.w);
    long o = (long)lay * NPACK * (DIM / 4) + (long)r * (DIM / 4) + c4;
    h[o] = hh; l[o] = ll;
}

__global__ void cvt4_k(const float4* __restrict__ s1, ushort4* __restrict__ h1, ushort4* __restrict__ l1, int n1,
                       const float4* __restrict__ s2, ushort4* __restrict__ h2, ushort4* __restrict__ l2, int n2,
                       const float4* __restrict__ s3, ushort4* __restrict__ h3, ushort4* __restrict__ l3, int n3,
                       const float4* __restrict__ s4, ushort4* __restrict__ h4, ushort4* __restrict__ l4, int n4)
{
    int i = blockIdx.x * 256 + threadIdx.x;
    const float4* s; ushort4 *h, *l; int j;
    if (i < n1) { s = s1; h = h1; l = l1; j = i; }
    else if (i < n1 + n2) { s = s2; h = h2; l = l2; j = i - n1; }
    else if (i < n1 + n2 + n3) { s = s3; h = h3; l = l3; j = i - n1 - n2; }
    else if (i < n1 + n2 + n3 + n4) { s = s4; h = h4; l = l4; j = i - n1 - n2 - n3; }
    else return;
    float4 v = s[j];
    ushort4 hh, ll;
    fsplit(v.x, hh.x, ll.x); fsplit(v.y, hh.y, ll.y);
    fsplit(v.z, hh.z, ll.z); fsplit(v.w, hh.w, ll.w);
    h[j] = hh; l[j] = ll;
}

// V^T planes (dense) from packed px
__global__ void vt_k(const float* __restrict__ px, u16* __restrict__ vh, u16* __restrict__ vl)
{
    __shared__ float t[32][33];
    int z = blockIdx.z, b = z >> 3, h = z & 7;
    int s0 = blockIdx.x * 32, d0 = blockIdx.y * 32;
    int tx = threadIdx.x, ty = threadIdx.y;
#pragma unroll
    for (int j = 0; j < 4; j++) {
        int s = s0 + ty + j * 8;
        t[ty + j * 8][tx] = px[((long)(b * SEQ + s)) * NPACK + 2 * DIM + h * HDIM + d0 + tx];
    }
    __syncthreads();
#pragma unroll
    for (int j = 0; j < 4; j++) {
        int d = d0 + ty + j * 8;
        long o = ((long)z * HDIM + d) * SEQ + s0 + tx;
        u16 hh, ll;
        fsplit(t[tx][ty + j * 8], hh, ll);
        vh[o] = hh; vl[o] = ll;
    }
}

// Vs^T planes (sparse) from packed px cols [COL_VS, COL_VS+512)
__global__ void vst_k(const float* __restrict__ px, u16* __restrict__ vh, u16* __restrict__ vl)
{
    __shared__ float t[32][33];
    int b = blockIdx.z;
    int s0 = blockIdx.x * 32, d0 = blockIdx.y * 32;
    int tx = threadIdx.x, ty = threadIdx.y;
#pragma unroll
    for (int j = 0; j < 4; j++) {
        int s = s0 + ty + j * 8;
        t[ty + j * 8][tx] = px[((long)(b * SEQ + s)) * NPACK + COL_VS + d0 + tx];
    }
    __syncthreads();
#pragma unroll
    for (int j = 0; j < 4; j++) {
        int d = d0 + ty + j * 8;
        long o = ((long)(b * DIM + d)) * SEQ + s0 + tx;
        u16 hh, ll;
        fsplit(t[tx][ty + j * 8], hh, ll);
        vh[o] = hh; vl[o] = ll;
    }
}

// ---------------- embedding (+ x planes) ----------------
__global__ void embed_k(const int* __restrict__ src, const float* __restrict__ emb,
                        const float* __restrict__ pe, float* __restrict__ x,
                        u16* __restrict__ xh, u16* __restrict__ xl)
{
    int t = blockIdx.x;
    int tid = threadIdx.x;
    int s = t & (SEQ - 1);
    int tok = src[t];
    int d = tid * 2;
    float2 e = *(const float2*)(emb + (long)tok * DIM + d);
    float2 p = *(const float2*)(pe + (long)s * DIM + d);
    float2 o;
    o.x = e.x * 22.627416998f + p.x;
    o.y = e.y * 22.627416998f + p.y;
    long off = (long)t * DIM + d;
    *(float2*)(x + off) = o;
    ushort2 hh, ll;
    fsplit(o.x, hh.x, ll.x); fsplit(o.y, hh.y, ll.y);
    *(ushort2*)(xh + off) = hh;
    *(ushort2*)(xl + off) = ll;
}

// ---------------- row softmax -> P hi/lo planes ----------------
__global__ void softmax_rows(const float* __restrict__ S, u16* __restrict__ Ph,
                             u16* __restrict__ Pl)
{
    __shared__ float red[256];
    long row = blockIdx.x;
    const float* p = S + row * (long)SEQ;
    int tid = threadIdx.x;
    float4 v0 = *(const float4*)(p + 4 * tid);
    float4 v1 = *(const float4*)(p + 4 * tid + 1024);
    float m = fmaxf(fmaxf(fmaxf(v0.x, v0.y), fmaxf(v0.z, v0.w)),
                    fmaxf(fmaxf(v1.x, v1.y), fmaxf(v1.z, v1.w)));
    red[tid] = m; __syncthreads();
    for (int s = 128; s > 0; s >>= 1) { if (tid < s) red[tid] = fmaxf(red[tid], red[tid + s]); __syncthreads(); }
    float M = red[0]; __syncthreads();
    v0.x = __expf(v0.x - M); v0.y = __expf(v0.y - M); v0.z = __expf(v0.z - M); v0.w = __expf(v0.w - M);
    v1.x = __expf(v1.x - M); v1.y = __expf(v1.y - M); v1.z = __expf(v1.z - M); v1.w = __expf(v1.w - M);
    float sum = v0.x + v0.y + v0.z + v0.w + v1.x + v1.y + v1.z + v1.w;
    red[tid] = sum; __syncthreads();
    for (int s = 128; s > 0; s >>= 1) { if (tid < s) red[tid] += red[tid + s]; __syncthreads(); }
    float inv = 1.f / red[0];
    v0.x *= inv; v0.y *= inv; v0.z *= inv; v0.w *= inv;
    v1.x *= inv; v1.y *= inv; v1.z *= inv; v1.w *= inv;
    long b0 = row * (long)SEQ + 4 * tid;
    ushort4 hh, ll;
    fsplit(v0.x, hh.x, ll.x); fsplit(v0.y, hh.y, ll.y);
    fsplit(v0.z, hh.z, ll.z); fsplit(v0.w, hh.w, ll.w);
    *(ushort4*)(Ph + b0) = hh; *(ushort4*)(Pl + b0) = ll;
    fsplit(v1.x, hh.x, ll.x); fsplit(v1.y, hh.y, ll.y);
    fsplit(v1.z, hh.z, ll.z); fsplit(v1.w, hh.w, ll.w);
    *(ushort4*)(Ph + b0 + 1024) = hh; *(ushort4*)(Pl + b0 + 1024) = ll;
}

// ---------------- sparse select ----------------
__device__ __forceinline__ unsigned f2k(float f)
{
    unsigned u = __float_as_uint(f);
    return (u & 0x80000000u) ? ~u : (u | 0x80000000u);
}

__global__ void __launch_bounds__(256) sparse_sel(
    const float* __restrict__ qk, u16* __restrict__ sph, u16* __restrict__ spl)
{
    __shared__ float logit[SEQ];
    __shared__ unsigned hist[256];
    __shared__ unsigned suf[256];
    __shared__ float red[256];
    __shared__ unsigned sh_prefix;
    __shared__ int sh_remaining;

    long row = blockIdx.x;
    int tid = threadIdx.x;
    const float* p = qk + row * (long)SEQ;

    for (int k = tid; k < SEQ; k += 256) logit[k] = p[k];
    __syncthreads();

    float lm = -3.4e38f;
    for (int k = tid; k < SEQ; k += 256) lm = fmaxf(lm, logit[k]);
    red[tid] = lm; __syncthreads();
    for (int s = 128; s > 0; s >>= 1) { if (tid < s) red[tid] = fmaxf(red[tid], red[tid + s]); __syncthreads(); }
    float Lmax = red[0]; __syncthreads();

    float zacc = 0.f;
    for (int k = tid; k < SEQ; k += 256) zacc += __expf(logit[k] - Lmax);
    red[tid] = zacc; __syncthreads();
    for (int s = 128; s > 0; s >>= 1) { if (tid < s) red[tid] += red[tid + s]; __syncthreads(); }
    float Z = red[0]; __syncthreads();

    unsigned prefix = 0; int remaining = KTOP;
    for (int shift = 24; shift >= 0; shift -= 8) {
        hist[tid] = 0; __syncthreads();
        unsigned upmask = (shift == 24) ? 0u : (0xFFFFFFFFu << (shift + 8));
        for (int k = tid; k < SEQ; k += 256) {
            unsigned key = f2k(logit[k]);
            if ((key & upmask) == prefix)
                atomicAdd(&hist[(key >> shift) & 255], 1u);
        }
        __syncthreads();
        suf[tid] = hist[tid]; __syncthreads();
        for (int off = 1; off < 256; off <<= 1) {
            unsigned add = (tid + off < 256) ? suf[tid + off] : 0u;
            __syncthreads();
            suf[tid] += add;
            __syncthreads();
        }
        unsigned shere = suf[tid];
        unsigned snext = (tid < 255) ? suf[tid + 1] : 0u;
        if (shere >= (unsigned)remaining && snext < (unsigned)remaining) {
            sh_prefix = prefix | ((unsigned)tid << shift);
            sh_remaining = remaining - (int)snext;
        }
        __syncthreads();
        prefix = sh_prefix; remaining = sh_remaining;
        __syncthreads();
    }
    unsigned thr = prefix;

    float w8[8];
    float dsum = 0.f;
#pragma unroll
    for (int j = 0; j < 8; j++) {
        int k = tid + 256 * j;
        float l = logit[k];
        bool keep = (f2k(l) >= thr);
        float w = keep ? __expf(l - Lmax) : 0.f;
        w8[j] = w;
        dsum += w;
    }
    red[tid] = dsum; __syncthreads();
    for (int s = 128; s > 0; s >>= 1) { if (tid < s) red[tid] += red[tid + s]; __syncthreads(); }
    float inv = 1.f / (red[0] + 1e-9f * Z);

#pragma unroll
    for (int j = 0; j < 8; j++) {
        int k = tid + 256 * j;
        float w = w8[j] * inv;
        u16 h, l;
        fsplit(w, h, l);
        long o = row * (long)SEQ + k;
        sph[o] = h; spl[o] = l;
    }
}

// ---------------- gated fusion + LN1 ----------------
__global__ void fuse_ln1_k(float* __restrict__ x, const float* __restrict__ dn,
                           const float* __restrict__ sp, const float* __restrict__ lam,
                           int layer, const float* __restrict__ gam, const float* __restrict__ bet,
                           u16* __restrict__ xh, u16* __restrict__ xl)
{
    __shared__ float red[256];
    int row = blockIdx.x, tid = threadIdx.x;
    long off = (long)row * DIM + 2 * tid;
    float g = 1.f / (1.f + expf(-lam[layer]));
    float2 xv = *(const float2*)(x + off);
    float2 dv = *(const float2*)(dn + off);
    float2 sv = *(const float2*)(sp + off);
    float y0 = xv.x + g * dv.x + (1.f - g) * sv.x;
    float y1 = xv.y + g * dv.y + (1.f - g) * sv.y;
    red[tid] = y0 + y1; __syncthreads();
    for (int s = 128; s > 0; s >>= 1) { if (tid < s) red[tid] += red[tid + s]; __syncthreads(); }
    float mean = red[0] * (1.f / DIM); __syncthreads();
    float d0 = y0 - mean, d1 = y1 - mean;
    red[tid] = d0 * d0 + d1 * d1; __syncthreads();
    for (int s = 128; s > 0; s >>= 1) { if (tid < s) red[tid] += red[tid + s]; __syncthreads(); }
    float inv = 1.f / sqrtf(red[0] * (1.f / DIM) + 1e-5f);
    int dc = 2 * tid;
    float2 gm = *(const float2*)(gam + dc);
    float2 bt = *(const float2*)(bet + dc);
    float2 o; o.x = d0 * inv * gm.x + bt.x; o.y = d1 * inv * gm.y + bt.y;
    *(float2*)(x + off) = o;
    ushort2 hh, ll;
    fsplit(o.x, hh.x, ll.x); fsplit(o.y, hh.y, ll.y);
    *(ushort2*)(xh + off) = hh;
    *(ushort2*)(xl + off) = ll;
}

// ---------------- residual + LN2 ----------------
__global__ void add_ln2_k(float* __restrict__ x, const float* __restrict__ f,
                          const float* __restrict__ gam, const float* __restrict__ bet,
                          u16* __restrict__ xh, u16* __restrict__ xl)
{
    __shared__ float red[256];
    int row = blockIdx.x, tid = threadIdx.x;
    long off = (long)row * DIM + 2 * tid;
    float2 xv = *(const float2*)(x + off);
    float2 fv = *(const float2*)(f + off);
    float y0 = xv.x + fv.x;
    float y1 = xv.y + fv.y;
    red[tid] = y0 + y1; __syncthreads();
    for (int s = 128; s > 0; s >>= 1) { if (tid < s) red[tid] += red[tid + s]; __syncthreads(); }
    float mean = red[0] * (1.f / DIM); __syncthreads();
    float d0 = y0 - mean, d1 = y1 - mean;
    red[tid] = d0 * d0 + d1 * d1; __syncthreads();
    for (int s = 128; s > 0; s >>= 1) { if (tid < s) red[tid] += red[tid + s]; __syncthreads(); }
    float inv = 1.f / sqrtf(red[0] * (1.f / DIM) + 1e-5f);
    int dc = 2 * tid;
    float2 gm = *(const float2*)(gam + dc);
    float2 bt = *(const float2*)(bet + dc);
    float2 o; o.x = d0 * inv * gm.x + bt.x; o.y = d1 * inv * gm.y + bt.y;
    *(float2*)(x + off) = o;
    ushort2 hh, ll;
    fsplit(o.x, hh.x, ll.x); fsplit(o.y, hh.y, ll.y);
    *(ushort2*)(xh + off) = hh;
    *(ushort2*)(xl + off) = ll;
}

// ---------------- host-side helpers ----------------
template <int TN>
static void launch_tc(const u16* Ah, const u16* Al, const u16* Bh, const u16* Bl,
                      const float* bias, float* C, u16* Ch, u16* Cl,
                      int M, int N, int K, int lda, int ldb, int ldc,
                      int Z = 1, long sAo = 0, long sAi = 0, long sBo = 0, long sBi = 0,
                      long sCo = 0, long sCi = 0, int zdiv = 1,
                      float alpha = 1.f, int relu = 0)
{
    constexpr int NT = (TN == 256) ? 512 : 256;
    constexpr int SM = 2 * (2 * 128 * 144 + 2 * TN * 144);
    static bool attr_set = false;
    if (!attr_set) {
        cudaFuncSetAttribute(mm_gemm<TN>, cudaFuncAttributeMaxDynamicSharedMemorySize, SM);
        attr_set = true;
    }
    dim3 g(N / TN, M / 128, Z);
    mm_gemm<TN><<<g, NT, SM>>>(Ah, Al, Bh, Bl, bias, C, Ch, Cl,
                               K, lda, ldb, ldc,
                               sAo, sAi, sBo, sBi, sCo, sCi, zdiv, alpha, relu);
}

extern "C" void kernel_launch(void* const* d_in, const int* in_sizes, int n_in,
                              void* d_out, int out_size)
{
    const int*   SRC   = (const int*)  d_in[0];
    const float* EMB   = (const float*)d_in[1];
    const float* PE    = (const float*)d_in[2];
    const float* IN_W  = (const float*)d_in[3];
    const float* IN_B  = (const float*)d_in[4];
    const float* OUT_W = (const float*)d_in[5];
    const float* OUT_B = (const float*)d_in[6];
    const float* QP_W  = (const float*)d_in[7];
    const float* QP_B  = (const float*)d_in[8];
    const float* KP_W  = (const float*)d_in[9];
    const float* KP_B  = (const float*)d_in[10];
    const float* VP_W  = (const float*)d_in[11];
    const float* VP_B  = (const float*)d_in[12];
    const float* LAM   = (const float*)d_in[13];
    const float* FF1_W = (const float*)d_in[14];
    const float* FF1_B = (const float*)d_in[15];
    const float* FF2_W = (const float*)d_in[16];
    const float* FF2_B = (const float*)d_in[17];
    const float* LN1S  = (const float*)d_in[18];
    const float* LN1B  = (const float*)d_in[19];
    const float* LN2S  = (const float*)d_in[20];
    const float* LN2B  = (const float*)d_in[21];
    const float* FIN_W = (const float*)d_in[22];
    const float* FIN_B = (const float*)d_in[23];
    float* OUT = (float*)d_out;

    float *px, *x, *scores, *aproj, *sp, *fft, *pb;
    cudaGetSymbolAddress((void**)&px, g_px);       cudaGetSymbolAddress((void**)&x, g_x);
    cudaGetSymbolAddress((void**)&scores, g_scores); cudaGetSymbolAddress((void**)&aproj, g_aproj);
    cudaGetSymbolAddress((void**)&sp, g_sparse);   cudaGetSymbolAddress((void**)&fft, g_fft);
    cudaGetSymbolAddress((void**)&pb, g_pb);

    u16 *pxh, *pxl, *xh, *xl, *Ph, *Pl, *dh, *dl, *fh, *fl, *vth, *vtl;
    u16 *sph, *spl, *vsth, *vstl;
    cudaGetSymbolAddress((void**)&pxh, g_pxh); cudaGetSymbolAddress((void**)&pxl, g_pxl);
    cudaGetSymbolAddress((void**)&xh, g_xh);   cudaGetSymbolAddress((void**)&xl, g_xl);
    cudaGetSymbolAddress((void**)&Ph, g_Ph);   cudaGetSymbolAddress((void**)&Pl, g_Pl);
    cudaGetSymbolAddress((void**)&dh, g_dh);   cudaGetSymbolAddress((void**)&dl, g_dl);
    cudaGetSymbolAddress((void**)&fh, g_fh);   cudaGetSymbolAddress((void**)&fl, g_fl);
    cudaGetSymbolAddress((void**)&vth, g_vth); cudaGetSymbolAddress((void**)&vtl, g_vtl);
    cudaGetSymbolAddress((void**)&sph, g_sph); cudaGetSymbolAddress((void**)&spl, g_spl);
    cudaGetSymbolAddress((void**)&vsth, g_vsth); cudaGetSymbolAddress((void**)&vstl, g_vstl);

    u16 *pwh, *pwl, *outwh, *outwl, *f1wh, *f1wl, *f2wh, *f2wl, *finwh, *finwl;
    cudaGetSymbolAddress((void**)&pwh, g_pwh);     cudaGetSymbolAddress((void**)&pwl, g_pwl);
    cudaGetSymbolAddress((void**)&outwh, g_outwh); cudaGetSymbolAddress((void**)&outwl, g_outwl);
    cudaGetSymbolAddress((void**)&f1wh, g_f1wh);   cudaGetSymbolAddress((void**)&f1wl, g_f1wl);
    cudaGetSymbolAddress((void**)&f2wh, g_f2wh);   cudaGetSymbolAddress((void**)&f2wl, g_f2wl);
    cudaGetSymbolAddress((void**)&finwh, g_finwh); cudaGetSymbolAddress((void**)&finwl, g_finwl);

    // launch 1: embedding
    embed_k<<<TOKENS, 256>>>(SRC, EMB, PE, x, xh, xl);

    // launch 2: packed weights + bias
    {
        int tot = LAYERS * NPACK * (DIM / 4);
        cvt_pack_k<<<(tot + 255) / 256, 256>>>(IN_W, QP_W, KP_W, VP_W,
                                               IN_B, QP_B, KP_B, VP_B,
                                               (ushort4*)pwh, (ushort4*)pwl, pb);
    }
    // launch 3: remaining weights fused
    {
        int n1 = LAYERS * DIM * DIM / 4, n2 = LAYERS * FFD * DIM / 4;
        int n3 = LAYERS * DIM * FFD / 4, n4 = VOCAB * DIM / 4;
        cvt4_k<<<(n1 + n2 + n3 + n4 + 255) / 256, 256>>>(
            (const float4*)OUT_W, (ushort4*)outwh, (ushort4*)outwl, n1,
            (const float4*)FF1_W, (ushort4*)f1wh, (ushort4*)f1wl, n2,
            (const float4*)FF2_W, (ushort4*)f2wh, (ushort4*)f2wl, n3,
            (const float4*)FIN_W, (ushort4*)finwh, (ushort4*)finwl, n4);
    }

    for (int l = 0; l < LAYERS; l++) {
        long wq  = (long)l * NPACK * DIM;
        long wo  = (long)l * DIM * DIM;
        long wf1 = (long)l * FFD * DIM;
        long wf2 = (long)l * DIM * FFD;

        // launch 4 (layer 0): packed projections -> px + planes  [PROFILED]
        launch_tc<256>(xh, xl, pwh + wq, pwl + wq, pb + (long)l * NPACK,
                       px, pxh, pxl, TOKENS, NPACK, DIM, DIM, DIM, NPACK);

        // dense scores = Q @ K^T / 8 per (b,h)
        launch_tc<256>(pxh, pxl, pxh + DIM, pxl + DIM, nullptr,
                       scores, nullptr, nullptr,
                       SEQ, SEQ, HDIM, NPACK, NPACK, SEQ,
                       16, (long)SEQ * NPACK, (long)HDIM,
                       (long)SEQ * NPACK, (long)HDIM,
                       (long)HEADS * SEQ * SEQ, (long)SEQ * SEQ,
                       HEADS, 0.125f, 0);

        softmax_rows<<<16 * SEQ, 256>>>(scores, Ph, Pl);

        vt_k<<<dim3(SEQ / 32, HDIM / 32, 16), dim3(32, 8)>>>(px, vth, vtl);

        // dense = P @ V per (b,h) -> planes only
        launch_tc<64>(Ph, Pl, vth, vtl, nullptr, nullptr, dh, dl,
                      SEQ, HDIM, SEQ, SEQ, SEQ, DIM,
                      16, (long)HEADS * SEQ * SEQ, (long)SEQ * SEQ,
                      (long)HEADS * HDIM * SEQ, (long)HDIM * SEQ,
                      (long)SEQ * DIM, (long)HDIM,
                      HEADS, 1.f, 0);

        // dense projection -> aproj fp32
        launch_tc<128>(dh, dl, outwh + wo, outwl + wo, OUT_B + (long)l * DIM,
                       aproj, nullptr, nullptr, TOKENS, DIM, DIM, DIM, DIM, DIM);

        // low-rank logits qk = Qs @ Ks^T / sqrt(R) per batch
        launch_tc<256>(pxh + COL_QS, pxl + COL_QS, pxh + COL_KS, pxl + COL_KS, nullptr,
                       scores, nullptr, nullptr,
                       SEQ, SEQ, RANK, NPACK, NPACK, SEQ,
                       2, (long)SEQ * NPACK, 0, (long)SEQ * NPACK, 0,
                       (long)SEQ * SEQ, 0, 1, 0.125f, 0);

        sparse_sel<<<TOKENS, 256>>>(scores, sph, spl);

        vst_k<<<dim3(SEQ / 32, DIM / 32, 2), dim3(32, 8)>>>(px, vsth, vstl);

        // sparse = sp @ Vs per batch
        launch_tc<128>(sph, spl, vsth, vstl, nullptr, sp, nullptr, nullptr,
                       SEQ, DIM, SEQ, SEQ, SEQ, DIM,
                       2, (long)SEQ * SEQ, 0, (long)DIM * SEQ, 0,
                       (long)SEQ * DIM, 0, 1, 1.f, 0);

        fuse_ln1_k<<<TOKENS, 256>>>(x, aproj, sp, LAM, l,
                                    LN1S + (long)l * DIM, LN1B + (long)l * DIM, xh, xl);

        // FFN
        launch_tc<256>(xh, xl, f1wh + wf1, f1wl + wf1, FF1_B + (long)l * FFD,
                       nullptr, fh, fl, TOKENS, FFD, DIM, DIM, DIM, FFD,
                       1, 0, 0, 0, 0, 0, 0, 1, 1.f, 1);
        launch_tc<128>(fh, fl, f2wh + wf2, f2wl + wf2, FF2_B + (long)l * DIM,
                       fft, nullptr, nullptr, TOKENS, DIM, FFD, FFD, FFD, DIM);

        add_ln2_k<<<TOKENS, 256>>>(x, fft, LN2S + (long)l * DIM, LN2B + (long)l * DIM, xh, xl);
    }

    // final vocab projection
    launch_tc<256>(xh, xl, finwh, finwl, FIN_B, OUT, nullptr, nullptr,
                   TOKENS, VOCAB, DIM, DIM, DIM, VOCAB);
}

// round 12
// speedup vs baseline: 1.8699x; 1.1365x over previous
#include <cuda_runtime.h>
#include <cuda_bf16.h>
#include <math.h>
#include <stdint.h>

#define SEQ    2048
#define TOKENS 4096
#define DIM    512
#define HEADS  8
#define HDIM   64
#define RANK   64
#define LAYERS 6
#define VOCAB  32000
#define FFD    2048
#define KTOP   409
#define NPACK  2304   // 1536 qkv | 64 qs | 64 ks | 512 vs | 128 pad
#define COL_QS 1536
#define COL_KS 1600
#define COL_VS 1664

typedef unsigned short u16;

// ---------------- fp32 scratch ----------------
__device__ float g_px[(size_t)TOKENS * NPACK];
__device__ float g_x[TOKENS * DIM];
__device__ float g_scores[(size_t)2 * SEQ * SEQ];   // sparse qk logits only
__device__ float g_aproj[TOKENS * DIM];
__device__ float g_sparse[TOKENS * DIM];
__device__ float g_fft[TOKENS * DIM];

// ---------------- bf16 hi/lo planes (activations) ----------------
__device__ alignas(16) u16 g_pxh[(size_t)TOKENS * NPACK], g_pxl[(size_t)TOKENS * NPACK];
__device__ alignas(16) u16 g_xh[TOKENS * DIM],       g_xl[TOKENS * DIM];
__device__ alignas(16) u16 g_dh[TOKENS * DIM],       g_dl[TOKENS * DIM];
__device__ alignas(16) u16 g_fh[TOKENS * FFD],       g_fl[TOKENS * FFD];
__device__ alignas(16) u16 g_vth[16 * HDIM * SEQ],   g_vtl[16 * HDIM * SEQ];
__device__ alignas(16) u16 g_sph[(size_t)2 * SEQ * SEQ], g_spl[(size_t)2 * SEQ * SEQ];
__device__ alignas(16) u16 g_vsth[2 * DIM * SEQ],    g_vstl[2 * DIM * SEQ];

// ---------------- bf16 hi/lo planes (weights) ----------------
__device__ alignas(16) u16 g_pwh[LAYERS * NPACK * DIM], g_pwl[LAYERS * NPACK * DIM];
__device__ float g_pb[LAYERS * NPACK];
__device__ alignas(16) u16 g_outwh[LAYERS * DIM * DIM],  g_outwl[LAYERS * DIM * DIM];
__device__ alignas(16) u16 g_f1wh[LAYERS * FFD * DIM],   g_f1wl[LAYERS * FFD * DIM];
__device__ alignas(16) u16 g_f2wh[LAYERS * DIM * FFD],   g_f2wl[LAYERS * DIM * FFD];
__device__ alignas(16) u16 g_finwh[VOCAB * DIM],         g_finwl[VOCAB * DIM];

// ---------------- small device helpers ----------------
__device__ __forceinline__ void fsplit(float x, u16& h, u16& l)
{
    __nv_bfloat16 bh = __float2bfloat16_rn(x);
    float fh = __bfloat162float(bh);
    __nv_bfloat16 bl = __float2bfloat16_rn(x - fh);
    h = *reinterpret_cast<u16*>(&bh);
    l = *reinterpret_cast<u16*>(&bl);
}

__device__ __forceinline__ uint32_t smem_u32(const void* p)
{
    uint32_t a;
    asm("{ .reg .u64 t; cvta.to.shared.u64 t, %1; cvt.u32.u64 %0, t; }" : "=r"(a) : "l"(p));
    return a;
}

__device__ __forceinline__ void cpa16(uint32_t dst, const void* src)
{
    asm volatile("cp.async.cg.shared.global [%0], [%1], 16;" :: "r"(dst), "l"(src) : "memory");
}

__device__ __forceinline__ void ldsm4(uint32_t* r, uint32_t addr)
{
    asm volatile("ldmatrix.sync.aligned.m8n8.x4.shared.b16 {%0,%1,%2,%3}, [%4];"
                 : "=r"(r[0]), "=r"(r[1]), "=r"(r[2]), "=r"(r[3]) : "r"(addr));
}

__device__ __forceinline__ void mma16816(float* c, const uint32_t* a, uint32_t b0, uint32_t b1)
{
    asm volatile(
        "mma.sync.aligned.m16n8k16.row.col.f32.bf16.bf16.f32 "
        "{%0,%1,%2,%3}, {%4,%5,%6,%7}, {%8,%9}, {%0,%1,%2,%3};"
        : "+f"(c[0]), "+f"(c[1]), "+f"(c[2]), "+f"(c[3])
        : "r"(a[0]), "r"(a[1]), "r"(a[2]), "r"(a[3]), "r"(b0), "r"(b1));
}

// ---------------- HMMA bf16x3 GEMM (R10 winner, unchanged) ----------------
template <int TN>
__global__ void __launch_bounds__((TN == 256) ? 512 : 256, (TN == 64) ? 2 : 1)
mm_gemm(const u16* __restrict__ Ah, const u16* __restrict__ Al,
        const u16* __restrict__ Bh, const u16* __restrict__ Bl,
        const float* __restrict__ bias, float* __restrict__ C,
        u16* __restrict__ Ch, u16* __restrict__ Cl,
        int K, int lda, int ldb, int ldc,
        long sAo, long sAi, long sBo, long sBi, long sCo, long sCi,
        int zdiv, float alpha, int relu)
{
    constexpr int NT  = (TN == 256) ? 512 : 256;
    constexpr int MI  = (TN == 128) ? 4 : 2;
    constexpr int NI  = (TN == 256) ? 4 : 2;
    constexpr int RB  = 144;
    constexpr int APB = 128 * RB;
    constexpr int BPB = TN * RB;
    constexpr int STAGE = 2 * APB + 2 * BPB;
    constexpr int ROWSP = NT / 8;

    extern __shared__ char smem[];
    const uint32_t su = smem_u32(smem);
    const int tid = threadIdx.x;
    const int wid = tid >> 5;
    const int lane = tid & 31;

    int z = blockIdx.z;
    int zo = z / zdiv, zi = z - zo * zdiv;
    long ao = (long)zo * sAo + (long)zi * sAi;
    long bo = (long)zo * sBo + (long)zi * sBi;
    long co = (long)zo * sCo + (long)zi * sCi;
    Ah += ao; Al += ao; Bh += bo; Bl += bo;
    if (C)  C  += co;
    if (Ch) { Ch += co; Cl += co; }
    const int m0 = blockIdx.y * 128;
    const int n0 = blockIdx.x * TN;

    const int wmBase = (TN == 256) ? (wid & 3) * 32
                     : (TN == 128) ? (wid & 1) * 64 : (wid & 3) * 32;
    const int wnBase = (TN == 256) ? (wid >> 2) * 64
                     : (TN == 128) ? (wid >> 1) * 32 : (wid >> 2) * 32;

    float acc[MI][2 * NI][4];
#pragma unroll
    for (int mi = 0; mi < MI; mi++)
#pragma unroll
        for (int n8 = 0; n8 < 2 * NI; n8++)
#pragma unroll
            for (int q = 0; q < 4; q++) acc[mi][n8][q] = 0.f;

    const int nsch = K >> 6;
    const int ar = tid >> 3, ac = tid & 7;
    auto issue = [&](int i) {
        int s = i & 1;
        int k0 = i << 6;
        uint32_t st = su + s * STAGE;
#pragma unroll
        for (int j = 0; j < 128 / ROWSP; j++) {
            int r = ar + ROWSP * j;
            long g = (long)(m0 + r) * lda + k0 + ac * 8;
            uint32_t d = st + r * RB + ac * 16;
            cpa16(d, Ah + g);
            cpa16(d + APB, Al + g);
        }
#pragma unroll
        for (int j = 0; j < TN / ROWSP; j++) {
            int r = ar + ROWSP * j;
            long g = (long)(n0 + r) * ldb + k0 + ac * 8;
            uint32_t d = st + 2 * APB + r * RB + ac * 16;
            cpa16(d, Bh + g);
            cpa16(d + BPB, Bl + g);
        }
        asm volatile("cp.async.commit_group;" ::: "memory");
    };

    issue(0);
    const uint32_t lrow = lane & 15;
    const uint32_t lcol = (lane >> 4) * 16;

    for (int i = 0; i < nsch; i++) {
        asm volatile("cp.async.wait_group 0;" ::: "memory");
        __syncthreads();
        if (i + 1 < nsch) issue(i + 1);

        int s = i & 1;
        uint32_t aH = su + s * STAGE;
        uint32_t aL = aH + APB;
        uint32_t bH = aH + 2 * APB;
        uint32_t bL = bH + BPB;

#pragma unroll
        for (int ks = 0; ks < 4; ks++) {
            uint32_t kb = ks * 32 + lcol;
            uint32_t a[MI][4], bh[NI][4];
#pragma unroll
            for (int mi = 0; mi < MI; mi++)
                ldsm4(a[mi], aH + (wmBase + mi * 16 + lrow) * RB + kb);
#pragma unroll
            for (int ni = 0; ni < NI; ni++)
                ldsm4(bh[ni], bH + (wnBase + ni * 16 + lrow) * RB + kb);
#pragma unroll
            for (int mi = 0; mi < MI; mi++)
#pragma unroll
                for (int ni = 0; ni < NI; ni++) {
                    mma16816(acc[mi][2 * ni],     a[mi], bh[ni][0], bh[ni][2]);
                    mma16816(acc[mi][2 * ni + 1], a[mi], bh[ni][1], bh[ni][3]);
                }
            {
                uint32_t al[MI][4];
#pragma unroll
                for (int mi = 0; mi < MI; mi++)
                    ldsm4(al[mi], aL + (wmBase + mi * 16 + lrow) * RB + kb);
#pragma unroll
                for (int mi = 0; mi < MI; mi++)
#pragma unroll
                    for (int ni = 0; ni < NI; ni++) {
                        mma16816(acc[mi][2 * ni],     al[mi], bh[ni][0], bh[ni][2]);
                        mma16816(acc[mi][2 * ni + 1], al[mi], bh[ni][1], bh[ni][3]);
                    }
            }
            {
                uint32_t bl[NI][4];
#pragma unroll
                for (int ni = 0; ni < NI; ni++)
                    ldsm4(bl[ni], bL + (wnBase + ni * 16 + lrow) * RB + kb);
#pragma unroll
                for (int mi = 0; mi < MI; mi++)
#pragma unroll
                    for (int ni = 0; ni < NI; ni++) {
                        mma16816(acc[mi][2 * ni],     a[mi], bl[ni][0], bl[ni][2]);
                        mma16816(acc[mi][2 * ni + 1], a[mi], bl[ni][1], bl[ni][3]);
                    }
            }
        }
    }

#pragma unroll
    for (int mi = 0; mi < MI; mi++) {
        int r0 = m0 + wmBase + mi * 16 + (lane >> 2);
#pragma unroll
        for (int n8 = 0; n8 < 2 * NI; n8++) {
            int c = n0 + wnBase + n8 * 8 + (lane & 3) * 2;
            float2 o0, o1;
            o0.x = acc[mi][n8][0] * alpha; o0.y = acc[mi][n8][1] * alpha;
            o1.x = acc[mi][n8][2] * alpha; o1.y = acc[mi][n8][3] * alpha;
            if (bias) {
                float b0 = bias[c], b1 = bias[c + 1];
                o0.x += b0; o0.y += b1; o1.x += b0; o1.y += b1;
            }
            if (relu) {
                o0.x = fmaxf(o0.x, 0.f); o0.y = fmaxf(o0.y, 0.f);
                o1.x = fmaxf(o1.x, 0.f); o1.y = fmaxf(o1.y, 0.f);
            }
            long off0 = (long)r0 * ldc + c;
            long off1 = off0 + (long)8 * ldc;
            if (C) {
                *(float2*)(C + off0) = o0;
                *(float2*)(C + off1) = o1;
            }
            if (Ch) {
                ushort2 hh, ll;
                fsplit(o0.x, hh.x, ll.x); fsplit(o0.y, hh.y, ll.y);
                *(ushort2*)(Ch + off0) = hh; *(ushort2*)(Cl + off0) = ll;
                fsplit(o1.x, hh.x, ll.x); fsplit(o1.y, hh.y, ll.y);
                *(ushort2*)(Ch + off1) = hh; *(ushort2*)(Cl + off1) = ll;
            }
        }
    }
}

// ---------------- fused flash attention (dense path) ----------------
// grid (8 qtiles, 16 z), 512 thr. Q-tile 256, KV-tile 64, bf16x3, online softmax.
__global__ void __launch_bounds__(512, 1)
fattn(const u16* __restrict__ pxh, const u16* __restrict__ pxl,
      const u16* __restrict__ vth, const u16* __restrict__ vtl,
      u16* __restrict__ dh, u16* __restrict__ dl)
{
    constexpr int QT = 256, KT = 64, RB = 144;
    constexpr int QB = QT * RB;
    constexpr int KB = KT * RB;
    constexpr int STG = 4 * KB;

    extern __shared__ char smem[];
    const uint32_t su = smem_u32(smem);
    const int tid = threadIdx.x, wid = tid >> 5, lane = tid & 31;
    const int z = blockIdx.y, b = z >> 3, h = z & 7;
    const int q0 = blockIdx.x * QT;

    const uint32_t sQh = su, sQl = su + QB;
    const uint32_t sKV = su + 2 * QB;

    const u16* qh = pxh + (long)(b * SEQ + q0) * NPACK + h * HDIM;
    const u16* ql = pxl + (long)(b * SEQ + q0) * NPACK + h * HDIM;
    const u16* kh = pxh + (long)(b * SEQ) * NPACK + DIM + h * HDIM;   // FIX: +DIM (K block)
    const u16* kl = pxl + (long)(b * SEQ) * NPACK + DIM + h * HDIM;   // FIX: +DIM (K block)
    const u16* vh = vth + (long)z * HDIM * SEQ;
    const u16* vl = vtl + (long)z * HDIM * SEQ;

    const int ar = tid >> 3, ac = tid & 7;
#pragma unroll
    for (int j = 0; j < 4; j++) {
        int r = ar + 64 * j;
        long g = (long)r * NPACK + ac * 8;
        uint32_t d = r * RB + ac * 16;
        cpa16(sQh + d, qh + g);
        cpa16(sQl + d, ql + g);
    }
    asm volatile("cp.async.commit_group;" ::: "memory");

    auto issue = [&](int i) {
        uint32_t st = sKV + (i & 1) * STG;
        int s0 = i * KT;
        long gk = (long)(s0 + ar) * NPACK + ac * 8;
        uint32_t d = ar * RB + ac * 16;
        cpa16(st + d, kh + gk);
        cpa16(st + KB + d, kl + gk);
        long gv = (long)ar * SEQ + s0 + ac * 8;
        cpa16(st + 2 * KB + d, vh + gv);
        cpa16(st + 3 * KB + d, vl + gv);
        asm volatile("cp.async.commit_group;" ::: "memory");
    };
    issue(0);

    const int qr = wid * 16;
    const uint32_t lrow = lane & 15;
    const uint32_t lcolb = (lane >> 4) * 16;

    float o[8][4];
#pragma unroll
    for (int j = 0; j < 8; j++)
#pragma unroll
        for (int q = 0; q < 4; q++) o[j][q] = 0.f;
    float m0 = -3.4e38f, m1 = -3.4e38f, l0 = 0.f, l1 = 0.f;

    for (int it = 0; it < SEQ / KT; it++) {
        asm volatile("cp.async.wait_group 0;" ::: "memory");
        __syncthreads();
        if (it + 1 < SEQ / KT) issue(it + 1);

        uint32_t st = sKV + (it & 1) * STG;
        uint32_t kH = st, kL = st + KB, vH = st + 2 * KB, vL = st + 3 * KB;

        // ---- S = Q K^T (bf16x3, fp32 acc) ----
        float s[8][4];
#pragma unroll
        for (int j = 0; j < 8; j++)
#pragma unroll
            for (int q = 0; q < 4; q++) s[j][q] = 0.f;

#pragma unroll
        for (int c = 0; c < 4; c++) {
            uint32_t kb = c * 32 + lcolb;
            uint32_t aq[4], bk[4][4];
            ldsm4(aq, sQh + (qr + lrow) * RB + kb);
#pragma unroll
            for (int ni = 0; ni < 4; ni++)
                ldsm4(bk[ni], kH + (ni * 16 + lrow) * RB + kb);
#pragma unroll
            for (int ni = 0; ni < 4; ni++) {
                mma16816(s[2 * ni],     aq, bk[ni][0], bk[ni][2]);
                mma16816(s[2 * ni + 1], aq, bk[ni][1], bk[ni][3]);
            }
            {
                uint32_t al[4];
                ldsm4(al, sQl + (qr + lrow) * RB + kb);
#pragma unroll
                for (int ni = 0; ni < 4; ni++) {
                    mma16816(s[2 * ni],     al, bk[ni][0], bk[ni][2]);
                    mma16816(s[2 * ni + 1], al, bk[ni][1], bk[ni][3]);
                }
            }
            {
                uint32_t bl[4];
#pragma unroll
                for (int ni = 0; ni < 4; ni++) {
                    ldsm4(bl, kL + (ni * 16 + lrow) * RB + kb);
                    mma16816(s[2 * ni],     aq, bl[0], bl[2]);
                    mma16816(s[2 * ni + 1], aq, bl[1], bl[3]);
                }
            }
        }

        // ---- online softmax (rows g = lane>>2 and g+8) ----
        float tm0 = -3.4e38f, tm1 = -3.4e38f;
#pragma unroll
        for (int j = 0; j < 8; j++) {
            s[j][0] *= 0.125f; s[j][1] *= 0.125f;
            s[j][2] *= 0.125f; s[j][3] *= 0.125f;
            tm0 = fmaxf(tm0, fmaxf(s[j][0], s[j][1]));
            tm1 = fmaxf(tm1, fmaxf(s[j][2], s[j][3]));
        }
        tm0 = fmaxf(tm0, __shfl_xor_sync(0xffffffffu, tm0, 1));
        tm0 = fmaxf(tm0, __shfl_xor_sync(0xffffffffu, tm0, 2));
        tm1 = fmaxf(tm1, __shfl_xor_sync(0xffffffffu, tm1, 1));
        tm1 = fmaxf(tm1, __shfl_xor_sync(0xffffffffu, tm1, 2));
        float mn0 = fmaxf(m0, tm0), mn1 = fmaxf(m1, tm1);
        float a0 = __expf(m0 - mn0), a1 = __expf(m1 - mn1);
        m0 = mn0; m1 = mn1;

        float ts0 = 0.f, ts1 = 0.f;
        uint32_t ph[4][4], pl[4][4];
#pragma unroll
        for (int j = 0; j < 8; j++) {
            float p00 = __expf(s[j][0] - mn0), p01 = __expf(s[j][1] - mn0);
            float p10 = __expf(s[j][2] - mn1), p11 = __expf(s[j][3] - mn1);
            ts0 += p00 + p01; ts1 += p10 + p11;
            u16 h00, l00, h01, l01, h10, l10, h11, l11;
            fsplit(p00, h00, l00); fsplit(p01, h01, l01);
            fsplit(p10, h10, l10); fsplit(p11, h11, l11);
            int t = j >> 1, hi = (j & 1) * 2;
            ph[t][hi]     = ((uint32_t)h01 << 16) | h00;
            ph[t][hi + 1] = ((uint32_t)h11 << 16) | h10;
            pl[t][hi]     = ((uint32_t)l01 << 16) | l00;
            pl[t][hi + 1] = ((uint32_t)l11 << 16) | l10;
        }
        ts0 += __shfl_xor_sync(0xffffffffu, ts0, 1);
        ts0 += __shfl_xor_sync(0xffffffffu, ts0, 2);
        ts1 += __shfl_xor_sync(0xffffffffu, ts1, 1);
        ts1 += __shfl_xor_sync(0xffffffffu, ts1, 2);
        l0 = l0 * a0 + ts0;
        l1 = l1 * a1 + ts1;
#pragma unroll
        for (int j = 0; j < 8; j++) {
            o[j][0] *= a0; o[j][1] *= a0;
            o[j][2] *= a1; o[j][3] *= a1;
        }

        // ---- O += P V (bf16x3: PhVh + PlVh + PhVl) ----
#pragma unroll
        for (int t = 0; t < 4; t++) {
            uint32_t kb = t * 32 + lcolb;
            uint32_t bv[4][4];
#pragma unroll
            for (int ni = 0; ni < 4; ni++)
                ldsm4(bv[ni], vH + (ni * 16 + lrow) * RB + kb);
#pragma unroll
            for (int ni = 0; ni < 4; ni++) {
                mma16816(o[2 * ni],     ph[t], bv[ni][0], bv[ni][2]);
                mma16816(o[2 * ni + 1], ph[t], bv[ni][1], bv[ni][3]);
            }
#pragma unroll
            for (int ni = 0; ni < 4; ni++) {
                mma16816(o[2 * ni],     pl[t], bv[ni][0], bv[ni][2]);
                mma16816(o[2 * ni + 1], pl[t], bv[ni][1], bv[ni][3]);
            }
            {
                uint32_t bvl[4];
#pragma unroll
                for (int ni = 0; ni < 4; ni++) {
                    ldsm4(bvl, vL + (ni * 16 + lrow) * RB + kb);
                    mma16816(o[2 * ni],     ph[t], bvl[0], bvl[2]);
                    mma16816(o[2 * ni + 1], ph[t], bvl[1], bvl[3]);
                }
            }
        }
    }

    // ---- epilogue: normalize and write dense planes ----
    float i0 = 1.f / l0, i1 = 1.f / l1;
    int g = lane >> 2;
    long row0 = (long)(b * SEQ + q0 + qr + g) * DIM;
    long row1 = row0 + 8 * DIM;
#pragma unroll
    for (int j = 0; j < 8; j++) {
        int col = h * HDIM + 8 * j + (lane & 3) * 2;
        ushort2 hh, ll;
        fsplit(o[j][0] * i0, hh.x, ll.x);
        fsplit(o[j][1] * i0, hh.y, ll.y);
        *(ushort2*)(dh + row0 + col) = hh;
        *(ushort2*)(dl + row0 + col) = ll;
        fsplit(o[j][2] * i1, hh.x, ll.x);
        fsplit(o[j][3] * i1, hh.y, ll.y);
        *(ushort2*)(dh + row1 + col) = hh;
        *(ushort2*)(dl + row1 + col) = ll;
    }
}

// ---------------- weight converters ----------------
__global__ void cvt_pack_k(const float* __restrict__ in_w, const float* __restrict__ qp_w,
                           const float* __restrict__ kp_w, const float* __restrict__ vp_w,
                           const float* __restrict__ in_b, const float* __restrict__ qp_b,
                           const float* __restrict__ kp_b, const float* __restrict__ vp_b,
                           ushort4* __restrict__ h, ushort4* __restrict__ l,
                           float* __restrict__ pb)
{
    int i = blockIdx.x * 256 + threadIdx.x;
    if (i < LAYERS * NPACK) {
        int lay = i / NPACK;
        int r = i - lay * NPACK;
        float v = 0.f;
        if (r < COL_QS) v = in_b[lay * 1536 + r];
        else if (r < COL_KS) v = qp_b[lay * RANK + (r - COL_QS)];
        else if (r < COL_VS) v = kp_b[lay * RANK + (r - COL_KS)];
        else if (r < COL_VS + DIM) v = vp_b[lay * DIM + (r - COL_VS)];
        pb[i] = v;
    }
    const int PER_L = NPACK * (DIM / 4);
    if (i >= LAYERS * PER_L) return;
    int lay = i / PER_L;
    int rem = i - lay * PER_L;
    int r = rem / (DIM / 4);
    int c4 = rem - r * (DIM / 4);
    float4 v = make_float4(0.f, 0.f, 0.f, 0.f);
    if (r < COL_QS)
        v = ((const float4*)(in_w + ((long)lay * 1536 + r) * DIM))[c4];
    else if (r < COL_KS)
        v = ((const float4*)(qp_w + ((long)lay * RANK + (r - COL_QS)) * DIM))[c4];
    else if (r < COL_VS)
        v = ((const float4*)(kp_w + ((long)lay * RANK + (r - COL_KS)) * DIM))[c4];
    else if (r < COL_VS + DIM)
        v = ((const float4*)(vp_w + ((long)lay * DIM + (r - COL_VS)) * DIM))[c4];
    ushort4 hh, ll;
    fsplit(v.x, hh.x, ll.x); fsplit(v.y, hh.y, ll.y);
    fsplit(v.z, hh.z, ll.z); fsplit(v.w, hh.w, ll.w);
    long o = (long)lay * NPACK * (DIM / 4) + (long)r * (DIM / 4) + c4;
    h[o] = hh; l[o] = ll;
}

__global__ void cvt4_k(const float4* __restrict__ s1, ushort4* __restrict__ h1, ushort4* __restrict__ l1, int n1,
                       const float4* __restrict__ s2, ushort4* __restrict__ h2, ushort4* __restrict__ l2, int n2,
                       const float4* __restrict__ s3, ushort4* __restrict__ h3, ushort4* __restrict__ l3, int n3,
                       const float4* __restrict__ s4, ushort4* __restrict__ h4, ushort4* __restrict__ l4, int n4)
{
    int i = blockIdx.x * 256 + threadIdx.x;
    const float4* s; ushort4 *h, *l; int j;
    if (i < n1) { s = s1; h = h1; l = l1; j = i; }
    else if (i < n1 + n2) { s = s2; h = h2; l = l2; j = i - n1; }
    else if (i < n1 + n2 + n3) { s = s3; h = h3; l = l3; j = i - n1 - n2; }
    else if (i < n1 + n2 + n3 + n4) { s = s4; h = h4; l = l4; j = i - n1 - n2 - n3; }
    else return;
    float4 v = s[j];
    ushort4 hh, ll;
    fsplit(v.x, hh.x, ll.x); fsplit(v.y, hh.y, ll.y);
    fsplit(v.z, hh.z, ll.z); fsplit(v.w, hh.w, ll.w);
    h[j] = hh; l[j] = ll;
}

// V^T planes (dense) from packed px
__global__ void vt_k(const float* __restrict__ px, u16* __restrict__ vh, u16* __restrict__ vl)
{
    __shared__ float t[32][33];
    int z = blockIdx.z, b = z >> 3, h = z & 7;
    int s0 = blockIdx.x * 32, d0 = blockIdx.y * 32;
    int tx = threadIdx.x, ty = threadIdx.y;
#pragma unroll
    for (int j = 0; j < 4; j++) {
        int s = s0 + ty + j * 8;
        t[ty + j * 8][tx] = px[((long)(b * SEQ + s)) * NPACK + 2 * DIM + h * HDIM + d0 + tx];
    }
    __syncthreads();
#pragma unroll
    for (int j = 0; j < 4; j++) {
        int d = d0 + ty + j * 8;
        long o = ((long)z * HDIM + d) * SEQ + s0 + tx;
        u16 hh, ll;
        fsplit(t[tx][ty + j * 8], hh, ll);
        vh[o] = hh; vl[o] = ll;
    }
}

// Vs^T planes (sparse)
__global__ void vst_k(const float* __restrict__ px, u16* __restrict__ vh, u16* __restrict__ vl)
{
    __shared__ float t[32][33];
    int b = blockIdx.z;
    int s0 = blockIdx.x * 32, d0 = blockIdx.y * 32;
    int tx = threadIdx.x, ty = threadIdx.y;
#pragma unroll
    for (int j = 0; j < 4; j++) {
        int s = s0 + ty + j * 8;
        t[ty + j * 8][tx] = px[((long)(b * SEQ + s)) * NPACK + COL_VS + d0 + tx];
    }
    __syncthreads();
#pragma unroll
    for (int j = 0; j < 4; j++) {
        int d = d0 + ty + j * 8;
        long o = ((long)(b * DIM + d)) * SEQ + s0 + tx;
        u16 hh, ll;
        fsplit(t[tx][ty + j * 8], hh, ll);
        vh[o] = hh; vl[o] = ll;
    }
}

// ---------------- embedding ----------------
__global__ void embed_k(const int* __restrict__ src, const float* __restrict__ emb,
                        const float* __restrict__ pe, float* __restrict__ x,
                        u16* __restrict__ xh, u16* __restrict__ xl)
{
    int t = blockIdx.x;
    int tid = threadIdx.x;
    int s = t & (SEQ - 1);
    int tok = src[t];
    int d = tid * 2;
    float2 e = *(const float2*)(emb + (long)tok * DIM + d);
    float2 p = *(const float2*)(pe + (long)s * DIM + d);
    float2 o;
    o.x = e.x * 22.627416998f + p.x;
    o.y = e.y * 22.627416998f + p.y;
    long off = (long)t * DIM + d;
    *(float2*)(x + off) = o;
    ushort2 hh, ll;
    fsplit(o.x, hh.x, ll.x); fsplit(o.y, hh.y, ll.y);
    *(ushort2*)(xh + off) = hh;
    *(ushort2*)(xl + off) = ll;
}

// ---------------- sparse select ----------------
__device__ __forceinline__ unsigned f2k(float f)
{
    unsigned u = __float_as_uint(f);
    return (u & 0x80000000u) ? ~u : (u | 0x80000000u);
}

__global__ void __launch_bounds__(256) sparse_sel(
    const float* __restrict__ qk, u16* __restrict__ sph, u16* __restrict__ spl)
{
    __shared__ float logit[SEQ];
    __shared__ unsigned hist[256];
    __shared__ unsigned suf[256];
    __shared__ float red[256];
    __shared__ unsigned sh_prefix;
    __shared__ int sh_remaining;

    long row = blockIdx.x;
    int tid = threadIdx.x;
    const float* p = qk + row * (long)SEQ;

    for (int k = tid; k < SEQ; k += 256) logit[k] = p[k];
    __syncthreads();

    float lm = -3.4e38f;
    for (int k = tid; k < SEQ; k += 256) lm = fmaxf(lm, logit[k]);
    red[tid] = lm; __syncthreads();
    for (int s = 128; s > 0; s >>= 1) { if (tid < s) red[tid] = fmaxf(red[tid], red[tid + s]); __syncthreads(); }
    float Lmax = red[0]; __syncthreads();

    float zacc = 0.f;
    for (int k = tid; k < SEQ; k += 256) zacc += __expf(logit[k] - Lmax);
    red[tid] = zacc; __syncthreads();
    for (int s = 128; s > 0; s >>= 1) { if (tid < s) red[tid] += red[tid + s]; __syncthreads(); }
    float Z = red[0]; __syncthreads();

    unsigned prefix = 0; int remaining = KTOP;
    for (int shift = 24; shift >= 0; shift -= 8) {
        hist[tid] = 0; __syncthreads();
        unsigned upmask = (shift == 24) ? 0u : (0xFFFFFFFFu << (shift + 8));
        for (int k = tid; k < SEQ; k += 256) {
            unsigned key = f2k(logit[k]);
            if ((key & upmask) == prefix)
                atomicAdd(&hist[(key >> shift) & 255], 1u);
        }
        __syncthreads();
        suf[tid] = hist[tid]; __syncthreads();
        for (int off = 1; off < 256; off <<= 1) {
            unsigned add = (tid + off < 256) ? suf[tid + off] : 0u;
            __syncthreads();
            suf[tid] += add;
            __syncthreads();
        }
        unsigned shere = suf[tid];
        unsigned snext = (tid < 255) ? suf[tid + 1] : 0u;
        if (shere >= (unsigned)remaining && snext < (unsigned)remaining) {
            sh_prefix = prefix | ((unsigned)tid << shift);
            sh_remaining = remaining - (int)snext;
        }
        __syncthreads();
        prefix = sh_prefix; remaining = sh_remaining;
        __syncthreads();
    }
    unsigned thr = prefix;

    float w8[8];
    float dsum = 0.f;
#pragma unroll
    for (int j = 0; j < 8; j++) {
        int k = tid + 256 * j;
        float l = logit[k];
        bool keep = (f2k(l) >= thr);
        float w = keep ? __expf(l - Lmax) : 0.f;
        w8[j] = w;
        dsum += w;
    }
    red[tid] = dsum; __syncthreads();
    for (int s = 128; s > 0; s >>= 1) { if (tid < s) red[tid] += red[tid + s]; __syncthreads(); }
    float inv = 1.f / (red[0] + 1e-9f * Z);

#pragma unroll
    for (int j = 0; j < 8; j++) {
        int k = tid + 256 * j;
        float w = w8[j] * inv;
        u16 h, l;
        fsplit(w, h, l);
        long o = row * (long)SEQ + k;
        sph[o] = h; spl[o] = l;
    }
}

// ---------------- gated fusion + LN1 ----------------
__global__ void fuse_ln1_k(float* __restrict__ x, const float* __restrict__ dn,
                           const float* __restrict__ sp, const float* __restrict__ lam,
                           int layer, const float* __restrict__ gam, const float* __restrict__ bet,
                           u16* __restrict__ xh, u16* __restrict__ xl)
{
    __shared__ float red[256];
    int row = blockIdx.x, tid = threadIdx.x;
    long off = (long)row * DIM + 2 * tid;
    float g = 1.f / (1.f + expf(-lam[layer]));
    float2 xv = *(const float2*)(x + off);
    float2 dv = *(const float2*)(dn + off);
    float2 sv = *(const float2*)(sp + off);
    float y0 = xv.x + g * dv.x + (1.f - g) * sv.x;
    float y1 = xv.y + g * dv.y + (1.f - g) * sv.y;
    red[tid] = y0 + y1; __syncthreads();
    for (int s = 128; s > 0; s >>= 1) { if (tid < s) red[tid] += red[tid + s]; __syncthreads(); }
    float mean = red[0] * (1.f / DIM); __syncthreads();
    float d0 = y0 - mean, d1 = y1 - mean;
    red[tid] = d0 * d0 + d1 * d1; __syncthreads();
    for (int s = 128; s > 0; s >>= 1) { if (tid < s) red[tid] += red[tid + s]; __syncthreads(); }
    float inv = 1.f / sqrtf(red[0] * (1.f / DIM) + 1e-5f);
    int dc = 2 * tid;
    float2 gm = *(const float2*)(gam + dc);
    float2 bt = *(const float2*)(bet + dc);
    float2 o; o.x = d0 * inv * gm.x + bt.x; o.y = d1 * inv * gm.y + bt.y;
    *(float2*)(x + off) = o;
    ushort2 hh, ll;
    fsplit(o.x, hh.x, ll.x); fsplit(o.y, hh.y, ll.y);
    *(ushort2*)(xh + off) = hh;
    *(ushort2*)(xl + off) = ll;
}

// ---------------- residual + LN2 ----------------
__global__ void add_ln2_k(float* __restrict__ x, const float* __restrict__ f,
                          const float* __restrict__ gam, const float* __restrict__ bet,
                          u16* __restrict__ xh, u16* __restrict__ xl)
{
    __shared__ float red[256];
    int row = blockIdx.x, tid = threadIdx.x;
    long off = (long)row * DIM + 2 * tid;
    float2 xv = *(const float2*)(x + off);
    float2 fv = *(const float2*)(f + off);
    float y0 = xv.x + fv.x;
    float y1 = xv.y + fv.y;
    red[tid] = y0 + y1; __syncthreads();
    for (int s = 128; s > 0; s >>= 1) { if (tid < s) red[tid] += red[tid + s]; __syncthreads(); }
    float mean = red[0] * (1.f / DIM); __syncthreads();
    float d0 = y0 - mean, d1 = y1 - mean;
    red[tid] = d0 * d0 + d1 * d1; __syncthreads();
    for (int s = 128; s > 0; s >>= 1) { if (tid < s) red[tid] += red[tid + s]; __syncthreads(); }
    float inv = 1.f / sqrtf(red[0] * (1.f / DIM) + 1e-5f);
    int dc = 2 * tid;
    float2 gm = *(const float2*)(gam + dc);
    float2 bt = *(const float2*)(bet + dc);
    float2 o; o.x = d0 * inv * gm.x + bt.x; o.y = d1 * inv * gm.y + bt.y;
    *(float2*)(x + off) = o;
    ushort2 hh, ll;
    fsplit(o.x, hh.x, ll.x); fsplit(o.y, hh.y, ll.y);
    *(ushort2*)(xh + off) = hh;
    *(ushort2*)(xl + off) = ll;
}

// ---------------- host-side helpers ----------------
template <int TN>
static void launch_tc(const u16* Ah, const u16* Al, const u16* Bh, const u16* Bl,
                      const float* bias, float* C, u16* Ch, u16* Cl,
                      int M, int N, int K, int lda, int ldb, int ldc,
                      int Z = 1, long sAo = 0, long sAi = 0, long sBo = 0, long sBi = 0,
                      long sCo = 0, long sCi = 0, int zdiv = 1,
                      float alpha = 1.f, int relu = 0)
{
    constexpr int NT = (TN == 256) ? 512 : 256;
    constexpr int SM = 2 * (2 * 128 * 144 + 2 * TN * 144);
    static bool attr_set = false;
    if (!attr_set) {
        cudaFuncSetAttribute(mm_gemm<TN>, cudaFuncAttributeMaxDynamicSharedMemorySize, SM);
        attr_set = true;
    }
    dim3 g(N / TN, M / 128, Z);
    mm_gemm<TN><<<g, NT, SM>>>(Ah, Al, Bh, Bl, bias, C, Ch, Cl,
                               K, lda, ldb, ldc,
                               sAo, sAi, sBo, sBi, sCo, sCi, zdiv, alpha, relu);
}

extern "C" void kernel_launch(void* const* d_in, const int* in_sizes, int n_in,
                              void* d_out, int out_size)
{
    const int*   SRC   = (const int*)  d_in[0];
    const float* EMB   = (const float*)d_in[1];
    const float* PE    = (const float*)d_in[2];
    const float* IN_W  = (const float*)d_in[3];
    const float* IN_B  = (const float*)d_in[4];
    const float* OUT_W = (const float*)d_in[5];
    const float* OUT_B = (const float*)d_in[6];
    const float* QP_W  = (const float*)d_in[7];
    const float* QP_B  = (const float*)d_in[8];
    const float* KP_W  = (const float*)d_in[9];
    const float* KP_B  = (const float*)d_in[10];
    const float* VP_W  = (const float*)d_in[11];
    const float* VP_B  = (const float*)d_in[12];
    const float* LAM   = (const float*)d_in[13];
    const float* FF1_W = (const float*)d_in[14];
    const float* FF1_B = (const float*)d_in[15];
    const float* FF2_W = (const float*)d_in[16];
    const float* FF2_B = (const float*)d_in[17];
    const float* LN1S  = (const float*)d_in[18];
    const float* LN1B  = (const float*)d_in[19];
    const float* LN2S  = (const float*)d_in[20];
    const float* LN2B  = (const float*)d_in[21];
    const float* FIN_W = (const float*)d_in[22];
    const float* FIN_B = (const float*)d_in[23];
    float* OUT = (float*)d_out;

    float *px, *x, *scores, *aproj, *sp, *fft, *pb;
    cudaGetSymbolAddress((void**)&px, g_px);       cudaGetSymbolAddress((void**)&x, g_x);
    cudaGetSymbolAddress((void**)&scores, g_scores); cudaGetSymbolAddress((void**)&aproj, g_aproj);
    cudaGetSymbolAddress((void**)&sp, g_sparse);   cudaGetSymbolAddress((void**)&fft, g_fft);
    cudaGetSymbolAddress((void**)&pb, g_pb);

    u16 *pxh, *pxl, *xh, *xl, *dh, *dl, *fh, *fl, *vth, *vtl;
    u16 *sph, *spl, *vsth, *vstl;
    cudaGetSymbolAddress((void**)&pxh, g_pxh); cudaGetSymbolAddress((void**)&pxl, g_pxl);
    cudaGetSymbolAddress((void**)&xh, g_xh);   cudaGetSymbolAddress((void**)&xl, g_xl);
    cudaGetSymbolAddress((void**)&dh, g_dh);   cudaGetSymbolAddress((void**)&dl, g_dl);
    cudaGetSymbolAddress((void**)&fh, g_fh);   cudaGetSymbolAddress((void**)&fl, g_fl);
    cudaGetSymbolAddress((void**)&vth, g_vth); cudaGetSymbolAddress((void**)&vtl, g_vtl);
    cudaGetSymbolAddress((void**)&sph, g_sph); cudaGetSymbolAddress((void**)&spl, g_spl);
    cudaGetSymbolAddress((void**)&vsth, g_vsth); cudaGetSymbolAddress((void**)&vstl, g_vstl);

    u16 *pwh, *pwl, *outwh, *outwl, *f1wh, *f1wl, *f2wh, *f2wl, *finwh, *finwl;
    cudaGetSymbolAddress((void**)&pwh, g_pwh);     cudaGetSymbolAddress((void**)&pwl, g_pwl);
    cudaGetSymbolAddress((void**)&outwh, g_outwh); cudaGetSymbolAddress((void**)&outwl, g_outwl);
    cudaGetSymbolAddress((void**)&f1wh, g_f1wh);   cudaGetSymbolAddress((void**)&f1wl, g_f1wl);
    cudaGetSymbolAddress((void**)&f2wh, g_f2wh);   cudaGetSymbolAddress((void**)&f2wl, g_f2wl);
    cudaGetSymbolAddress((void**)&finwh, g_finwh); cudaGetSymbolAddress((void**)&finwl, g_finwl);

    // launch 1: embedding
    embed_k<<<TOKENS, 256>>>(SRC, EMB, PE, x, xh, xl);

    // launch 2: packed weights + bias
    {
        int tot = LAYERS * NPACK * (DIM / 4);
        cvt_pack_k<<<(tot + 255) / 256, 256>>>(IN_W, QP_W, KP_W, VP_W,
                                               IN_B, QP_B, KP_B, VP_B,
                                               (ushort4*)pwh, (ushort4*)pwl, pb);
    }
    // launch 3: remaining weights fused
    {
        int n1 = LAYERS * DIM * DIM / 4, n2 = LAYERS * FFD * DIM / 4;
        int n3 = LAYERS * DIM * FFD / 4, n4 = VOCAB * DIM / 4;
        cvt4_k<<<(n1 + n2 + n3 + n4 + 255) / 256, 256>>>(
            (const float4*)OUT_W, (ushort4*)outwh, (ushort4*)outwl, n1,
            (const float4*)FF1_W, (ushort4*)f1wh, (ushort4*)f1wl, n2,
            (const float4*)FF2_W, (ushort4*)f2wh, (ushort4*)f2wl, n3,
            (const float4*)FIN_W, (ushort4*)finwh, (ushort4*)finwl, n4);
    }

    {
        constexpr int FSM = 2 * 256 * 144 + 2 * 4 * 64 * 144;  // Q + 2 KV stages
        cudaFuncSetAttribute(fattn, cudaFuncAttributeMaxDynamicSharedMemorySize, FSM);
    }

    for (int l = 0; l < LAYERS; l++) {
        long wq  = (long)l * NPACK * DIM;
        long wo  = (long)l * DIM * DIM;
        long wf1 = (long)l * FFD * DIM;
        long wf2 = (long)l * DIM * FFD;

        // launch 4 (layer 0): packed projections -> px + planes  [PROFILED]
        launch_tc<256>(xh, xl, pwh + wq, pwl + wq, pb + (long)l * NPACK,
                       px, pxh, pxl, TOKENS, NPACK, DIM, DIM, DIM, NPACK);

        // V^T planes for dense attention
        vt_k<<<dim3(SEQ / 32, HDIM / 32, 16), dim3(32, 8)>>>(px, vth, vtl);

        // fused flash attention -> dense planes dh/dl
        {
            constexpr int FSM = 2 * 256 * 144 + 2 * 4 * 64 * 144;
            fattn<<<dim3(SEQ / 256, 16), 512, FSM>>>(pxh, pxl, vth, vtl, dh, dl);
        }

        // dense projection -> aproj fp32
        launch_tc<128>(dh, dl, outwh + wo, outwl + wo, OUT_B + (long)l * DIM,
                       aproj, nullptr, nullptr, TOKENS, DIM, DIM, DIM, DIM, DIM);

        // low-rank logits qk = Qs @ Ks^T / sqrt(R) per batch
        launch_tc<256>(pxh + COL_QS, pxl + COL_QS, pxh + COL_KS, pxl + COL_KS, nullptr,
                       scores, nullptr, nullptr,
                       SEQ, SEQ, RANK, NPACK, NPACK, SEQ,
                       2, (long)SEQ * NPACK, 0, (long)SEQ * NPACK, 0,
                       (long)SEQ * SEQ, 0, 1, 0.125f, 0);

        sparse_sel<<<TOKENS, 256>>>(scores, sph, spl);

        vst_k<<<dim3(SEQ / 32, DIM / 32, 2), dim3(32, 8)>>>(px, vsth, vstl);

        // sparse = sp @ Vs per batch
        launch_tc<128>(sph, spl, vsth, vstl, nullptr, sp, nullptr, nullptr,
                       SEQ, DIM, SEQ, SEQ, SEQ, DIM,
                       2, (long)SEQ * SEQ, 0, (long)DIM * SEQ, 0,
                       (long)SEQ * DIM, 0, 1, 1.f, 0);

        fuse_ln1_k<<<TOKENS, 256>>>(x, aproj, sp, LAM, l,
                                    LN1S + (long)l * DIM, LN1B + (long)l * DIM, xh, xl);

        // FFN
        launch_tc<256>(xh, xl, f1wh + wf1, f1wl + wf1, FF1_B + (long)l * FFD,
                       nullptr, fh, fl, TOKENS, FFD, DIM, DIM, DIM, FFD,
                       1, 0, 0, 0, 0, 0, 0, 1, 1.f, 1);
        launch_tc<128>(fh, fl, f2wh + wf2, f2wl + wf2, FF2_B + (long)l * DIM,
                       fft, nullptr, nullptr, TOKENS, DIM, FFD, FFD, FFD, DIM);

        add_ln2_k<<<TOKENS, 256>>>(x, fft, LN2S + (long)l * DIM, LN2B + (long)l * DIM, xh, xl);
    }

    // final vocab projection
    launch_tc<256>(xh, xl, finwh, finwl, FIN_B, OUT, nullptr, nullptr,
                   TOKENS, VOCAB, DIM, DIM, DIM, VOCAB);
}

// round 14
// speedup vs baseline: 2.0202x; 1.0803x over previous
#include <cuda_runtime.h>
#include <cuda_bf16.h>
#include <cuda_fp16.h>
#include <math.h>
#include <stdint.h>

#define SEQ    2048
#define TOKENS 4096
#define DIM    512
#define HEADS  8
#define HDIM   64
#define RANK   64
#define LAYERS 6
#define VOCAB  32000
#define FFD    2048
#define KTOP   409
#define NPACK  2304   // 1536 qkv | 64 qs | 64 ks | 512 vs | 128 pad
#define COL_QS 1536
#define COL_KS 1600
#define COL_VS 1664

typedef unsigned short u16;

// ---------------- fp32 scratch ----------------
__device__ float g_px[(size_t)TOKENS * NPACK];
__device__ float g_x[TOKENS * DIM];
__device__ float g_scores[(size_t)2 * SEQ * SEQ];   // sparse qk logits only
__device__ float g_aproj[TOKENS * DIM];
__device__ float g_sparse[TOKENS * DIM];
__device__ float g_fft[TOKENS * DIM];

// ---------------- bf16 hi/lo planes (activations) ----------------
__device__ alignas(16) u16 g_pxh[(size_t)TOKENS * NPACK], g_pxl[(size_t)TOKENS * NPACK];
__device__ alignas(16) u16 g_xh[TOKENS * DIM],       g_xl[TOKENS * DIM];
__device__ alignas(16) u16 g_dh[TOKENS * DIM],       g_dl[TOKENS * DIM];
__device__ alignas(16) u16 g_fh[TOKENS * FFD],       g_fl[TOKENS * FFD];
__device__ alignas(16) u16 g_vth[16 * HDIM * SEQ],   g_vtl[16 * HDIM * SEQ];
__device__ alignas(16) u16 g_sph[(size_t)2 * SEQ * SEQ], g_spl[(size_t)2 * SEQ * SEQ];
__device__ alignas(16) u16 g_vsth[2 * DIM * SEQ],    g_vstl[2 * DIM * SEQ];
// fp16 planes for final vocab projection
__device__ alignas(16) u16 g_xh2[TOKENS * DIM],      g_xl2[TOKENS * DIM];

// ---------------- bf16 hi/lo planes (weights) ----------------
__device__ alignas(16) u16 g_pwh[LAYERS * NPACK * DIM], g_pwl[LAYERS * NPACK * DIM];
__device__ float g_pb[LAYERS * NPACK];
__device__ alignas(16) u16 g_outwh[LAYERS * DIM * DIM],  g_outwl[LAYERS * DIM * DIM];
__device__ alignas(16) u16 g_f1wh[LAYERS * FFD * DIM],   g_f1wl[LAYERS * FFD * DIM];
__device__ alignas(16) u16 g_f2wh[LAYERS * DIM * FFD],   g_f2wl[LAYERS * DIM * FFD];
__device__ alignas(16) u16 g_finh2[VOCAB * DIM],         g_finl2[VOCAB * DIM];  // fp16

// ---------------- small device helpers ----------------
__device__ __forceinline__ void fsplit(float x, u16& h, u16& l)
{
    __nv_bfloat16 bh = __float2bfloat16_rn(x);
    float fh = __bfloat162float(bh);
    __nv_bfloat16 bl = __float2bfloat16_rn(x - fh);
    h = *reinterpret_cast<u16*>(&bh);
    l = *reinterpret_cast<u16*>(&bl);
}

__device__ __forceinline__ void hsplit(float x, u16& h, u16& l)
{
    __half hh = __float2half_rn(x);
    float fh = __half2float(hh);
    __half hl = __float2half_rn(x - fh);
    h = *reinterpret_cast<u16*>(&hh);
    l = *reinterpret_cast<u16*>(&hl);
}

__device__ __forceinline__ uint32_t smem_u32(const void* p)
{
    uint32_t a;
    asm("{ .reg .u64 t; cvta.to.shared.u64 t, %1; cvt.u32.u64 %0, t; }" : "=r"(a) : "l"(p));
    return a;
}

__device__ __forceinline__ void cpa16(uint32_t dst, const void* src)
{
    asm volatile("cp.async.cg.shared.global [%0], [%1], 16;" :: "r"(dst), "l"(src) : "memory");
}

__device__ __forceinline__ void ldsm4(uint32_t* r, uint32_t addr)
{
    asm volatile("ldmatrix.sync.aligned.m8n8.x4.shared.b16 {%0,%1,%2,%3}, [%4];"
                 : "=r"(r[0]), "=r"(r[1]), "=r"(r[2]), "=r"(r[3]) : "r"(addr));
}

__device__ __forceinline__ void mma16816(float* c, const uint32_t* a, uint32_t b0, uint32_t b1)
{
    asm volatile(
        "mma.sync.aligned.m16n8k16.row.col.f32.bf16.bf16.f32 "
        "{%0,%1,%2,%3}, {%4,%5,%6,%7}, {%8,%9}, {%0,%1,%2,%3};"
        : "+f"(c[0]), "+f"(c[1]), "+f"(c[2]), "+f"(c[3])
        : "r"(a[0]), "r"(a[1]), "r"(a[2]), "r"(a[3]), "r"(b0), "r"(b1));
}

__device__ __forceinline__ void mma16816h(float* c, const uint32_t* a, uint32_t b0, uint32_t b1)
{
    asm volatile(
        "mma.sync.aligned.m16n8k16.row.col.f32.f16.f16.f32 "
        "{%0,%1,%2,%3}, {%4,%5,%6,%7}, {%8,%9}, {%0,%1,%2,%3};"
        : "+f"(c[0]), "+f"(c[1]), "+f"(c[2]), "+f"(c[3])
        : "r"(a[0]), "r"(a[1]), "r"(a[2]), "r"(a[3]), "r"(b0), "r"(b1));
}

// ---------------- HMMA bf16x3 GEMM (R10 winner, unchanged) ----------------
template <int TN>
__global__ void __launch_bounds__((TN == 256) ? 512 : 256, (TN == 64) ? 2 : 1)
mm_gemm(const u16* __restrict__ Ah, const u16* __restrict__ Al,
        const u16* __restrict__ Bh, const u16* __restrict__ Bl,
        const float* __restrict__ bias, float* __restrict__ C,
        u16* __restrict__ Ch, u16* __restrict__ Cl,
        int K, int lda, int ldb, int ldc,
        long sAo, long sAi, long sBo, long sBi, long sCo, long sCi,
        int zdiv, float alpha, int relu)
{
    constexpr int NT  = (TN == 256) ? 512 : 256;
    constexpr int MI  = (TN == 128) ? 4 : 2;
    constexpr int NI  = (TN == 256) ? 4 : 2;
    constexpr int RB  = 144;
    constexpr int APB = 128 * RB;
    constexpr int BPB = TN * RB;
    constexpr int STAGE = 2 * APB + 2 * BPB;
    constexpr int ROWSP = NT / 8;

    extern __shared__ char smem[];
    const uint32_t su = smem_u32(smem);
    const int tid = threadIdx.x;
    const int wid = tid >> 5;
    const int lane = tid & 31;

    int z = blockIdx.z;
    int zo = z / zdiv, zi = z - zo * zdiv;
    long ao = (long)zo * sAo + (long)zi * sAi;
    long bo = (long)zo * sBo + (long)zi * sBi;
    long co = (long)zo * sCo + (long)zi * sCi;
    Ah += ao; Al += ao; Bh += bo; Bl += bo;
    if (C)  C  += co;
    if (Ch) { Ch += co; Cl += co; }
    const int m0 = blockIdx.y * 128;
    const int n0 = blockIdx.x * TN;

    const int wmBase = (TN == 256) ? (wid & 3) * 32
                     : (TN == 128) ? (wid & 1) * 64 : (wid & 3) * 32;
    const int wnBase = (TN == 256) ? (wid >> 2) * 64
                     : (TN == 128) ? (wid >> 1) * 32 : (wid >> 2) * 32;

    float acc[MI][2 * NI][4];
#pragma unroll
    for (int mi = 0; mi < MI; mi++)
#pragma unroll
        for (int n8 = 0; n8 < 2 * NI; n8++)
#pragma unroll
            for (int q = 0; q < 4; q++) acc[mi][n8][q] = 0.f;

    const int nsch = K >> 6;
    const int ar = tid >> 3, ac = tid & 7;
    auto issue = [&](int i) {
        int s = i & 1;
        int k0 = i << 6;
        uint32_t st = su + s * STAGE;
#pragma unroll
        for (int j = 0; j < 128 / ROWSP; j++) {
            int r = ar + ROWSP * j;
            long g = (long)(m0 + r) * lda + k0 + ac * 8;
            uint32_t d = st + r * RB + ac * 16;
            cpa16(d, Ah + g);
            cpa16(d + APB, Al + g);
        }
#pragma unroll
        for (int j = 0; j < TN / ROWSP; j++) {
            int r = ar + ROWSP * j;
            long g = (long)(n0 + r) * ldb + k0 + ac * 8;
            uint32_t d = st + 2 * APB + r * RB + ac * 16;
            cpa16(d, Bh + g);
            cpa16(d + BPB, Bl + g);
        }
        asm volatile("cp.async.commit_group;" ::: "memory");
    };

    issue(0);
    const uint32_t lrow = lane & 15;
    const uint32_t lcol = (lane >> 4) * 16;

    for (int i = 0; i < nsch; i++) {
        asm volatile("cp.async.wait_group 0;" ::: "memory");
        __syncthreads();
        if (i + 1 < nsch) issue(i + 1);

        int s = i & 1;
        uint32_t aH = su + s * STAGE;
        uint32_t aL = aH + APB;
        uint32_t bH = aH + 2 * APB;
        uint32_t bL = bH + BPB;

#pragma unroll
        for (int ks = 0; ks < 4; ks++) {
            uint32_t kb = ks * 32 + lcol;
            uint32_t a[MI][4], bh[NI][4];
#pragma unroll
            for (int mi = 0; mi < MI; mi++)
                ldsm4(a[mi], aH + (wmBase + mi * 16 + lrow) * RB + kb);
#pragma unroll
            for (int ni = 0; ni < NI; ni++)
                ldsm4(bh[ni], bH + (wnBase + ni * 16 + lrow) * RB + kb);
#pragma unroll
            for (int mi = 0; mi < MI; mi++)
#pragma unroll
                for (int ni = 0; ni < NI; ni++) {
                    mma16816(acc[mi][2 * ni],     a[mi], bh[ni][0], bh[ni][2]);
                    mma16816(acc[mi][2 * ni + 1], a[mi], bh[ni][1], bh[ni][3]);
                }
            {
                uint32_t al[MI][4];
#pragma unroll
                for (int mi = 0; mi < MI; mi++)
                    ldsm4(al[mi], aL + (wmBase + mi * 16 + lrow) * RB + kb);
#pragma unroll
                for (int mi = 0; mi < MI; mi++)
#pragma unroll
                    for (int ni = 0; ni < NI; ni++) {
                        mma16816(acc[mi][2 * ni],     al[mi], bh[ni][0], bh[ni][2]);
                        mma16816(acc[mi][2 * ni + 1], al[mi], bh[ni][1], bh[ni][3]);
                    }
            }
            {
                uint32_t bl[NI][4];
#pragma unroll
                for (int ni = 0; ni < NI; ni++)
                    ldsm4(bl[ni], bL + (wnBase + ni * 16 + lrow) * RB + kb);
#pragma unroll
                for (int mi = 0; mi < MI; mi++)
#pragma unroll
                    for (int ni = 0; ni < NI; ni++) {
                        mma16816(acc[mi][2 * ni],     a[mi], bl[ni][0], bl[ni][2]);
                        mma16816(acc[mi][2 * ni + 1], a[mi], bl[ni][1], bl[ni][3]);
                    }
            }
        }
    }

#pragma unroll
    for (int mi = 0; mi < MI; mi++) {
        int r0 = m0 + wmBase + mi * 16 + (lane >> 2);
#pragma unroll
        for (int n8 = 0; n8 < 2 * NI; n8++) {
            int c = n0 + wnBase + n8 * 8 + (lane & 3) * 2;
            float2 o0, o1;
            o0.x = acc[mi][n8][0] * alpha; o0.y = acc[mi][n8][1] * alpha;
            o1.x = acc[mi][n8][2] * alpha; o1.y = acc[mi][n8][3] * alpha;
            if (bias) {
                float b0 = bias[c], b1 = bias[c + 1];
                o0.x += b0; o0.y += b1; o1.x += b0; o1.y += b1;
            }
            if (relu) {
                o0.x = fmaxf(o0.x, 0.f); o0.y = fmaxf(o0.y, 0.f);
                o1.x = fmaxf(o1.x, 0.f); o1.y = fmaxf(o1.y, 0.f);
            }
            long off0 = (long)r0 * ldc + c;
            long off1 = off0 + (long)8 * ldc;
            if (C) {
                *(float2*)(C + off0) = o0;
                *(float2*)(C + off1) = o1;
            }
            if (Ch) {
                ushort2 hh, ll;
                fsplit(o0.x, hh.x, ll.x); fsplit(o0.y, hh.y, ll.y);
                *(ushort2*)(Ch + off0) = hh; *(ushort2*)(Cl + off0) = ll;
                fsplit(o1.x, hh.x, ll.x); fsplit(o1.y, hh.y, ll.y);
                *(ushort2*)(Ch + off1) = hh; *(ushort2*)(Cl + off1) = ll;
            }
        }
    }
}

// ---------------- fp16 2-pass vocab GEMM: C = xh @ (Wh + Wl)^T + bias ----------------
__global__ void __launch_bounds__(512, 1)
mm_vocab(const u16* __restrict__ Ah,
         const u16* __restrict__ Bh, const u16* __restrict__ Bl,
         const float* __restrict__ bias, float* __restrict__ C,
         int K, int lda, int ldb, int ldc)
{
    constexpr int RB  = 144;
    constexpr int APB = 128 * RB;
    constexpr int BPB = 256 * RB;
    constexpr int STAGE = APB + 2 * BPB;

    extern __shared__ char smem[];
    const uint32_t su = smem_u32(smem);
    const int tid = threadIdx.x;
    const int wid = tid >> 5;
    const int lane = tid & 31;
    const int m0 = blockIdx.y * 128;
    const int n0 = blockIdx.x * 256;
    const int wmBase = (wid & 3) * 32;
    const int wnBase = (wid >> 2) * 64;

    float acc[2][8][4];
#pragma unroll
    for (int mi = 0; mi < 2; mi++)
#pragma unroll
        for (int n8 = 0; n8 < 8; n8++)
#pragma unroll
            for (int q = 0; q < 4; q++) acc[mi][n8][q] = 0.f;

    const int nsch = K >> 6;
    const int ar = tid >> 3, ac = tid & 7;
    auto issue = [&](int i) {
        int s = i & 1;
        int k0 = i << 6;
        uint32_t st = su + s * STAGE;
#pragma unroll
        for (int j = 0; j < 2; j++) {
            int r = ar + 64 * j;
            cpa16(st + r * RB + ac * 16, Ah + (long)(m0 + r) * lda + k0 + ac * 8);
        }
#pragma unroll
        for (int j = 0; j < 4; j++) {
            int r = ar + 64 * j;
            long g = (long)(n0 + r) * ldb + k0 + ac * 8;
            uint32_t d = st + APB + r * RB + ac * 16;
            cpa16(d, Bh + g);
            cpa16(d + BPB, Bl + g);
        }
        asm volatile("cp.async.commit_group;" ::: "memory");
    };

    issue(0);
    const uint32_t lrow = lane & 15;
    const uint32_t lcol = (lane >> 4) * 16;

    for (int i = 0; i < nsch; i++) {
        asm volatile("cp.async.wait_group 0;" ::: "memory");
        __syncthreads();
        if (i + 1 < nsch) issue(i + 1);

        uint32_t st = su + (i & 1) * STAGE;
        uint32_t aH = st, bH = st + APB, bL = bH + BPB;

#pragma unroll
        for (int ks = 0; ks < 4; ks++) {
            uint32_t kb = ks * 32 + lcol;
            uint32_t a[2][4], bh[4][4];
#pragma unroll
            for (int mi = 0; mi < 2; mi++)
                ldsm4(a[mi], aH + (wmBase + mi * 16 + lrow) * RB + kb);
#pragma unroll
            for (int ni = 0; ni < 4; ni++)
                ldsm4(bh[ni], bH + (wnBase + ni * 16 + lrow) * RB + kb);
#pragma unroll
            for (int mi = 0; mi < 2; mi++)
#pragma unroll
                for (int ni = 0; ni < 4; ni++) {
                    mma16816h(acc[mi][2 * ni],     a[mi], bh[ni][0], bh[ni][2]);
                    mma16816h(acc[mi][2 * ni + 1], a[mi], bh[ni][1], bh[ni][3]);
                }
            {
                uint32_t bl[4][4];
#pragma unroll
                for (int ni = 0; ni < 4; ni++)
                    ldsm4(bl[ni], bL + (wnBase + ni * 16 + lrow) * RB + kb);
#pragma unroll
                for (int mi = 0; mi < 2; mi++)
#pragma unroll
                    for (int ni = 0; ni < 4; ni++) {
                        mma16816h(acc[mi][2 * ni],     a[mi], bl[ni][0], bl[ni][2]);
                        mma16816h(acc[mi][2 * ni + 1], a[mi], bl[ni][1], bl[ni][3]);
                    }
            }
        }
    }

#pragma unroll
    for (int mi = 0; mi < 2; mi++) {
        int r0 = m0 + wmBase + mi * 16 + (lane >> 2);
#pragma unroll
        for (int n8 = 0; n8 < 8; n8++) {
            int c = n0 + wnBase + n8 * 8 + (lane & 3) * 2;
            float2 o0, o1;
            o0.x = acc[mi][n8][0] + bias[c];
            o0.y = acc[mi][n8][1] + bias[c + 1];
            o1.x = acc[mi][n8][2] + bias[c];
            o1.y = acc[mi][n8][3] + bias[c + 1];
            long off0 = (long)r0 * ldc + c;
            *(float2*)(C + off0) = o0;
            *(float2*)(C + off0 + (long)8 * ldc) = o1;
        }
    }
}

// ---------------- fused flash attention (dense path) ----------------
__global__ void __launch_bounds__(512, 1)
fattn(const u16* __restrict__ pxh, const u16* __restrict__ pxl,
      const u16* __restrict__ vth, const u16* __restrict__ vtl,
      u16* __restrict__ dh, u16* __restrict__ dl)
{
    constexpr int QT = 256, KT = 64, RB = 144;
    constexpr int QB = QT * RB;
    constexpr int KB = KT * RB;
    constexpr int STG = 4 * KB;

    extern __shared__ char smem[];
    const uint32_t su = smem_u32(smem);
    const int tid = threadIdx.x, wid = tid >> 5, lane = tid & 31;
    const int z = blockIdx.y, b = z >> 3, h = z & 7;
    const int q0 = blockIdx.x * QT;

    const uint32_t sQh = su, sQl = su + QB;
    const uint32_t sKV = su + 2 * QB;

    const u16* qh = pxh + (long)(b * SEQ + q0) * NPACK + h * HDIM;
    const u16* ql = pxl + (long)(b * SEQ + q0) * NPACK + h * HDIM;
    const u16* kh = pxh + (long)(b * SEQ) * NPACK + DIM + h * HDIM;
    const u16* kl = pxl + (long)(b * SEQ) * NPACK + DIM + h * HDIM;
    const u16* vh = vth + (long)z * HDIM * SEQ;
    const u16* vl = vtl + (long)z * HDIM * SEQ;

    const int ar = tid >> 3, ac = tid & 7;
#pragma unroll
    for (int j = 0; j < 4; j++) {
        int r = ar + 64 * j;
        long g = (long)r * NPACK + ac * 8;
        uint32_t d = r * RB + ac * 16;
        cpa16(sQh + d, qh + g);
        cpa16(sQl + d, ql + g);
    }
    asm volatile("cp.async.commit_group;" ::: "memory");

    auto issue = [&](int i) {
        uint32_t st = sKV + (i & 1) * STG;
        int s0 = i * KT;
        long gk = (long)(s0 + ar) * NPACK + ac * 8;
        uint32_t d = ar * RB + ac * 16;
        cpa16(st + d, kh + gk);
        cpa16(st + KB + d, kl + gk);
        long gv = (long)ar * SEQ + s0 + ac * 8;
        cpa16(st + 2 * KB + d, vh + gv);
        cpa16(st + 3 * KB + d, vl + gv);
        asm volatile("cp.async.commit_group;" ::: "memory");
    };
    issue(0);

    const int qr = wid * 16;
    const uint32_t lrow = lane & 15;
    const uint32_t lcolb = (lane >> 4) * 16;

    float o[8][4];
#pragma unroll
    for (int j = 0; j < 8; j++)
#pragma unroll
        for (int q = 0; q < 4; q++) o[j][q] = 0.f;
    float m0 = -3.4e38f, m1 = -3.4e38f, l0 = 0.f, l1 = 0.f;

    for (int it = 0; it < SEQ / KT; it++) {
        asm volatile("cp.async.wait_group 0;" ::: "memory");
        __syncthreads();
        if (it + 1 < SEQ / KT) issue(it + 1);

        uint32_t st = sKV + (it & 1) * STG;
        uint32_t kH = st, kL = st + KB, vH = st + 2 * KB, vL = st + 3 * KB;

        float s[8][4];
#pragma unroll
        for (int j = 0; j < 8; j++)
#pragma unroll
            for (int q = 0; q < 4; q++) s[j][q] = 0.f;

#pragma unroll
        for (int c = 0; c < 4; c++) {
            uint32_t kb = c * 32 + lcolb;
            uint32_t aq[4], bk[4][4];
            ldsm4(aq, sQh + (qr + lrow) * RB + kb);
#pragma unroll
            for (int ni = 0; ni < 4; ni++)
                ldsm4(bk[ni], kH + (ni * 16 + lrow) * RB + kb);
#pragma unroll
            for (int ni = 0; ni < 4; ni++) {
                mma16816(s[2 * ni],     aq, bk[ni][0], bk[ni][2]);
                mma16816(s[2 * ni + 1], aq, bk[ni][1], bk[ni][3]);
            }
            {
                uint32_t al[4];
                ldsm4(al, sQl + (qr + lrow) * RB + kb);
#pragma unroll
                for (int ni = 0; ni < 4; ni++) {
                    mma16816(s[2 * ni],     al, bk[ni][0], bk[ni][2]);
                    mma16816(s[2 * ni + 1], al, bk[ni][1], bk[ni][3]);
                }
            }
            {
                uint32_t bl[4];
#pragma unroll
                for (int ni = 0; ni < 4; ni++) {
                    ldsm4(bl, kL + (ni * 16 + lrow) * RB + kb);
                    mma16816(s[2 * ni],     aq, bl[0], bl[2]);
                    mma16816(s[2 * ni + 1], aq, bl[1], bl[3]);
                }
            }
        }

        float tm0 = -3.4e38f, tm1 = -3.4e38f;
#pragma unroll
        for (int j = 0; j < 8; j++) {
            s[j][0] *= 0.125f; s[j][1] *= 0.125f;
            s[j][2] *= 0.125f; s[j][3] *= 0.125f;
            tm0 = fmaxf(tm0, fmaxf(s[j][0], s[j][1]));
            tm1 = fmaxf(tm1, fmaxf(s[j][2], s[j][3]));
        }
        tm0 = fmaxf(tm0, __shfl_xor_sync(0xffffffffu, tm0, 1));
        tm0 = fmaxf(tm0, __shfl_xor_sync(0xffffffffu, tm0, 2));
        tm1 = fmaxf(tm1, __shfl_xor_sync(0xffffffffu, tm1, 1));
        tm1 = fmaxf(tm1, __shfl_xor_sync(0xffffffffu, tm1, 2));
        float mn0 = fmaxf(m0, tm0), mn1 = fmaxf(m1, tm1);
        float a0 = __expf(m0 - mn0), a1 = __expf(m1 - mn1);
        m0 = mn0; m1 = mn1;

        float ts0 = 0.f, ts1 = 0.f;
        uint32_t ph[4][4], pl[4][4];
#pragma unroll
        for (int j = 0; j < 8; j++) {
            float p00 = __expf(s[j][0] - mn0), p01 = __expf(s[j][1] - mn0);
            float p10 = __expf(s[j][2] - mn1), p11 = __expf(s[j][3] - mn1);
            ts0 += p00 + p01; ts1 += p10 + p11;
            u16 h00, l00, h01, l01, h10, l10, h11, l11;
            fsplit(p00, h00, l00); fsplit(p01, h01, l01);
            fsplit(p10, h10, l10); fsplit(p11, h11, l11);
            int t = j >> 1, hi = (j & 1) * 2;
            ph[t][hi]     = ((uint32_t)h01 << 16) | h00;
            ph[t][hi + 1] = ((uint32_t)h11 << 16) | h10;
            pl[t][hi]     = ((uint32_t)l01 << 16) | l00;
            pl[t][hi + 1] = ((uint32_t)l11 << 16) | l10;
        }
        ts0 += __shfl_xor_sync(0xffffffffu, ts0, 1);
        ts0 += __shfl_xor_sync(0xffffffffu, ts0, 2);
        ts1 += __shfl_xor_sync(0xffffffffu, ts1, 1);
        ts1 += __shfl_xor_sync(0xffffffffu, ts1, 2);
        l0 = l0 * a0 + ts0;
        l1 = l1 * a1 + ts1;
#pragma unroll
        for (int j = 0; j < 8; j++) {
            o[j][0] *= a0; o[j][1] *= a0;
            o[j][2] *= a1; o[j][3] *= a1;
        }

#pragma unroll
        for (int t = 0; t < 4; t++) {
            uint32_t kb = t * 32 + lcolb;
            uint32_t bv[4][4];
#pragma unroll
            for (int ni = 0; ni < 4; ni++)
                ldsm4(bv[ni], vH + (ni * 16 + lrow) * RB + kb);
#pragma unroll
            for (int ni = 0; ni < 4; ni++) {
                mma16816(o[2 * ni],     ph[t], bv[ni][0], bv[ni][2]);
                mma16816(o[2 * ni + 1], ph[t], bv[ni][1], bv[ni][3]);
            }
#pragma unroll
            for (int ni = 0; ni < 4; ni++) {
                mma16816(o[2 * ni],     pl[t], bv[ni][0], bv[ni][2]);
                mma16816(o[2 * ni + 1], pl[t], bv[ni][1], bv[ni][3]);
            }
            {
                uint32_t bvl[4];
#pragma unroll
                for (int ni = 0; ni < 4; ni++) {
                    ldsm4(bvl, vL + (ni * 16 + lrow) * RB + kb);
                    mma16816(o[2 * ni],     ph[t], bvl[0], bvl[2]);
                    mma16816(o[2 * ni + 1], ph[t], bvl[1], bvl[3]);
                }
            }
        }
    }

    float i0 = 1.f / l0, i1 = 1.f / l1;
    int g = lane >> 2;
    long row0 = (long)(b * SEQ + q0 + qr + g) * DIM;
    long row1 = row0 + 8 * DIM;
#pragma unroll
    for (int j = 0; j < 8; j++) {
        int col = h * HDIM + 8 * j + (lane & 3) * 2;
        ushort2 hh, ll;
        fsplit(o[j][0] * i0, hh.x, ll.x);
        fsplit(o[j][1] * i0, hh.y, ll.y);
        *(ushort2*)(dh + row0 + col) = hh;
        *(ushort2*)(dl + row0 + col) = ll;
        fsplit(o[j][2] * i1, hh.x, ll.x);
        fsplit(o[j][3] * i1, hh.y, ll.y);
        *(ushort2*)(dh + row1 + col) = hh;
        *(ushort2*)(dl + row1 + col) = ll;
    }
}

// ---------------- weight converters ----------------
__global__ void cvt_pack_k(const float* __restrict__ in_w, const float* __restrict__ qp_w,
                           const float* __restrict__ kp_w, const float* __restrict__ vp_w,
                           const float* __restrict__ in_b, const float* __restrict__ qp_b,
                           const float* __restrict__ kp_b, const float* __restrict__ vp_b,
                           ushort4* __restrict__ h, ushort4* __restrict__ l,
                           float* __restrict__ pb)
{
    int i = blockIdx.x * 256 + threadIdx.x;
    if (i < LAYERS * NPACK) {
        int lay = i / NPACK;
        int r = i - lay * NPACK;
        float v = 0.f;
        if (r < COL_QS) v = in_b[lay * 1536 + r];
        else if (r < COL_KS) v = qp_b[lay * RANK + (r - COL_QS)];
        else if (r < COL_VS) v = kp_b[lay * RANK + (r - COL_KS)];
        else if (r < COL_VS + DIM) v = vp_b[lay * DIM + (r - COL_VS)];
        pb[i] = v;
    }
    const int PER_L = NPACK * (DIM / 4);
    if (i >= LAYERS * PER_L) return;
    int lay = i / PER_L;
    int rem = i - lay * PER_L;
    int r = rem / (DIM / 4);
    int c4 = rem - r * (DIM / 4);
    float4 v = make_float4(0.f, 0.f, 0.f, 0.f);
    if (r < COL_QS)
        v = ((const float4*)(in_w + ((long)lay * 1536 + r) * DIM))[c4];
    else if (r < COL_KS)
        v = ((const float4*)(qp_w + ((long)lay * RANK + (r - COL_QS)) * DIM))[c4];
    else if (r < COL_VS)
        v = ((const float4*)(kp_w + ((long)lay * RANK + (r - COL_KS)) * DIM))[c4];
    else if (r < COL_VS + DIM)
        v = ((const float4*)(vp_w + ((long)lay * DIM + (r - COL_VS)) * DIM))[c4];
    ushort4 hh, ll;
    fsplit(v.x, hh.x, ll.x); fsplit(v.y, hh.y, ll.y);
    fsplit(v.z, hh.z, ll.z); fsplit(v.w, hh.w, ll.w);
    long o = (long)lay * NPACK * (DIM / 4) + (long)r * (DIM / 4) + c4;
    h[o] = hh; l[o] = ll;
}

// segments 1-3: bf16 split; segment 4: fp16 split (vocab weights)
__global__ void cvt4_k(const float4* __restrict__ s1, ushort4* __restrict__ h1, ushort4* __restrict__ l1, int n1,
                       const float4* __restrict__ s2, ushort4* __restrict__ h2, ushort4* __restrict__ l2, int n2,
                       const float4* __restrict__ s3, ushort4* __restrict__ h3, ushort4* __restrict__ l3, int n3,
                       const float4* __restrict__ s4, ushort4* __restrict__ h4, ushort4* __restrict__ l4, int n4)
{
    int i = blockIdx.x * 256 + threadIdx.x;
    const float4* s; ushort4 *h, *l; int j; int seg;
    if (i < n1) { s = s1; h = h1; l = l1; j = i; seg = 0; }
    else if (i < n1 + n2) { s = s2; h = h2; l = l2; j = i - n1; seg = 1; }
    else if (i < n1 + n2 + n3) { s = s3; h = h3; l = l3; j = i - n1 - n2; seg = 2; }
    else if (i < n1 + n2 + n3 + n4) { s = s4; h = h4; l = l4; j = i - n1 - n2 - n3; seg = 3; }
    else return;
    float4 v = s[j];
    ushort4 hh, ll;
    if (seg == 3) {
        hsplit(v.x, hh.x, ll.x); hsplit(v.y, hh.y, ll.y);
        hsplit(v.z, hh.z, ll.z); hsplit(v.w, hh.w, ll.w);
    } else {
        fsplit(v.x, hh.x, ll.x); fsplit(v.y, hh.y, ll.y);
        fsplit(v.z, hh.z, ll.z); fsplit(v.w, hh.w, ll.w);
    }
    h[j] = hh; l[j] = ll;
}

// V^T planes (dense) from packed px
__global__ void vt_k(const float* __restrict__ px, u16* __restrict__ vh, u16* __restrict__ vl)
{
    __shared__ float t[32][33];
    int z = blockIdx.z, b = z >> 3, h = z & 7;
    int s0 = blockIdx.x * 32, d0 = blockIdx.y * 32;
    int tx = threadIdx.x, ty = threadIdx.y;
#pragma unroll
    for (int j = 0; j < 4; j++) {
        int s = s0 + ty + j * 8;
        t[ty + j * 8][tx] = px[((long)(b * SEQ + s)) * NPACK + 2 * DIM + h * HDIM + d0 + tx];
    }
    __syncthreads();
#pragma unroll
    for (int j = 0; j < 4; j++) {
        int d = d0 + ty + j * 8;
        long o = ((long)z * HDIM + d) * SEQ + s0 + tx;
        u16 hh, ll;
        fsplit(t[tx][ty + j * 8], hh, ll);
        vh[o] = hh; vl[o] = ll;
    }
}

// Vs^T planes (sparse)
__global__ void vst_k(const float* __restrict__ px, u16* __restrict__ vh, u16* __restrict__ vl)
{
    __shared__ float t[32][33];
    int b = blockIdx.z;
    int s0 = blockIdx.x * 32, d0 = blockIdx.y * 32;
    int tx = threadIdx.x, ty = threadIdx.y;
#pragma unroll
    for (int j = 0; j < 4; j++) {
        int s = s0 + ty + j * 8;
        t[ty + j * 8][tx] = px[((long)(b * SEQ + s)) * NPACK + COL_VS + d0 + tx];
    }
    __syncthreads();
#pragma unroll
    for (int j = 0; j < 4; j++) {
        int d = d0 + ty + j * 8;
        long o = ((long)(b * DIM + d)) * SEQ + s0 + tx;
        u16 hh, ll;
        fsplit(t[tx][ty + j * 8], hh, ll);
        vh[o] = hh; vl[o] = ll;
    }
}

// ---------------- embedding ----------------
__global__ void embed_k(const int* __restrict__ src, const float* __restrict__ emb,
                        const float* __restrict__ pe, float* __restrict__ x,
                        u16* __restrict__ xh, u16* __restrict__ xl)
{
    int t = blockIdx.x;
    int tid = threadIdx.x;
    int s = t & (SEQ - 1);
    int tok = src[t];
    int d = tid * 2;
    float2 e = *(const float2*)(emb + (long)tok * DIM + d);
    float2 p = *(const float2*)(pe + (long)s * DIM + d);
    float2 o;
    o.x = e.x * 22.627416998f + p.x;
    o.y = e.y * 22.627416998f + p.y;
    long off = (long)t * DIM + d;
    *(float2*)(x + off) = o;
    ushort2 hh, ll;
    fsplit(o.x, hh.x, ll.x); fsplit(o.y, hh.y, ll.y);
    *(ushort2*)(xh + off) = hh;
    *(ushort2*)(xl + off) = ll;
}

// ---------------- sparse select ----------------
__device__ __forceinline__ unsigned f2k(float f)
{
    unsigned u = __float_as_uint(f);
    return (u & 0x80000000u) ? ~u : (u | 0x80000000u);
}

__global__ void __launch_bounds__(256) sparse_sel(
    const float* __restrict__ qk, u16* __restrict__ sph, u16* __restrict__ spl)
{
    __shared__ float logit[SEQ];
    __shared__ unsigned hist[256];
    __shared__ unsigned suf[256];
    __shared__ float red[256];
    __shared__ unsigned sh_prefix;
    __shared__ int sh_remaining;

    long row = blockIdx.x;
    int tid = threadIdx.x;
    const float* p = qk + row * (long)SEQ;

    for (int k = tid; k < SEQ; k += 256) logit[k] = p[k];
    __syncthreads();

    float lm = -3.4e38f;
    for (int k = tid; k < SEQ; k += 256) lm = fmaxf(lm, logit[k]);
    red[tid] = lm; __syncthreads();
    for (int s = 128; s > 0; s >>= 1) { if (tid < s) red[tid] = fmaxf(red[tid], red[tid + s]); __syncthreads(); }
    float Lmax = red[0]; __syncthreads();

    float zacc = 0.f;
    for (int k = tid; k < SEQ; k += 256) zacc += __expf(logit[k] - Lmax);
    red[tid] = zacc; __syncthreads();
    for (int s = 128; s > 0; s >>= 1) { if (tid < s) red[tid] += red[tid + s]; __syncthreads(); }
    float Z = red[0]; __syncthreads();

    unsigned prefix = 0; int remaining = KTOP;
    for (int shift = 24; shift >= 0; shift -= 8) {
        hist[tid] = 0; __syncthreads();
        unsigned upmask = (shift == 24) ? 0u : (0xFFFFFFFFu << (shift + 8));
        for (int k = tid; k < SEQ; k += 256) {
            unsigned key = f2k(logit[k]);
            if ((key & upmask) == prefix)
                atomicAdd(&hist[(key >> shift) & 255], 1u);
        }
        __syncthreads();
        suf[tid] = hist[tid]; __syncthreads();
        for (int off = 1; off < 256; off <<= 1) {
            unsigned add = (tid + off < 256) ? suf[tid + off] : 0u;
            __syncthreads();
            suf[tid] += add;
            __syncthreads();
        }
        unsigned shere = suf[tid];
        unsigned snext = (tid < 255) ? suf[tid + 1] : 0u;
        if (shere >= (unsigned)remaining && snext < (unsigned)remaining) {
            sh_prefix = prefix | ((unsigned)tid << shift);
            sh_remaining = remaining - (int)snext;
        }
        __syncthreads();
        prefix = sh_prefix; remaining = sh_remaining;
        __syncthreads();
    }
    unsigned thr = prefix;

    float w8[8];
    float dsum = 0.f;
#pragma unroll
    for (int j = 0; j < 8; j++) {
        int k = tid + 256 * j;
        float l = logit[k];
        bool keep = (f2k(l) >= thr);
        float w = keep ? __expf(l - Lmax) : 0.f;
        w8[j] = w;
        dsum += w;
    }
    red[tid] = dsum; __syncthreads();
    for (int s = 128; s > 0; s >>= 1) { if (tid < s) red[tid] += red[tid + s]; __syncthreads(); }
    float inv = 1.f / (red[0] + 1e-9f * Z);

#pragma unroll
    for (int j = 0; j < 8; j++) {
        int k = tid + 256 * j;
        float w = w8[j] * inv;
        u16 h, l;
        fsplit(w, h, l);
        long o = row * (long)SEQ + k;
        sph[o] = h; spl[o] = l;
    }
}

// ---------------- gated fusion + LN1 ----------------
__global__ void fuse_ln1_k(float* __restrict__ x, const float* __restrict__ dn,
                           const float* __restrict__ sp, const float* __restrict__ lam,
                           int layer, const float* __restrict__ gam, const float* __restrict__ bet,
                           u16* __restrict__ xh, u16* __restrict__ xl)
{
    __shared__ float red[256];
    int row = blockIdx.x, tid = threadIdx.x;
    long off = (long)row * DIM + 2 * tid;
    float g = 1.f / (1.f + expf(-lam[layer]));
    float2 xv = *(const float2*)(x + off);
    float2 dv = *(const float2*)(dn + off);
    float2 sv = *(const float2*)(sp + off);
    float y0 = xv.x + g * dv.x + (1.f - g) * sv.x;
    float y1 = xv.y + g * dv.y + (1.f - g) * sv.y;
    red[tid] = y0 + y1; __syncthreads();
    for (int s = 128; s > 0; s >>= 1) { if (tid < s) red[tid] += red[tid + s]; __syncthreads(); }
    float mean = red[0] * (1.f / DIM); __syncthreads();
    float d0 = y0 - mean, d1 = y1 - mean;
    red[tid] = d0 * d0 + d1 * d1; __syncthreads();
    for (int s = 128; s > 0; s >>= 1) { if (tid < s) red[tid] += red[tid + s]; __syncthreads(); }
    float inv = 1.f / sqrtf(red[0] * (1.f / DIM) + 1e-5f);
    int dc = 2 * tid;
    float2 gm = *(const float2*)(gam + dc);
    float2 bt = *(const float2*)(bet + dc);
    float2 o; o.x = d0 * inv * gm.x + bt.x; o.y = d1 * inv * gm.y + bt.y;
    *(float2*)(x + off) = o;
    ushort2 hh, ll;
    fsplit(o.x, hh.x, ll.x); fsplit(o.y, hh.y, ll.y);
    *(ushort2*)(xh + off) = hh;
    *(ushort2*)(xl + off) = ll;
}

// ---------------- residual + LN2 (also emits fp16 planes for vocab) ----------------
__global__ void add_ln2_k(float* __restrict__ x, const float* __restrict__ f,
                          const float* __restrict__ gam, const float* __restrict__ bet,
                          u16* __restrict__ xh, u16* __restrict__ xl,
                          u16* __restrict__ xh2, u16* __restrict__ xl2)
{
    __shared__ float red[256];
    int row = blockIdx.x, tid = threadIdx.x;
    long off = (long)row * DIM + 2 * tid;
    float2 xv = *(const float2*)(x + off);
    float2 fv = *(const float2*)(f + off);
    float y0 = xv.x + fv.x;
    float y1 = xv.y + fv.y;
    red[tid] = y0 + y1; __syncthreads();
    for (int s = 128; s > 0; s >>= 1) { if (tid < s) red[tid] += red[tid + s]; __syncthreads(); }
    float mean = red[0] * (1.f / DIM); __syncthreads();
    float d0 = y0 - mean, d1 = y1 - mean;
    red[tid] = d0 * d0 + d1 * d1; __syncthreads();
    for (int s = 128; s > 0; s >>= 1) { if (tid < s) red[tid] += red[tid + s]; __syncthreads(); }
    float inv = 1.f / sqrtf(red[0] * (1.f / DIM) + 1e-5f);
    int dc = 2 * tid;
    float2 gm = *(const float2*)(gam + dc);
    float2 bt = *(const float2*)(bet + dc);
    float2 o; o.x = d0 * inv * gm.x + bt.x; o.y = d1 * inv * gm.y + bt.y;
    *(float2*)(x + off) = o;
    ushort2 hh, ll;
    fsplit(o.x, hh.x, ll.x); fsplit(o.y, hh.y, ll.y);
    *(ushort2*)(xh + off) = hh;
    *(ushort2*)(xl + off) = ll;
    hsplit(o.x, hh.x, ll.x); hsplit(o.y, hh.y, ll.y);
    *(ushort2*)(xh2 + off) = hh;
    *(ushort2*)(xl2 + off) = ll;
}

// ---------------- host-side helpers ----------------
template <int TN>
static void launch_tc(const u16* Ah, const u16* Al, const u16* Bh, const u16* Bl,
                      const float* bias, float* C, u16* Ch, u16* Cl,
                      int M, int N, int K, int lda, int ldb, int ldc,
                      int Z = 1, long sAo = 0, long sAi = 0, long sBo = 0, long sBi = 0,
                      long sCo = 0, long sCi = 0, int zdiv = 1,
                      float alpha = 1.f, int relu = 0)
{
    constexpr int NT = (TN == 256) ? 512 : 256;
    constexpr int SM = 2 * (2 * 128 * 144 + 2 * TN * 144);
    static bool attr_set = false;
    if (!attr_set) {
        cudaFuncSetAttribute(mm_gemm<TN>, cudaFuncAttributeMaxDynamicSharedMemorySize, SM);
        attr_set = true;
    }
    dim3 g(N / TN, M / 128, Z);
    mm_gemm<TN><<<g, NT, SM>>>(Ah, Al, Bh, Bl, bias, C, Ch, Cl,
                               K, lda, ldb, ldc,
                               sAo, sAi, sBo, sBi, sCo, sCi, zdiv, alpha, relu);
}

extern "C" void kernel_launch(void* const* d_in, const int* in_sizes, int n_in,
                              void* d_out, int out_size)
{
    const int*   SRC   = (const int*)  d_in[0];
    const float* EMB   = (const float*)d_in[1];
    const float* PE    = (const float*)d_in[2];
    const float* IN_W  = (const float*)d_in[3];
    const float* IN_B  = (const float*)d_in[4];
    const float* OUT_W = (const float*)d_in[5];
    const float* OUT_B = (const float*)d_in[6];
    const float* QP_W  = (const float*)d_in[7];
    const float* QP_B  = (const float*)d_in[8];
    const float* KP_W  = (const float*)d_in[9];
    const float* KP_B  = (const float*)d_in[10];
    const float* VP_W  = (const float*)d_in[11];
    const float* VP_B  = (const float*)d_in[12];
    const float* LAM   = (const float*)d_in[13];
    const float* FF1_W = (const float*)d_in[14];
    const float* FF1_B = (const float*)d_in[15];
    const float* FF2_W = (const float*)d_in[16];
    const float* FF2_B = (const float*)d_in[17];
    const float* LN1S  = (const float*)d_in[18];
    const float* LN1B  = (const float*)d_in[19];
    const float* LN2S  = (const float*)d_in[20];
    const float* LN2B  = (const float*)d_in[21];
    const float* FIN_W = (const float*)d_in[22];
    const float* FIN_B = (const float*)d_in[23];
    float* OUT = (float*)d_out;

    float *px, *x, *scores, *aproj, *sp, *fft, *pb;
    cudaGetSymbolAddress((void**)&px, g_px);       cudaGetSymbolAddress((void**)&x, g_x);
    cudaGetSymbolAddress((void**)&scores, g_scores); cudaGetSymbolAddress((void**)&aproj, g_aproj);
    cudaGetSymbolAddress((void**)&sp, g_sparse);   cudaGetSymbolAddress((void**)&fft, g_fft);
    cudaGetSymbolAddress((void**)&pb, g_pb);

    u16 *pxh, *pxl, *xh, *xl, *dh, *dl, *fh, *fl, *vth, *vtl;
    u16 *sph, *spl, *vsth, *vstl, *xh2, *xl2;
    cudaGetSymbolAddress((void**)&pxh, g_pxh); cudaGetSymbolAddress((void**)&pxl, g_pxl);
    cudaGetSymbolAddress((void**)&xh, g_xh);   cudaGetSymbolAddress((void**)&xl, g_xl);
    cudaGetSymbolAddress((void**)&dh, g_dh);   cudaGetSymbolAddress((void**)&dl, g_dl);
    cudaGetSymbolAddress((void**)&fh, g_fh);   cudaGetSymbolAddress((void**)&fl, g_fl);
    cudaGetSymbolAddress((void**)&vth, g_vth); cudaGetSymbolAddress((void**)&vtl, g_vtl);
    cudaGetSymbolAddress((void**)&sph, g_sph); cudaGetSymbolAddress((void**)&spl, g_spl);
    cudaGetSymbolAddress((void**)&vsth, g_vsth); cudaGetSymbolAddress((void**)&vstl, g_vstl);
    cudaGetSymbolAddress((void**)&xh2, g_xh2); cudaGetSymbolAddress((void**)&xl2, g_xl2);

    u16 *pwh, *pwl, *outwh, *outwl, *f1wh, *f1wl, *f2wh, *f2wl, *finh2, *finl2;
    cudaGetSymbolAddress((void**)&pwh, g_pwh);     cudaGetSymbolAddress((void**)&pwl, g_pwl);
    cudaGetSymbolAddress((void**)&outwh, g_outwh); cudaGetSymbolAddress((void**)&outwl, g_outwl);
    cudaGetSymbolAddress((void**)&f1wh, g_f1wh);   cudaGetSymbolAddress((void**)&f1wl, g_f1wl);
    cudaGetSymbolAddress((void**)&f2wh, g_f2wh);   cudaGetSymbolAddress((void**)&f2wl, g_f2wl);
    cudaGetSymbolAddress((void**)&finh2, g_finh2); cudaGetSymbolAddress((void**)&finl2, g_finl2);

    // launch 1: embedding
    embed_k<<<TOKENS, 256>>>(SRC, EMB, PE, x, xh, xl);

    // launch 2: packed weights + bias
    {
        int tot = LAYERS * NPACK * (DIM / 4);
        cvt_pack_k<<<(tot + 255) / 256, 256>>>(IN_W, QP_W, KP_W, VP_W,
                                               IN_B, QP_B, KP_B, VP_B,
                                               (ushort4*)pwh, (ushort4*)pwl, pb);
    }
    // launch 3: remaining weights (vocab weights fp16-split in segment 4)
    {
        int n1 = LAYERS * DIM * DIM / 4, n2 = LAYERS * FFD * DIM / 4;
        int n3 = LAYERS * DIM * FFD / 4, n4 = VOCAB * DIM / 4;
        cvt4_k<<<(n1 + n2 + n3 + n4 + 255) / 256, 256>>>(
            (const float4*)OUT_W, (ushort4*)outwh, (ushort4*)outwl, n1,
            (const float4*)FF1_W, (ushort4*)f1wh, (ushort4*)f1wl, n2,
            (const float4*)FF2_W, (ushort4*)f2wh, (ushort4*)f2wl, n3,
            (const float4*)FIN_W, (ushort4*)finh2, (ushort4*)finl2, n4);
    }

    {
        constexpr int FSM = 2 * 256 * 144 + 2 * 4 * 64 * 144;
        cudaFuncSetAttribute(fattn, cudaFuncAttributeMaxDynamicSharedMemorySize, FSM);
        constexpr int VSM = 2 * (128 * 144 + 2 * 256 * 144);
        cudaFuncSetAttribute(mm_vocab, cudaFuncAttributeMaxDynamicSharedMemorySize, VSM);
    }

    for (int l = 0; l < LAYERS; l++) {
        long wq  = (long)l * NPACK * DIM;
        long wo  = (long)l * DIM * DIM;
        long wf1 = (long)l * FFD * DIM;
        long wf2 = (long)l * DIM * FFD;

        // launch 4 (layer 0): packed projections -> px + planes  [PROFILED]
        launch_tc<256>(xh, xl, pwh + wq, pwl + wq, pb + (long)l * NPACK,
                       px, pxh, pxl, TOKENS, NPACK, DIM, DIM, DIM, NPACK);

        // V^T planes for dense attention
        vt_k<<<dim3(SEQ / 32, HDIM / 32, 16), dim3(32, 8)>>>(px, vth, vtl);

        // fused flash attention -> dense planes dh/dl
        {
            constexpr int FSM = 2 * 256 * 144 + 2 * 4 * 64 * 144;
            fattn<<<dim3(SEQ / 256, 16), 512, FSM>>>(pxh, pxl, vth, vtl, dh, dl);
        }

        // dense projection -> aproj fp32
        launch_tc<128>(dh, dl, outwh + wo, outwl + wo, OUT_B + (long)l * DIM,
                       aproj, nullptr, nullptr, TOKENS, DIM, DIM, DIM, DIM, DIM);

        // low-rank logits qk = Qs @ Ks^T / sqrt(R) per batch
        launch_tc<256>(pxh + COL_QS, pxl + COL_QS, pxh + COL_KS, pxl + COL_KS, nullptr,
                       scores, nullptr, nullptr,
                       SEQ, SEQ, RANK, NPACK, NPACK, SEQ,
                       2, (long)SEQ * NPACK, 0, (long)SEQ * NPACK, 0,
                       (long)SEQ * SEQ, 0, 1, 0.125f, 0);

        sparse_sel<<<TOKENS, 256>>>(scores, sph, spl);

        vst_k<<<dim3(SEQ / 32, DIM / 32, 2), dim3(32, 8)>>>(px, vsth, vstl);

        // sparse = sp @ Vs per batch
        launch_tc<128>(sph, spl, vsth, vstl, nullptr, sp, nullptr, nullptr,
                       SEQ, DIM, SEQ, SEQ, SEQ, DIM,
                       2, (long)SEQ * SEQ, 0, (long)DIM * SEQ, 0,
                       (long)SEQ * DIM, 0, 1, 1.f, 0);

        fuse_ln1_k<<<TOKENS, 256>>>(x, aproj, sp, LAM, l,
                                    LN1S + (long)l * DIM, LN1B + (long)l * DIM, xh, xl);

        // FFN
        launch_tc<256>(xh, xl, f1wh + wf1, f1wl + wf1, FF1_B + (long)l * FFD,
                       nullptr, fh, fl, TOKENS, FFD, DIM, DIM, DIM, FFD,
                       1, 0, 0, 0, 0, 0, 0, 1, 1.f, 1);
        launch_tc<128>(fh, fl, f2wh + wf2, f2wl + wf2, FF2_B + (long)l * DIM,
                       fft, nullptr, nullptr, TOKENS, DIM, FFD, FFD, FFD, DIM);

        add_ln2_k<<<TOKENS, 256>>>(x, fft, LN2S + (long)l * DIM, LN2B + (long)l * DIM,
                                   xh, xl, xh2, xl2);
    }

    // final vocab projection: fp16 2-pass
    {
        constexpr int VSM = 2 * (128 * 144 + 2 * 256 * 144);
        dim3 g(VOCAB / 256, TOKENS / 128);
        mm_vocab<<<g, 512, VSM>>>(xh2, finh2, finl2, FIN_B, OUT,
                                  DIM, DIM, DIM, VOCAB);
    }
}

// round 15
// speedup vs baseline: 2.2095x; 1.0937x over previous
#include <cuda_runtime.h>
#include <cuda_bf16.h>
#include <cuda_fp16.h>
#include <math.h>
#include <stdint.h>

#define SEQ    2048
#define TOKENS 4096
#define DIM    512
#define HEADS  8
#define HDIM   64
#define RANK   64
#define LAYERS 6
#define VOCAB  32000
#define FFD    2048
#define KTOP   409
#define NPACK  2304   // 1536 qkv | 64 qs | 64 ks | 512 vs | 128 pad
#define COL_QS 1536
#define COL_KS 1600
#define COL_VS 1664

typedef unsigned short u16;

// ---------------- fp32 scratch ----------------
__device__ float g_px[(size_t)TOKENS * NPACK];
__device__ float g_x[TOKENS * DIM];
__device__ float g_scores[(size_t)2 * SEQ * SEQ];
__device__ float g_aproj[TOKENS * DIM];
__device__ float g_sparse[TOKENS * DIM];
__device__ float g_fft[TOKENS * DIM];

// ---------------- activation planes ----------------
__device__ alignas(16) u16 g_pxh[(size_t)TOKENS * NPACK], g_pxl[(size_t)TOKENS * NPACK];
__device__ alignas(16) u16 g_xh[TOKENS * DIM],       g_xl[TOKENS * DIM];
__device__ alignas(16) u16 g_dh[TOKENS * DIM];                     // fp16 (dense attn out)
__device__ alignas(16) u16 g_fh[TOKENS * FFD],       g_fl[TOKENS * FFD];
__device__ alignas(16) u16 g_vth[16 * HDIM * SEQ],   g_vtl[16 * HDIM * SEQ];
__device__ alignas(16) u16 g_sph[(size_t)2 * SEQ * SEQ];           // fp16 sparse weights
__device__ alignas(16) u16 g_vsth[2 * DIM * SEQ],    g_vstl[2 * DIM * SEQ];  // fp16
__device__ alignas(16) u16 g_xh2[TOKENS * DIM];                    // fp16 (vocab A)

// ---------------- weight planes ----------------
__device__ alignas(16) u16 g_pwh[LAYERS * NPACK * DIM], g_pwl[LAYERS * NPACK * DIM];  // bf16
__device__ float g_pb[LAYERS * NPACK];
__device__ alignas(16) u16 g_outwh[LAYERS * DIM * DIM],  g_outwl[LAYERS * DIM * DIM]; // fp16
__device__ alignas(16) u16 g_f1wh[LAYERS * FFD * DIM],   g_f1wl[LAYERS * FFD * DIM];  // fp16
__device__ alignas(16) u16 g_f2wh[LAYERS * DIM * FFD],   g_f2wl[LAYERS * DIM * FFD];  // bf16
__device__ alignas(16) u16 g_finh2[VOCAB * DIM],         g_finl2[VOCAB * DIM];        // fp16

// ---------------- small device helpers ----------------
__device__ __forceinline__ void fsplit(float x, u16& h, u16& l)
{
    __nv_bfloat16 bh = __float2bfloat16_rn(x);
    float fh = __bfloat162float(bh);
    __nv_bfloat16 bl = __float2bfloat16_rn(x - fh);
    h = *reinterpret_cast<u16*>(&bh);
    l = *reinterpret_cast<u16*>(&bl);
}

__device__ __forceinline__ void hsplit(float x, u16& h, u16& l)
{
    __half hh = __float2half_rn(x);
    float fh = __half2float(hh);
    __half hl = __float2half_rn(x - fh);
    h = *reinterpret_cast<u16*>(&hh);
    l = *reinterpret_cast<u16*>(&hl);
}

__device__ __forceinline__ u16 h16(float x)
{
    __half hh = __float2half_rn(x);
    return *reinterpret_cast<u16*>(&hh);
}

__device__ __forceinline__ uint32_t smem_u32(const void* p)
{
    uint32_t a;
    asm("{ .reg .u64 t; cvta.to.shared.u64 t, %1; cvt.u32.u64 %0, t; }" : "=r"(a) : "l"(p));
    return a;
}

__device__ __forceinline__ void cpa16(uint32_t dst, const void* src)
{
    asm volatile("cp.async.cg.shared.global [%0], [%1], 16;" :: "r"(dst), "l"(src) : "memory");
}

__device__ __forceinline__ void ldsm4(uint32_t* r, uint32_t addr)
{
    asm volatile("ldmatrix.sync.aligned.m8n8.x4.shared.b16 {%0,%1,%2,%3}, [%4];"
                 : "=r"(r[0]), "=r"(r[1]), "=r"(r[2]), "=r"(r[3]) : "r"(addr));
}

__device__ __forceinline__ void mma16816(float* c, const uint32_t* a, uint32_t b0, uint32_t b1)
{
    asm volatile(
        "mma.sync.aligned.m16n8k16.row.col.f32.bf16.bf16.f32 "
        "{%0,%1,%2,%3}, {%4,%5,%6,%7}, {%8,%9}, {%0,%1,%2,%3};"
        : "+f"(c[0]), "+f"(c[1]), "+f"(c[2]), "+f"(c[3])
        : "r"(a[0]), "r"(a[1]), "r"(a[2]), "r"(a[3]), "r"(b0), "r"(b1));
}

__device__ __forceinline__ void mma16816h(float* c, const uint32_t* a, uint32_t b0, uint32_t b1)
{
    asm volatile(
        "mma.sync.aligned.m16n8k16.row.col.f32.f16.f16.f32 "
        "{%0,%1,%2,%3}, {%4,%5,%6,%7}, {%8,%9}, {%0,%1,%2,%3};"
        : "+f"(c[0]), "+f"(c[1]), "+f"(c[2]), "+f"(c[3])
        : "r"(a[0]), "r"(a[1]), "r"(a[2]), "r"(a[3]), "r"(b0), "r"(b1));
}

// ---------------- HMMA bf16x3 GEMM (unchanged core) ----------------
template <int TN>
__global__ void __launch_bounds__((TN == 256) ? 512 : 256, (TN == 64) ? 2 : 1)
mm_gemm(const u16* __restrict__ Ah, const u16* __restrict__ Al,
        const u16* __restrict__ Bh, const u16* __restrict__ Bl,
        const float* __restrict__ bias, float* __restrict__ C,
        u16* __restrict__ Ch, u16* __restrict__ Cl,
        int K, int lda, int ldb, int ldc,
        long sAo, long sAi, long sBo, long sBi, long sCo, long sCi,
        int zdiv, float alpha, int relu)
{
    constexpr int NT  = (TN == 256) ? 512 : 256;
    constexpr int MI  = (TN == 128) ? 4 : 2;
    constexpr int NI  = (TN == 256) ? 4 : 2;
    constexpr int RB  = 144;
    constexpr int APB = 128 * RB;
    constexpr int BPB = TN * RB;
    constexpr int STAGE = 2 * APB + 2 * BPB;
    constexpr int ROWSP = NT / 8;

    extern __shared__ char smem[];
    const uint32_t su = smem_u32(smem);
    const int tid = threadIdx.x;
    const int wid = tid >> 5;
    const int lane = tid & 31;

    int z = blockIdx.z;
    int zo = z / zdiv, zi = z - zo * zdiv;
    long ao = (long)zo * sAo + (long)zi * sAi;
    long bo = (long)zo * sBo + (long)zi * sBi;
    long co = (long)zo * sCo + (long)zi * sCi;
    Ah += ao; Al += ao; Bh += bo; Bl += bo;
    if (C)  C  += co;
    if (Ch) { Ch += co; Cl += co; }
    const int m0 = blockIdx.y * 128;
    const int n0 = blockIdx.x * TN;

    const int wmBase = (TN == 256) ? (wid & 3) * 32
                     : (TN == 128) ? (wid & 1) * 64 : (wid & 3) * 32;
    const int wnBase = (TN == 256) ? (wid >> 2) * 64
                     : (TN == 128) ? (wid >> 1) * 32 : (wid >> 2) * 32;

    float acc[MI][2 * NI][4];
#pragma unroll
    for (int mi = 0; mi < MI; mi++)
#pragma unroll
        for (int n8 = 0; n8 < 2 * NI; n8++)
#pragma unroll
            for (int q = 0; q < 4; q++) acc[mi][n8][q] = 0.f;

    const int nsch = K >> 6;
    const int ar = tid >> 3, ac = tid & 7;
    auto issue = [&](int i) {
        int s = i & 1;
        int k0 = i << 6;
        uint32_t st = su + s * STAGE;
#pragma unroll
        for (int j = 0; j < 128 / ROWSP; j++) {
            int r = ar + ROWSP * j;
            long g = (long)(m0 + r) * lda + k0 + ac * 8;
            uint32_t d = st + r * RB + ac * 16;
            cpa16(d, Ah + g);
            cpa16(d + APB, Al + g);
        }
#pragma unroll
        for (int j = 0; j < TN / ROWSP; j++) {
            int r = ar + ROWSP * j;
            long g = (long)(n0 + r) * ldb + k0 + ac * 8;
            uint32_t d = st + 2 * APB + r * RB + ac * 16;
            cpa16(d, Bh + g);
            cpa16(d + BPB, Bl + g);
        }
        asm volatile("cp.async.commit_group;" ::: "memory");
    };

    issue(0);
    const uint32_t lrow = lane & 15;
    const uint32_t lcol = (lane >> 4) * 16;

    for (int i = 0; i < nsch; i++) {
        asm volatile("cp.async.wait_group 0;" ::: "memory");
        __syncthreads();
        if (i + 1 < nsch) issue(i + 1);

        int s = i & 1;
        uint32_t aH = su + s * STAGE;
        uint32_t aL = aH + APB;
        uint32_t bH = aH + 2 * APB;
        uint32_t bL = bH + BPB;

#pragma unroll
        for (int ks = 0; ks < 4; ks++) {
            uint32_t kb = ks * 32 + lcol;
            uint32_t a[MI][4], bh[NI][4];
#pragma unroll
            for (int mi = 0; mi < MI; mi++)
                ldsm4(a[mi], aH + (wmBase + mi * 16 + lrow) * RB + kb);
#pragma unroll
            for (int ni = 0; ni < NI; ni++)
                ldsm4(bh[ni], bH + (wnBase + ni * 16 + lrow) * RB + kb);
#pragma unroll
            for (int mi = 0; mi < MI; mi++)
#pragma unroll
                for (int ni = 0; ni < NI; ni++) {
                    mma16816(acc[mi][2 * ni],     a[mi], bh[ni][0], bh[ni][2]);
                    mma16816(acc[mi][2 * ni + 1], a[mi], bh[ni][1], bh[ni][3]);
                }
            {
                uint32_t al[MI][4];
#pragma unroll
                for (int mi = 0; mi < MI; mi++)
                    ldsm4(al[mi], aL + (wmBase + mi * 16 + lrow) * RB + kb);
#pragma unroll
                for (int mi = 0; mi < MI; mi++)
#pragma unroll
                    for (int ni = 0; ni < NI; ni++) {
                        mma16816(acc[mi][2 * ni],     al[mi], bh[ni][0], bh[ni][2]);
                        mma16816(acc[mi][2 * ni + 1], al[mi], bh[ni][1], bh[ni][3]);
                    }
            }
            {
                uint32_t bl[NI][4];
#pragma unroll
                for (int ni = 0; ni < NI; ni++)
                    ldsm4(bl[ni], bL + (wnBase + ni * 16 + lrow) * RB + kb);
#pragma unroll
                for (int mi = 0; mi < MI; mi++)
#pragma unroll
                    for (int ni = 0; ni < NI; ni++) {
                        mma16816(acc[mi][2 * ni],     a[mi], bl[ni][0], bl[ni][2]);
                        mma16816(acc[mi][2 * ni + 1], a[mi], bl[ni][1], bl[ni][3]);
                    }
            }
        }
    }

#pragma unroll
    for (int mi = 0; mi < MI; mi++) {
        int r0 = m0 + wmBase + mi * 16 + (lane >> 2);
#pragma unroll
        for (int n8 = 0; n8 < 2 * NI; n8++) {
            int c = n0 + wnBase + n8 * 8 + (lane & 3) * 2;
            float2 o0, o1;
            o0.x = acc[mi][n8][0] * alpha; o0.y = acc[mi][n8][1] * alpha;
            o1.x = acc[mi][n8][2] * alpha; o1.y = acc[mi][n8][3] * alpha;
            if (bias) {
                float b0 = bias[c], b1 = bias[c + 1];
                o0.x += b0; o0.y += b1; o1.x += b0; o1.y += b1;
            }
            if (relu) {
                o0.x = fmaxf(o0.x, 0.f); o0.y = fmaxf(o0.y, 0.f);
                o1.x = fmaxf(o1.x, 0.f); o1.y = fmaxf(o1.y, 0.f);
            }
            long off0 = (long)r0 * ldc + c;
            long off1 = off0 + (long)8 * ldc;
            if (C) {
                *(float2*)(C + off0) = o0;
                *(float2*)(C + off1) = o1;
            }
            if (Ch) {
                ushort2 hh, ll;
                fsplit(o0.x, hh.x, ll.x); fsplit(o0.y, hh.y, ll.y);
                *(ushort2*)(Ch + off0) = hh; *(ushort2*)(Cl + off0) = ll;
                fsplit(o1.x, hh.x, ll.x); fsplit(o1.y, hh.y, ll.y);
                *(ushort2*)(Ch + off1) = hh; *(ushort2*)(Cl + off1) = ll;
            }
        }
    }
}

// ---------------- fp16 2-pass GEMM: C = alpha*(Ah @ (Bh+Bl)^T) + bias ----------------
// Single fp16 A plane, fp16 B hi/lo. Optional bf16-plane output (for FFN1 -> FFN2).
template <int TN>
__global__ void __launch_bounds__((TN == 256) ? 512 : 256)
mm_h2(const u16* __restrict__ Ah,
      const u16* __restrict__ Bh, const u16* __restrict__ Bl,
      const float* __restrict__ bias, float* __restrict__ C,
      u16* __restrict__ Ch, u16* __restrict__ Cl,
      int K, int lda, int ldb, int ldc,
      long sAo, long sAi, long sBo, long sBi, long sCo, long sCi,
      int zdiv, float alpha, int relu)
{
    constexpr int NT  = (TN == 256) ? 512 : 256;
    constexpr int MI  = (TN == 128) ? 4 : 2;
    constexpr int NI  = (TN == 256) ? 4 : 2;
    constexpr int RB  = 144;
    constexpr int APB = 128 * RB;
    constexpr int BPB = TN * RB;
    constexpr int STAGE = APB + 2 * BPB;
    constexpr int ROWSP = NT / 8;

    extern __shared__ char smem[];
    const uint32_t su = smem_u32(smem);
    const int tid = threadIdx.x;
    const int wid = tid >> 5;
    const int lane = tid & 31;

    int z = blockIdx.z;
    int zo = z / zdiv, zi = z - zo * zdiv;
    long ao = (long)zo * sAo + (long)zi * sAi;
    long bo = (long)zo * sBo + (long)zi * sBi;
    long co = (long)zo * sCo + (long)zi * sCi;
    Ah += ao; Bh += bo; Bl += bo;
    if (C)  C  += co;
    if (Ch) { Ch += co; Cl += co; }
    const int m0 = blockIdx.y * 128;
    const int n0 = blockIdx.x * TN;

    const int wmBase = (TN == 256) ? (wid & 3) * 32
                     : (wid & 1) * 64;
    const int wnBase = (TN == 256) ? (wid >> 2) * 64
                     : (wid >> 1) * 32;

    float acc[MI][2 * NI][4];
#pragma unroll
    for (int mi = 0; mi < MI; mi++)
#pragma unroll
        for (int n8 = 0; n8 < 2 * NI; n8++)
#pragma unroll
            for (int q = 0; q < 4; q++) acc[mi][n8][q] = 0.f;

    const int nsch = K >> 6;
    const int ar = tid >> 3, ac = tid & 7;
    auto issue = [&](int i) {
        int s = i & 1;
        int k0 = i << 6;
        uint32_t st = su + s * STAGE;
#pragma unroll
        for (int j = 0; j < 128 / ROWSP; j++) {
            int r = ar + ROWSP * j;
            cpa16(st + r * RB + ac * 16, Ah + (long)(m0 + r) * lda + k0 + ac * 8);
        }
#pragma unroll
        for (int j = 0; j < TN / ROWSP; j++) {
            int r = ar + ROWSP * j;
            long g = (long)(n0 + r) * ldb + k0 + ac * 8;
            uint32_t d = st + APB + r * RB + ac * 16;
            cpa16(d, Bh + g);
            cpa16(d + BPB, Bl + g);
        }
        asm volatile("cp.async.commit_group;" ::: "memory");
    };

    issue(0);
    const uint32_t lrow = lane & 15;
    const uint32_t lcol = (lane >> 4) * 16;

    for (int i = 0; i < nsch; i++) {
        asm volatile("cp.async.wait_group 0;" ::: "memory");
        __syncthreads();
        if (i + 1 < nsch) issue(i + 1);

        uint32_t st = su + (i & 1) * STAGE;
        uint32_t aH = st, bH = st + APB, bL = bH + BPB;

#pragma unroll
        for (int ks = 0; ks < 4; ks++) {
            uint32_t kb = ks * 32 + lcol;
            uint32_t a[MI][4], bh[NI][4];
#pragma unroll
            for (int mi = 0; mi < MI; mi++)
                ldsm4(a[mi], aH + (wmBase + mi * 16 + lrow) * RB + kb);
#pragma unroll
            for (int ni = 0; ni < NI; ni++)
                ldsm4(bh[ni], bH + (wnBase + ni * 16 + lrow) * RB + kb);
#pragma unroll
            for (int mi = 0; mi < MI; mi++)
#pragma unroll
                for (int ni = 0; ni < NI; ni++) {
                    mma16816h(acc[mi][2 * ni],     a[mi], bh[ni][0], bh[ni][2]);
                    mma16816h(acc[mi][2 * ni + 1], a[mi], bh[ni][1], bh[ni][3]);
                }
            {
                uint32_t bl[NI][4];
#pragma unroll
                for (int ni = 0; ni < NI; ni++)
                    ldsm4(bl[ni], bL + (wnBase + ni * 16 + lrow) * RB + kb);
#pragma unroll
                for (int mi = 0; mi < MI; mi++)
#pragma unroll
                    for (int ni = 0; ni < NI; ni++) {
                        mma16816h(acc[mi][2 * ni],     a[mi], bl[ni][0], bl[ni][2]);
                        mma16816h(acc[mi][2 * ni + 1], a[mi], bl[ni][1], bl[ni][3]);
                    }
            }
        }
    }

#pragma unroll
    for (int mi = 0; mi < MI; mi++) {
        int r0 = m0 + wmBase + mi * 16 + (lane >> 2);
#pragma unroll
        for (int n8 = 0; n8 < 2 * NI; n8++) {
            int c = n0 + wnBase + n8 * 8 + (lane & 3) * 2;
            float2 o0, o1;
            o0.x = acc[mi][n8][0] * alpha; o0.y = acc[mi][n8][1] * alpha;
            o1.x = acc[mi][n8][2] * alpha; o1.y = acc[mi][n8][3] * alpha;
            if (bias) {
                float b0 = bias[c], b1 = bias[c + 1];
                o0.x += b0; o0.y += b1; o1.x += b0; o1.y += b1;
            }
            if (relu) {
                o0.x = fmaxf(o0.x, 0.f); o0.y = fmaxf(o0.y, 0.f);
                o1.x = fmaxf(o1.x, 0.f); o1.y = fmaxf(o1.y, 0.f);
            }
            long off0 = (long)r0 * ldc + c;
            long off1 = off0 + (long)8 * ldc;
            if (C) {
                *(float2*)(C + off0) = o0;
                *(float2*)(C + off1) = o1;
            }
            if (Ch) {
                ushort2 hh, ll;
                fsplit(o0.x, hh.x, ll.x); fsplit(o0.y, hh.y, ll.y);
                *(ushort2*)(Ch + off0) = hh; *(ushort2*)(Cl + off0) = ll;
                fsplit(o1.x, hh.x, ll.x); fsplit(o1.y, hh.y, ll.y);
                *(ushort2*)(Ch + off1) = hh; *(ushort2*)(Cl + off1) = ll;
            }
        }
    }
}

// ---------------- fused flash attention (bf16x3, fp16 output plane) ----------------
__global__ void __launch_bounds__(512, 1)
fattn(const u16* __restrict__ pxh, const u16* __restrict__ pxl,
      const u16* __restrict__ vth, const u16* __restrict__ vtl,
      u16* __restrict__ dh)
{
    constexpr int QT = 256, KT = 64, RB = 144;
    constexpr int QB = QT * RB;
    constexpr int KB = KT * RB;
    constexpr int STG = 4 * KB;

    extern __shared__ char smem[];
    const uint32_t su = smem_u32(smem);
    const int tid = threadIdx.x, wid = tid >> 5, lane = tid & 31;
    const int z = blockIdx.y, b = z >> 3, h = z & 7;
    const int q0 = blockIdx.x * QT;

    const uint32_t sQh = su, sQl = su + QB;
    const uint32_t sKV = su + 2 * QB;

    const u16* qh = pxh + (long)(b * SEQ + q0) * NPACK + h * HDIM;
    const u16* ql = pxl + (long)(b * SEQ + q0) * NPACK + h * HDIM;
    const u16* kh = pxh + (long)(b * SEQ) * NPACK + DIM + h * HDIM;
    const u16* kl = pxl + (long)(b * SEQ) * NPACK + DIM + h * HDIM;
    const u16* vh = vth + (long)z * HDIM * SEQ;
    const u16* vl = vtl + (long)z * HDIM * SEQ;

    const int ar = tid >> 3, ac = tid & 7;
#pragma unroll
    for (int j = 0; j < 4; j++) {
        int r = ar + 64 * j;
        long g = (long)r * NPACK + ac * 8;
        uint32_t d = r * RB + ac * 16;
        cpa16(sQh + d, qh + g);
        cpa16(sQl + d, ql + g);
    }
    asm volatile("cp.async.commit_group;" ::: "memory");

    auto issue = [&](int i) {
        uint32_t st = sKV + (i & 1) * STG;
        int s0 = i * KT;
        long gk = (long)(s0 + ar) * NPACK + ac * 8;
        uint32_t d = ar * RB + ac * 16;
        cpa16(st + d, kh + gk);
        cpa16(st + KB + d, kl + gk);
        long gv = (long)ar * SEQ + s0 + ac * 8;
        cpa16(st + 2 * KB + d, vh + gv);
        cpa16(st + 3 * KB + d, vl + gv);
        asm volatile("cp.async.commit_group;" ::: "memory");
    };
    issue(0);

    const int qr = wid * 16;
    const uint32_t lrow = lane & 15;
    const uint32_t lcolb = (lane >> 4) * 16;

    float o[8][4];
#pragma unroll
    for (int j = 0; j < 8; j++)
#pragma unroll
        for (int q = 0; q < 4; q++) o[j][q] = 0.f;
    float m0 = -3.4e38f, m1 = -3.4e38f, l0 = 0.f, l1 = 0.f;

    for (int it = 0; it < SEQ / KT; it++) {
        asm volatile("cp.async.wait_group 0;" ::: "memory");
        __syncthreads();
        if (it + 1 < SEQ / KT) issue(it + 1);

        uint32_t st = sKV + (it & 1) * STG;
        uint32_t kH = st, kL = st + KB, vH = st + 2 * KB, vL = st + 3 * KB;

        float s[8][4];
#pragma unroll
        for (int j = 0; j < 8; j++)
#pragma unroll
            for (int q = 0; q < 4; q++) s[j][q] = 0.f;

#pragma unroll
        for (int c = 0; c < 4; c++) {
            uint32_t kb = c * 32 + lcolb;
            uint32_t aq[4], bk[4][4];
            ldsm4(aq, sQh + (qr + lrow) * RB + kb);
#pragma unroll
            for (int ni = 0; ni < 4; ni++)
                ldsm4(bk[ni], kH + (ni * 16 + lrow) * RB + kb);
#pragma unroll
            for (int ni = 0; ni < 4; ni++) {
                mma16816(s[2 * ni],     aq, bk[ni][0], bk[ni][2]);
                mma16816(s[2 * ni + 1], aq, bk[ni][1], bk[ni][3]);
            }
            {
                uint32_t al[4];
                ldsm4(al, sQl + (qr + lrow) * RB + kb);
#pragma unroll
                for (int ni = 0; ni < 4; ni++) {
                    mma16816(s[2 * ni],     al, bk[ni][0], bk[ni][2]);
                    mma16816(s[2 * ni + 1], al, bk[ni][1], bk[ni][3]);
                }
            }
            {
                uint32_t bl[4];
#pragma unroll
                for (int ni = 0; ni < 4; ni++) {
                    ldsm4(bl, kL + (ni * 16 + lrow) * RB + kb);
                    mma16816(s[2 * ni],     aq, bl[0], bl[2]);
                    mma16816(s[2 * ni + 1], aq, bl[1], bl[3]);
                }
            }
        }

        float tm0 = -3.4e38f, tm1 = -3.4e38f;
#pragma unroll
        for (int j = 0; j < 8; j++) {
            s[j][0] *= 0.125f; s[j][1] *= 0.125f;
            s[j][2] *= 0.125f; s[j][3] *= 0.125f;
            tm0 = fmaxf(tm0, fmaxf(s[j][0], s[j][1]));
            tm1 = fmaxf(tm1, fmaxf(s[j][2], s[j][3]));
        }
        tm0 = fmaxf(tm0, __shfl_xor_sync(0xffffffffu, tm0, 1));
        tm0 = fmaxf(tm0, __shfl_xor_sync(0xffffffffu, tm0, 2));
        tm1 = fmaxf(tm1, __shfl_xor_sync(0xffffffffu, tm1, 1));
        tm1 = fmaxf(tm1, __shfl_xor_sync(0xffffffffu, tm1, 2));
        float mn0 = fmaxf(m0, tm0), mn1 = fmaxf(m1, tm1);
        float a0 = __expf(m0 - mn0), a1 = __expf(m1 - mn1);
        m0 = mn0; m1 = mn1;

        float ts0 = 0.f, ts1 = 0.f;
        uint32_t ph[4][4], pl[4][4];
#pragma unroll
        for (int j = 0; j < 8; j++) {
            float p00 = __expf(s[j][0] - mn0), p01 = __expf(s[j][1] - mn0);
            float p10 = __expf(s[j][2] - mn1), p11 = __expf(s[j][3] - mn1);
            ts0 += p00 + p01; ts1 += p10 + p11;
            u16 h00, l00, h01, l01, h10, l10, h11, l11;
            fsplit(p00, h00, l00); fsplit(p01, h01, l01);
            fsplit(p10, h10, l10); fsplit(p11, h11, l11);
            int t = j >> 1, hi = (j & 1) * 2;
            ph[t][hi]     = ((uint32_t)h01 << 16) | h00;
            ph[t][hi + 1] = ((uint32_t)h11 << 16) | h10;
            pl[t][hi]     = ((uint32_t)l01 << 16) | l00;
            pl[t][hi + 1] = ((uint32_t)l11 << 16) | l10;
        }
        ts0 += __shfl_xor_sync(0xffffffffu, ts0, 1);
        ts0 += __shfl_xor_sync(0xffffffffu, ts0, 2);
        ts1 += __shfl_xor_sync(0xffffffffu, ts1, 1);
        ts1 += __shfl_xor_sync(0xffffffffu, ts1, 2);
        l0 = l0 * a0 + ts0;
        l1 = l1 * a1 + ts1;
#pragma unroll
        for (int j = 0; j < 8; j++) {
            o[j][0] *= a0; o[j][1] *= a0;
            o[j][2] *= a1; o[j][3] *= a1;
        }

#pragma unroll
        for (int t = 0; t < 4; t++) {
            uint32_t kb = t * 32 + lcolb;
            uint32_t bv[4][4];
#pragma unroll
            for (int ni = 0; ni < 4; ni++)
                ldsm4(bv[ni], vH + (ni * 16 + lrow) * RB + kb);
#pragma unroll
            for (int ni = 0; ni < 4; ni++) {
                mma16816(o[2 * ni],     ph[t], bv[ni][0], bv[ni][2]);
                mma16816(o[2 * ni + 1], ph[t], bv[ni][1], bv[ni][3]);
            }
#pragma unroll
            for (int ni = 0; ni < 4; ni++) {
                mma16816(o[2 * ni],     pl[t], bv[ni][0], bv[ni][2]);
                mma16816(o[2 * ni + 1], pl[t], bv[ni][1], bv[ni][3]);
            }
            {
                uint32_t bvl[4];
#pragma unroll
                for (int ni = 0; ni < 4; ni++) {
                    ldsm4(bvl, vL + (ni * 16 + lrow) * RB + kb);
                    mma16816(o[2 * ni],     ph[t], bvl[0], bvl[2]);
                    mma16816(o[2 * ni + 1], ph[t], bvl[1], bvl[3]);
                }
            }
        }
    }

    float i0 = 1.f / l0, i1 = 1.f / l1;
    int g = lane >> 2;
    long row0 = (long)(b * SEQ + q0 + qr + g) * DIM;
    long row1 = row0 + 8 * DIM;
#pragma unroll
    for (int j = 0; j < 8; j++) {
        int col = h * HDIM + 8 * j + (lane & 3) * 2;
        ushort2 hh;
        hh.x = h16(o[j][0] * i0);
        hh.y = h16(o[j][1] * i0);
        *(ushort2*)(dh + row0 + col) = hh;
        hh.x = h16(o[j][2] * i1);
        hh.y = h16(o[j][3] * i1);
        *(ushort2*)(dh + row1 + col) = hh;
    }
}

// ---------------- weight converters ----------------
__global__ void cvt_pack_k(const float* __restrict__ in_w, const float* __restrict__ qp_w,
                           const float* __restrict__ kp_w, const float* __restrict__ vp_w,
                           const float* __restrict__ in_b, const float* __restrict__ qp_b,
                           const float* __restrict__ kp_b, const float* __restrict__ vp_b,
                           ushort4* __restrict__ h, ushort4* __restrict__ l,
                           float* __restrict__ pb)
{
    int i = blockIdx.x * 256 + threadIdx.x;
    if (i < LAYERS * NPACK) {
        int lay = i / NPACK;
        int r = i - lay * NPACK;
        float v = 0.f;
        if (r < COL_QS) v = in_b[lay * 1536 + r];
        else if (r < COL_KS) v = qp_b[lay * RANK + (r - COL_QS)];
        else if (r < COL_VS) v = kp_b[lay * RANK + (r - COL_KS)];
        else if (r < COL_VS + DIM) v = vp_b[lay * DIM + (r - COL_VS)];
        pb[i] = v;
    }
    const int PER_L = NPACK * (DIM / 4);
    if (i >= LAYERS * PER_L) return;
    int lay = i / PER_L;
    int rem = i - lay * PER_L;
    int r = rem / (DIM / 4);
    int c4 = rem - r * (DIM / 4);
    float4 v = make_float4(0.f, 0.f, 0.f, 0.f);
    if (r < COL_QS)
        v = ((const float4*)(in_w + ((long)lay * 1536 + r) * DIM))[c4];
    else if (r < COL_KS)
        v = ((const float4*)(qp_w + ((long)lay * RANK + (r - COL_QS)) * DIM))[c4];
    else if (r < COL_VS)
        v = ((const float4*)(kp_w + ((long)lay * RANK + (r - COL_KS)) * DIM))[c4];
    else if (r < COL_VS + DIM)
        v = ((const float4*)(vp_w + ((long)lay * DIM + (r - COL_VS)) * DIM))[c4];
    ushort4 hh, ll;
    fsplit(v.x, hh.x, ll.x); fsplit(v.y, hh.y, ll.y);
    fsplit(v.z, hh.z, ll.z); fsplit(v.w, hh.w, ll.w);
    long o = (long)lay * NPACK * (DIM / 4) + (long)r * (DIM / 4) + c4;
    h[o] = hh; l[o] = ll;
}

// seg0 (OUT_W): fp16 | seg1 (FF1_W): fp16 | seg2 (FF2_W): bf16 | seg3 (FIN_W): fp16
__global__ void cvt4_k(const float4* __restrict__ s1, ushort4* __restrict__ h1, ushort4* __restrict__ l1, int n1,
                       const float4* __restrict__ s2, ushort4* __restrict__ h2, ushort4* __restrict__ l2, int n2,
                       const float4* __restrict__ s3, ushort4* __restrict__ h3, ushort4* __restrict__ l3, int n3,
                       const float4* __restrict__ s4, ushort4* __restrict__ h4, ushort4* __restrict__ l4, int n4)
{
    int i = blockIdx.x * 256 + threadIdx.x;
    const float4* s; ushort4 *h, *l; int j; int seg;
    if (i < n1) { s = s1; h = h1; l = l1; j = i; seg = 0; }
    else if (i < n1 + n2) { s = s2; h = h2; l = l2; j = i - n1; seg = 1; }
    else if (i < n1 + n2 + n3) { s = s3; h = h3; l = l3; j = i - n1 - n2; seg = 2; }
    else if (i < n1 + n2 + n3 + n4) { s = s4; h = h4; l = l4; j = i - n1 - n2 - n3; seg = 3; }
    else return;
    float4 v = s[j];
    ushort4 hh, ll;
    if (seg != 2) {
        hsplit(v.x, hh.x, ll.x); hsplit(v.y, hh.y, ll.y);
        hsplit(v.z, hh.z, ll.z); hsplit(v.w, hh.w, ll.w);
    } else {
        fsplit(v.x, hh.x, ll.x); fsplit(v.y, hh.y, ll.y);
        fsplit(v.z, hh.z, ll.z); fsplit(v.w, hh.w, ll.w);
    }
    h[j] = hh; l[j] = ll;
}

// V^T planes (dense, bf16) from packed px
__global__ void vt_k(const float* __restrict__ px, u16* __restrict__ vh, u16* __restrict__ vl)
{
    __shared__ float t[32][33];
    int z = blockIdx.z, b = z >> 3, h = z & 7;
    int s0 = blockIdx.x * 32, d0 = blockIdx.y * 32;
    int tx = threadIdx.x, ty = threadIdx.y;
#pragma unroll
    for (int j = 0; j < 4; j++) {
        int s = s0 + ty + j * 8;
        t[ty + j * 8][tx] = px[((long)(b * SEQ + s)) * NPACK + 2 * DIM + h * HDIM + d0 + tx];
    }
    __syncthreads();
#pragma unroll
    for (int j = 0; j < 4; j++) {
        int d = d0 + ty + j * 8;
        long o = ((long)z * HDIM + d) * SEQ + s0 + tx;
        u16 hh, ll;
        fsplit(t[tx][ty + j * 8], hh, ll);
        vh[o] = hh; vl[o] = ll;
    }
}

// Vs^T planes (sparse, fp16)
__global__ void vst_k(const float* __restrict__ px, u16* __restrict__ vh, u16* __restrict__ vl)
{
    __shared__ float t[32][33];
    int b = blockIdx.z;
    int s0 = blockIdx.x * 32, d0 = blockIdx.y * 32;
    int tx = threadIdx.x, ty = threadIdx.y;
#pragma unroll
    for (int j = 0; j < 4; j++) {
        int s = s0 + ty + j * 8;
        t[ty + j * 8][tx] = px[((long)(b * SEQ + s)) * NPACK + COL_VS + d0 + tx];
    }
    __syncthreads();
#pragma unroll
    for (int j = 0; j < 4; j++) {
        int d = d0 + ty + j * 8;
        long o = ((long)(b * DIM + d)) * SEQ + s0 + tx;
        u16 hh, ll;
        hsplit(t[tx][ty + j * 8], hh, ll);
        vh[o] = hh; vl[o] = ll;
    }
}

// ---------------- embedding ----------------
__global__ void embed_k(const int* __restrict__ src, const float* __restrict__ emb,
                        const float* __restrict__ pe, float* __restrict__ x,
                        u16* __restrict__ xh, u16* __restrict__ xl)
{
    int t = blockIdx.x;
    int tid = threadIdx.x;
    int s = t & (SEQ - 1);
    int tok = src[t];
    int d = tid * 2;
    float2 e = *(const float2*)(emb + (long)tok * DIM + d);
    float2 p = *(const float2*)(pe + (long)s * DIM + d);
    float2 o;
    o.x = e.x * 22.627416998f + p.x;
    o.y = e.y * 22.627416998f + p.y;
    long off = (long)t * DIM + d;
    *(float2*)(x + off) = o;
    ushort2 hh, ll;
    fsplit(o.x, hh.x, ll.x); fsplit(o.y, hh.y, ll.y);
    *(ushort2*)(xh + off) = hh;
    *(ushort2*)(xl + off) = ll;
}

// ---------------- sparse select (emits fp16 weight plane) ----------------
__device__ __forceinline__ unsigned f2k(float f)
{
    unsigned u = __float_as_uint(f);
    return (u & 0x80000000u) ? ~u : (u | 0x80000000u);
}

__global__ void __launch_bounds__(256) sparse_sel(
    const float* __restrict__ qk, u16* __restrict__ sph)
{
    __shared__ float logit[SEQ];
    __shared__ unsigned hist[256];
    __shared__ unsigned suf[256];
    __shared__ float red[256];
    __shared__ unsigned sh_prefix;
    __shared__ int sh_remaining;

    long row = blockIdx.x;
    int tid = threadIdx.x;
    const float* p = qk + row * (long)SEQ;

    for (int k = tid; k < SEQ; k += 256) logit[k] = p[k];
    __syncthreads();

    float lm = -3.4e38f;
    for (int k = tid; k < SEQ; k += 256) lm = fmaxf(lm, logit[k]);
    red[tid] = lm; __syncthreads();
    for (int s = 128; s > 0; s >>= 1) { if (tid < s) red[tid] = fmaxf(red[tid], red[tid + s]); __syncthreads(); }
    float Lmax = red[0]; __syncthreads();

    float zacc = 0.f;
    for (int k = tid; k < SEQ; k += 256) zacc += __expf(logit[k] - Lmax);
    red[tid] = zacc; __syncthreads();
    for (int s = 128; s > 0; s >>= 1) { if (tid < s) red[tid] += red[tid + s]; __syncthreads(); }
    float Z = red[0]; __syncthreads();

    unsigned prefix = 0; int remaining = KTOP;
    for (int shift = 24; shift >= 0; shift -= 8) {
        hist[tid] = 0; __syncthreads();
        unsigned upmask = (shift == 24) ? 0u : (0xFFFFFFFFu << (shift + 8));
        for (int k = tid; k < SEQ; k += 256) {
            unsigned key = f2k(logit[k]);
            if ((key & upmask) == prefix)
                atomicAdd(&hist[(key >> shift) & 255], 1u);
        }
        __syncthreads();
        suf[tid] = hist[tid]; __syncthreads();
        for (int off = 1; off < 256; off <<= 1) {
            unsigned add = (tid + off < 256) ? suf[tid + off] : 0u;
            __syncthreads();
            suf[tid] += add;
            __syncthreads();
        }
        unsigned shere = suf[tid];
        unsigned snext = (tid < 255) ? suf[tid + 1] : 0u;
        if (shere >= (unsigned)remaining && snext < (unsigned)remaining) {
            sh_prefix = prefix | ((unsigned)tid << shift);
            sh_remaining = remaining - (int)snext;
        }
        __syncthreads();
        prefix = sh_prefix; remaining = sh_remaining;
        __syncthreads();
    }
    unsigned thr = prefix;

    float w8[8];
    float dsum = 0.f;
#pragma unroll
    for (int j = 0; j < 8; j++) {
        int k = tid + 256 * j;
        float l = logit[k];
        bool keep = (f2k(l) >= thr);
        float w = keep ? __expf(l - Lmax) : 0.f;
        w8[j] = w;
        dsum += w;
    }
    red[tid] = dsum; __syncthreads();
    for (int s = 128; s > 0; s >>= 1) { if (tid < s) red[tid] += red[tid + s]; __syncthreads(); }
    float inv = 1.f / (red[0] + 1e-9f * Z);

#pragma unroll
    for (int j = 0; j < 8; j++) {
        int k = tid + 256 * j;
        sph[row * (long)SEQ + k] = h16(w8[j] * inv);
    }
}

// ---------------- gated fusion + LN1 (emits fp16 A plane for FFN1) ----------------
__global__ void fuse_ln1_k(float* __restrict__ x, const float* __restrict__ dn,
                           const float* __restrict__ sp, const float* __restrict__ lam,
                           int layer, const float* __restrict__ gam, const float* __restrict__ bet,
                           u16* __restrict__ xh)
{
    __shared__ float red[256];
    int row = blockIdx.x, tid = threadIdx.x;
    long off = (long)row * DIM + 2 * tid;
    float g = 1.f / (1.f + expf(-lam[layer]));
    float2 xv = *(const float2*)(x + off);
    float2 dv = *(const float2*)(dn + off);
    float2 sv = *(const float2*)(sp + off);
    float y0 = xv.x + g * dv.x + (1.f - g) * sv.x;
    float y1 = xv.y + g * dv.y + (1.f - g) * sv.y;
    red[tid] = y0 + y1; __syncthreads();
    for (int s = 128; s > 0; s >>= 1) { if (tid < s) red[tid] += red[tid + s]; __syncthreads(); }
    float mean = red[0] * (1.f / DIM); __syncthreads();
    float d0 = y0 - mean, d1 = y1 - mean;
    red[tid] = d0 * d0 + d1 * d1; __syncthreads();
    for (int s = 128; s > 0; s >>= 1) { if (tid < s) red[tid] += red[tid + s]; __syncthreads(); }
    float inv = 1.f / sqrtf(red[0] * (1.f / DIM) + 1e-5f);
    int dc = 2 * tid;
    float2 gm = *(const float2*)(gam + dc);
    float2 bt = *(const float2*)(bet + dc);
    float2 o; o.x = d0 * inv * gm.x + bt.x; o.y = d1 * inv * gm.y + bt.y;
    *(float2*)(x + off) = o;
    ushort2 hh;
    hh.x = h16(o.x); hh.y = h16(o.y);
    *(ushort2*)(xh + off) = hh;
}

// ---------------- residual + LN2 (bf16 planes for packed proj, fp16 for vocab) ----------------
__global__ void add_ln2_k(float* __restrict__ x, const float* __restrict__ f,
                          const float* __restrict__ gam, const float* __restrict__ bet,
                          u16* __restrict__ xh, u16* __restrict__ xl,
                          u16* __restrict__ xh2)
{
    __shared__ float red[256];
    int row = blockIdx.x, tid = threadIdx.x;
    long off = (long)row * DIM + 2 * tid;
    float2 xv = *(const float2*)(x + off);
    float2 fv = *(const float2*)(f + off);
    float y0 = xv.x + fv.x;
    float y1 = xv.y + fv.y;
    red[tid] = y0 + y1; __syncthreads();
    for (int s = 128; s > 0; s >>= 1) { if (tid < s) red[tid] += red[tid + s]; __syncthreads(); }
    float mean = red[0] * (1.f / DIM); __syncthreads();
    float d0 = y0 - mean, d1 = y1 - mean;
    red[tid] = d0 * d0 + d1 * d1; __syncthreads();
    for (int s = 128; s > 0; s >>= 1) { if (tid < s) red[tid] += red[tid + s]; __syncthreads(); }
    float inv = 1.f / sqrtf(red[0] * (1.f / DIM) + 1e-5f);
    int dc = 2 * tid;
    float2 gm = *(const float2*)(gam + dc);
    float2 bt = *(const float2*)(bet + dc);
    float2 o; o.x = d0 * inv * gm.x + bt.x; o.y = d1 * inv * gm.y + bt.y;
    *(float2*)(x + off) = o;
    ushort2 hh, ll;
    fsplit(o.x, hh.x, ll.x); fsplit(o.y, hh.y, ll.y);
    *(ushort2*)(xh + off) = hh;
    *(ushort2*)(xl + off) = ll;
    hh.x = h16(o.x); hh.y = h16(o.y);
    *(ushort2*)(xh2 + off) = hh;
}

// ---------------- host-side helpers ----------------
template <int TN>
static void launch_tc(const u16* Ah, const u16* Al, const u16* Bh, const u16* Bl,
                      const float* bias, float* C, u16* Ch, u16* Cl,
                      int M, int N, int K, int lda, int ldb, int ldc,
                      int Z = 1, long sAo = 0, long sAi = 0, long sBo = 0, long sBi = 0,
                      long sCo = 0, long sCi = 0, int zdiv = 1,
                      float alpha = 1.f, int relu = 0)
{
    constexpr int NT = (TN == 256) ? 512 : 256;
    constexpr int SM = 2 * (2 * 128 * 144 + 2 * TN * 144);
    static bool attr_set = false;
    if (!attr_set) {
        cudaFuncSetAttribute(mm_gemm<TN>, cudaFuncAttributeMaxDynamicSharedMemorySize, SM);
        attr_set = true;
    }
    dim3 g(N / TN, M / 128, Z);
    mm_gemm<TN><<<g, NT, SM>>>(Ah, Al, Bh, Bl, bias, C, Ch, Cl,
                               K, lda, ldb, ldc,
                               sAo, sAi, sBo, sBi, sCo, sCi, zdiv, alpha, relu);
}

template <int TN>
static void launch_h2(const u16* Ah, const u16* Bh, const u16* Bl,
                      const float* bias, float* C, u16* Ch, u16* Cl,
                      int M, int N, int K, int lda, int ldb, int ldc,
                      int Z = 1, long sAo = 0, long sAi = 0, long sBo = 0, long sBi = 0,
                      long sCo = 0, long sCi = 0, int zdiv = 1,
                      float alpha = 1.f, int relu = 0)
{
    constexpr int NT = (TN == 256) ? 512 : 256;
    constexpr int SM = 2 * (128 * 144 + 2 * TN * 144);
    static bool attr_set = false;
    if (!attr_set) {
        cudaFuncSetAttribute(mm_h2<TN>, cudaFuncAttributeMaxDynamicSharedMemorySize, SM);
        attr_set = true;
    }
    dim3 g(N / TN, M / 128, Z);
    mm_h2<TN><<<g, NT, SM>>>(Ah, Bh, Bl, bias, C, Ch, Cl,
                             K, lda, ldb, ldc,
                             sAo, sAi, sBo, sBi, sCo, sCi, zdiv, alpha, relu);
}

extern "C" void kernel_launch(void* const* d_in, const int* in_sizes, int n_in,
                              void* d_out, int out_size)
{
    const int*   SRC   = (const int*)  d_in[0];
    const float* EMB   = (const float*)d_in[1];
    const float* PE    = (const float*)d_in[2];
    const float* IN_W  = (const float*)d_in[3];
    const float* IN_B  = (const float*)d_in[4];
    const float* OUT_W = (const float*)d_in[5];
    const float* OUT_B = (const float*)d_in[6];
    const float* QP_W  = (const float*)d_in[7];
    const float* QP_B  = (const float*)d_in[8];
    const float* KP_W  = (const float*)d_in[9];
    const float* KP_B  = (const float*)d_in[10];
    const float* VP_W  = (const float*)d_in[11];
    const float* VP_B  = (const float*)d_in[12];
    const float* LAM   = (const float*)d_in[13];
    const float* FF1_W = (const float*)d_in[14];
    const float* FF1_B = (const float*)d_in[15];
    const float* FF2_W = (const float*)d_in[16];
    const float* FF2_B = (const float*)d_in[17];
    const float* LN1S  = (const float*)d_in[18];
    const float* LN1B  = (const float*)d_in[19];
    const float* LN2S  = (const float*)d_in[20];
    const float* LN2B  = (const float*)d_in[21];
    const float* FIN_W = (const float*)d_in[22];
    const float* FIN_B = (const float*)d_in[23];
    float* OUT = (float*)d_out;

    float *px, *x, *scores, *aproj, *sp, *fft, *pb;
    cudaGetSymbolAddress((void**)&px, g_px);       cudaGetSymbolAddress((void**)&x, g_x);
    cudaGetSymbolAddress((void**)&scores, g_scores); cudaGetSymbolAddress((void**)&aproj, g_aproj);
    cudaGetSymbolAddress((void**)&sp, g_sparse);   cudaGetSymbolAddress((void**)&fft, g_fft);
    cudaGetSymbolAddress((void**)&pb, g_pb);

    u16 *pxh, *pxl, *xh, *xl, *dh, *fh, *fl, *vth, *vtl;
    u16 *sph, *vsth, *vstl, *xh2;
    cudaGetSymbolAddress((void**)&pxh, g_pxh); cudaGetSymbolAddress((void**)&pxl, g_pxl);
    cudaGetSymbolAddress((void**)&xh, g_xh);   cudaGetSymbolAddress((void**)&xl, g_xl);
    cudaGetSymbolAddress((void**)&dh, g_dh);
    cudaGetSymbolAddress((void**)&fh, g_fh);   cudaGetSymbolAddress((void**)&fl, g_fl);
    cudaGetSymbolAddress((void**)&vth, g_vth); cudaGetSymbolAddress((void**)&vtl, g_vtl);
    cudaGetSymbolAddress((void**)&sph, g_sph);
    cudaGetSymbolAddress((void**)&vsth, g_vsth); cudaGetSymbolAddress((void**)&vstl, g_vstl);
    cudaGetSymbolAddress((void**)&xh2, g_xh2);

    u16 *pwh, *pwl, *outwh, *outwl, *f1wh, *f1wl, *f2wh, *f2wl, *finh2, *finl2;
    cudaGetSymbolAddress((void**)&pwh, g_pwh);     cudaGetSymbolAddress((void**)&pwl, g_pwl);
    cudaGetSymbolAddress((void**)&outwh, g_outwh); cudaGetSymbolAddress((void**)&outwl, g_outwl);
    cudaGetSymbolAddress((void**)&f1wh, g_f1wh);   cudaGetSymbolAddress((void**)&f1wl, g_f1wl);
    cudaGetSymbolAddress((void**)&f2wh, g_f2wh);   cudaGetSymbolAddress((void**)&f2wl, g_f2wl);
    cudaGetSymbolAddress((void**)&finh2, g_finh2); cudaGetSymbolAddress((void**)&finl2, g_finl2);

    // launch 1: embedding
    embed_k<<<TOKENS, 256>>>(SRC, EMB, PE, x, xh, xl);

    // launch 2: packed weights + bias (bf16)
    {
        int tot = LAYERS * NPACK * (DIM / 4);
        cvt_pack_k<<<(tot + 255) / 256, 256>>>(IN_W, QP_W, KP_W, VP_W,
                                               IN_B, QP_B, KP_B, VP_B,
                                               (ushort4*)pwh, (ushort4*)pwl, pb);
    }
    // launch 3: remaining weights (fp16 except FF2_W)
    {
        int n1 = LAYERS * DIM * DIM / 4, n2 = LAYERS * FFD * DIM / 4;
        int n3 = LAYERS * DIM * FFD / 4, n4 = VOCAB * DIM / 4;
        cvt4_k<<<(n1 + n2 + n3 + n4 + 255) / 256, 256>>>(
            (const float4*)OUT_W, (ushort4*)outwh, (ushort4*)outwl, n1,
            (const float4*)FF1_W, (ushort4*)f1wh, (ushort4*)f1wl, n2,
            (const float4*)FF2_W, (ushort4*)f2wh, (ushort4*)f2wl, n3,
            (const float4*)FIN_W, (ushort4*)finh2, (ushort4*)finl2, n4);
    }

    {
        constexpr int FSM = 2 * 256 * 144 + 2 * 4 * 64 * 144;
        cudaFuncSetAttribute(fattn, cudaFuncAttributeMaxDynamicSharedMemorySize, FSM);
    }

    for (int l = 0; l < LAYERS; l++) {
        long wq  = (long)l * NPACK * DIM;
        long wo  = (long)l * DIM * DIM;
        long wf1 = (long)l * FFD * DIM;
        long wf2 = (long)l * DIM * FFD;

        // launch 4 (layer 0): packed projections (bf16x3) -> px + planes  [PROFILED]
        launch_tc<256>(xh, xl, pwh + wq, pwl + wq, pb + (long)l * NPACK,
                       px, pxh, pxl, TOKENS, NPACK, DIM, DIM, DIM, NPACK);

        // V^T planes for dense attention (bf16)
        vt_k<<<dim3(SEQ / 32, HDIM / 32, 16), dim3(32, 8)>>>(px, vth, vtl);

        // fused flash attention -> dh (fp16)
        {
            constexpr int FSM = 2 * 256 * 144 + 2 * 4 * 64 * 144;
            fattn<<<dim3(SEQ / 256, 16), 512, FSM>>>(pxh, pxl, vth, vtl, dh);
        }

        // dense projection (fp16 2-pass) -> aproj fp32
        launch_h2<128>(dh, outwh + wo, outwl + wo, OUT_B + (long)l * DIM,
                       aproj, nullptr, nullptr, TOKENS, DIM, DIM, DIM, DIM, DIM);

        // low-rank logits qk = Qs @ Ks^T / sqrt(R) per batch (bf16x3)
        launch_tc<256>(pxh + COL_QS, pxl + COL_QS, pxh + COL_KS, pxl + COL_KS, nullptr,
                       scores, nullptr, nullptr,
                       SEQ, SEQ, RANK, NPACK, NPACK, SEQ,
                       2, (long)SEQ * NPACK, 0, (long)SEQ * NPACK, 0,
                       (long)SEQ * SEQ, 0, 1, 0.125f, 0);

        sparse_sel<<<TOKENS, 256>>>(scores, sph);

        vst_k<<<dim3(SEQ / 32, DIM / 32, 2), dim3(32, 8)>>>(px, vsth, vstl);

        // sparse = sp @ Vs per batch (fp16 2-pass)
        launch_h2<128>(sph, vsth, vstl, nullptr, sp, nullptr, nullptr,
                       SEQ, DIM, SEQ, SEQ, SEQ, DIM,
                       2, (long)SEQ * SEQ, 0, (long)DIM * SEQ, 0,
                       (long)SEQ * DIM, 0, 1, 1.f, 0);

        fuse_ln1_k<<<TOKENS, 256>>>(x, aproj, sp, LAM, l,
                                    LN1S + (long)l * DIM, LN1B + (long)l * DIM, xh);

        // FFN1 (fp16 2-pass) -> bf16 planes for FFN2
        launch_h2<256>(xh, f1wh + wf1, f1wl + wf1, FF1_B + (long)l * FFD,
                       nullptr, fh, fl, TOKENS, FFD, DIM, DIM, DIM, FFD,
                       1, 0, 0, 0, 0, 0, 0, 1, 1.f, 1);
        // FFN2 (bf16x3, writes residual)
        launch_tc<128>(fh, fl, f2wh + wf2, f2wl + wf2, FF2_B + (long)l * DIM,
                       fft, nullptr, nullptr, TOKENS, DIM, FFD, FFD, FFD, DIM);

        add_ln2_k<<<TOKENS, 256>>>(x, fft, LN2S + (long)l * DIM, LN2B + (long)l * DIM,
                                   xh, xl, xh2);
    }

    // final vocab projection (fp16 2-pass)
    launch_h2<256>(xh2, finh2, finl2, FIN_B, OUT, nullptr, nullptr,
                   TOKENS, VOCAB, DIM, DIM, DIM, VOCAB);
}

// round 16
// speedup vs baseline: 2.3586x; 1.0675x over previous
#include <cuda_runtime.h>
#include <cuda_bf16.h>
#include <cuda_fp16.h>
#include <math.h>
#include <stdint.h>

#define SEQ    2048
#define TOKENS 4096
#define DIM    512
#define HEADS  8
#define HDIM   64
#define RANK   64
#define LAYERS 6
#define VOCAB  32000
#define FFD    2048
#define KTOP   409
#define NPACK  2304   // 1536 qkv | 64 qs | 64 ks | 512 vs | 128 pad
#define COL_QS 1536
#define COL_KS 1600
#define COL_VS 1664

typedef unsigned short u16;

// ---------------- fp32 scratch ----------------
__device__ float g_x[TOKENS * DIM];
__device__ float g_scores[(size_t)2 * SEQ * SEQ];
__device__ float g_aproj[TOKENS * DIM];
__device__ float g_sparse[TOKENS * DIM];
__device__ float g_fft[TOKENS * DIM];

// ---------------- activation planes ----------------
__device__ alignas(16) u16 g_pxh[(size_t)TOKENS * NPACK], g_pxl[(size_t)TOKENS * NPACK]; // bf16
__device__ alignas(16) u16 g_xh[TOKENS * DIM],       g_xl[TOKENS * DIM];   // bf16
__device__ alignas(16) u16 g_dh[TOKENS * DIM];                     // fp16 (dense attn out)
__device__ alignas(16) u16 g_fh[TOKENS * FFD],       g_fl[TOKENS * FFD];   // bf16
__device__ alignas(16) u16 g_vth[16 * HDIM * SEQ],   g_vtl[16 * HDIM * SEQ]; // fp16 (V^T)
__device__ alignas(16) u16 g_sph[(size_t)2 * SEQ * SEQ];           // fp16 sparse weights
__device__ alignas(16) u16 g_vsth[2 * DIM * SEQ],    g_vstl[2 * DIM * SEQ];  // fp16
__device__ alignas(16) u16 g_xh2[TOKENS * DIM];                    // fp16 (vocab A)

// ---------------- weight planes ----------------
__device__ alignas(16) u16 g_pwh[LAYERS * NPACK * DIM], g_pwl[LAYERS * NPACK * DIM];  // bf16
__device__ float g_pb[LAYERS * NPACK];
__device__ alignas(16) u16 g_outwh[LAYERS * DIM * DIM],  g_outwl[LAYERS * DIM * DIM]; // fp16
__device__ alignas(16) u16 g_f1wh[LAYERS * FFD * DIM],   g_f1wl[LAYERS * FFD * DIM];  // fp16
__device__ alignas(16) u16 g_f2wh[LAYERS * DIM * FFD],   g_f2wl[LAYERS * DIM * FFD];  // bf16
__device__ alignas(16) u16 g_finh2[VOCAB * DIM],         g_finl2[VOCAB * DIM];        // fp16

// ---------------- small device helpers ----------------
__device__ __forceinline__ void fsplit(float x, u16& h, u16& l)
{
    __nv_bfloat16 bh = __float2bfloat16_rn(x);
    float fh = __bfloat162float(bh);
    __nv_bfloat16 bl = __float2bfloat16_rn(x - fh);
    h = *reinterpret_cast<u16*>(&bh);
    l = *reinterpret_cast<u16*>(&bl);
}

__device__ __forceinline__ void hsplit(float x, u16& h, u16& l)
{
    __half hh = __float2half_rn(x);
    float fh = __half2float(hh);
    __half hl = __float2half_rn(x - fh);
    h = *reinterpret_cast<u16*>(&hh);
    l = *reinterpret_cast<u16*>(&hl);
}

__device__ __forceinline__ u16 h16(float x)
{
    __half hh = __float2half_rn(x);
    return *reinterpret_cast<u16*>(&hh);
}

__device__ __forceinline__ float bf2f(u16 v)
{
    __nv_bfloat16 b = *reinterpret_cast<__nv_bfloat16*>(&v);
    return __bfloat162float(b);
}

__device__ __forceinline__ uint32_t smem_u32(const void* p)
{
    uint32_t a;
    asm("{ .reg .u64 t; cvta.to.shared.u64 t, %1; cvt.u32.u64 %0, t; }" : "=r"(a) : "l"(p));
    return a;
}

__device__ __forceinline__ void cpa16(uint32_t dst, const void* src)
{
    asm volatile("cp.async.cg.shared.global [%0], [%1], 16;" :: "r"(dst), "l"(src) : "memory");
}

__device__ __forceinline__ void ldsm4(uint32_t* r, uint32_t addr)
{
    asm volatile("ldmatrix.sync.aligned.m8n8.x4.shared.b16 {%0,%1,%2,%3}, [%4];"
                 : "=r"(r[0]), "=r"(r[1]), "=r"(r[2]), "=r"(r[3]) : "r"(addr));
}

__device__ __forceinline__ void mma16816(float* c, const uint32_t* a, uint32_t b0, uint32_t b1)
{
    asm volatile(
        "mma.sync.aligned.m16n8k16.row.col.f32.bf16.bf16.f32 "
        "{%0,%1,%2,%3}, {%4,%5,%6,%7}, {%8,%9}, {%0,%1,%2,%3};"
        : "+f"(c[0]), "+f"(c[1]), "+f"(c[2]), "+f"(c[3])
        : "r"(a[0]), "r"(a[1]), "r"(a[2]), "r"(a[3]), "r"(b0), "r"(b1));
}

__device__ __forceinline__ void mma16816h(float* c, const uint32_t* a, uint32_t b0, uint32_t b1)
{
    asm volatile(
        "mma.sync.aligned.m16n8k16.row.col.f32.f16.f16.f32 "
        "{%0,%1,%2,%3}, {%4,%5,%6,%7}, {%8,%9}, {%0,%1,%2,%3};"
        : "+f"(c[0]), "+f"(c[1]), "+f"(c[2]), "+f"(c[3])
        : "r"(a[0]), "r"(a[1]), "r"(a[2]), "r"(a[3]), "r"(b0), "r"(b1));
}

// ---------------- HMMA bf16x3 GEMM (unchanged core) ----------------
template <int TN>
__global__ void __launch_bounds__((TN == 256) ? 512 : 256, (TN == 64) ? 2 : 1)
mm_gemm(const u16* __restrict__ Ah, const u16* __restrict__ Al,
        const u16* __restrict__ Bh, const u16* __restrict__ Bl,
        const float* __restrict__ bias, float* __restrict__ C,
        u16* __restrict__ Ch, u16* __restrict__ Cl,
        int K, int lda, int ldb, int ldc,
        long sAo, long sAi, long sBo, long sBi, long sCo, long sCi,
        int zdiv, float alpha, int relu)
{
    constexpr int NT  = (TN == 256) ? 512 : 256;
    constexpr int MI  = (TN == 128) ? 4 : 2;
    constexpr int NI  = (TN == 256) ? 4 : 2;
    constexpr int RB  = 144;
    constexpr int APB = 128 * RB;
    constexpr int BPB = TN * RB;
    constexpr int STAGE = 2 * APB + 2 * BPB;
    constexpr int ROWSP = NT / 8;

    extern __shared__ char smem[];
    const uint32_t su = smem_u32(smem);
    const int tid = threadIdx.x;
    const int wid = tid >> 5;
    const int lane = tid & 31;

    int z = blockIdx.z;
    int zo = z / zdiv, zi = z - zo * zdiv;
    long ao = (long)zo * sAo + (long)zi * sAi;
    long bo = (long)zo * sBo + (long)zi * sBi;
    long co = (long)zo * sCo + (long)zi * sCi;
    Ah += ao; Al += ao; Bh += bo; Bl += bo;
    if (C)  C  += co;
    if (Ch) { Ch += co; Cl += co; }
    const int m0 = blockIdx.y * 128;
    const int n0 = blockIdx.x * TN;

    const int wmBase = (TN == 256) ? (wid & 3) * 32
                     : (TN == 128) ? (wid & 1) * 64 : (wid & 3) * 32;
    const int wnBase = (TN == 256) ? (wid >> 2) * 64
                     : (TN == 128) ? (wid >> 1) * 32 : (wid >> 2) * 32;

    float acc[MI][2 * NI][4];
#pragma unroll
    for (int mi = 0; mi < MI; mi++)
#pragma unroll
        for (int n8 = 0; n8 < 2 * NI; n8++)
#pragma unroll
            for (int q = 0; q < 4; q++) acc[mi][n8][q] = 0.f;

    const int nsch = K >> 6;
    const int ar = tid >> 3, ac = tid & 7;
    auto issue = [&](int i) {
        int s = i & 1;
        int k0 = i << 6;
        uint32_t st = su + s * STAGE;
#pragma unroll
        for (int j = 0; j < 128 / ROWSP; j++) {
            int r = ar + ROWSP * j;
            long g = (long)(m0 + r) * lda + k0 + ac * 8;
            uint32_t d = st + r * RB + ac * 16;
            cpa16(d, Ah + g);
            cpa16(d + APB, Al + g);
        }
#pragma unroll
        for (int j = 0; j < TN / ROWSP; j++) {
            int r = ar + ROWSP * j;
            long g = (long)(n0 + r) * ldb + k0 + ac * 8;
            uint32_t d = st + 2 * APB + r * RB + ac * 16;
            cpa16(d, Bh + g);
            cpa16(d + BPB, Bl + g);
        }
        asm volatile("cp.async.commit_group;" ::: "memory");
    };

    issue(0);
    const uint32_t lrow = lane & 15;
    const uint32_t lcol = (lane >> 4) * 16;

    for (int i = 0; i < nsch; i++) {
        asm volatile("cp.async.wait_group 0;" ::: "memory");
        __syncthreads();
        if (i + 1 < nsch) issue(i + 1);

        int s = i & 1;
        uint32_t aH = su + s * STAGE;
        uint32_t aL = aH + APB;
        uint32_t bH = aH + 2 * APB;
        uint32_t bL = bH + BPB;

#pragma unroll
        for (int ks = 0; ks < 4; ks++) {
            uint32_t kb = ks * 32 + lcol;
            uint32_t a[MI][4], bh[NI][4];
#pragma unroll
            for (int mi = 0; mi < MI; mi++)
                ldsm4(a[mi], aH + (wmBase + mi * 16 + lrow) * RB + kb);
#pragma unroll
            for (int ni = 0; ni < NI; ni++)
                ldsm4(bh[ni], bH + (wnBase + ni * 16 + lrow) * RB + kb);
#pragma unroll
            for (int mi = 0; mi < MI; mi++)
#pragma unroll
                for (int ni = 0; ni < NI; ni++) {
                    mma16816(acc[mi][2 * ni],     a[mi], bh[ni][0], bh[ni][2]);
                    mma16816(acc[mi][2 * ni + 1], a[mi], bh[ni][1], bh[ni][3]);
                }
            {
                uint32_t al[MI][4];
#pragma unroll
                for (int mi = 0; mi < MI; mi++)
                    ldsm4(al[mi], aL + (wmBase + mi * 16 + lrow) * RB + kb);
#pragma unroll
                for (int mi = 0; mi < MI; mi++)
#pragma unroll
                    for (int ni = 0; ni < NI; ni++) {
                        mma16816(acc[mi][2 * ni],     al[mi], bh[ni][0], bh[ni][2]);
                        mma16816(acc[mi][2 * ni + 1], al[mi], bh[ni][1], bh[ni][3]);
                    }
            }
            {
                uint32_t bl[NI][4];
#pragma unroll
                for (int ni = 0; ni < NI; ni++)
                    ldsm4(bl[ni], bL + (wnBase + ni * 16 + lrow) * RB + kb);
#pragma unroll
                for (int mi = 0; mi < MI; mi++)
#pragma unroll
                    for (int ni = 0; ni < NI; ni++) {
                        mma16816(acc[mi][2 * ni],     a[mi], bl[ni][0], bl[ni][2]);
                        mma16816(acc[mi][2 * ni + 1], a[mi], bl[ni][1], bl[ni][3]);
                    }
            }
        }
    }

#pragma unroll
    for (int mi = 0; mi < MI; mi++) {
        int r0 = m0 + wmBase + mi * 16 + (lane >> 2);
#pragma unroll
        for (int n8 = 0; n8 < 2 * NI; n8++) {
            int c = n0 + wnBase + n8 * 8 + (lane & 3) * 2;
            float2 o0, o1;
            o0.x = acc[mi][n8][0] * alpha; o0.y = acc[mi][n8][1] * alpha;
            o1.x = acc[mi][n8][2] * alpha; o1.y = acc[mi][n8][3] * alpha;
            if (bias) {
                float b0 = bias[c], b1 = bias[c + 1];
                o0.x += b0; o0.y += b1; o1.x += b0; o1.y += b1;
            }
            if (relu) {
                o0.x = fmaxf(o0.x, 0.f); o0.y = fmaxf(o0.y, 0.f);
                o1.x = fmaxf(o1.x, 0.f); o1.y = fmaxf(o1.y, 0.f);
            }
            long off0 = (long)r0 * ldc + c;
            long off1 = off0 + (long)8 * ldc;
            if (C) {
                *(float2*)(C + off0) = o0;
                *(float2*)(C + off1) = o1;
            }
            if (Ch) {
                ushort2 hh, ll;
                fsplit(o0.x, hh.x, ll.x); fsplit(o0.y, hh.y, ll.y);
                *(ushort2*)(Ch + off0) = hh; *(ushort2*)(Cl + off0) = ll;
                fsplit(o1.x, hh.x, ll.x); fsplit(o1.y, hh.y, ll.y);
                *(ushort2*)(Ch + off1) = hh; *(ushort2*)(Cl + off1) = ll;
            }
        }
    }
}

// ---------------- fp16 2-pass GEMM: C = alpha*(Ah @ (Bh+Bl)^T) + bias ----------------
template <int TN>
__global__ void __launch_bounds__((TN == 256) ? 512 : 256)
mm_h2(const u16* __restrict__ Ah,
      const u16* __restrict__ Bh, const u16* __restrict__ Bl,
      const float* __restrict__ bias, float* __restrict__ C,
      u16* __restrict__ Ch, u16* __restrict__ Cl,
      int K, int lda, int ldb, int ldc,
      long sAo, long sAi, long sBo, long sBi, long sCo, long sCi,
      int zdiv, float alpha, int relu)
{
    constexpr int NT  = (TN == 256) ? 512 : 256;
    constexpr int MI  = (TN == 128) ? 4 : 2;
    constexpr int NI  = (TN == 256) ? 4 : 2;
    constexpr int RB  = 144;
    constexpr int APB = 128 * RB;
    constexpr int BPB = TN * RB;
    constexpr int STAGE = APB + 2 * BPB;
    constexpr int ROWSP = NT / 8;

    extern __shared__ char smem[];
    const uint32_t su = smem_u32(smem);
    const int tid = threadIdx.x;
    const int wid = tid >> 5;
    const int lane = tid & 31;

    int z = blockIdx.z;
    int zo = z / zdiv, zi = z - zo * zdiv;
    long ao = (long)zo * sAo + (long)zi * sAi;
    long bo = (long)zo * sBo + (long)zi * sBi;
    long co = (long)zo * sCo + (long)zi * sCi;
    Ah += ao; Bh += bo; Bl += bo;
    if (C)  C  += co;
    if (Ch) { Ch += co; Cl += co; }
    const int m0 = blockIdx.y * 128;
    const int n0 = blockIdx.x * TN;

    const int wmBase = (TN == 256) ? (wid & 3) * 32
                     : (wid & 1) * 64;
    const int wnBase = (TN == 256) ? (wid >> 2) * 64
                     : (wid >> 1) * 32;

    float acc[MI][2 * NI][4];
#pragma unroll
    for (int mi = 0; mi < MI; mi++)
#pragma unroll
        for (int n8 = 0; n8 < 2 * NI; n8++)
#pragma unroll
            for (int q = 0; q < 4; q++) acc[mi][n8][q] = 0.f;

    const int nsch = K >> 6;
    const int ar = tid >> 3, ac = tid & 7;
    auto issue = [&](int i) {
        int s = i & 1;
        int k0 = i << 6;
        uint32_t st = su + s * STAGE;
#pragma unroll
        for (int j = 0; j < 128 / ROWSP; j++) {
            int r = ar + ROWSP * j;
            cpa16(st + r * RB + ac * 16, Ah + (long)(m0 + r) * lda + k0 + ac * 8);
        }
#pragma unroll
        for (int j = 0; j < TN / ROWSP; j++) {
            int r = ar + ROWSP * j;
            long g = (long)(n0 + r) * ldb + k0 + ac * 8;
            uint32_t d = st + APB + r * RB + ac * 16;
            cpa16(d, Bh + g);
            cpa16(d + BPB, Bl + g);
        }
        asm volatile("cp.async.commit_group;" ::: "memory");
    };

    issue(0);
    const uint32_t lrow = lane & 15;
    const uint32_t lcol = (lane >> 4) * 16;

    for (int i = 0; i < nsch; i++) {
        asm volatile("cp.async.wait_group 0;" ::: "memory");
        __syncthreads();
        if (i + 1 < nsch) issue(i + 1);

        uint32_t st = su + (i & 1) * STAGE;
        uint32_t aH = st, bH = st + APB, bL = bH + BPB;

#pragma unroll
        for (int ks = 0; ks < 4; ks++) {
            uint32_t kb = ks * 32 + lcol;
            uint32_t a[MI][4], bh[NI][4];
#pragma unroll
            for (int mi = 0; mi < MI; mi++)
                ldsm4(a[mi], aH + (wmBase + mi * 16 + lrow) * RB + kb);
#pragma unroll
            for (int ni = 0; ni < NI; ni++)
                ldsm4(bh[ni], bH + (wnBase + ni * 16 + lrow) * RB + kb);
#pragma unroll
            for (int mi = 0; mi < MI; mi++)
#pragma unroll
                for (int ni = 0; ni < NI; ni++) {
                    mma16816h(acc[mi][2 * ni],     a[mi], bh[ni][0], bh[ni][2]);
                    mma16816h(acc[mi][2 * ni + 1], a[mi], bh[ni][1], bh[ni][3]);
                }
            {
                uint32_t bl[NI][4];
#pragma unroll
                for (int ni = 0; ni < NI; ni++)
                    ldsm4(bl[ni], bL + (wnBase + ni * 16 + lrow) * RB + kb);
#pragma unroll
                for (int mi = 0; mi < MI; mi++)
#pragma unroll
                    for (int ni = 0; ni < NI; ni++) {
                        mma16816h(acc[mi][2 * ni],     a[mi], bl[ni][0], bl[ni][2]);
                        mma16816h(acc[mi][2 * ni + 1], a[mi], bl[ni][1], bl[ni][3]);
                    }
            }
        }
    }

#pragma unroll
    for (int mi = 0; mi < MI; mi++) {
        int r0 = m0 + wmBase + mi * 16 + (lane >> 2);
#pragma unroll
        for (int n8 = 0; n8 < 2 * NI; n8++) {
            int c = n0 + wnBase + n8 * 8 + (lane & 3) * 2;
            float2 o0, o1;
            o0.x = acc[mi][n8][0] * alpha; o0.y = acc[mi][n8][1] * alpha;
            o1.x = acc[mi][n8][2] * alpha; o1.y = acc[mi][n8][3] * alpha;
            if (bias) {
                float b0 = bias[c], b1 = bias[c + 1];
                o0.x += b0; o0.y += b1; o1.x += b0; o1.y += b1;
            }
            if (relu) {
                o0.x = fmaxf(o0.x, 0.f); o0.y = fmaxf(o0.y, 0.f);
                o1.x = fmaxf(o1.x, 0.f); o1.y = fmaxf(o1.y, 0.f);
            }
            long off0 = (long)r0 * ldc + c;
            long off1 = off0 + (long)8 * ldc;
            if (C) {
                *(float2*)(C + off0) = o0;
                *(float2*)(C + off1) = o1;
            }
            if (Ch) {
                ushort2 hh, ll;
                fsplit(o0.x, hh.x, ll.x); fsplit(o0.y, hh.y, ll.y);
                *(ushort2*)(Ch + off0) = hh; *(ushort2*)(Cl + off0) = ll;
                fsplit(o1.x, hh.x, ll.x); fsplit(o1.y, hh.y, ll.y);
                *(ushort2*)(Ch + off1) = hh; *(ushort2*)(Cl + off1) = ll;
            }
        }
    }
}

// ---------------- fused flash attention (QK bf16x3, PV fp16x2) ----------------
__global__ void __launch_bounds__(512, 1)
fattn(const u16* __restrict__ pxh, const u16* __restrict__ pxl,
      const u16* __restrict__ vth, const u16* __restrict__ vtl,
      u16* __restrict__ dh)
{
    constexpr int QT = 256, KT = 64, RB = 144;
    constexpr int QB = QT * RB;
    constexpr int KB = KT * RB;
    constexpr int STG = 4 * KB;

    extern __shared__ char smem[];
    const uint32_t su = smem_u32(smem);
    const int tid = threadIdx.x, wid = tid >> 5, lane = tid & 31;
    const int z = blockIdx.y, b = z >> 3, h = z & 7;
    const int q0 = blockIdx.x * QT;

    const uint32_t sQh = su, sQl = su + QB;
    const uint32_t sKV = su + 2 * QB;

    const u16* qh = pxh + (long)(b * SEQ + q0) * NPACK + h * HDIM;
    const u16* ql = pxl + (long)(b * SEQ + q0) * NPACK + h * HDIM;
    const u16* kh = pxh + (long)(b * SEQ) * NPACK + DIM + h * HDIM;
    const u16* kl = pxl + (long)(b * SEQ) * NPACK + DIM + h * HDIM;
    const u16* vh = vth + (long)z * HDIM * SEQ;
    const u16* vl = vtl + (long)z * HDIM * SEQ;

    const int ar = tid >> 3, ac = tid & 7;
#pragma unroll
    for (int j = 0; j < 4; j++) {
        int r = ar + 64 * j;
        long g = (long)r * NPACK + ac * 8;
        uint32_t d = r * RB + ac * 16;
        cpa16(sQh + d, qh + g);
        cpa16(sQl + d, ql + g);
    }
    asm volatile("cp.async.commit_group;" ::: "memory");

    auto issue = [&](int i) {
        uint32_t st = sKV + (i & 1) * STG;
        int s0 = i * KT;
        long gk = (long)(s0 + ar) * NPACK + ac * 8;
        uint32_t d = ar * RB + ac * 16;
        cpa16(st + d, kh + gk);
        cpa16(st + KB + d, kl + gk);
        long gv = (long)ar * SEQ + s0 + ac * 8;
        cpa16(st + 2 * KB + d, vh + gv);
        cpa16(st + 3 * KB + d, vl + gv);
        asm volatile("cp.async.commit_group;" ::: "memory");
    };
    issue(0);

    const int qr = wid * 16;
    const uint32_t lrow = lane & 15;
    const uint32_t lcolb = (lane >> 4) * 16;

    float o[8][4];
#pragma unroll
    for (int j = 0; j < 8; j++)
#pragma unroll
        for (int q = 0; q < 4; q++) o[j][q] = 0.f;
    float m0 = -3.4e38f, m1 = -3.4e38f, l0 = 0.f, l1 = 0.f;

    for (int it = 0; it < SEQ / KT; it++) {
        asm volatile("cp.async.wait_group 0;" ::: "memory");
        __syncthreads();
        if (it + 1 < SEQ / KT) issue(it + 1);

        uint32_t st = sKV + (it & 1) * STG;
        uint32_t kH = st, kL = st + KB, vH = st + 2 * KB, vL = st + 3 * KB;

        // ---- S = Q K^T (bf16x3) ----
        float s[8][4];
#pragma unroll
        for (int j = 0; j < 8; j++)
#pragma unroll
            for (int q = 0; q < 4; q++) s[j][q] = 0.f;

#pragma unroll
        for (int c = 0; c < 4; c++) {
            uint32_t kb = c * 32 + lcolb;
            uint32_t aq[4], bk[4][4];
            ldsm4(aq, sQh + (qr + lrow) * RB + kb);
#pragma unroll
            for (int ni = 0; ni < 4; ni++)
                ldsm4(bk[ni], kH + (ni * 16 + lrow) * RB + kb);
#pragma unroll
            for (int ni = 0; ni < 4; ni++) {
                mma16816(s[2 * ni],     aq, bk[ni][0], bk[ni][2]);
                mma16816(s[2 * ni + 1], aq, bk[ni][1], bk[ni][3]);
            }
            {
                uint32_t al[4];
                ldsm4(al, sQl + (qr + lrow) * RB + kb);
#pragma unroll
                for (int ni = 0; ni < 4; ni++) {
                    mma16816(s[2 * ni],     al, bk[ni][0], bk[ni][2]);
                    mma16816(s[2 * ni + 1], al, bk[ni][1], bk[ni][3]);
                }
            }
            {
                uint32_t bl[4];
#pragma unroll
                for (int ni = 0; ni < 4; ni++) {
                    ldsm4(bl, kL + (ni * 16 + lrow) * RB + kb);
                    mma16816(s[2 * ni],     aq, bl[0], bl[2]);
                    mma16816(s[2 * ni + 1], aq, bl[1], bl[3]);
                }
            }
        }

        // ---- online softmax ----
        float tm0 = -3.4e38f, tm1 = -3.4e38f;
#pragma unroll
        for (int j = 0; j < 8; j++) {
            s[j][0] *= 0.125f; s[j][1] *= 0.125f;
            s[j][2] *= 0.125f; s[j][3] *= 0.125f;
            tm0 = fmaxf(tm0, fmaxf(s[j][0], s[j][1]));
            tm1 = fmaxf(tm1, fmaxf(s[j][2], s[j][3]));
        }
        tm0 = fmaxf(tm0, __shfl_xor_sync(0xffffffffu, tm0, 1));
        tm0 = fmaxf(tm0, __shfl_xor_sync(0xffffffffu, tm0, 2));
        tm1 = fmaxf(tm1, __shfl_xor_sync(0xffffffffu, tm1, 1));
        tm1 = fmaxf(tm1, __shfl_xor_sync(0xffffffffu, tm1, 2));
        float mn0 = fmaxf(m0, tm0), mn1 = fmaxf(m1, tm1);
        float a0 = __expf(m0 - mn0), a1 = __expf(m1 - mn1);
        m0 = mn0; m1 = mn1;

        float ts0 = 0.f, ts1 = 0.f;
        uint32_t ph[4][4];                 // fp16 P fragments (hi only)
#pragma unroll
        for (int j = 0; j < 8; j++) {
            float p00 = __expf(s[j][0] - mn0), p01 = __expf(s[j][1] - mn0);
            float p10 = __expf(s[j][2] - mn1), p11 = __expf(s[j][3] - mn1);
            ts0 += p00 + p01; ts1 += p10 + p11;
            int t = j >> 1, hi = (j & 1) * 2;
            ph[t][hi]     = ((uint32_t)h16(p01) << 16) | h16(p00);
            ph[t][hi + 1] = ((uint32_t)h16(p11) << 16) | h16(p10);
        }
        ts0 += __shfl_xor_sync(0xffffffffu, ts0, 1);
        ts0 += __shfl_xor_sync(0xffffffffu, ts0, 2);
        ts1 += __shfl_xor_sync(0xffffffffu, ts1, 1);
        ts1 += __shfl_xor_sync(0xffffffffu, ts1, 2);
        l0 = l0 * a0 + ts0;
        l1 = l1 * a1 + ts1;
#pragma unroll
        for (int j = 0; j < 8; j++) {
            o[j][0] *= a0; o[j][1] *= a0;
            o[j][2] *= a1; o[j][3] *= a1;
        }

        // ---- O += P V (fp16x2: Ph*Vh + Ph*Vl) ----
#pragma unroll
        for (int t = 0; t < 4; t++) {
            uint32_t kb = t * 32 + lcolb;
            uint32_t bv[4][4];
#pragma unroll
            for (int ni = 0; ni < 4; ni++)
                ldsm4(bv[ni], vH + (ni * 16 + lrow) * RB + kb);
#pragma unroll
            for (int ni = 0; ni < 4; ni++) {
                mma16816h(o[2 * ni],     ph[t], bv[ni][0], bv[ni][2]);
                mma16816h(o[2 * ni + 1], ph[t], bv[ni][1], bv[ni][3]);
            }
            {
                uint32_t bvl[4];
#pragma unroll
                for (int ni = 0; ni < 4; ni++) {
                    ldsm4(bvl, vL + (ni * 16 + lrow) * RB + kb);
                    mma16816h(o[2 * ni],     ph[t], bvl[0], bvl[2]);
                    mma16816h(o[2 * ni + 1], ph[t], bvl[1], bvl[3]);
                }
            }
        }
    }

    float i0 = 1.f / l0, i1 = 1.f / l1;
    int g = lane >> 2;
    long row0 = (long)(b * SEQ + q0 + qr + g) * DIM;
    long row1 = row0 + 8 * DIM;
#pragma unroll
    for (int j = 0; j < 8; j++) {
        int col = h * HDIM + 8 * j + (lane & 3) * 2;
        ushort2 hh;
        hh.x = h16(o[j][0] * i0);
        hh.y = h16(o[j][1] * i0);
        *(ushort2*)(dh + row0 + col) = hh;
        hh.x = h16(o[j][2] * i1);
        hh.y = h16(o[j][3] * i1);
        *(ushort2*)(dh + row1 + col) = hh;
    }
}

// ---------------- weight converters ----------------
__global__ void cvt_pack_k(const float* __restrict__ in_w, const float* __restrict__ qp_w,
                           const float* __restrict__ kp_w, const float* __restrict__ vp_w,
                           const float* __restrict__ in_b, const float* __restrict__ qp_b,
                           const float* __restrict__ kp_b, const float* __restrict__ vp_b,
                           ushort4* __restrict__ h, ushort4* __restrict__ l,
                           float* __restrict__ pb)
{
    int i = blockIdx.x * 256 + threadIdx.x;
    if (i < LAYERS * NPACK) {
        int lay = i / NPACK;
        int r = i - lay * NPACK;
        float v = 0.f;
        if (r < COL_QS) v = in_b[lay * 1536 + r];
        else if (r < COL_KS) v = qp_b[lay * RANK + (r - COL_QS)];
        else if (r < COL_VS) v = kp_b[lay * RANK + (r - COL_KS)];
        else if (r < COL_VS + DIM) v = vp_b[lay * DIM + (r - COL_VS)];
        pb[i] = v;
    }
    const int PER_L = NPACK * (DIM / 4);
    if (i >= LAYERS * PER_L) return;
    int lay = i / PER_L;
    int rem = i - lay * PER_L;
    int r = rem / (DIM / 4);
    int c4 = rem - r * (DIM / 4);
    float4 v = make_float4(0.f, 0.f, 0.f, 0.f);
    if (r < COL_QS)
        v = ((const float4*)(in_w + ((long)lay * 1536 + r) * DIM))[c4];
    else if (r < COL_KS)
        v = ((const float4*)(qp_w + ((long)lay * RANK + (r - COL_QS)) * DIM))[c4];
    else if (r < COL_VS)
        v = ((const float4*)(kp_w + ((long)lay * RANK + (r - COL_KS)) * DIM))[c4];
    else if (r < COL_VS + DIM)
        v = ((const float4*)(vp_w + ((long)lay * DIM + (r - COL_VS)) * DIM))[c4];
    ushort4 hh, ll;
    fsplit(v.x, hh.x, ll.x); fsplit(v.y, hh.y, ll.y);
    fsplit(v.z, hh.z, ll.z); fsplit(v.w, hh.w, ll.w);
    long o = (long)lay * NPACK * (DIM / 4) + (long)r * (DIM / 4) + c4;
    h[o] = hh; l[o] = ll;
}

// seg0 (OUT_W): fp16 | seg1 (FF1_W): fp16 | seg2 (FF2_W): bf16 | seg3 (FIN_W): fp16
__global__ void cvt4_k(const float4* __restrict__ s1, ushort4* __restrict__ h1, ushort4* __restrict__ l1, int n1,
                       const float4* __restrict__ s2, ushort4* __restrict__ h2, ushort4* __restrict__ l2, int n2,
                       const float4* __restrict__ s3, ushort4* __restrict__ h3, ushort4* __restrict__ l3, int n3,
                       const float4* __restrict__ s4, ushort4* __restrict__ h4, ushort4* __restrict__ l4, int n4)
{
    int i = blockIdx.x * 256 + threadIdx.x;
    const float4* s; ushort4 *h, *l; int j; int seg;
    if (i < n1) { s = s1; h = h1; l = l1; j = i; seg = 0; }
    else if (i < n1 + n2) { s = s2; h = h2; l = l2; j = i - n1; seg = 1; }
    else if (i < n1 + n2 + n3) { s = s3; h = h3; l = l3; j = i - n1 - n2; seg = 2; }
    else if (i < n1 + n2 + n3 + n4) { s = s4; h = h4; l = l4; j = i - n1 - n2 - n3; seg = 3; }
    else return;
    float4 v = s[j];
    ushort4 hh, ll;
    if (seg != 2) {
        hsplit(v.x, hh.x, ll.x); hsplit(v.y, hh.y, ll.y);
        hsplit(v.z, hh.z, ll.z); hsplit(v.w, hh.w, ll.w);
    } else {
        fsplit(v.x, hh.x, ll.x); fsplit(v.y, hh.y, ll.y);
        fsplit(v.z, hh.z, ll.z); fsplit(v.w, hh.w, ll.w);
    }
    h[j] = hh; l[j] = ll;
}

// V^T planes (dense, fp16) from bf16 px planes
__global__ void vt_k(const u16* __restrict__ pxh, const u16* __restrict__ pxl,
                     u16* __restrict__ vh, u16* __restrict__ vl)
{
    __shared__ float t[32][33];
    int z = blockIdx.z, b = z >> 3, h = z & 7;
    int s0 = blockIdx.x * 32, d0 = blockIdx.y * 32;
    int tx = threadIdx.x, ty = threadIdx.y;
#pragma unroll
    for (int j = 0; j < 4; j++) {
        int s = s0 + ty + j * 8;
        long g = ((long)(b * SEQ + s)) * NPACK + 2 * DIM + h * HDIM + d0 + tx;
        t[ty + j * 8][tx] = bf2f(pxh[g]) + bf2f(pxl[g]);
    }
    __syncthreads();
#pragma unroll
    for (int j = 0; j < 4; j++) {
        int d = d0 + ty + j * 8;
        long o = ((long)z * HDIM + d) * SEQ + s0 + tx;
        u16 hh, ll;
        hsplit(t[tx][ty + j * 8], hh, ll);
        vh[o] = hh; vl[o] = ll;
    }
}

// Vs^T planes (sparse, fp16) from bf16 px planes
__global__ void vst_k(const u16* __restrict__ pxh, const u16* __restrict__ pxl,
                      u16* __restrict__ vh, u16* __restrict__ vl)
{
    __shared__ float t[32][33];
    int b = blockIdx.z;
    int s0 = blockIdx.x * 32, d0 = blockIdx.y * 32;
    int tx = threadIdx.x, ty = threadIdx.y;
#pragma unroll
    for (int j = 0; j < 4; j++) {
        int s = s0 + ty + j * 8;
        long g = ((long)(b * SEQ + s)) * NPACK + COL_VS + d0 + tx;
        t[ty + j * 8][tx] = bf2f(pxh[g]) + bf2f(pxl[g]);
    }
    __syncthreads();
#pragma unroll
    for (int j = 0; j < 4; j++) {
        int d = d0 + ty + j * 8;
        long o = ((long)(b * DIM + d)) * SEQ + s0 + tx;
        u16 hh, ll;
        hsplit(t[tx][ty + j * 8], hh, ll);
        vh[o] = hh; vl[o] = ll;
    }
}

// ---------------- embedding ----------------
__global__ void embed_k(const int* __restrict__ src, const float* __restrict__ emb,
                        const float* __restrict__ pe, float* __restrict__ x,
                        u16* __restrict__ xh, u16* __restrict__ xl)
{
    int t = blockIdx.x;
    int tid = threadIdx.x;
    int s = t & (SEQ - 1);
    int tok = src[t];
    int d = tid * 2;
    float2 e = *(const float2*)(emb + (long)tok * DIM + d);
    float2 p = *(const float2*)(pe + (long)s * DIM + d);
    float2 o;
    o.x = e.x * 22.627416998f + p.x;
    o.y = e.y * 22.627416998f + p.y;
    long off = (long)t * DIM + d;
    *(float2*)(x + off) = o;
    ushort2 hh, ll;
    fsplit(o.x, hh.x, ll.x); fsplit(o.y, hh.y, ll.y);
    *(ushort2*)(xh + off) = hh;
    *(ushort2*)(xl + off) = ll;
}

// ---------------- sparse select (emits fp16 weight plane) ----------------
__device__ __forceinline__ unsigned f2k(float f)
{
    unsigned u = __float_as_uint(f);
    return (u & 0x80000000u) ? ~u : (u | 0x80000000u);
}

__global__ void __launch_bounds__(256) sparse_sel(
    const float* __restrict__ qk, u16* __restrict__ sph)
{
    __shared__ float logit[SEQ];
    __shared__ unsigned hist[256];
    __shared__ unsigned suf[256];
    __shared__ float red[256];
    __shared__ unsigned sh_prefix;
    __shared__ int sh_remaining;

    long row = blockIdx.x;
    int tid = threadIdx.x;
    const float* p = qk + row * (long)SEQ;

    for (int k = tid; k < SEQ; k += 256) logit[k] = p[k];
    __syncthreads();

    float lm = -3.4e38f;
    for (int k = tid; k < SEQ; k += 256) lm = fmaxf(lm, logit[k]);
    red[tid] = lm; __syncthreads();
    for (int s = 128; s > 0; s >>= 1) { if (tid < s) red[tid] = fmaxf(red[tid], red[tid + s]); __syncthreads(); }
    float Lmax = red[0]; __syncthreads();

    float zacc = 0.f;
    for (int k = tid; k < SEQ; k += 256) zacc += __expf(logit[k] - Lmax);
    red[tid] = zacc; __syncthreads();
    for (int s = 128; s > 0; s >>= 1) { if (tid < s) red[tid] += red[tid + s]; __syncthreads(); }
    float Z = red[0]; __syncthreads();

    unsigned prefix = 0; int remaining = KTOP;
    for (int shift = 24; shift >= 0; shift -= 8) {
        hist[tid] = 0; __syncthreads();
        unsigned upmask = (shift == 24) ? 0u : (0xFFFFFFFFu << (shift + 8));
        for (int k = tid; k < SEQ; k += 256) {
            unsigned key = f2k(logit[k]);
            if ((key & upmask) == prefix)
                atomicAdd(&hist[(key >> shift) & 255], 1u);
        }
        __syncthreads();
        suf[tid] = hist[tid]; __syncthreads();
        for (int off = 1; off < 256; off <<= 1) {
            unsigned add = (tid + off < 256) ? suf[tid + off] : 0u;
            __syncthreads();
            suf[tid] += add;
            __syncthreads();
        }
        unsigned shere = suf[tid];
        unsigned snext = (tid < 255) ? suf[tid + 1] : 0u;
        if (shere >= (unsigned)remaining && snext < (unsigned)remaining) {
            sh_prefix = prefix | ((unsigned)tid << shift);
            sh_remaining = remaining - (int)snext;
        }
        __syncthreads();
        prefix = sh_prefix; remaining = sh_remaining;
        __syncthreads();
    }
    unsigned thr = prefix;

    float w8[8];
    float dsum = 0.f;
#pragma unroll
    for (int j = 0; j < 8; j++) {
        int k = tid + 256 * j;
        float l = logit[k];
        bool keep = (f2k(l) >= thr);
        float w = keep ? __expf(l - Lmax) : 0.f;
        w8[j] = w;
        dsum += w;
    }
    red[tid] = dsum; __syncthreads();
    for (int s = 128; s > 0; s >>= 1) { if (tid < s) red[tid] += red[tid + s]; __syncthreads(); }
    float inv = 1.f / (red[0] + 1e-9f * Z);

#pragma unroll
    for (int j = 0; j < 8; j++) {
        int k = tid + 256 * j;
        sph[row * (long)SEQ + k] = h16(w8[j] * inv);
    }
}

// ---------------- gated fusion + LN1 (emits fp16 A plane for FFN1) ----------------
__global__ void fuse_ln1_k(float* __restrict__ x, const float* __restrict__ dn,
                           const float* __restrict__ sp, const float* __restrict__ lam,
                           int layer, const float* __restrict__ gam, const float* __restrict__ bet,
                           u16* __restrict__ xh)
{
    __shared__ float red[256];
    int row = blockIdx.x, tid = threadIdx.x;
    long off = (long)row * DIM + 2 * tid;
    float g = 1.f / (1.f + expf(-lam[layer]));
    float2 xv = *(const float2*)(x + off);
    float2 dv = *(const float2*)(dn + off);
    float2 sv = *(const float2*)(sp + off);
    float y0 = xv.x + g * dv.x + (1.f - g) * sv.x;
    float y1 = xv.y + g * dv.y + (1.f - g) * sv.y;
    red[tid] = y0 + y1; __syncthreads();
    for (int s = 128; s > 0; s >>= 1) { if (tid < s) red[tid] += red[tid + s]; __syncthreads(); }
    float mean = red[0] * (1.f / DIM); __syncthreads();
    float d0 = y0 - mean, d1 = y1 - mean;
    red[tid] = d0 * d0 + d1 * d1; __syncthreads();
    for (int s = 128; s > 0; s >>= 1) { if (tid < s) red[tid] += red[tid + s]; __syncthreads(); }
    float inv = 1.f / sqrtf(red[0] * (1.f / DIM) + 1e-5f);
    int dc = 2 * tid;
    float2 gm = *(const float2*)(gam + dc);
    float2 bt = *(const float2*)(bet + dc);
    float2 o; o.x = d0 * inv * gm.x + bt.x; o.y = d1 * inv * gm.y + bt.y;
    *(float2*)(x + off) = o;
    ushort2 hh;
    hh.x = h16(o.x); hh.y = h16(o.y);
    *(ushort2*)(xh + off) = hh;
}

// ---------------- residual + LN2 ----------------
__global__ void add_ln2_k(float* __restrict__ x, const float* __restrict__ f,
                          const float* __restrict__ gam, const float* __restrict__ bet,
                          u16* __restrict__ xh, u16* __restrict__ xl,
                          u16* __restrict__ xh2)
{
    __shared__ float red[256];
    int row = blockIdx.x, tid = threadIdx.x;
    long off = (long)row * DIM + 2 * tid;
    float2 xv = *(const float2*)(x + off);
    float2 fv = *(const float2*)(f + off);
    float y0 = xv.x + fv.x;
    float y1 = xv.y + fv.y;
    red[tid] = y0 + y1; __syncthreads();
    for (int s = 128; s > 0; s >>= 1) { if (tid < s) red[tid] += red[tid + s]; __syncthreads(); }
    float mean = red[0] * (1.f / DIM); __syncthreads();
    float d0 = y0 - mean, d1 = y1 - mean;
    red[tid] = d0 * d0 + d1 * d1; __syncthreads();
    for (int s = 128; s > 0; s >>= 1) { if (tid < s) red[tid] += red[tid + s]; __syncthreads(); }
    float inv = 1.f / sqrtf(red[0] * (1.f / DIM) + 1e-5f);
    int dc = 2 * tid;
    float2 gm = *(const float2*)(gam + dc);
    float2 bt = *(const float2*)(bet + dc);
    float2 o; o.x = d0 * inv * gm.x + bt.x; o.y = d1 * inv * gm.y + bt.y;
    *(float2*)(x + off) = o;
    ushort2 hh, ll;
    fsplit(o.x, hh.x, ll.x); fsplit(o.y, hh.y, ll.y);
    *(ushort2*)(xh + off) = hh;
    *(ushort2*)(xl + off) = ll;
    hh.x = h16(o.x); hh.y = h16(o.y);
    *(ushort2*)(xh2 + off) = hh;
}

// ---------------- host-side helpers ----------------
template <int TN>
static void launch_tc(const u16* Ah, const u16* Al, const u16* Bh, const u16* Bl,
                      const float* bias, float* C, u16* Ch, u16* Cl,
                      int M, int N, int K, int lda, int ldb, int ldc,
                      int Z = 1, long sAo = 0, long sAi = 0, long sBo = 0, long sBi = 0,
                      long sCo = 0, long sCi = 0, int zdiv = 1,
                      float alpha = 1.f, int relu = 0)
{
    constexpr int NT = (TN == 256) ? 512 : 256;
    constexpr int SM = 2 * (2 * 128 * 144 + 2 * TN * 144);
    static bool attr_set = false;
    if (!attr_set) {
        cudaFuncSetAttribute(mm_gemm<TN>, cudaFuncAttributeMaxDynamicSharedMemorySize, SM);
        attr_set = true;
    }
    dim3 g(N / TN, M / 128, Z);
    mm_gemm<TN><<<g, NT, SM>>>(Ah, Al, Bh, Bl, bias, C, Ch, Cl,
                               K, lda, ldb, ldc,
                               sAo, sAi, sBo, sBi, sCo, sCi, zdiv, alpha, relu);
}

template <int TN>
static void launch_h2(const u16* Ah, const u16* Bh, const u16* Bl,
                      const float* bias, float* C, u16* Ch, u16* Cl,
                      int M, int N, int K, int lda, int ldb, int ldc,
                      int Z = 1, long sAo = 0, long sAi = 0, long sBo = 0, long sBi = 0,
                      long sCo = 0, long sCi = 0, int zdiv = 1,
                      float alpha = 1.f, int relu = 0)
{
    constexpr int NT = (TN == 256) ? 512 : 256;
    constexpr int SM = 2 * (128 * 144 + 2 * TN * 144);
    static bool attr_set = false;
    if (!attr_set) {
        cudaFuncSetAttribute(mm_h2<TN>, cudaFuncAttributeMaxDynamicSharedMemorySize, SM);
        attr_set = true;
    }
    dim3 g(N / TN, M / 128, Z);
    mm_h2<TN><<<g, NT, SM>>>(Ah, Bh, Bl, bias, C, Ch, Cl,
                             K, lda, ldb, ldc,
                             sAo, sAi, sBo, sBi, sCo, sCi, zdiv, alpha, relu);
}

extern "C" void kernel_launch(void* const* d_in, const int* in_sizes, int n_in,
                              void* d_out, int out_size)
{
    const int*   SRC   = (const int*)  d_in[0];
    const float* EMB   = (const float*)d_in[1];
    const float* PE    = (const float*)d_in[2];
    const float* IN_W  = (const float*)d_in[3];
    const float* IN_B  = (const float*)d_in[4];
    const float* OUT_W = (const float*)d_in[5];
    const float* OUT_B = (const float*)d_in[6];
    const float* QP_W  = (const float*)d_in[7];
    const float* QP_B  = (const float*)d_in[8];
    const float* KP_W  = (const float*)d_in[9];
    const float* KP_B  = (const float*)d_in[10];
    const float* VP_W  = (const float*)d_in[11];
    const float* VP_B  = (const float*)d_in[12];
    const float* LAM   = (const float*)d_in[13];
    const float* FF1_W = (const float*)d_in[14];
    const float* FF1_B = (const float*)d_in[15];
    const float* FF2_W = (const float*)d_in[16];
    const float* FF2_B = (const float*)d_in[17];
    const float* LN1S  = (const float*)d_in[18];
    const float* LN1B  = (const float*)d_in[19];
    const float* LN2S  = (const float*)d_in[20];
    const float* LN2B  = (const float*)d_in[21];
    const float* FIN_W = (const float*)d_in[22];
    const float* FIN_B = (const float*)d_in[23];
    float* OUT = (float*)d_out;

    float *x, *scores, *aproj, *sp, *fft, *pb;
    cudaGetSymbolAddress((void**)&x, g_x);
    cudaGetSymbolAddress((void**)&scores, g_scores); cudaGetSymbolAddress((void**)&aproj, g_aproj);
    cudaGetSymbolAddress((void**)&sp, g_sparse);   cudaGetSymbolAddress((void**)&fft, g_fft);
    cudaGetSymbolAddress((void**)&pb, g_pb);

    u16 *pxh, *pxl, *xh, *xl, *dh, *fh, *fl, *vth, *vtl;
    u16 *sph, *vsth, *vstl, *xh2;
    cudaGetSymbolAddress((void**)&pxh, g_pxh); cudaGetSymbolAddress((void**)&pxl, g_pxl);
    cudaGetSymbolAddress((void**)&xh, g_xh);   cudaGetSymbolAddress((void**)&xl, g_xl);
    cudaGetSymbolAddress((void**)&dh, g_dh);
    cudaGetSymbolAddress((void**)&fh, g_fh);   cudaGetSymbolAddress((void**)&fl, g_fl);
    cudaGetSymbolAddress((void**)&vth, g_vth); cudaGetSymbolAddress((void**)&vtl, g_vtl);
    cudaGetSymbolAddress((void**)&sph, g_sph);
    cudaGetSymbolAddress((void**)&vsth, g_vsth); cudaGetSymbolAddress((void**)&vstl, g_vstl);
    cudaGetSymbolAddress((void**)&xh2, g_xh2);

    u16 *pwh, *pwl, *outwh, *outwl, *f1wh, *f1wl, *f2wh, *f2wl, *finh2, *finl2;
    cudaGetSymbolAddress((void**)&pwh, g_pwh);     cudaGetSymbolAddress((void**)&pwl, g_pwl);
    cudaGetSymbolAddress((void**)&outwh, g_outwh); cudaGetSymbolAddress((void**)&outwl, g_outwl);
    cudaGetSymbolAddress((void**)&f1wh, g_f1wh);   cudaGetSymbolAddress((void**)&f1wl, g_f1wl);
    cudaGetSymbolAddress((void**)&f2wh, g_f2wh);   cudaGetSymbolAddress((void**)&f2wl, g_f2wl);
    cudaGetSymbolAddress((void**)&finh2, g_finh2); cudaGetSymbolAddress((void**)&finl2, g_finl2);

    // launch 1: embedding
    embed_k<<<TOKENS, 256>>>(SRC, EMB, PE, x, xh, xl);

    // launch 2: packed weights + bias (bf16)
    {
        int tot = LAYERS * NPACK * (DIM / 4);
        cvt_pack_k<<<(tot + 255) / 256, 256>>>(IN_W, QP_W, KP_W, VP_W,
                                               IN_B, QP_B, KP_B, VP_B,
                                               (ushort4*)pwh, (ushort4*)pwl, pb);
    }
    // launch 3: remaining weights (fp16 except FF2_W)
    {
        int n1 = LAYERS * DIM * DIM / 4, n2 = LAYERS * FFD * DIM / 4;
        int n3 = LAYERS * DIM * FFD / 4, n4 = VOCAB * DIM / 4;
        cvt4_k<<<(n1 + n2 + n3 + n4 + 255) / 256, 256>>>(
            (const float4*)OUT_W, (ushort4*)outwh, (ushort4*)outwl, n1,
            (const float4*)FF1_W, (ushort4*)f1wh, (ushort4*)f1wl, n2,
            (const float4*)FF2_W, (ushort4*)f2wh, (ushort4*)f2wl, n3,
            (const float4*)FIN_W, (ushort4*)finh2, (ushort4*)finl2, n4);
    }

    {
        constexpr int FSM = 2 * 256 * 144 + 2 * 4 * 64 * 144;
        cudaFuncSetAttribute(fattn, cudaFuncAttributeMaxDynamicSharedMemorySize, FSM);
    }

    for (int l = 0; l < LAYERS; l++) {
        long wq  = (long)l * NPACK * DIM;
        long wo  = (long)l * DIM * DIM;
        long wf1 = (long)l * FFD * DIM;
        long wf2 = (long)l * DIM * FFD;

        // launch 4 (layer 0): packed projections (bf16x3) -> planes only  [PROFILED]
        launch_tc<256>(xh, xl, pwh + wq, pwl + wq, pb + (long)l * NPACK,
                       nullptr, pxh, pxl, TOKENS, NPACK, DIM, DIM, DIM, NPACK);

        // V^T planes for dense attention (fp16, from bf16 px planes)
        vt_k<<<dim3(SEQ / 32, HDIM / 32, 16), dim3(32, 8)>>>(pxh, pxl, vth, vtl);

        // fused flash attention -> dh (fp16)
        {
            constexpr int FSM = 2 * 256 * 144 + 2 * 4 * 64 * 144;
            fattn<<<dim3(SEQ / 256, 16), 512, FSM>>>(pxh, pxl, vth, vtl, dh);
        }

        // dense projection (fp16 2-pass) -> aproj fp32
        launch_h2<128>(dh, outwh + wo, outwl + wo, OUT_B + (long)l * DIM,
                       aproj, nullptr, nullptr, TOKENS, DIM, DIM, DIM, DIM, DIM);

        // low-rank logits qk = Qs @ Ks^T / sqrt(R) per batch (bf16x3)
        launch_tc<256>(pxh + COL_QS, pxl + COL_QS, pxh + COL_KS, pxl + COL_KS, nullptr,
                       scores, nullptr, nullptr,
                       SEQ, SEQ, RANK, NPACK, NPACK, SEQ,
                       2, (long)SEQ * NPACK, 0, (long)SEQ * NPACK, 0,
                       (long)SEQ * SEQ, 0, 1, 0.125f, 0);

        sparse_sel<<<TOKENS, 256>>>(scores, sph);

        vst_k<<<dim3(SEQ / 32, DIM / 32, 2), dim3(32, 8)>>>(pxh, pxl, vsth, vstl);

        // sparse = sp @ Vs per batch (fp16 2-pass)
        launch_h2<128>(sph, vsth, vstl, nullptr, sp, nullptr, nullptr,
                       SEQ, DIM, SEQ, SEQ, SEQ, DIM,
                       2, (long)SEQ * SEQ, 0, (long)DIM * SEQ, 0,
                       (long)SEQ * DIM, 0, 1, 1.f, 0);

        fuse_ln1_k<<<TOKENS, 256>>>(x, aproj, sp, LAM, l,
                                    LN1S + (long)l * DIM, LN1B + (long)l * DIM, xh);

        // FFN1 (fp16 2-pass) -> bf16 planes for FFN2
        launch_h2<256>(xh, f1wh + wf1, f1wl + wf1, FF1_B + (long)l * FFD,
                       nullptr, fh, fl, TOKENS, FFD, DIM, DIM, DIM, FFD,
                       1, 0, 0, 0, 0, 0, 0, 1, 1.f, 1);
        // FFN2 (bf16x3, writes residual)
        launch_tc<128>(fh, fl, f2wh + wf2, f2wl + wf2, FF2_B + (long)l * DIM,
                       fft, nullptr, nullptr, TOKENS, DIM, FFD, FFD, FFD, DIM);

        add_ln2_k<<<TOKENS, 256>>>(x, fft, LN2S + (long)l * DIM, LN2B + (long)l * DIM,
                                   xh, xl, xh2);
    }

    // final vocab projection (fp16 2-pass)
    launch_h2<256>(xh2, finh2, finl2, FIN_B, OUT, nullptr, nullptr,
                   TOKENS, VOCAB, DIM, DIM, DIM, VOCAB);
}

// round 17
// speedup vs baseline: 2.5478x; 1.0802x over previous
#include <cuda_runtime.h>
#include <cuda_bf16.h>
#include <cuda_fp16.h>
#include <math.h>
#include <stdint.h>

#define SEQ    2048
#define TOKENS 4096
#define DIM    512
#define HEADS  8
#define HDIM   64
#define RANK   64
#define LAYERS 6
#define VOCAB  32000
#define FFD    2048
#define KTOP   409
#define NPACK  2304   // 1536 qkv | 64 qs | 64 ks | 512 vs | 128 pad
#define COL_QS 1536
#define COL_KS 1600
#define COL_VS 1664

typedef unsigned short u16;

// ---------------- fp32 scratch ----------------
__device__ float g_x[TOKENS * DIM];
__device__ float g_scores[(size_t)2 * SEQ * SEQ];
__device__ float g_aproj[TOKENS * DIM];
__device__ float g_sparse[TOKENS * DIM];
__device__ float g_fft[TOKENS * DIM];

// ---------------- activation planes ----------------
__device__ alignas(16) u16 g_pxh[(size_t)TOKENS * NPACK], g_pxl[(size_t)TOKENS * NPACK]; // fp16
__device__ alignas(16) u16 g_xh[TOKENS * DIM];                     // fp16 (FFN1 A, from LN1)
__device__ alignas(16) u16 g_dh[TOKENS * DIM];                     // fp16 (dense attn out)
__device__ alignas(16) u16 g_fh[TOKENS * FFD],       g_fl[TOKENS * FFD];   // bf16 (FFN2 A)
__device__ alignas(16) u16 g_vth[16 * HDIM * SEQ],   g_vtl[16 * HDIM * SEQ]; // fp16 (V^T)
__device__ alignas(16) u16 g_sph[(size_t)2 * SEQ * SEQ];           // fp16 sparse weights
__device__ alignas(16) u16 g_vsth[2 * DIM * SEQ],    g_vstl[2 * DIM * SEQ];  // fp16
__device__ alignas(16) u16 g_xh2[TOKENS * DIM];                    // fp16 (residual x plane)

// ---------------- weight planes ----------------
__device__ alignas(16) u16 g_pwh[LAYERS * NPACK * DIM], g_pwl[LAYERS * NPACK * DIM];  // fp16
__device__ float g_pb[LAYERS * NPACK];
__device__ alignas(16) u16 g_outwh[LAYERS * DIM * DIM],  g_outwl[LAYERS * DIM * DIM]; // fp16
__device__ alignas(16) u16 g_f1wh[LAYERS * FFD * DIM],   g_f1wl[LAYERS * FFD * DIM];  // fp16
__device__ alignas(16) u16 g_f2wh[LAYERS * DIM * FFD],   g_f2wl[LAYERS * DIM * FFD];  // bf16
__device__ alignas(16) u16 g_finh2[VOCAB * DIM],         g_finl2[VOCAB * DIM];        // fp16

// ---------------- small device helpers ----------------
__device__ __forceinline__ void fsplit(float x, u16& h, u16& l)
{
    __nv_bfloat16 bh = __float2bfloat16_rn(x);
    float fh = __bfloat162float(bh);
    __nv_bfloat16 bl = __float2bfloat16_rn(x - fh);
    h = *reinterpret_cast<u16*>(&bh);
    l = *reinterpret_cast<u16*>(&bl);
}

__device__ __forceinline__ void hsplit(float x, u16& h, u16& l)
{
    __half hh = __float2half_rn(x);
    float fh = __half2float(hh);
    __half hl = __float2half_rn(x - fh);
    h = *reinterpret_cast<u16*>(&hh);
    l = *reinterpret_cast<u16*>(&hl);
}

__device__ __forceinline__ u16 h16(float x)
{
    __half hh = __float2half_rn(x);
    return *reinterpret_cast<u16*>(&hh);
}

__device__ __forceinline__ float h2f(u16 v)
{
    __half h = *reinterpret_cast<__half*>(&v);
    return __half2float(h);
}

__device__ __forceinline__ uint32_t smem_u32(const void* p)
{
    uint32_t a;
    asm("{ .reg .u64 t; cvta.to.shared.u64 t, %1; cvt.u32.u64 %0, t; }" : "=r"(a) : "l"(p));
    return a;
}

__device__ __forceinline__ void cpa16(uint32_t dst, const void* src)
{
    asm volatile("cp.async.cg.shared.global [%0], [%1], 16;" :: "r"(dst), "l"(src) : "memory");
}

__device__ __forceinline__ void ldsm4(uint32_t* r, uint32_t addr)
{
    asm volatile("ldmatrix.sync.aligned.m8n8.x4.shared.b16 {%0,%1,%2,%3}, [%4];"
                 : "=r"(r[0]), "=r"(r[1]), "=r"(r[2]), "=r"(r[3]) : "r"(addr));
}

__device__ __forceinline__ void mma16816(float* c, const uint32_t* a, uint32_t b0, uint32_t b1)
{
    asm volatile(
        "mma.sync.aligned.m16n8k16.row.col.f32.bf16.bf16.f32 "
        "{%0,%1,%2,%3}, {%4,%5,%6,%7}, {%8,%9}, {%0,%1,%2,%3};"
        : "+f"(c[0]), "+f"(c[1]), "+f"(c[2]), "+f"(c[3])
        : "r"(a[0]), "r"(a[1]), "r"(a[2]), "r"(a[3]), "r"(b0), "r"(b1));
}

__device__ __forceinline__ void mma16816h(float* c, const uint32_t* a, uint32_t b0, uint32_t b1)
{
    asm volatile(
        "mma.sync.aligned.m16n8k16.row.col.f32.f16.f16.f32 "
        "{%0,%1,%2,%3}, {%4,%5,%6,%7}, {%8,%9}, {%0,%1,%2,%3};"
        : "+f"(c[0]), "+f"(c[1]), "+f"(c[2]), "+f"(c[3])
        : "r"(a[0]), "r"(a[1]), "r"(a[2]), "r"(a[3]), "r"(b0), "r"(b1));
}

// ---------------- HMMA bf16x3 GEMM (kept for FFN2) ----------------
template <int TN>
__global__ void __launch_bounds__((TN == 256) ? 512 : 256)
mm_gemm(const u16* __restrict__ Ah, const u16* __restrict__ Al,
        const u16* __restrict__ Bh, const u16* __restrict__ Bl,
        const float* __restrict__ bias, float* __restrict__ C,
        u16* __restrict__ Ch, u16* __restrict__ Cl,
        int K, int lda, int ldb, int ldc,
        long sAo, long sAi, long sBo, long sBi, long sCo, long sCi,
        int zdiv, float alpha, int relu)
{
    constexpr int NT  = (TN == 256) ? 512 : 256;
    constexpr int MI  = (TN == 128) ? 4 : 2;
    constexpr int NI  = (TN == 256) ? 4 : 2;
    constexpr int RB  = 144;
    constexpr int APB = 128 * RB;
    constexpr int BPB = TN * RB;
    constexpr int STAGE = 2 * APB + 2 * BPB;
    constexpr int ROWSP = NT / 8;

    extern __shared__ char smem[];
    const uint32_t su = smem_u32(smem);
    const int tid = threadIdx.x;
    const int wid = tid >> 5;
    const int lane = tid & 31;

    int z = blockIdx.z;
    int zo = z / zdiv, zi = z - zo * zdiv;
    long ao = (long)zo * sAo + (long)zi * sAi;
    long bo = (long)zo * sBo + (long)zi * sBi;
    long co = (long)zo * sCo + (long)zi * sCi;
    Ah += ao; Al += ao; Bh += bo; Bl += bo;
    if (C)  C  += co;
    if (Ch) { Ch += co; Cl += co; }
    const int m0 = blockIdx.y * 128;
    const int n0 = blockIdx.x * TN;

    const int wmBase = (TN == 256) ? (wid & 3) * 32 : (wid & 1) * 64;
    const int wnBase = (TN == 256) ? (wid >> 2) * 64 : (wid >> 1) * 32;

    float acc[MI][2 * NI][4];
#pragma unroll
    for (int mi = 0; mi < MI; mi++)
#pragma unroll
        for (int n8 = 0; n8 < 2 * NI; n8++)
#pragma unroll
            for (int q = 0; q < 4; q++) acc[mi][n8][q] = 0.f;

    const int nsch = K >> 6;
    const int ar = tid >> 3, ac = tid & 7;
    auto issue = [&](int i) {
        int s = i & 1;
        int k0 = i << 6;
        uint32_t st = su + s * STAGE;
#pragma unroll
        for (int j = 0; j < 128 / ROWSP; j++) {
            int r = ar + ROWSP * j;
            long g = (long)(m0 + r) * lda + k0 + ac * 8;
            uint32_t d = st + r * RB + ac * 16;
            cpa16(d, Ah + g);
            cpa16(d + APB, Al + g);
        }
#pragma unroll
        for (int j = 0; j < TN / ROWSP; j++) {
            int r = ar + ROWSP * j;
            long g = (long)(n0 + r) * ldb + k0 + ac * 8;
            uint32_t d = st + 2 * APB + r * RB + ac * 16;
            cpa16(d, Bh + g);
            cpa16(d + BPB, Bl + g);
        }
        asm volatile("cp.async.commit_group;" ::: "memory");
    };

    issue(0);
    const uint32_t lrow = lane & 15;
    const uint32_t lcol = (lane >> 4) * 16;

    for (int i = 0; i < nsch; i++) {
        asm volatile("cp.async.wait_group 0;" ::: "memory");
        __syncthreads();
        if (i + 1 < nsch) issue(i + 1);

        int s = i & 1;
        uint32_t aH = su + s * STAGE;
        uint32_t aL = aH + APB;
        uint32_t bH = aH + 2 * APB;
        uint32_t bL = bH + BPB;

#pragma unroll
        for (int ks = 0; ks < 4; ks++) {
            uint32_t kb = ks * 32 + lcol;
            uint32_t a[MI][4], bh[NI][4];
#pragma unroll
            for (int mi = 0; mi < MI; mi++)
                ldsm4(a[mi], aH + (wmBase + mi * 16 + lrow) * RB + kb);
#pragma unroll
            for (int ni = 0; ni < NI; ni++)
                ldsm4(bh[ni], bH + (wnBase + ni * 16 + lrow) * RB + kb);
#pragma unroll
            for (int mi = 0; mi < MI; mi++)
#pragma unroll
                for (int ni = 0; ni < NI; ni++) {
                    mma16816(acc[mi][2 * ni],     a[mi], bh[ni][0], bh[ni][2]);
                    mma16816(acc[mi][2 * ni + 1], a[mi], bh[ni][1], bh[ni][3]);
                }
            {
                uint32_t al[MI][4];
#pragma unroll
                for (int mi = 0; mi < MI; mi++)
                    ldsm4(al[mi], aL + (wmBase + mi * 16 + lrow) * RB + kb);
#pragma unroll
                for (int mi = 0; mi < MI; mi++)
#pragma unroll
                    for (int ni = 0; ni < NI; ni++) {
                        mma16816(acc[mi][2 * ni],     al[mi], bh[ni][0], bh[ni][2]);
                        mma16816(acc[mi][2 * ni + 1], al[mi], bh[ni][1], bh[ni][3]);
                    }
            }
            {
                uint32_t bl[NI][4];
#pragma unroll
                for (int ni = 0; ni < NI; ni++)
                    ldsm4(bl[ni], bL + (wnBase + ni * 16 + lrow) * RB + kb);
#pragma unroll
                for (int mi = 0; mi < MI; mi++)
#pragma unroll
                    for (int ni = 0; ni < NI; ni++) {
                        mma16816(acc[mi][2 * ni],     a[mi], bl[ni][0], bl[ni][2]);
                        mma16816(acc[mi][2 * ni + 1], a[mi], bl[ni][1], bl[ni][3]);
                    }
            }
        }
    }

#pragma unroll
    for (int mi = 0; mi < MI; mi++) {
        int r0 = m0 + wmBase + mi * 16 + (lane >> 2);
#pragma unroll
        for (int n8 = 0; n8 < 2 * NI; n8++) {
            int c = n0 + wnBase + n8 * 8 + (lane & 3) * 2;
            float2 o0, o1;
            o0.x = acc[mi][n8][0] * alpha; o0.y = acc[mi][n8][1] * alpha;
            o1.x = acc[mi][n8][2] * alpha; o1.y = acc[mi][n8][3] * alpha;
            if (bias) {
                float b0 = bias[c], b1 = bias[c + 1];
                o0.x += b0; o0.y += b1; o1.x += b0; o1.y += b1;
            }
            if (relu) {
                o0.x = fmaxf(o0.x, 0.f); o0.y = fmaxf(o0.y, 0.f);
                o1.x = fmaxf(o1.x, 0.f); o1.y = fmaxf(o1.y, 0.f);
            }
            long off0 = (long)r0 * ldc + c;
            long off1 = off0 + (long)8 * ldc;
            if (C) {
                *(float2*)(C + off0) = o0;
                *(float2*)(C + off1) = o1;
            }
            if (Ch) {
                ushort2 hh, ll;
                fsplit(o0.x, hh.x, ll.x); fsplit(o0.y, hh.y, ll.y);
                *(ushort2*)(Ch + off0) = hh; *(ushort2*)(Cl + off0) = ll;
                fsplit(o1.x, hh.x, ll.x); fsplit(o1.y, hh.y, ll.y);
                *(ushort2*)(Ch + off1) = hh; *(ushort2*)(Cl + off1) = ll;
            }
        }
    }
}

// ---------------- fp16 2-pass GEMM: C = alpha*(Ah @ (Bh+Bl)^T) + bias ----------------
// HOUT: plane-output precision (true=fp16 hsplit, false=bf16 fsplit).
template <int TN, bool HOUT>
__global__ void __launch_bounds__((TN == 256) ? 512 : 256)
mm_h2(const u16* __restrict__ Ah,
      const u16* __restrict__ Bh, const u16* __restrict__ Bl,
      const float* __restrict__ bias, float* __restrict__ C,
      u16* __restrict__ Ch, u16* __restrict__ Cl,
      int K, int lda, int ldb, int ldc,
      long sAo, long sAi, long sBo, long sBi, long sCo, long sCi,
      int zdiv, float alpha, int relu)
{
    constexpr int NT  = (TN == 256) ? 512 : 256;
    constexpr int MI  = (TN == 128) ? 4 : 2;
    constexpr int NI  = (TN == 256) ? 4 : 2;
    constexpr int RB  = 144;
    constexpr int APB = 128 * RB;
    constexpr int BPB = TN * RB;
    constexpr int STAGE = APB + 2 * BPB;
    constexpr int ROWSP = NT / 8;

    extern __shared__ char smem[];
    const uint32_t su = smem_u32(smem);
    const int tid = threadIdx.x;
    const int wid = tid >> 5;
    const int lane = tid & 31;

    int z = blockIdx.z;
    int zo = z / zdiv, zi = z - zo * zdiv;
    long ao = (long)zo * sAo + (long)zi * sAi;
    long bo = (long)zo * sBo + (long)zi * sBi;
    long co = (long)zo * sCo + (long)zi * sCi;
    Ah += ao; Bh += bo; Bl += bo;
    if (C)  C  += co;
    if (Ch) { Ch += co; Cl += co; }
    const int m0 = blockIdx.y * 128;
    const int n0 = blockIdx.x * TN;

    const int wmBase = (TN == 256) ? (wid & 3) * 32 : (wid & 1) * 64;
    const int wnBase = (TN == 256) ? (wid >> 2) * 64 : (wid >> 1) * 32;

    float acc[MI][2 * NI][4];
#pragma unroll
    for (int mi = 0; mi < MI; mi++)
#pragma unroll
        for (int n8 = 0; n8 < 2 * NI; n8++)
#pragma unroll
            for (int q = 0; q < 4; q++) acc[mi][n8][q] = 0.f;

    const int nsch = K >> 6;
    const int ar = tid >> 3, ac = tid & 7;
    auto issue = [&](int i) {
        int s = i & 1;
        int k0 = i << 6;
        uint32_t st = su + s * STAGE;
#pragma unroll
        for (int j = 0; j < 128 / ROWSP; j++) {
            int r = ar + ROWSP * j;
            cpa16(st + r * RB + ac * 16, Ah + (long)(m0 + r) * lda + k0 + ac * 8);
        }
#pragma unroll
        for (int j = 0; j < TN / ROWSP; j++) {
            int r = ar + ROWSP * j;
            long g = (long)(n0 + r) * ldb + k0 + ac * 8;
            uint32_t d = st + APB + r * RB + ac * 16;
            cpa16(d, Bh + g);
            cpa16(d + BPB, Bl + g);
        }
        asm volatile("cp.async.commit_group;" ::: "memory");
    };

    issue(0);
    const uint32_t lrow = lane & 15;
    const uint32_t lcol = (lane >> 4) * 16;

    for (int i = 0; i < nsch; i++) {
        asm volatile("cp.async.wait_group 0;" ::: "memory");
        __syncthreads();
        if (i + 1 < nsch) issue(i + 1);

        uint32_t st = su + (i & 1) * STAGE;
        uint32_t aH = st, bH = st + APB, bL = bH + BPB;

#pragma unroll
        for (int ks = 0; ks < 4; ks++) {
            uint32_t kb = ks * 32 + lcol;
            uint32_t a[MI][4], bh[NI][4];
#pragma unroll
            for (int mi = 0; mi < MI; mi++)
                ldsm4(a[mi], aH + (wmBase + mi * 16 + lrow) * RB + kb);
#pragma unroll
            for (int ni = 0; ni < NI; ni++)
                ldsm4(bh[ni], bH + (wnBase + ni * 16 + lrow) * RB + kb);
#pragma unroll
            for (int mi = 0; mi < MI; mi++)
#pragma unroll
                for (int ni = 0; ni < NI; ni++) {
                    mma16816h(acc[mi][2 * ni],     a[mi], bh[ni][0], bh[ni][2]);
                    mma16816h(acc[mi][2 * ni + 1], a[mi], bh[ni][1], bh[ni][3]);
                }
            {
                uint32_t bl[NI][4];
#pragma unroll
                for (int ni = 0; ni < NI; ni++)
                    ldsm4(bl[ni], bL + (wnBase + ni * 16 + lrow) * RB + kb);
#pragma unroll
                for (int mi = 0; mi < MI; mi++)
#pragma unroll
                    for (int ni = 0; ni < NI; ni++) {
                        mma16816h(acc[mi][2 * ni],     a[mi], bl[ni][0], bl[ni][2]);
                        mma16816h(acc[mi][2 * ni + 1], a[mi], bl[ni][1], bl[ni][3]);
                    }
            }
        }
    }

#pragma unroll
    for (int mi = 0; mi < MI; mi++) {
        int r0 = m0 + wmBase + mi * 16 + (lane >> 2);
#pragma unroll
        for (int n8 = 0; n8 < 2 * NI; n8++) {
            int c = n0 + wnBase + n8 * 8 + (lane & 3) * 2;
            float2 o0, o1;
            o0.x = acc[mi][n8][0] * alpha; o0.y = acc[mi][n8][1] * alpha;
            o1.x = acc[mi][n8][2] * alpha; o1.y = acc[mi][n8][3] * alpha;
            if (bias) {
                float b0 = bias[c], b1 = bias[c + 1];
                o0.x += b0; o0.y += b1; o1.x += b0; o1.y += b1;
            }
            if (relu) {
                o0.x = fmaxf(o0.x, 0.f); o0.y = fmaxf(o0.y, 0.f);
                o1.x = fmaxf(o1.x, 0.f); o1.y = fmaxf(o1.y, 0.f);
            }
            long off0 = (long)r0 * ldc + c;
            long off1 = off0 + (long)8 * ldc;
            if (C) {
                *(float2*)(C + off0) = o0;
                *(float2*)(C + off1) = o1;
            }
            if (Ch) {
                ushort2 hh, ll;
                if (HOUT) {
                    hsplit(o0.x, hh.x, ll.x); hsplit(o0.y, hh.y, ll.y);
                } else {
                    fsplit(o0.x, hh.x, ll.x); fsplit(o0.y, hh.y, ll.y);
                }
                *(ushort2*)(Ch + off0) = hh; *(ushort2*)(Cl + off0) = ll;
                if (HOUT) {
                    hsplit(o1.x, hh.x, ll.x); hsplit(o1.y, hh.y, ll.y);
                } else {
                    fsplit(o1.x, hh.x, ll.x); fsplit(o1.y, hh.y, ll.y);
                }
                *(ushort2*)(Ch + off1) = hh; *(ushort2*)(Cl + off1) = ll;
            }
        }
    }
}

// ---------------- fused flash attention (fp16: QK 2-pass, PV 2-pass) ----------------
__global__ void __launch_bounds__(512, 1)
fattn(const u16* __restrict__ pxh, const u16* __restrict__ pxl,
      const u16* __restrict__ vth, const u16* __restrict__ vtl,
      u16* __restrict__ dh)
{
    constexpr int QT = 256, KT = 64, RB = 144;
    constexpr int QB = QT * RB;
    constexpr int KB = KT * RB;
    constexpr int STG = 4 * KB;

    extern __shared__ char smem[];
    const uint32_t su = smem_u32(smem);
    const int tid = threadIdx.x, wid = tid >> 5, lane = tid & 31;
    const int z = blockIdx.y, b = z >> 3, h = z & 7;
    const int q0 = blockIdx.x * QT;

    const uint32_t sQh = su;
    const uint32_t sKV = su + QB;

    const u16* qh = pxh + (long)(b * SEQ + q0) * NPACK + h * HDIM;
    const u16* kh = pxh + (long)(b * SEQ) * NPACK + DIM + h * HDIM;
    const u16* kl = pxl + (long)(b * SEQ) * NPACK + DIM + h * HDIM;
    const u16* vh = vth + (long)z * HDIM * SEQ;
    const u16* vl = vtl + (long)z * HDIM * SEQ;

    const int ar = tid >> 3, ac = tid & 7;
#pragma unroll
    for (int j = 0; j < 4; j++) {
        int r = ar + 64 * j;
        cpa16(sQh + r * RB + ac * 16, qh + (long)r * NPACK + ac * 8);
    }
    asm volatile("cp.async.commit_group;" ::: "memory");

    auto issue = [&](int i) {
        uint32_t st = sKV + (i & 1) * STG;
        int s0 = i * KT;
        long gk = (long)(s0 + ar) * NPACK + ac * 8;
        uint32_t d = ar * RB + ac * 16;
        cpa16(st + d, kh + gk);
        cpa16(st + KB + d, kl + gk);
        long gv = (long)ar * SEQ + s0 + ac * 8;
        cpa16(st + 2 * KB + d, vh + gv);
        cpa16(st + 3 * KB + d, vl + gv);
        asm volatile("cp.async.commit_group;" ::: "memory");
    };
    issue(0);

    const int qr = wid * 16;
    const uint32_t lrow = lane & 15;
    const uint32_t lcolb = (lane >> 4) * 16;

    float o[8][4];
#pragma unroll
    for (int j = 0; j < 8; j++)
#pragma unroll
        for (int q = 0; q < 4; q++) o[j][q] = 0.f;
    float m0 = -3.4e38f, m1 = -3.4e38f, l0 = 0.f, l1 = 0.f;

    for (int it = 0; it < SEQ / KT; it++) {
        asm volatile("cp.async.wait_group 0;" ::: "memory");
        __syncthreads();
        if (it + 1 < SEQ / KT) issue(it + 1);

        uint32_t st = sKV + (it & 1) * STG;
        uint32_t kH = st, kL = st + KB, vH = st + 2 * KB, vL = st + 3 * KB;

        // ---- S = Qh (Kh + Kl)^T (fp16 2-pass) ----
        float s[8][4];
#pragma unroll
        for (int j = 0; j < 8; j++)
#pragma unroll
            for (int q = 0; q < 4; q++) s[j][q] = 0.f;

#pragma unroll
        for (int c = 0; c < 4; c++) {
            uint32_t kb = c * 32 + lcolb;
            uint32_t aq[4], bk[4][4];
            ldsm4(aq, sQh + (qr + lrow) * RB + kb);
#pragma unroll
            for (int ni = 0; ni < 4; ni++)
                ldsm4(bk[ni], kH + (ni * 16 + lrow) * RB + kb);
#pragma unroll
            for (int ni = 0; ni < 4; ni++) {
                mma16816h(s[2 * ni],     aq, bk[ni][0], bk[ni][2]);
                mma16816h(s[2 * ni + 1], aq, bk[ni][1], bk[ni][3]);
            }
            {
                uint32_t bl[4];
#pragma unroll
                for (int ni = 0; ni < 4; ni++) {
                    ldsm4(bl, kL + (ni * 16 + lrow) * RB + kb);
                    mma16816h(s[2 * ni],     aq, bl[0], bl[2]);
                    mma16816h(s[2 * ni + 1], aq, bl[1], bl[3]);
                }
            }
        }

        // ---- online softmax ----
        float tm0 = -3.4e38f, tm1 = -3.4e38f;
#pragma unroll
        for (int j = 0; j < 8; j++) {
            s[j][0] *= 0.125f; s[j][1] *= 0.125f;
            s[j][2] *= 0.125f; s[j][3] *= 0.125f;
            tm0 = fmaxf(tm0, fmaxf(s[j][0], s[j][1]));
            tm1 = fmaxf(tm1, fmaxf(s[j][2], s[j][3]));
        }
        tm0 = fmaxf(tm0, __shfl_xor_sync(0xffffffffu, tm0, 1));
        tm0 = fmaxf(tm0, __shfl_xor_sync(0xffffffffu, tm0, 2));
        tm1 = fmaxf(tm1, __shfl_xor_sync(0xffffffffu, tm1, 1));
        tm1 = fmaxf(tm1, __shfl_xor_sync(0xffffffffu, tm1, 2));
        float mn0 = fmaxf(m0, tm0), mn1 = fmaxf(m1, tm1);
        float a0 = __expf(m0 - mn0), a1 = __expf(m1 - mn1);
        m0 = mn0; m1 = mn1;

        float ts0 = 0.f, ts1 = 0.f;
        uint32_t ph[4][4];
#pragma unroll
        for (int j = 0; j < 8; j++) {
            float p00 = __expf(s[j][0] - mn0), p01 = __expf(s[j][1] - mn0);
            float p10 = __expf(s[j][2] - mn1), p11 = __expf(s[j][3] - mn1);
            ts0 += p00 + p01; ts1 += p10 + p11;
            int t = j >> 1, hi = (j & 1) * 2;
            ph[t][hi]     = ((uint32_t)h16(p01) << 16) | h16(p00);
            ph[t][hi + 1] = ((uint32_t)h16(p11) << 16) | h16(p10);
        }
        ts0 += __shfl_xor_sync(0xffffffffu, ts0, 1);
        ts0 += __shfl_xor_sync(0xffffffffu, ts0, 2);
        ts1 += __shfl_xor_sync(0xffffffffu, ts1, 1);
        ts1 += __shfl_xor_sync(0xffffffffu, ts1, 2);
        l0 = l0 * a0 + ts0;
        l1 = l1 * a1 + ts1;
#pragma unroll
        for (int j = 0; j < 8; j++) {
            o[j][0] *= a0; o[j][1] *= a0;
            o[j][2] *= a1; o[j][3] *= a1;
        }

        // ---- O += P V (fp16 2-pass: Ph*Vh + Ph*Vl) ----
#pragma unroll
        for (int t = 0; t < 4; t++) {
            uint32_t kb = t * 32 + lcolb;
            uint32_t bv[4][4];
#pragma unroll
            for (int ni = 0; ni < 4; ni++)
                ldsm4(bv[ni], vH + (ni * 16 + lrow) * RB + kb);
#pragma unroll
            for (int ni = 0; ni < 4; ni++) {
                mma16816h(o[2 * ni],     ph[t], bv[ni][0], bv[ni][2]);
                mma16816h(o[2 * ni + 1], ph[t], bv[ni][1], bv[ni][3]);
            }
            {
                uint32_t bvl[4];
#pragma unroll
                for (int ni = 0; ni < 4; ni++) {
                    ldsm4(bvl, vL + (ni * 16 + lrow) * RB + kb);
                    mma16816h(o[2 * ni],     ph[t], bvl[0], bvl[2]);
                    mma16816h(o[2 * ni + 1], ph[t], bvl[1], bvl[3]);
                }
            }
        }
    }

    float i0 = 1.f / l0, i1 = 1.f / l1;
    int g = lane >> 2;
    long row0 = (long)(b * SEQ + q0 + qr + g) * DIM;
    long row1 = row0 + 8 * DIM;
#pragma unroll
    for (int j = 0; j < 8; j++) {
        int col = h * HDIM + 8 * j + (lane & 3) * 2;
        ushort2 hh;
        hh.x = h16(o[j][0] * i0);
        hh.y = h16(o[j][1] * i0);
        *(ushort2*)(dh + row0 + col) = hh;
        hh.x = h16(o[j][2] * i1);
        hh.y = h16(o[j][3] * i1);
        *(ushort2*)(dh + row1 + col) = hh;
    }
}

// ---------------- weight converters ----------------
// packed projection weights now fp16
__global__ void cvt_pack_k(const float* __restrict__ in_w, const float* __restrict__ qp_w,
                           const float* __restrict__ kp_w, const float* __restrict__ vp_w,
                           const float* __restrict__ in_b, const float* __restrict__ qp_b,
                           const float* __restrict__ kp_b, const float* __restrict__ vp_b,
                           ushort4* __restrict__ h, ushort4* __restrict__ l,
                           float* __restrict__ pb)
{
    int i = blockIdx.x * 256 + threadIdx.x;
    if (i < LAYERS * NPACK) {
        int lay = i / NPACK;
        int r = i - lay * NPACK;
        float v = 0.f;
        if (r < COL_QS) v = in_b[lay * 1536 + r];
        else if (r < COL_KS) v = qp_b[lay * RANK + (r - COL_QS)];
        else if (r < COL_VS) v = kp_b[lay * RANK + (r - COL_KS)];
        else if (r < COL_VS + DIM) v = vp_b[lay * DIM + (r - COL_VS)];
        pb[i] = v;
    }
    const int PER_L = NPACK * (DIM / 4);
    if (i >= LAYERS * PER_L) return;
    int lay = i / PER_L;
    int rem = i - lay * PER_L;
    int r = rem / (DIM / 4);
    int c4 = rem - r * (DIM / 4);
    float4 v = make_float4(0.f, 0.f, 0.f, 0.f);
    if (r < COL_QS)
        v = ((const float4*)(in_w + ((long)lay * 1536 + r) * DIM))[c4];
    else if (r < COL_KS)
        v = ((const float4*)(qp_w + ((long)lay * RANK + (r - COL_QS)) * DIM))[c4];
    else if (r < COL_VS)
        v = ((const float4*)(kp_w + ((long)lay * RANK + (r - COL_KS)) * DIM))[c4];
    else if (r < COL_VS + DIM)
        v = ((const float4*)(vp_w + ((long)lay * DIM + (r - COL_VS)) * DIM))[c4];
    ushort4 hh, ll;
    hsplit(v.x, hh.x, ll.x); hsplit(v.y, hh.y, ll.y);
    hsplit(v.z, hh.z, ll.z); hsplit(v.w, hh.w, ll.w);
    long o = (long)lay * NPACK * (DIM / 4) + (long)r * (DIM / 4) + c4;
    h[o] = hh; l[o] = ll;
}

// seg0 (OUT_W): fp16 | seg1 (FF1_W): fp16 | seg2 (FF2_W): bf16 | seg3 (FIN_W): fp16
__global__ void cvt4_k(const float4* __restrict__ s1, ushort4* __restrict__ h1, ushort4* __restrict__ l1, int n1,
                       const float4* __restrict__ s2, ushort4* __restrict__ h2, ushort4* __restrict__ l2, int n2,
                       const float4* __restrict__ s3, ushort4* __restrict__ h3, ushort4* __restrict__ l3, int n3,
                       const float4* __restrict__ s4, ushort4* __restrict__ h4, ushort4* __restrict__ l4, int n4)
{
    int i = blockIdx.x * 256 + threadIdx.x;
    const float4* s; ushort4 *h, *l; int j; int seg;
    if (i < n1) { s = s1; h = h1; l = l1; j = i; seg = 0; }
    else if (i < n1 + n2) { s = s2; h = h2; l = l2; j = i - n1; seg = 1; }
    else if (i < n1 + n2 + n3) { s = s3; h = h3; l = l3; j = i - n1 - n2; seg = 2; }
    else if (i < n1 + n2 + n3 + n4) { s = s4; h = h4; l = l4; j = i - n1 - n2 - n3; seg = 3; }
    else return;
    float4 v = s[j];
    ushort4 hh, ll;
    if (seg != 2) {
        hsplit(v.x, hh.x, ll.x); hsplit(v.y, hh.y, ll.y);
        hsplit(v.z, hh.z, ll.z); hsplit(v.w, hh.w, ll.w);
    } else {
        fsplit(v.x, hh.x, ll.x); fsplit(v.y, hh.y, ll.y);
        fsplit(v.z, hh.z, ll.z); fsplit(v.w, hh.w, ll.w);
    }
    h[j] = hh; l[j] = ll;
}

// V^T planes (dense, fp16) from fp16 px planes
__global__ void vt_k(const u16* __restrict__ pxh, const u16* __restrict__ pxl,
                     u16* __restrict__ vh, u16* __restrict__ vl)
{
    __shared__ float t[32][33];
    int z = blockIdx.z, b = z >> 3, h = z & 7;
    int s0 = blockIdx.x * 32, d0 = blockIdx.y * 32;
    int tx = threadIdx.x, ty = threadIdx.y;
#pragma unroll
    for (int j = 0; j < 4; j++) {
        int s = s0 + ty + j * 8;
        long g = ((long)(b * SEQ + s)) * NPACK + 2 * DIM + h * HDIM + d0 + tx;
        t[ty + j * 8][tx] = h2f(pxh[g]) + h2f(pxl[g]);
    }
    __syncthreads();
#pragma unroll
    for (int j = 0; j < 4; j++) {
        int d = d0 + ty + j * 8;
        long o = ((long)z * HDIM + d) * SEQ + s0 + tx;
        u16 hh, ll;
        hsplit(t[tx][ty + j * 8], hh, ll);
        vh[o] = hh; vl[o] = ll;
    }
}

// Vs^T planes (sparse, fp16) from fp16 px planes
__global__ void vst_k(const u16* __restrict__ pxh, const u16* __restrict__ pxl,
                      u16* __restrict__ vh, u16* __restrict__ vl)
{
    __shared__ float t[32][33];
    int b = blockIdx.z;
    int s0 = blockIdx.x * 32, d0 = blockIdx.y * 32;
    int tx = threadIdx.x, ty = threadIdx.y;
#pragma unroll
    for (int j = 0; j < 4; j++) {
        int s = s0 + ty + j * 8;
        long g = ((long)(b * SEQ + s)) * NPACK + COL_VS + d0 + tx;
        t[ty + j * 8][tx] = h2f(pxh[g]) + h2f(pxl[g]);
    }
    __syncthreads();
#pragma unroll
    for (int j = 0; j < 4; j++) {
        int d = d0 + ty + j * 8;
        long o = ((long)(b * DIM + d)) * SEQ + s0 + tx;
        u16 hh, ll;
        hsplit(t[tx][ty + j * 8], hh, ll);
        vh[o] = hh; vl[o] = ll;
    }
}

// ---------------- embedding (fp32 + fp16 plane) ----------------
__global__ void embed_k(const int* __restrict__ src, const float* __restrict__ emb,
                        const float* __restrict__ pe, float* __restrict__ x,
                        u16* __restrict__ xh2)
{
    int t = blockIdx.x;
    int tid = threadIdx.x;
    int s = t & (SEQ - 1);
    int tok = src[t];
    int d = tid * 2;
    float2 e = *(const float2*)(emb + (long)tok * DIM + d);
    float2 p = *(const float2*)(pe + (long)s * DIM + d);
    float2 o;
    o.x = e.x * 22.627416998f + p.x;
    o.y = e.y * 22.627416998f + p.y;
    long off = (long)t * DIM + d;
    *(float2*)(x + off) = o;
    ushort2 hh;
    hh.x = h16(o.x); hh.y = h16(o.y);
    *(ushort2*)(xh2 + off) = hh;
}

// ---------------- sparse select (emits fp16 weight plane) ----------------
__device__ __forceinline__ unsigned f2k(float f)
{
    unsigned u = __float_as_uint(f);
    return (u & 0x80000000u) ? ~u : (u | 0x80000000u);
}

__global__ void __launch_bounds__(256) sparse_sel(
    const float* __restrict__ qk, u16* __restrict__ sph)
{
    __shared__ float logit[SEQ];
    __shared__ unsigned hist[256];
    __shared__ unsigned suf[256];
    __shared__ float red[256];
    __shared__ unsigned sh_prefix;
    __shared__ int sh_remaining;

    long row = blockIdx.x;
    int tid = threadIdx.x;
    const float* p = qk + row * (long)SEQ;

    for (int k = tid; k < SEQ; k += 256) logit[k] = p[k];
    __syncthreads();

    float lm = -3.4e38f;
    for (int k = tid; k < SEQ; k += 256) lm = fmaxf(lm, logit[k]);
    red[tid] = lm; __syncthreads();
    for (int s = 128; s > 0; s >>= 1) { if (tid < s) red[tid] = fmaxf(red[tid], red[tid + s]); __syncthreads(); }
    float Lmax = red[0]; __syncthreads();

    float zacc = 0.f;
    for (int k = tid; k < SEQ; k += 256) zacc += __expf(logit[k] - Lmax);
    red[tid] = zacc; __syncthreads();
    for (int s = 128; s > 0; s >>= 1) { if (tid < s) red[tid] += red[tid + s]; __syncthreads(); }
    float Z = red[0]; __syncthreads();

    unsigned prefix = 0; int remaining = KTOP;
    for (int shift = 24; shift >= 0; shift -= 8) {
        hist[tid] = 0; __syncthreads();
        unsigned upmask = (shift == 24) ? 0u : (0xFFFFFFFFu << (shift + 8));
        for (int k = tid; k < SEQ; k += 256) {
            unsigned key = f2k(logit[k]);
            if ((key & upmask) == prefix)
                atomicAdd(&hist[(key >> shift) & 255], 1u);
        }
        __syncthreads();
        suf[tid] = hist[tid]; __syncthreads();
        for (int off = 1; off < 256; off <<= 1) {
            unsigned add = (tid + off < 256) ? suf[tid + off] : 0u;
            __syncthreads();
            suf[tid] += add;
            __syncthreads();
        }
        unsigned shere = suf[tid];
        unsigned snext = (tid < 255) ? suf[tid + 1] : 0u;
        if (shere >= (unsigned)remaining && snext < (unsigned)remaining) {
            sh_prefix = prefix | ((unsigned)tid << shift);
            sh_remaining = remaining - (int)snext;
        }
        __syncthreads();
        prefix = sh_prefix; remaining = sh_remaining;
        __syncthreads();
    }
    unsigned thr = prefix;

    float w8[8];
    float dsum = 0.f;
#pragma unroll
    for (int j = 0; j < 8; j++) {
        int k = tid + 256 * j;
        float l = logit[k];
        bool keep = (f2k(l) >= thr);
        float w = keep ? __expf(l - Lmax) : 0.f;
        w8[j] = w;
        dsum += w;
    }
    red[tid] = dsum; __syncthreads();
    for (int s = 128; s > 0; s >>= 1) { if (tid < s) red[tid] += red[tid + s]; __syncthreads(); }
    float inv = 1.f / (red[0] + 1e-9f * Z);

#pragma unroll
    for (int j = 0; j < 8; j++) {
        int k = tid + 256 * j;
        sph[row * (long)SEQ + k] = h16(w8[j] * inv);
    }
}

// ---------------- gated fusion + LN1 (emits fp16 A plane for FFN1) ----------------
__global__ void fuse_ln1_k(float* __restrict__ x, const float* __restrict__ dn,
                           const float* __restrict__ sp, const float* __restrict__ lam,
                           int layer, const float* __restrict__ gam, const float* __restrict__ bet,
                           u16* __restrict__ xh)
{
    __shared__ float red[256];
    int row = blockIdx.x, tid = threadIdx.x;
    long off = (long)row * DIM + 2 * tid;
    float g = 1.f / (1.f + expf(-lam[layer]));
    float2 xv = *(const float2*)(x + off);
    float2 dv = *(const float2*)(dn + off);
    float2 sv = *(const float2*)(sp + off);
    float y0 = xv.x + g * dv.x + (1.f - g) * sv.x;
    float y1 = xv.y + g * dv.y + (1.f - g) * sv.y;
    red[tid] = y0 + y1; __syncthreads();
    for (int s = 128; s > 0; s >>= 1) { if (tid < s) red[tid] += red[tid + s]; __syncthreads(); }
    float mean = red[0] * (1.f / DIM); __syncthreads();
    float d0 = y0 - mean, d1 = y1 - mean;
    red[tid] = d0 * d0 + d1 * d1; __syncthreads();
    for (int s = 128; s > 0; s >>= 1) { if (tid < s) red[tid] += red[tid + s]; __syncthreads(); }
    float inv = 1.f / sqrtf(red[0] * (1.f / DIM) + 1e-5f);
    int dc = 2 * tid;
    float2 gm = *(const float2*)(gam + dc);
    float2 bt = *(const float2*)(bet + dc);
    float2 o; o.x = d0 * inv * gm.x + bt.x; o.y = d1 * inv * gm.y + bt.y;
    *(float2*)(x + off) = o;
    ushort2 hh;
    hh.x = h16(o.x); hh.y = h16(o.y);
    *(ushort2*)(xh + off) = hh;
}

// ---------------- residual + LN2 (emits fp16 x plane) ----------------
__global__ void add_ln2_k(float* __restrict__ x, const float* __restrict__ f,
                          const float* __restrict__ gam, const float* __restrict__ bet,
                          u16* __restrict__ xh2)
{
    __shared__ float red[256];
    int row = blockIdx.x, tid = threadIdx.x;
    long off = (long)row * DIM + 2 * tid;
    float2 xv = *(const float2*)(x + off);
    float2 fv = *(const float2*)(f + off);
    float y0 = xv.x + fv.x;
    float y1 = xv.y + fv.y;
    red[tid] = y0 + y1; __syncthreads();
    for (int s = 128; s > 0; s >>= 1) { if (tid < s) red[tid] += red[tid + s]; __syncthreads(); }
    float mean = red[0] * (1.f / DIM); __syncthreads();
    float d0 = y0 - mean, d1 = y1 - mean;
    red[tid] = d0 * d0 + d1 * d1; __syncthreads();
    for (int s = 128; s > 0; s >>= 1) { if (tid < s) red[tid] += red[tid + s]; __syncthreads(); }
    float inv = 1.f / sqrtf(red[0] * (1.f / DIM) + 1e-5f);
    int dc = 2 * tid;
    float2 gm = *(const float2*)(gam + dc);
    float2 bt = *(const float2*)(bet + dc);
    float2 o; o.x = d0 * inv * gm.x + bt.x; o.y = d1 * inv * gm.y + bt.y;
    *(float2*)(x + off) = o;
    ushort2 hh;
    hh.x = h16(o.x); hh.y = h16(o.y);
    *(ushort2*)(xh2 + off) = hh;
}

// ---------------- host-side helpers ----------------
template <int TN>
static void launch_tc(const u16* Ah, const u16* Al, const u16* Bh, const u16* Bl,
                      const float* bias, float* C, u16* Ch, u16* Cl,
                      int M, int N, int K, int lda, int ldb, int ldc,
                      int Z = 1, long sAo = 0, long sAi = 0, long sBo = 0, long sBi = 0,
                      long sCo = 0, long sCi = 0, int zdiv = 1,
                      float alpha = 1.f, int relu = 0)
{
    constexpr int NT = (TN == 256) ? 512 : 256;
    constexpr int SM = 2 * (2 * 128 * 144 + 2 * TN * 144);
    static bool attr_set = false;
    if (!attr_set) {
        cudaFuncSetAttribute(mm_gemm<TN>, cudaFuncAttributeMaxDynamicSharedMemorySize, SM);
        attr_set = true;
    }
    dim3 g(N / TN, M / 128, Z);
    mm_gemm<TN><<<g, NT, SM>>>(Ah, Al, Bh, Bl, bias, C, Ch, Cl,
                               K, lda, ldb, ldc,
                               sAo, sAi, sBo, sBi, sCo, sCi, zdiv, alpha, relu);
}

template <int TN, bool HOUT = false>
static void launch_h2(const u16* Ah, const u16* Bh, const u16* Bl,
                      const float* bias, float* C, u16* Ch, u16* Cl,
                      int M, int N, int K, int lda, int ldb, int ldc,
                      int Z = 1, long sAo = 0, long sAi = 0, long sBo = 0, long sBi = 0,
                      long sCo = 0, long sCi = 0, int zdiv = 1,
                      float alpha = 1.f, int relu = 0)
{
    constexpr int NT = (TN == 256) ? 512 : 256;
    constexpr int SM = 2 * (128 * 144 + 2 * TN * 144);
    static bool attr_set = false;
    if (!attr_set) {
        cudaFuncSetAttribute(mm_h2<TN, HOUT>, cudaFuncAttributeMaxDynamicSharedMemorySize, SM);
        attr_set = true;
    }
    dim3 g(N / TN, M / 128, Z);
    mm_h2<TN, HOUT><<<g, NT, SM>>>(Ah, Bh, Bl, bias, C, Ch, Cl,
                                   K, lda, ldb, ldc,
                                   sAo, sAi, sBo, sBi, sCo, sCi, zdiv, alpha, relu);
}

extern "C" void kernel_launch(void* const* d_in, const int* in_sizes, int n_in,
                              void* d_out, int out_size)
{
    const int*   SRC   = (const int*)  d_in[0];
    const float* EMB   = (const float*)d_in[1];
    const float* PE    = (const float*)d_in[2];
    const float* IN_W  = (const float*)d_in[3];
    const float* IN_B  = (const float*)d_in[4];
    const float* OUT_W = (const float*)d_in[5];
    const float* OUT_B = (const float*)d_in[6];
    const float* QP_W  = (const float*)d_in[7];
    const float* QP_B  = (const float*)d_in[8];
    const float* KP_W  = (const float*)d_in[9];
    const float* KP_B  = (const float*)d_in[10];
    const float* VP_W  = (const float*)d_in[11];
    const float* VP_B  = (const float*)d_in[12];
    const float* LAM   = (const float*)d_in[13];
    const float* FF1_W = (const float*)d_in[14];
    const float* FF1_B = (const float*)d_in[15];
    const float* FF2_W = (const float*)d_in[16];
    const float* FF2_B = (const float*)d_in[17];
    const float* LN1S  = (const float*)d_in[18];
    const float* LN1B  = (const float*)d_in[19];
    const float* LN2S  = (const float*)d_in[20];
    const float* LN2B  = (const float*)d_in[21];
    const float* FIN_W = (const float*)d_in[22];
    const float* FIN_B = (const float*)d_in[23];
    float* OUT = (float*)d_out;

    float *x, *scores, *aproj, *sp, *fft, *pb;
    cudaGetSymbolAddress((void**)&x, g_x);
    cudaGetSymbolAddress((void**)&scores, g_scores); cudaGetSymbolAddress((void**)&aproj, g_aproj);
    cudaGetSymbolAddress((void**)&sp, g_sparse);   cudaGetSymbolAddress((void**)&fft, g_fft);
    cudaGetSymbolAddress((void**)&pb, g_pb);

    u16 *pxh, *pxl, *xh, *dh, *fh, *fl, *vth, *vtl;
    u16 *sph, *vsth, *vstl, *xh2;
    cudaGetSymbolAddress((void**)&pxh, g_pxh); cudaGetSymbolAddress((void**)&pxl, g_pxl);
    cudaGetSymbolAddress((void**)&xh, g_xh);
    cudaGetSymbolAddress((void**)&dh, g_dh);
    cudaGetSymbolAddress((void**)&fh, g_fh);   cudaGetSymbolAddress((void**)&fl, g_fl);
    cudaGetSymbolAddress((void**)&vth, g_vth); cudaGetSymbolAddress((void**)&vtl, g_vtl);
    cudaGetSymbolAddress((void**)&sph, g_sph);
    cudaGetSymbolAddress((void**)&vsth, g_vsth); cudaGetSymbolAddress((void**)&vstl, g_vstl);
    cudaGetSymbolAddress((void**)&xh2, g_xh2);

    u16 *pwh, *pwl, *outwh, *outwl, *f1wh, *f1wl, *f2wh, *f2wl, *finh2, *finl2;
    cudaGetSymbolAddress((void**)&pwh, g_pwh);     cudaGetSymbolAddress((void**)&pwl, g_pwl);
    cudaGetSymbolAddress((void**)&outwh, g_outwh); cudaGetSymbolAddress((void**)&outwl, g_outwl);
    cudaGetSymbolAddress((void**)&f1wh, g_f1wh);   cudaGetSymbolAddress((void**)&f1wl, g_f1wl);
    cudaGetSymbolAddress((void**)&f2wh, g_f2wh);   cudaGetSymbolAddress((void**)&f2wl, g_f2wl);
    cudaGetSymbolAddress((void**)&finh2, g_finh2); cudaGetSymbolAddress((void**)&finl2, g_finl2);

    // launch 1: embedding
    embed_k<<<TOKENS, 256>>>(SRC, EMB, PE, x, xh2);

    // launch 2: packed weights + bias (fp16)
    {
        int tot = LAYERS * NPACK * (DIM / 4);
        cvt_pack_k<<<(tot + 255) / 256, 256>>>(IN_W, QP_W, KP_W, VP_W,
                                               IN_B, QP_B, KP_B, VP_B,
                                               (ushort4*)pwh, (ushort4*)pwl, pb);
    }
    // launch 3: remaining weights (fp16 except FF2_W)
    {
        int n1 = LAYERS * DIM * DIM / 4, n2 = LAYERS * FFD * DIM / 4;
        int n3 = LAYERS * DIM * FFD / 4, n4 = VOCAB * DIM / 4;
        cvt4_k<<<(n1 + n2 + n3 + n4 + 255) / 256, 256>>>(
            (const float4*)OUT_W, (ushort4*)outwh, (ushort4*)outwl, n1,
            (const float4*)FF1_W, (ushort4*)f1wh, (ushort4*)f1wl, n2,
            (const float4*)FF2_W, (ushort4*)f2wh, (ushort4*)f2wl, n3,
            (const float4*)FIN_W, (ushort4*)finh2, (ushort4*)finl2, n4);
    }

    {
        constexpr int FSM = 256 * 144 + 2 * 4 * 64 * 144;  // Qh + 2 KV stages
        cudaFuncSetAttribute(fattn, cudaFuncAttributeMaxDynamicSharedMemorySize, FSM);
    }

    for (int l = 0; l < LAYERS; l++) {
        long wq  = (long)l * NPACK * DIM;
        long wo  = (long)l * DIM * DIM;
        long wf1 = (long)l * FFD * DIM;
        long wf2 = (long)l * DIM * FFD;

        // launch 4 (layer 0): packed projections (fp16 2-pass) -> px fp16 planes  [PROFILED]
        launch_h2<256, true>(xh2, pwh + wq, pwl + wq, pb + (long)l * NPACK,
                             nullptr, pxh, pxl, TOKENS, NPACK, DIM, DIM, DIM, NPACK);

        // V^T planes for dense attention (fp16)
        vt_k<<<dim3(SEQ / 32, HDIM / 32, 16), dim3(32, 8)>>>(pxh, pxl, vth, vtl);

        // fused flash attention -> dh (fp16)
        {
            constexpr int FSM = 256 * 144 + 2 * 4 * 64 * 144;
            fattn<<<dim3(SEQ / 256, 16), 512, FSM>>>(pxh, pxl, vth, vtl, dh);
        }

        // dense projection (fp16 2-pass) -> aproj fp32
        launch_h2<128>(dh, outwh + wo, outwl + wo, OUT_B + (long)l * DIM,
                       aproj, nullptr, nullptr, TOKENS, DIM, DIM, DIM, DIM, DIM);

        // low-rank logits qk = Qs_h @ (Ks_h+Ks_l)^T / sqrt(R) per batch (fp16 2-pass)
        launch_h2<256>(pxh + COL_QS, pxh + COL_KS, pxl + COL_KS, nullptr,
                       scores, nullptr, nullptr,
                       SEQ, SEQ, RANK, NPACK, NPACK, SEQ,
                       2, (long)SEQ * NPACK, 0, (long)SEQ * NPACK, 0,
                       (long)SEQ * SEQ, 0, 1, 0.125f, 0);

        sparse_sel<<<TOKENS, 256>>>(scores, sph);

        vst_k<<<dim3(SEQ / 32, DIM / 32, 2), dim3(32, 8)>>>(pxh, pxl, vsth, vstl);

        // sparse = sp @ Vs per batch (fp16 2-pass)
        launch_h2<128>(sph, vsth, vstl, nullptr, sp, nullptr, nullptr,
                       SEQ, DIM, SEQ, SEQ, SEQ, DIM,
                       2, (long)SEQ * SEQ, 0, (long)DIM * SEQ, 0,
                       (long)SEQ * DIM, 0, 1, 1.f, 0);

        fuse_ln1_k<<<TOKENS, 256>>>(x, aproj, sp, LAM, l,
                                    LN1S + (long)l * DIM, LN1B + (long)l * DIM, xh);

        // FFN1 (fp16 2-pass) -> bf16 planes for FFN2
        launch_h2<256>(xh, f1wh + wf1, f1wl + wf1, FF1_B + (long)l * FFD,
                       nullptr, fh, fl, TOKENS, FFD, DIM, DIM, DIM, FFD,
                       1, 0, 0, 0, 0, 0, 0, 1, 1.f, 1);
        // FFN2 (bf16x3, writes residual)
        launch_tc<128>(fh, fl, f2wh + wf2, f2wl + wf2, FF2_B + (long)l * DIM,
                       fft, nullptr, nullptr, TOKENS, DIM, FFD, FFD, FFD, DIM);

        add_ln2_k<<<TOKENS, 256>>>(x, fft, LN2S + (long)l * DIM, LN2B + (long)l * DIM, xh2);
    }

    // final vocab projection (fp16 2-pass)
    launch_h2<256>(xh2, finh2, finl2, FIN_B, OUT, nullptr, nullptr,
                   TOKENS, VOCAB, DIM, DIM, DIM, VOCAB);
}